// round 1
// baseline (speedup 1.0000x reference)
#include <cuda_runtime.h>
#include <math.h>

#define BV 2
#define LV 3073
#define EV 768
#define HH 12
#define DHv 64
#define ML (BV*LV)          // 6146 rows
#define NP 3072             // patches per batch

// ---------------- scratch (device globals; no allocations allowed) ----------
__device__ float g_h  [(size_t)ML*EV];
__device__ float g_hn [(size_t)ML*EV];
__device__ float g_q  [(size_t)ML*EV];
__device__ float g_k  [(size_t)ML*EV];
__device__ float g_v  [(size_t)ML*EV];
__device__ float g_a  [(size_t)ML*EV];
__device__ float g_m1 [(size_t)ML*3072];
__device__ float g_col[(size_t)BV*NP*1024];
__device__ float g_S  [(size_t)120*768*768];   // max units (branch 0) * 768*768
__device__ float g_obr[(size_t)288*768*64];    // all branches' per-unit outputs
__device__ float g_lse[(size_t)288*768];

// ---------------- helpers ----------------------------------------------------
__device__ __forceinline__ float geluf(float v) {
    return 0.5f * v * (1.f + erff(v * 0.70710678118654752f));
}
__device__ __forceinline__ float warpMax(float v) {
    #pragma unroll
    for (int o = 16; o; o >>= 1) v = fmaxf(v, __shfl_xor_sync(0xffffffffu, v, o));
    return v;
}
__device__ __forceinline__ float warpSum(float v) {
    #pragma unroll
    for (int o = 16; o; o >>= 1) v += __shfl_xor_sync(0xffffffffu, v, o);
    return v;
}

// ---------------- im2col for 3D patch embed ---------------------------------
__global__ void im2col_kernel(const float* __restrict__ x) {
    int idx = blockIdx.x * 256 + threadIdx.x;
    if (idx >= BV * NP * 1024) return;
    int kk = idx & 1023;
    int p  = (idx >> 10) % NP;
    int b  = (idx >> 10) / NP;
    int pw_ = kk & 15, ph_ = (kk >> 4) & 15, pd_ = kk >> 8;     // (pd,ph,pw) = (4,16,16)
    int bz = p & 15, by = (p >> 4) & 15, bx = p >> 8;           // (12,16,16)
    g_col[idx] = x[(((size_t)b * 48 + bx * 4 + pd_) * 256 + by * 16 + ph_) * 256 + bz * 16 + pw_];
}

// ---------------- generic tiled SGEMM ----------------------------------------
// C[M,N] = act( A[M,K] @ B + bias ) + res   ; transB: B is (N,K) row-major
__global__ void sgemm_kernel(const float* __restrict__ A, const float* __restrict__ Bm,
                             const float* __restrict__ bias, const float* __restrict__ res,
                             float* __restrict__ C,
                             int M, int N, int K, int transB, int act)
{
    __shared__ float As[16][64];
    __shared__ float Bs[16][68];
    int tid = threadIdx.x;
    int m0 = blockIdx.x * 64, n0 = blockIdx.y * 64;
    int tx = tid & 15, ty = tid >> 4;
    float acc[4][4] = {};
    for (int k0 = 0; k0 < K; k0 += 16) {
        #pragma unroll
        for (int it = 0; it < 4; ++it) {
            int l = it * 256 + tid;
            int i = l >> 4, kk = l & 15;
            int m = m0 + i;
            As[kk][i] = (m < M) ? A[(size_t)m * K + k0 + kk] : 0.f;
        }
        if (!transB) {
            #pragma unroll
            for (int it = 0; it < 4; ++it) {
                int l = it * 256 + tid;
                int nn = l & 63, kk = l >> 6;
                int n = n0 + nn;
                Bs[kk][nn] = (n < N) ? Bm[(size_t)(k0 + kk) * N + n] : 0.f;
            }
        } else {
            #pragma unroll
            for (int it = 0; it < 4; ++it) {
                int l = it * 256 + tid;
                int kk = l & 15, nn = l >> 4;
                int n = n0 + nn;
                Bs[kk][nn] = (n < N) ? Bm[(size_t)n * K + k0 + kk] : 0.f;
            }
        }
        __syncthreads();
        #pragma unroll
        for (int kk = 0; kk < 16; ++kk) {
            float av[4], bv[4];
            #pragma unroll
            for (int i = 0; i < 4; ++i) av[i] = As[kk][ty * 4 + i];
            #pragma unroll
            for (int j = 0; j < 4; ++j) bv[j] = Bs[kk][tx * 4 + j];
            #pragma unroll
            for (int i = 0; i < 4; ++i)
                #pragma unroll
                for (int j = 0; j < 4; ++j) acc[i][j] = fmaf(av[i], bv[j], acc[i][j]);
        }
        __syncthreads();
    }
    #pragma unroll
    for (int i = 0; i < 4; ++i) {
        int m = m0 + ty * 4 + i;
        if (m >= M) continue;
        #pragma unroll
        for (int j = 0; j < 4; ++j) {
            int n = n0 + tx * 4 + j;
            if (n >= N) continue;
            float c = acc[i][j] + (bias ? bias[n] : 0.f);
            if (act == 1) c = geluf(c);
            if (res) c += res[(size_t)m * N + n];
            C[(size_t)m * N + n] = c;
        }
    }
}

// ---------------- assemble h = [cls+pos0 ; tok+pos1:] ------------------------
__global__ void assemble_kernel(const float* __restrict__ cls, const float* __restrict__ pos) {
    size_t idx = (size_t)blockIdx.x * 256 + threadIdx.x;
    if (idx >= (size_t)ML * EV) return;
    int e = idx % EV;
    size_t t = idx / EV;
    int l = (int)(t % LV);
    int b = (int)(t / LV);
    float v;
    if (l == 0) v = cls[e] + pos[e];
    else        v = g_hn[((size_t)b * NP + (l - 1)) * EV + e] + pos[(size_t)l * EV + e];
    g_h[idx] = v;
}

// ---------------- layernorm ---------------------------------------------------
__global__ void layernorm_kernel(const float* __restrict__ x, const float* __restrict__ g,
                                 const float* __restrict__ bta, float* __restrict__ y)
{
    int row = blockIdx.x;
    const float* xr = x + (size_t)row * EV;
    int tid = threadIdx.x;
    float v0 = xr[tid], v1 = xr[tid + 256], v2 = xr[tid + 512];
    float s = v0 + v1 + v2;
    float s2 = v0 * v0 + v1 * v1 + v2 * v2;
    __shared__ float shA[8], shB[8];
    float ws = warpSum(s), ws2 = warpSum(s2);
    int lane = tid & 31, wid = tid >> 5;
    if (lane == 0) { shA[wid] = ws; shB[wid] = ws2; }
    __syncthreads();
    if (tid == 0) {
        float a = 0, bb = 0;
        #pragma unroll
        for (int i = 0; i < 8; ++i) { a += shA[i]; bb += shB[i]; }
        shA[0] = a; shB[0] = bb;
    }
    __syncthreads();
    float mu = shA[0] * (1.f / 768.f);
    float var = shB[0] * (1.f / 768.f) - mu * mu;
    float inv = rsqrtf(var + 1e-5f);
    float* yr = y + (size_t)row * EV;
    yr[tid      ] = (v0 - mu) * inv * g[tid      ] + bta[tid      ];
    yr[tid + 256] = (v1 - mu) * inv * g[tid + 256] + bta[tid + 256];
    yr[tid + 512] = (v2 - mu) * inv * g[tid + 512] + bta[tid + 512];
}

// ---------------- dilated attention: scores S = QK^T / 8 ---------------------
__global__ void scores_kernel(const float* __restrict__ q, const float* __restrict__ kmat,
                              int w, int r, int gsz, int n)
{
    __shared__ float Qs[64][65];
    __shared__ float Ks[64][65];
    int z = blockIdx.z;
    int h = z % HH;
    int seg = (z / HH) % n;
    int b = z / (HH * n);
    int off = h / gsz;
    int tid = threadIdx.x;
    int qbase = blockIdx.x * 64, kbase = blockIdx.y * 64;
    #pragma unroll
    for (int it = 0; it < 16; ++it) {
        int l = it * 256 + tid;
        int d = l & 63, i = l >> 6;
        int posq = seg * w + (qbase + i) * r + off;
        Qs[i][d] = (posq < LV) ? q[((size_t)(b * LV + posq)) * EV + h * DHv + d] : 0.f;
        int posk = seg * w + (kbase + i) * r + off;
        Ks[i][d] = (posk < LV) ? kmat[((size_t)(b * LV + posk)) * EV + h * DHv + d] : 0.f;
    }
    __syncthreads();
    int tx = tid & 15, ty = tid >> 4;
    float acc[4][4] = {};
    #pragma unroll
    for (int kk = 0; kk < 64; ++kk) {
        float av[4], bv[4];
        #pragma unroll
        for (int i = 0; i < 4; ++i) av[i] = Qs[ty * 4 + i][kk];
        #pragma unroll
        for (int j = 0; j < 4; ++j) bv[j] = Ks[tx * 4 + j][kk];
        #pragma unroll
        for (int i = 0; i < 4; ++i)
            #pragma unroll
            for (int j = 0; j < 4; ++j) acc[i][j] = fmaf(av[i], bv[j], acc[i][j]);
    }
    float* Sp = g_S + (size_t)z * 589824;
    #pragma unroll
    for (int i = 0; i < 4; ++i) {
        int rowq = qbase + ty * 4 + i;
        #pragma unroll
        for (int j = 0; j < 4; ++j)
            Sp[(size_t)rowq * 768 + kbase + tx * 4 + j] = acc[i][j] * 0.125f;
    }
}

// ---------------- softmax over each row of S + lse ---------------------------
__global__ void softmax_kernel(int lseBase)
{
    int row = blockIdx.x;
    float* sr = g_S + (size_t)row * 768;
    int tid = threadIdx.x;
    float v0 = sr[tid], v1 = sr[tid + 256], v2 = sr[tid + 512];
    float mx = fmaxf(v0, fmaxf(v1, v2));
    __shared__ float shA[8], shB[8];
    mx = warpMax(mx);
    int lane = tid & 31, wid = tid >> 5;
    if (lane == 0) shA[wid] = mx;
    __syncthreads();
    if (tid == 0) {
        float m = shA[0];
        #pragma unroll
        for (int i = 1; i < 8; ++i) m = fmaxf(m, shA[i]);
        shA[0] = m;
    }
    __syncthreads();
    mx = shA[0];
    float e0 = expf(v0 - mx), e1 = expf(v1 - mx), e2 = expf(v2 - mx);
    float s = warpSum(e0 + e1 + e2);
    if (lane == 0) shB[wid] = s;
    __syncthreads();
    if (tid == 0) {
        float a = 0;
        #pragma unroll
        for (int i = 0; i < 8; ++i) a += shB[i];
        shB[0] = a;
    }
    __syncthreads();
    s = shB[0];
    float inv = 1.f / s;
    sr[tid] = e0 * inv; sr[tid + 256] = e1 * inv; sr[tid + 512] = e2 * inv;
    if (tid == 0) g_lse[(size_t)lseBase * 768 + row] = mx + logf(s);
}

// ---------------- O = P @ V (gathered) ----------------------------------------
__global__ void pv_kernel(const float* __restrict__ vmat, int w, int r, int gsz, int n, int ub)
{
    __shared__ float Ps[64][65];
    __shared__ float Vs[64][65];
    int z = blockIdx.z;
    int h = z % HH;
    int seg = (z / HH) % n;
    int b = z / (HH * n);
    int off = h / gsz;
    int tid = threadIdx.x;
    int qbase = blockIdx.x * 64;
    const float* Sp = g_S + (size_t)z * 589824;
    int tx = tid & 15, ty = tid >> 4;
    float acc[4][4] = {};
    for (int kt = 0; kt < 12; ++kt) {
        #pragma unroll
        for (int it = 0; it < 16; ++it) {
            int l = it * 256 + tid;
            int c = l & 63, i = l >> 6;
            Ps[i][c] = Sp[(size_t)(qbase + i) * 768 + kt * 64 + c];
            int pos = seg * w + (kt * 64 + i) * r + off;
            Vs[i][c] = (pos < LV) ? vmat[((size_t)(b * LV + pos)) * EV + h * DHv + c] : 0.f;
        }
        __syncthreads();
        #pragma unroll
        for (int kk = 0; kk < 64; ++kk) {
            float av[4], bv[4];
            #pragma unroll
            for (int i = 0; i < 4; ++i) av[i] = Ps[ty * 4 + i][kk];
            #pragma unroll
            for (int j = 0; j < 4; ++j) bv[j] = Vs[kk][tx * 4 + j];
            #pragma unroll
            for (int i = 0; i < 4; ++i)
                #pragma unroll
                for (int j = 0; j < 4; ++j) acc[i][j] = fmaf(av[i], bv[j], acc[i][j]);
        }
        __syncthreads();
    }
    float* Op = g_obr + (size_t)(ub + z) * 49152;
    #pragma unroll
    for (int i = 0; i < 4; ++i) {
        int rowq = qbase + ty * 4 + i;
        #pragma unroll
        for (int j = 0; j < 4; ++j)
            Op[(size_t)rowq * 64 + tx * 4 + j] = acc[i][j];
    }
}

// ---------------- branch recombination (softmax over branch lse) -------------
__global__ void combine_kernel()
{
    int blk = blockIdx.x;
    int h = blk % HH;
    int p = (blk / HH) % LV;
    int b = blk / (HH * LV);
    int d = threadIdx.x;
    const int ws[5] = {768, 1536, 3072, 6144, 12288};
    const int rs[5] = {1, 2, 4, 8, 16};
    const int gs[5] = {12, 6, 3, 2, 1};
    const int ns[5] = {5, 3, 2, 1, 1};
    const int ub[5] = {0, 120, 192, 240, 264};
    float lses[5];
    size_t oix[5];
    bool cov[5];
    float mx = -1e30f;
    #pragma unroll
    for (int br = 0; br < 5; ++br) {
        int seg = p / ws[br];
        int jj = p - seg * ws[br];
        int off = h / gs[br];
        int rr = jj & (rs[br] - 1);
        cov[br] = (rr == off);
        if (cov[br]) {
            int j = jj / rs[br];
            int unit = ub[br] + (b * ns[br] + seg) * HH + h;
            lses[br] = g_lse[(size_t)unit * 768 + j];
            oix[br] = (size_t)unit * 49152 + (size_t)j * 64;
            mx = fmaxf(mx, lses[br]);
        }
    }
    float sw = 0.f, out = 0.f;
    #pragma unroll
    for (int br = 0; br < 5; ++br) {
        if (cov[br]) {
            float wgt = expf(lses[br] - mx);
            sw += wgt;
            out += wgt * g_obr[oix[br] + d];
        }
    }
    g_a[((size_t)(b * LV + p)) * EV + h * DHv + d] = out / sw;
}

// ---------------- classification head ----------------------------------------
__global__ void head_kernel(const float* __restrict__ hn, const float* __restrict__ W,
                            const float* __restrict__ bias, float* __restrict__ out)
{
    int nidx = blockIdx.x * blockDim.x + threadIdx.x;
    int b = blockIdx.y;
    if (nidx >= 1000) return;
    const float* row = hn + (size_t)b * LV * EV;   // token 0 (cls)
    float acc = bias[nidx];
    for (int e = 0; e < EV; ++e) acc = fmaf(row[e], W[(size_t)e * 1000 + nidx], acc);
    out[b * 1000 + nidx] = acc;
}

// ---------------- host orchestration ------------------------------------------
extern "C" void kernel_launch(void* const* d_in, const int* in_sizes, int n_in,
                              void* d_out, int out_size)
{
    (void)in_sizes; (void)n_in; (void)out_size;
    const float* x        = (const float*)d_in[0];
    const float* patch_w  = (const float*)d_in[1];
    const float* patch_b  = (const float*)d_in[2];
    const float* cls_tok  = (const float*)d_in[3];
    const float* pos_emb  = (const float*)d_in[4];
    const float* ln1_g    = (const float*)d_in[5];
    const float* ln1_b    = (const float*)d_in[6];
    const float* wq       = (const float*)d_in[7];
    const float* bq       = (const float*)d_in[8];
    const float* wk       = (const float*)d_in[9];
    const float* bk       = (const float*)d_in[10];
    const float* wv       = (const float*)d_in[11];
    const float* bv_      = (const float*)d_in[12];
    const float* wo       = (const float*)d_in[13];
    const float* bo       = (const float*)d_in[14];
    const float* ln2_g    = (const float*)d_in[15];
    const float* ln2_b    = (const float*)d_in[16];
    const float* w1       = (const float*)d_in[17];
    const float* b1       = (const float*)d_in[18];
    const float* w2       = (const float*)d_in[19];
    const float* b2       = (const float*)d_in[20];
    const float* normf_g  = (const float*)d_in[21];
    const float* normf_b  = (const float*)d_in[22];
    const float* head_w   = (const float*)d_in[23];
    const float* head_b   = (const float*)d_in[24];
    float* out = (float*)d_out;

    float *p_h, *p_hn, *p_q, *p_k, *p_v, *p_a, *p_m1, *p_col;
    cudaGetSymbolAddress((void**)&p_h, g_h);
    cudaGetSymbolAddress((void**)&p_hn, g_hn);
    cudaGetSymbolAddress((void**)&p_q, g_q);
    cudaGetSymbolAddress((void**)&p_k, g_k);
    cudaGetSymbolAddress((void**)&p_v, g_v);
    cudaGetSymbolAddress((void**)&p_a, g_a);
    cudaGetSymbolAddress((void**)&p_m1, g_m1);
    cudaGetSymbolAddress((void**)&p_col, g_col);

    const int ws[5] = {768, 1536, 3072, 6144, 12288};
    const int rs[5] = {1, 2, 4, 8, 16};
    const int gs[5] = {12, 6, 3, 2, 1};
    const int ns[5] = {5, 3, 2, 1, 1};
    const int ub[5] = {0, 120, 192, 240, 264};

    // 1) patch embed: im2col + GEMM (A=(6144,1024), B=patch_w (768,1024) transB) -> g_hn
    im2col_kernel<<<(BV * NP * 1024 + 255) / 256, 256>>>(x);
    {
        dim3 g((BV * NP + 63) / 64, (EV + 63) / 64);
        sgemm_kernel<<<g, 256>>>(p_col, patch_w, patch_b, nullptr, p_hn,
                                 BV * NP, EV, 1024, 1, 0);
    }
    // 2) assemble h
    assemble_kernel<<<(int)(((size_t)ML * EV + 255) / 256), 256>>>(cls_tok, pos_emb);

    dim3 gEE((ML + 63) / 64, EV / 64);
    dim3 gE4((ML + 63) / 64, 3072 / 64);

    for (int layer = 0; layer < 2; ++layer) {
        size_t oEE = (size_t)layer * EV * EV;
        size_t oE  = (size_t)layer * EV;
        size_t oE4 = (size_t)layer * EV * 3072;
        size_t o4  = (size_t)layer * 3072;

        layernorm_kernel<<<ML, 256>>>(p_h, ln1_g + oE, ln1_b + oE, p_hn);
        sgemm_kernel<<<gEE, 256>>>(p_hn, wq + oEE, bq + oE, nullptr, p_q, ML, EV, EV, 0, 0);
        sgemm_kernel<<<gEE, 256>>>(p_hn, wk + oEE, bk + oE, nullptr, p_k, ML, EV, EV, 0, 0);
        sgemm_kernel<<<gEE, 256>>>(p_hn, wv + oEE, bv_ + oE, nullptr, p_v, ML, EV, EV, 0, 0);

        for (int br = 0; br < 5; ++br) {
            int units = BV * ns[br] * HH;
            dim3 gsc(12, 12, units);
            scores_kernel<<<gsc, 256>>>(p_q, p_k, ws[br], rs[br], gs[br], ns[br]);
            softmax_kernel<<<units * 768, 256>>>(ub[br]);
            dim3 gpv(12, 1, units);
            pv_kernel<<<gpv, 256>>>(p_v, ws[br], rs[br], gs[br], ns[br], ub[br]);
        }
        combine_kernel<<<BV * LV * HH, 64>>>();

        sgemm_kernel<<<gEE, 256>>>(p_a, wo + oEE, bo + oE, p_h, p_h, ML, EV, EV, 0, 0);
        layernorm_kernel<<<ML, 256>>>(p_h, ln2_g + oE, ln2_b + oE, p_hn);
        sgemm_kernel<<<gE4, 256>>>(p_hn, w1 + oE4, b1 + o4, nullptr, p_m1, ML, 3072, EV, 0, 1);
        sgemm_kernel<<<gEE, 256>>>(p_m1, w2 + oE4, b2 + oE, p_h, p_h, ML, EV, 3072, 0, 0);
    }

    layernorm_kernel<<<ML, 256>>>(p_h, normf_g, normf_b, p_hn);
    head_kernel<<<dim3(4, BV), 256>>>(p_hn, head_w, head_b, out);
}

// round 2
// speedup vs baseline: 1.7468x; 1.7468x over previous
#include <cuda_runtime.h>
#include <math.h>

#define BV 2
#define LV 3073
#define EV 768
#define HH 12
#define DHv 64
#define ML (BV*LV)          // 6146 rows
#define NP 3072             // patches per batch

// ---------------- scratch (device globals; no allocations allowed) ----------
__device__ float g_h  [(size_t)ML*EV];
__device__ float g_hn [(size_t)ML*EV];
__device__ float g_q  [(size_t)ML*EV];
__device__ float g_k  [(size_t)ML*EV];
__device__ float g_v  [(size_t)ML*EV];
__device__ float g_a  [(size_t)ML*EV];
__device__ float g_m1 [(size_t)ML*3072];
__device__ float g_col[(size_t)BV*NP*1024];
__device__ float g_S  [(size_t)120*768*768];   // max units (branch 0) * 768*768
__device__ float g_obr[(size_t)288*768*64];    // all branches' per-unit outputs
__device__ float g_lse[(size_t)288*768];

// ---------------- helpers ----------------------------------------------------
__device__ __forceinline__ float geluf(float v) {
    return 0.5f * v * (1.f + erff(v * 0.70710678118654752f));
}
__device__ __forceinline__ float warpMax(float v) {
    #pragma unroll
    for (int o = 16; o; o >>= 1) v = fmaxf(v, __shfl_xor_sync(0xffffffffu, v, o));
    return v;
}
__device__ __forceinline__ float warpSum(float v) {
    #pragma unroll
    for (int o = 16; o; o >>= 1) v += __shfl_xor_sync(0xffffffffu, v, o);
    return v;
}

// ---------------- im2col for 3D patch embed ---------------------------------
__global__ void im2col_kernel(const float* __restrict__ x) {
    int idx = blockIdx.x * 256 + threadIdx.x;
    if (idx >= BV * NP * 1024) return;
    int kk = idx & 1023;
    int p  = (idx >> 10) % NP;
    int b  = (idx >> 10) / NP;
    int pw_ = kk & 15, ph_ = (kk >> 4) & 15, pd_ = kk >> 8;
    int bz = p & 15, by = (p >> 4) & 15, bx = p >> 8;
    g_col[idx] = x[(((size_t)b * 48 + bx * 4 + pd_) * 256 + by * 16 + ph_) * 256 + bz * 16 + pw_];
}

// ---------------- 128x128x8 register-blocked SGEMM ---------------------------
// C[M,N] = act( A[M,K] @ B + bias ) + res ; TRANSB: B is (N,K) row-major
template<int TRANSB, int ACT>
__global__ void __launch_bounds__(256, 2)
sgemm128(const float* __restrict__ A, const float* __restrict__ Bm,
         const float* __restrict__ bias, const float* __restrict__ res,
         float* __restrict__ C, int M, int N, int K)
{
    __shared__ float As[2][8][128];
    __shared__ float Bs[2][8][128];
    const int tid = threadIdx.x;
    const int m0 = blockIdx.x * 128, n0 = blockIdx.y * 128;
    const int arow = tid >> 1, acol = (tid & 1) * 4;   // A (and B when TRANSB) staging
    const int bkr  = tid >> 5, bnc = (tid & 31) * 4;   // B staging when !TRANSB
    const int tx = tid & 15, ty = tid >> 4;
    const int tm = ty * 8, tn = tx * 8;

    float acc[8][8] = {};
    const int KT = K >> 3;
    float4 fa, fb;

    // prefetch tile 0
    {
        int m = m0 + arow;
        fa = (m < M) ? *(const float4*)(A + (size_t)m * K + acol) : make_float4(0,0,0,0);
        if (TRANSB) fb = *(const float4*)(Bm + (size_t)(n0 + arow) * K + acol);
        else        fb = *(const float4*)(Bm + (size_t)bkr * N + n0 + bnc);
    }
    As[0][acol+0][arow] = fa.x; As[0][acol+1][arow] = fa.y;
    As[0][acol+2][arow] = fa.z; As[0][acol+3][arow] = fa.w;
    if (TRANSB) {
        Bs[0][acol+0][arow] = fb.x; Bs[0][acol+1][arow] = fb.y;
        Bs[0][acol+2][arow] = fb.z; Bs[0][acol+3][arow] = fb.w;
    } else {
        *(float4*)&Bs[0][bkr][bnc] = fb;
    }
    __syncthreads();

    int buf = 0;
    for (int kt = 0; kt < KT; ++kt) {
        const bool more = (kt + 1 < KT);
        if (more) {
            int k0 = (kt + 1) << 3;
            int m = m0 + arow;
            fa = (m < M) ? *(const float4*)(A + (size_t)m * K + k0 + acol) : make_float4(0,0,0,0);
            if (TRANSB) fb = *(const float4*)(Bm + (size_t)(n0 + arow) * K + k0 + acol);
            else        fb = *(const float4*)(Bm + (size_t)(k0 + bkr) * N + n0 + bnc);
        }
        #pragma unroll
        for (int kk = 0; kk < 8; ++kk) {
            float4 a0 = *(const float4*)&As[buf][kk][tm];
            float4 a1 = *(const float4*)&As[buf][kk][tm + 4];
            float4 b0 = *(const float4*)&Bs[buf][kk][tn];
            float4 b1 = *(const float4*)&Bs[buf][kk][tn + 4];
            float av[8] = {a0.x,a0.y,a0.z,a0.w,a1.x,a1.y,a1.z,a1.w};
            float bvv[8] = {b0.x,b0.y,b0.z,b0.w,b1.x,b1.y,b1.z,b1.w};
            #pragma unroll
            for (int i = 0; i < 8; ++i)
                #pragma unroll
                for (int j = 0; j < 8; ++j)
                    acc[i][j] = fmaf(av[i], bvv[j], acc[i][j]);
        }
        if (more) {
            int nb = buf ^ 1;
            As[nb][acol+0][arow] = fa.x; As[nb][acol+1][arow] = fa.y;
            As[nb][acol+2][arow] = fa.z; As[nb][acol+3][arow] = fa.w;
            if (TRANSB) {
                Bs[nb][acol+0][arow] = fb.x; Bs[nb][acol+1][arow] = fb.y;
                Bs[nb][acol+2][arow] = fb.z; Bs[nb][acol+3][arow] = fb.w;
            } else {
                *(float4*)&Bs[nb][bkr][bnc] = fb;
            }
            buf = nb;
        }
        __syncthreads();
    }

    #pragma unroll
    for (int i = 0; i < 8; ++i) {
        int m = m0 + tm + i;
        if (m >= M) continue;
        float o[8];
        #pragma unroll
        for (int j = 0; j < 8; ++j) {
            float c = acc[i][j] + bias[n0 + tn + j];
            if (ACT == 1) c = geluf(c);
            if (res) c += res[(size_t)m * N + n0 + tn + j];
            o[j] = c;
        }
        *(float4*)(C + (size_t)m * N + n0 + tn)     = make_float4(o[0],o[1],o[2],o[3]);
        *(float4*)(C + (size_t)m * N + n0 + tn + 4) = make_float4(o[4],o[5],o[6],o[7]);
    }
}

// ---------------- assemble h = [cls+pos0 ; tok+pos1:] ------------------------
__global__ void assemble_kernel(const float* __restrict__ cls, const float* __restrict__ pos) {
    size_t idx = (size_t)blockIdx.x * 256 + threadIdx.x;
    if (idx >= (size_t)ML * EV) return;
    int e = idx % EV;
    size_t t = idx / EV;
    int l = (int)(t % LV);
    int b = (int)(t / LV);
    float v;
    if (l == 0) v = cls[e] + pos[e];
    else        v = g_hn[((size_t)b * NP + (l - 1)) * EV + e] + pos[(size_t)l * EV + e];
    g_h[idx] = v;
}

// ---------------- layernorm ---------------------------------------------------
__global__ void layernorm_kernel(const float* __restrict__ x, const float* __restrict__ g,
                                 const float* __restrict__ bta, float* __restrict__ y)
{
    int row = blockIdx.x;
    const float* xr = x + (size_t)row * EV;
    int tid = threadIdx.x;
    float v0 = xr[tid], v1 = xr[tid + 256], v2 = xr[tid + 512];
    float s = v0 + v1 + v2;
    float s2 = v0 * v0 + v1 * v1 + v2 * v2;
    __shared__ float shA[8], shB[8];
    float ws = warpSum(s), ws2 = warpSum(s2);
    int lane = tid & 31, wid = tid >> 5;
    if (lane == 0) { shA[wid] = ws; shB[wid] = ws2; }
    __syncthreads();
    if (tid == 0) {
        float a = 0, bb = 0;
        #pragma unroll
        for (int i = 0; i < 8; ++i) { a += shA[i]; bb += shB[i]; }
        shA[0] = a; shB[0] = bb;
    }
    __syncthreads();
    float mu = shA[0] * (1.f / 768.f);
    float var = shB[0] * (1.f / 768.f) - mu * mu;
    float inv = rsqrtf(var + 1e-5f);
    float* yr = y + (size_t)row * EV;
    yr[tid      ] = (v0 - mu) * inv * g[tid      ] + bta[tid      ];
    yr[tid + 256] = (v1 - mu) * inv * g[tid + 256] + bta[tid + 256];
    yr[tid + 512] = (v2 - mu) * inv * g[tid + 512] + bta[tid + 512];
}

// ---------------- dilated attention scores: S = QK^T / 8 (128x128 tiles) -----
__global__ void __launch_bounds__(256, 2)
scores128(const float* __restrict__ q, const float* __restrict__ kmat,
          int w, int r, int gsz, int n)
{
    __shared__ float Qs[32][128];
    __shared__ float Ks[32][128];
    int z = blockIdx.z;
    int h = z % HH;
    int seg = (z / HH) % n;
    int b = z / (HH * n);
    int off = h / gsz;
    int tid = threadIdx.x;
    int m0 = blockIdx.x * 128, n0 = blockIdx.y * 128;
    int tx = tid & 15, ty = tid >> 4;
    int tm = ty * 8, tn = tx * 8;
    float acc[8][8] = {};

    #pragma unroll
    for (int kt = 0; kt < 2; ++kt) {
        int k0 = kt * 32;
        #pragma unroll
        for (int it = 0; it < 4; ++it) {
            int l = it * 256 + tid;
            int mm = l >> 3, k4 = (l & 7) * 4;
            int posq = seg * w + (m0 + mm) * r + off;
            float4 vq = make_float4(0,0,0,0);
            if (posq < LV) vq = *(const float4*)(q + (size_t)(b * LV + posq) * EV + h * DHv + k0 + k4);
            Qs[k4+0][mm] = vq.x; Qs[k4+1][mm] = vq.y; Qs[k4+2][mm] = vq.z; Qs[k4+3][mm] = vq.w;
            int posk = seg * w + (n0 + mm) * r + off;
            float4 vk = make_float4(0,0,0,0);
            if (posk < LV) vk = *(const float4*)(kmat + (size_t)(b * LV + posk) * EV + h * DHv + k0 + k4);
            Ks[k4+0][mm] = vk.x; Ks[k4+1][mm] = vk.y; Ks[k4+2][mm] = vk.z; Ks[k4+3][mm] = vk.w;
        }
        __syncthreads();
        #pragma unroll
        for (int kk = 0; kk < 32; ++kk) {
            float4 a0 = *(const float4*)&Qs[kk][tm];
            float4 a1 = *(const float4*)&Qs[kk][tm + 4];
            float4 b0 = *(const float4*)&Ks[kk][tn];
            float4 b1 = *(const float4*)&Ks[kk][tn + 4];
            float av[8] = {a0.x,a0.y,a0.z,a0.w,a1.x,a1.y,a1.z,a1.w};
            float bvv[8] = {b0.x,b0.y,b0.z,b0.w,b1.x,b1.y,b1.z,b1.w};
            #pragma unroll
            for (int i = 0; i < 8; ++i)
                #pragma unroll
                for (int j = 0; j < 8; ++j)
                    acc[i][j] = fmaf(av[i], bvv[j], acc[i][j]);
        }
        __syncthreads();
    }

    float* Sp = g_S + (size_t)z * 589824;
    #pragma unroll
    for (int i = 0; i < 8; ++i) {
        int rowq = m0 + tm + i;
        *(float4*)(Sp + (size_t)rowq * 768 + n0 + tn) =
            make_float4(acc[i][0]*0.125f, acc[i][1]*0.125f, acc[i][2]*0.125f, acc[i][3]*0.125f);
        *(float4*)(Sp + (size_t)rowq * 768 + n0 + tn + 4) =
            make_float4(acc[i][4]*0.125f, acc[i][5]*0.125f, acc[i][6]*0.125f, acc[i][7]*0.125f);
    }
}

// ---------------- softmax over each row of S + lse ---------------------------
__global__ void softmax_kernel(int lseBase)
{
    int row = blockIdx.x;
    float* sr = g_S + (size_t)row * 768;
    int tid = threadIdx.x;
    float v0 = sr[tid], v1 = sr[tid + 256], v2 = sr[tid + 512];
    float mx = fmaxf(v0, fmaxf(v1, v2));
    __shared__ float shA[8], shB[8];
    mx = warpMax(mx);
    int lane = tid & 31, wid = tid >> 5;
    if (lane == 0) shA[wid] = mx;
    __syncthreads();
    if (tid == 0) {
        float m = shA[0];
        #pragma unroll
        for (int i = 1; i < 8; ++i) m = fmaxf(m, shA[i]);
        shA[0] = m;
    }
    __syncthreads();
    mx = shA[0];
    float e0 = expf(v0 - mx), e1 = expf(v1 - mx), e2 = expf(v2 - mx);
    float s = warpSum(e0 + e1 + e2);
    if (lane == 0) shB[wid] = s;
    __syncthreads();
    if (tid == 0) {
        float a = 0;
        #pragma unroll
        for (int i = 0; i < 8; ++i) a += shB[i];
        shB[0] = a;
    }
    __syncthreads();
    s = shB[0];
    float inv = 1.f / s;
    sr[tid] = e0 * inv; sr[tid + 256] = e1 * inv; sr[tid + 512] = e2 * inv;
    if (tid == 0) g_lse[(size_t)lseBase * 768 + row] = mx + logf(s);
}

// ---------------- O = P @ V (gathered), 128x64 tiles --------------------------
__global__ void __launch_bounds__(256, 2)
pv128(const float* __restrict__ vmat, int w, int r, int gsz, int n, int ub)
{
    __shared__ float Ps[32][128];
    __shared__ float Vs[32][64];
    int z = blockIdx.z;
    int h = z % HH;
    int seg = (z / HH) % n;
    int b = z / (HH * n);
    int off = h / gsz;
    int tid = threadIdx.x;
    int qbase = blockIdx.x * 128;
    const float* Sp = g_S + (size_t)z * 589824;
    int tx = tid & 7, ty = tid >> 3;
    int tm = ty * 4, tn = tx * 8;
    float acc[4][8] = {};

    for (int kt = 0; kt < 24; ++kt) {
        int k0 = kt * 32;
        #pragma unroll
        for (int it = 0; it < 4; ++it) {
            int l = it * 256 + tid;
            int mm = l >> 3, k4 = (l & 7) * 4;
            float4 pv4 = *(const float4*)(Sp + (size_t)(qbase + mm) * 768 + k0 + k4);
            Ps[k4+0][mm] = pv4.x; Ps[k4+1][mm] = pv4.y; Ps[k4+2][mm] = pv4.z; Ps[k4+3][mm] = pv4.w;
        }
        #pragma unroll
        for (int it = 0; it < 2; ++it) {
            int l = it * 256 + tid;
            int kk = l >> 4, d4 = (l & 15) * 4;
            int pos = seg * w + (k0 + kk) * r + off;
            float4 vv = make_float4(0,0,0,0);
            if (pos < LV) vv = *(const float4*)(vmat + (size_t)(b * LV + pos) * EV + h * DHv + d4);
            *(float4*)&Vs[kk][d4] = vv;
        }
        __syncthreads();
        #pragma unroll
        for (int kk = 0; kk < 32; ++kk) {
            float4 a = *(const float4*)&Ps[kk][tm];
            float4 b0 = *(const float4*)&Vs[kk][tn];
            float4 b1 = *(const float4*)&Vs[kk][tn + 4];
            float av[4] = {a.x,a.y,a.z,a.w};
            float bvv[8] = {b0.x,b0.y,b0.z,b0.w,b1.x,b1.y,b1.z,b1.w};
            #pragma unroll
            for (int i = 0; i < 4; ++i)
                #pragma unroll
                for (int j = 0; j < 8; ++j)
                    acc[i][j] = fmaf(av[i], bvv[j], acc[i][j]);
        }
        __syncthreads();
    }

    float* Op = g_obr + (size_t)(ub + z) * 49152;
    #pragma unroll
    for (int i = 0; i < 4; ++i) {
        int rowq = qbase + tm + i;
        *(float4*)(Op + (size_t)rowq * 64 + tn)     = make_float4(acc[i][0],acc[i][1],acc[i][2],acc[i][3]);
        *(float4*)(Op + (size_t)rowq * 64 + tn + 4) = make_float4(acc[i][4],acc[i][5],acc[i][6],acc[i][7]);
    }
}

// ---------------- branch recombination (softmax over branch lse) -------------
__global__ void combine_kernel()
{
    int blk = blockIdx.x;
    int h = blk % HH;
    int p = (blk / HH) % LV;
    int b = blk / (HH * LV);
    int d = threadIdx.x;
    const int ws[5] = {768, 1536, 3072, 6144, 12288};
    const int rs[5] = {1, 2, 4, 8, 16};
    const int gs[5] = {12, 6, 3, 2, 1};
    const int ns[5] = {5, 3, 2, 1, 1};
    const int ub[5] = {0, 120, 192, 240, 264};
    float lses[5];
    size_t oix[5];
    bool cov[5];
    float mx = -1e30f;
    #pragma unroll
    for (int br = 0; br < 5; ++br) {
        int seg = p / ws[br];
        int jj = p - seg * ws[br];
        int off = h / gs[br];
        int rr = jj & (rs[br] - 1);
        cov[br] = (rr == off);
        if (cov[br]) {
            int j = jj / rs[br];
            int unit = ub[br] + (b * ns[br] + seg) * HH + h;
            lses[br] = g_lse[(size_t)unit * 768 + j];
            oix[br] = (size_t)unit * 49152 + (size_t)j * 64;
            mx = fmaxf(mx, lses[br]);
        }
    }
    float sw = 0.f, out = 0.f;
    #pragma unroll
    for (int br = 0; br < 5; ++br) {
        if (cov[br]) {
            float wgt = expf(lses[br] - mx);
            sw += wgt;
            out += wgt * g_obr[oix[br] + d];
        }
    }
    g_a[((size_t)(b * LV + p)) * EV + h * DHv + d] = out / sw;
}

// ---------------- classification head ----------------------------------------
__global__ void head_kernel(const float* __restrict__ hn, const float* __restrict__ W,
                            const float* __restrict__ bias, float* __restrict__ out)
{
    int nidx = blockIdx.x * blockDim.x + threadIdx.x;
    int b = blockIdx.y;
    if (nidx >= 1000) return;
    const float* row = hn + (size_t)b * LV * EV;   // token 0 (cls)
    float acc = bias[nidx];
    for (int e = 0; e < EV; ++e) acc = fmaf(row[e], W[(size_t)e * 1000 + nidx], acc);
    out[b * 1000 + nidx] = acc;
}

// ---------------- host orchestration ------------------------------------------
extern "C" void kernel_launch(void* const* d_in, const int* in_sizes, int n_in,
                              void* d_out, int out_size)
{
    (void)in_sizes; (void)n_in; (void)out_size;
    const float* x        = (const float*)d_in[0];
    const float* patch_w  = (const float*)d_in[1];
    const float* patch_b  = (const float*)d_in[2];
    const float* cls_tok  = (const float*)d_in[3];
    const float* pos_emb  = (const float*)d_in[4];
    const float* ln1_g    = (const float*)d_in[5];
    const float* ln1_b    = (const float*)d_in[6];
    const float* wq       = (const float*)d_in[7];
    const float* bq       = (const float*)d_in[8];
    const float* wk       = (const float*)d_in[9];
    const float* bk       = (const float*)d_in[10];
    const float* wv       = (const float*)d_in[11];
    const float* bv_      = (const float*)d_in[12];
    const float* wo       = (const float*)d_in[13];
    const float* bo       = (const float*)d_in[14];
    const float* ln2_g    = (const float*)d_in[15];
    const float* ln2_b    = (const float*)d_in[16];
    const float* w1       = (const float*)d_in[17];
    const float* b1       = (const float*)d_in[18];
    const float* w2       = (const float*)d_in[19];
    const float* b2       = (const float*)d_in[20];
    const float* normf_g  = (const float*)d_in[21];
    const float* normf_b  = (const float*)d_in[22];
    const float* head_w   = (const float*)d_in[23];
    const float* head_b   = (const float*)d_in[24];
    float* out = (float*)d_out;

    float *p_h, *p_hn, *p_q, *p_k, *p_v, *p_a, *p_m1, *p_col;
    cudaGetSymbolAddress((void**)&p_h, g_h);
    cudaGetSymbolAddress((void**)&p_hn, g_hn);
    cudaGetSymbolAddress((void**)&p_q, g_q);
    cudaGetSymbolAddress((void**)&p_k, g_k);
    cudaGetSymbolAddress((void**)&p_v, g_v);
    cudaGetSymbolAddress((void**)&p_a, g_a);
    cudaGetSymbolAddress((void**)&p_m1, g_m1);
    cudaGetSymbolAddress((void**)&p_col, g_col);

    const int ws[5] = {768, 1536, 3072, 6144, 12288};
    const int rs[5] = {1, 2, 4, 8, 16};
    const int gs[5] = {12, 6, 3, 2, 1};
    const int ns[5] = {5, 3, 2, 1, 1};
    const int ub[5] = {0, 120, 192, 240, 264};

    // 1) patch embed: im2col + GEMM
    im2col_kernel<<<(BV * NP * 1024 + 255) / 256, 256>>>(x);
    {
        dim3 g((BV * NP + 127) / 128, EV / 128);
        sgemm128<1,0><<<g, 256>>>(p_col, patch_w, patch_b, nullptr, p_hn, BV * NP, EV, 1024);
    }
    // 2) assemble h
    assemble_kernel<<<(int)(((size_t)ML * EV + 255) / 256), 256>>>(cls_tok, pos_emb);

    dim3 gEE((ML + 127) / 128, EV / 128);
    dim3 gE4((ML + 127) / 128, 3072 / 128);

    for (int layer = 0; layer < 2; ++layer) {
        size_t oEE = (size_t)layer * EV * EV;
        size_t oE  = (size_t)layer * EV;
        size_t oE4 = (size_t)layer * EV * 3072;
        size_t o4  = (size_t)layer * 3072;

        layernorm_kernel<<<ML, 256>>>(p_h, ln1_g + oE, ln1_b + oE, p_hn);
        sgemm128<0,0><<<gEE, 256>>>(p_hn, wq + oEE, bq + oE, nullptr, p_q, ML, EV, EV);
        sgemm128<0,0><<<gEE, 256>>>(p_hn, wk + oEE, bk + oE, nullptr, p_k, ML, EV, EV);
        sgemm128<0,0><<<gEE, 256>>>(p_hn, wv + oEE, bv_ + oE, nullptr, p_v, ML, EV, EV);

        for (int br = 0; br < 5; ++br) {
            int units = BV * ns[br] * HH;
            dim3 gsc(6, 6, units);
            scores128<<<gsc, 256>>>(p_q, p_k, ws[br], rs[br], gs[br], ns[br]);
            softmax_kernel<<<units * 768, 256>>>(ub[br]);
            dim3 gpv(6, 1, units);
            pv128<<<gpv, 256>>>(p_v, ws[br], rs[br], gs[br], ns[br], ub[br]);
        }
        combine_kernel<<<BV * LV * HH, 64>>>();

        sgemm128<0,0><<<gEE, 256>>>(p_a, wo + oEE, bo + oE, p_h, p_h, ML, EV, EV);
        layernorm_kernel<<<ML, 256>>>(p_h, ln2_g + oE, ln2_b + oE, p_hn);
        sgemm128<0,1><<<gE4, 256>>>(p_hn, w1 + oE4, b1 + o4, nullptr, p_m1, ML, 3072, EV);
        sgemm128<0,0><<<gEE, 256>>>(p_m1, w2 + oE4, b2 + oE, p_h, p_h, ML, EV, 3072);
    }

    layernorm_kernel<<<ML, 256>>>(p_h, normf_g, normf_b, p_hn);
    head_kernel<<<dim3(4, BV), 256>>>(p_hn, head_w, head_b, out);
}

// round 3
// speedup vs baseline: 1.7614x; 1.0084x over previous
#include <cuda_runtime.h>
#include <math.h>

#define BV 2
#define LV 3073
#define EV 768
#define HH 12
#define DHv 64
#define ML (BV*LV)          // 6146 rows
#define NP 3072             // patches per batch

// ---------------- scratch (device globals; no allocations allowed) ----------
__device__ float g_h  [(size_t)ML*EV];
__device__ float g_hn [(size_t)ML*EV];
__device__ float g_q  [(size_t)ML*EV];
__device__ float g_k  [(size_t)ML*EV];
__device__ float g_v  [(size_t)ML*EV];
__device__ float g_a  [(size_t)ML*EV];
__device__ float g_m1 [(size_t)ML*3072];
__device__ float g_col[(size_t)BV*NP*1024];
__device__ float g_S  [(size_t)120*768*768];   // max units (branch 0) * 768*768
__device__ float g_obr[(size_t)288*768*64];    // all branches' per-unit outputs
__device__ float g_lse[(size_t)288*768];

// ---------------- f32x2 packed-FMA helpers (Blackwell FFMA2) -----------------
__device__ __forceinline__ unsigned long long pk2(float lo, float hi) {
    unsigned long long r;
    asm("mov.b64 %0, {%1, %2};" : "=l"(r) : "r"(__float_as_uint(lo)), "r"(__float_as_uint(hi)));
    return r;
}
__device__ __forceinline__ void upk2(unsigned long long v, float& lo, float& hi) {
    unsigned int a, b;
    asm("mov.b64 {%0, %1}, %2;" : "=r"(a), "=r"(b) : "l"(v));
    lo = __uint_as_float(a); hi = __uint_as_float(b);
}
__device__ __forceinline__ void ffma2(unsigned long long& c, unsigned long long a, unsigned long long b) {
    asm("fma.rn.f32x2 %0, %1, %2, %0;" : "+l"(c) : "l"(a), "l"(b));
}

// ---------------- helpers ----------------------------------------------------
__device__ __forceinline__ float geluf(float v) {
    return 0.5f * v * (1.f + erff(v * 0.70710678118654752f));
}
__device__ __forceinline__ float warpMax(float v) {
    #pragma unroll
    for (int o = 16; o; o >>= 1) v = fmaxf(v, __shfl_xor_sync(0xffffffffu, v, o));
    return v;
}
__device__ __forceinline__ float warpSum(float v) {
    #pragma unroll
    for (int o = 16; o; o >>= 1) v += __shfl_xor_sync(0xffffffffu, v, o);
    return v;
}

// ---------------- im2col for 3D patch embed ---------------------------------
__global__ void im2col_kernel(const float* __restrict__ x) {
    int idx = blockIdx.x * 256 + threadIdx.x;
    if (idx >= BV * NP * 1024) return;
    int kk = idx & 1023;
    int p  = (idx >> 10) % NP;
    int b  = (idx >> 10) / NP;
    int pw_ = kk & 15, ph_ = (kk >> 4) & 15, pd_ = kk >> 8;
    int bz = p & 15, by = (p >> 4) & 15, bx = p >> 8;
    g_col[idx] = x[(((size_t)b * 48 + bx * 4 + pd_) * 256 + by * 16 + ph_) * 256 + bz * 16 + pw_];
}

// ---------------- 128x128x8 register-blocked SGEMM (f32x2 core) --------------
// C[M,N] = act( A[M,K] @ B + bias ) + res ; TRANSB: B is (N,K) row-major
template<int TRANSB, int ACT>
__global__ void __launch_bounds__(256, 2)
sgemm128(const float* __restrict__ A, const float* __restrict__ Bm,
         const float* __restrict__ bias, const float* __restrict__ res,
         float* __restrict__ C, int M, int N, int K)
{
    __shared__ float As[2][8][128];
    __shared__ float Bs[2][8][128];
    const int tid = threadIdx.x;
    const int m0 = blockIdx.x * 128, n0 = blockIdx.y * 128;
    const int arow = tid >> 1, acol = (tid & 1) * 4;   // A (and B when TRANSB) staging
    const int bkr  = tid >> 5, bnc = (tid & 31) * 4;   // B staging when !TRANSB
    const int tx = tid & 15, ty = tid >> 4;
    const int tm = ty * 8, tn = tx * 8;

    unsigned long long acc2[8][4];
    #pragma unroll
    for (int i = 0; i < 8; ++i)
        #pragma unroll
        for (int j = 0; j < 4; ++j) acc2[i][j] = 0ull;

    const int KT = K >> 3;
    float4 fa, fb;

    // prefetch tile 0
    {
        int m = m0 + arow;
        fa = (m < M) ? *(const float4*)(A + (size_t)m * K + acol) : make_float4(0,0,0,0);
        if (TRANSB) fb = *(const float4*)(Bm + (size_t)(n0 + arow) * K + acol);
        else        fb = *(const float4*)(Bm + (size_t)bkr * N + n0 + bnc);
    }
    As[0][acol+0][arow] = fa.x; As[0][acol+1][arow] = fa.y;
    As[0][acol+2][arow] = fa.z; As[0][acol+3][arow] = fa.w;
    if (TRANSB) {
        Bs[0][acol+0][arow] = fb.x; Bs[0][acol+1][arow] = fb.y;
        Bs[0][acol+2][arow] = fb.z; Bs[0][acol+3][arow] = fb.w;
    } else {
        *(float4*)&Bs[0][bkr][bnc] = fb;
    }
    __syncthreads();

    int buf = 0;
    for (int kt = 0; kt < KT; ++kt) {
        const bool more = (kt + 1 < KT);
        if (more) {
            int k0 = (kt + 1) << 3;
            int m = m0 + arow;
            fa = (m < M) ? *(const float4*)(A + (size_t)m * K + k0 + acol) : make_float4(0,0,0,0);
            if (TRANSB) fb = *(const float4*)(Bm + (size_t)(n0 + arow) * K + k0 + acol);
            else        fb = *(const float4*)(Bm + (size_t)(k0 + bkr) * N + n0 + bnc);
        }
        #pragma unroll
        for (int kk = 0; kk < 8; ++kk) {
            float4 a0 = *(const float4*)&As[buf][kk][tm];
            float4 a1 = *(const float4*)&As[buf][kk][tm + 4];
            float4 b0 = *(const float4*)&Bs[buf][kk][tn];
            float4 b1 = *(const float4*)&Bs[buf][kk][tn + 4];
            unsigned long long bp[4];
            bp[0] = pk2(b0.x, b0.y); bp[1] = pk2(b0.z, b0.w);
            bp[2] = pk2(b1.x, b1.y); bp[3] = pk2(b1.z, b1.w);
            float av[8] = {a0.x,a0.y,a0.z,a0.w,a1.x,a1.y,a1.z,a1.w};
            #pragma unroll
            for (int i = 0; i < 8; ++i) {
                unsigned long long ad = pk2(av[i], av[i]);
                #pragma unroll
                for (int j = 0; j < 4; ++j) ffma2(acc2[i][j], ad, bp[j]);
            }
        }
        if (more) {
            int nb = buf ^ 1;
            As[nb][acol+0][arow] = fa.x; As[nb][acol+1][arow] = fa.y;
            As[nb][acol+2][arow] = fa.z; As[nb][acol+3][arow] = fa.w;
            if (TRANSB) {
                Bs[nb][acol+0][arow] = fb.x; Bs[nb][acol+1][arow] = fb.y;
                Bs[nb][acol+2][arow] = fb.z; Bs[nb][acol+3][arow] = fb.w;
            } else {
                *(float4*)&Bs[nb][bkr][bnc] = fb;
            }
            buf = nb;
        }
        __syncthreads();
    }

    #pragma unroll
    for (int i = 0; i < 8; ++i) {
        int m = m0 + tm + i;
        if (m >= M) continue;
        float o[8];
        #pragma unroll
        for (int j = 0; j < 4; ++j) upk2(acc2[i][j], o[2*j], o[2*j+1]);
        #pragma unroll
        for (int j = 0; j < 8; ++j) {
            float c = o[j] + bias[n0 + tn + j];
            if (ACT == 1) c = geluf(c);
            if (res) c += res[(size_t)m * N + n0 + tn + j];
            o[j] = c;
        }
        *(float4*)(C + (size_t)m * N + n0 + tn)     = make_float4(o[0],o[1],o[2],o[3]);
        *(float4*)(C + (size_t)m * N + n0 + tn + 4) = make_float4(o[4],o[5],o[6],o[7]);
    }
}

// ---------------- assemble h = [cls+pos0 ; tok+pos1:] ------------------------
__global__ void assemble_kernel(const float* __restrict__ cls, const float* __restrict__ pos) {
    size_t idx = (size_t)blockIdx.x * 256 + threadIdx.x;
    if (idx >= (size_t)ML * EV) return;
    int e = idx % EV;
    size_t t = idx / EV;
    int l = (int)(t % LV);
    int b = (int)(t / LV);
    float v;
    if (l == 0) v = cls[e] + pos[e];
    else        v = g_hn[((size_t)b * NP + (l - 1)) * EV + e] + pos[(size_t)l * EV + e];
    g_h[idx] = v;
}

// ---------------- layernorm ---------------------------------------------------
__global__ void layernorm_kernel(const float* __restrict__ x, const float* __restrict__ g,
                                 const float* __restrict__ bta, float* __restrict__ y)
{
    int row = blockIdx.x;
    const float* xr = x + (size_t)row * EV;
    int tid = threadIdx.x;
    float v0 = xr[tid], v1 = xr[tid + 256], v2 = xr[tid + 512];
    float s = v0 + v1 + v2;
    float s2 = v0 * v0 + v1 * v1 + v2 * v2;
    __shared__ float shA[8], shB[8];
    float ws = warpSum(s), ws2 = warpSum(s2);
    int lane = tid & 31, wid = tid >> 5;
    if (lane == 0) { shA[wid] = ws; shB[wid] = ws2; }
    __syncthreads();
    if (tid == 0) {
        float a = 0, bb = 0;
        #pragma unroll
        for (int i = 0; i < 8; ++i) { a += shA[i]; bb += shB[i]; }
        shA[0] = a; shB[0] = bb;
    }
    __syncthreads();
    float mu = shA[0] * (1.f / 768.f);
    float var = shB[0] * (1.f / 768.f) - mu * mu;
    float inv = rsqrtf(var + 1e-5f);
    float* yr = y + (size_t)row * EV;
    yr[tid      ] = (v0 - mu) * inv * g[tid      ] + bta[tid      ];
    yr[tid + 256] = (v1 - mu) * inv * g[tid + 256] + bta[tid + 256];
    yr[tid + 512] = (v2 - mu) * inv * g[tid + 512] + bta[tid + 512];
}

// ---------------- dilated attention scores: S = QK^T / 8 (128x128 tiles) -----
__global__ void __launch_bounds__(256, 2)
scores128(const float* __restrict__ q, const float* __restrict__ kmat,
          int w, int r, int gsz, int n)
{
    __shared__ float Qs[32][128];
    __shared__ float Ks[32][128];
    int z = blockIdx.z;
    int h = z % HH;
    int seg = (z / HH) % n;
    int b = z / (HH * n);
    int off = h / gsz;
    int tid = threadIdx.x;
    int m0 = blockIdx.x * 128, n0 = blockIdx.y * 128;
    int tx = tid & 15, ty = tid >> 4;
    int tm = ty * 8, tn = tx * 8;

    unsigned long long acc2[8][4];
    #pragma unroll
    for (int i = 0; i < 8; ++i)
        #pragma unroll
        for (int j = 0; j < 4; ++j) acc2[i][j] = 0ull;

    #pragma unroll
    for (int kt = 0; kt < 2; ++kt) {
        int k0 = kt * 32;
        #pragma unroll
        for (int it = 0; it < 4; ++it) {
            int l = it * 256 + tid;
            int mm = l >> 3, k4 = (l & 7) * 4;
            int posq = seg * w + (m0 + mm) * r + off;
            float4 vq = make_float4(0,0,0,0);
            if (posq < LV) vq = *(const float4*)(q + (size_t)(b * LV + posq) * EV + h * DHv + k0 + k4);
            Qs[k4+0][mm] = vq.x; Qs[k4+1][mm] = vq.y; Qs[k4+2][mm] = vq.z; Qs[k4+3][mm] = vq.w;
            int posk = seg * w + (n0 + mm) * r + off;
            float4 vk = make_float4(0,0,0,0);
            if (posk < LV) vk = *(const float4*)(kmat + (size_t)(b * LV + posk) * EV + h * DHv + k0 + k4);
            Ks[k4+0][mm] = vk.x; Ks[k4+1][mm] = vk.y; Ks[k4+2][mm] = vk.z; Ks[k4+3][mm] = vk.w;
        }
        __syncthreads();
        #pragma unroll
        for (int kk = 0; kk < 32; ++kk) {
            float4 a0 = *(const float4*)&Qs[kk][tm];
            float4 a1 = *(const float4*)&Qs[kk][tm + 4];
            float4 b0 = *(const float4*)&Ks[kk][tn];
            float4 b1 = *(const float4*)&Ks[kk][tn + 4];
            unsigned long long bp[4];
            bp[0] = pk2(b0.x, b0.y); bp[1] = pk2(b0.z, b0.w);
            bp[2] = pk2(b1.x, b1.y); bp[3] = pk2(b1.z, b1.w);
            float av[8] = {a0.x,a0.y,a0.z,a0.w,a1.x,a1.y,a1.z,a1.w};
            #pragma unroll
            for (int i = 0; i < 8; ++i) {
                unsigned long long ad = pk2(av[i], av[i]);
                #pragma unroll
                for (int j = 0; j < 4; ++j) ffma2(acc2[i][j], ad, bp[j]);
            }
        }
        __syncthreads();
    }

    float* Sp = g_S + (size_t)z * 589824;
    #pragma unroll
    for (int i = 0; i < 8; ++i) {
        int rowq = m0 + tm + i;
        float o[8];
        #pragma unroll
        for (int j = 0; j < 4; ++j) upk2(acc2[i][j], o[2*j], o[2*j+1]);
        *(float4*)(Sp + (size_t)rowq * 768 + n0 + tn) =
            make_float4(o[0]*0.125f, o[1]*0.125f, o[2]*0.125f, o[3]*0.125f);
        *(float4*)(Sp + (size_t)rowq * 768 + n0 + tn + 4) =
            make_float4(o[4]*0.125f, o[5]*0.125f, o[6]*0.125f, o[7]*0.125f);
    }
}

// ---------------- softmax over each row of S + lse ---------------------------
__global__ void softmax_kernel(int lseBase)
{
    int row = blockIdx.x;
    float* sr = g_S + (size_t)row * 768;
    int tid = threadIdx.x;
    float v0 = sr[tid], v1 = sr[tid + 256], v2 = sr[tid + 512];
    float mx = fmaxf(v0, fmaxf(v1, v2));
    __shared__ float shA[8], shB[8];
    mx = warpMax(mx);
    int lane = tid & 31, wid = tid >> 5;
    if (lane == 0) shA[wid] = mx;
    __syncthreads();
    if (tid == 0) {
        float m = shA[0];
        #pragma unroll
        for (int i = 1; i < 8; ++i) m = fmaxf(m, shA[i]);
        shA[0] = m;
    }
    __syncthreads();
    mx = shA[0];
    float e0 = expf(v0 - mx), e1 = expf(v1 - mx), e2 = expf(v2 - mx);
    float s = warpSum(e0 + e1 + e2);
    if (lane == 0) shB[wid] = s;
    __syncthreads();
    if (tid == 0) {
        float a = 0;
        #pragma unroll
        for (int i = 0; i < 8; ++i) a += shB[i];
        shB[0] = a;
    }
    __syncthreads();
    s = shB[0];
    float inv = 1.f / s;
    sr[tid] = e0 * inv; sr[tid + 256] = e1 * inv; sr[tid + 512] = e2 * inv;
    if (tid == 0) g_lse[(size_t)lseBase * 768 + row] = mx + logf(s);
}

// ---------------- O = P @ V (gathered), 128x64 tiles --------------------------
__global__ void __launch_bounds__(256, 2)
pv128(const float* __restrict__ vmat, int w, int r, int gsz, int n, int ub)
{
    __shared__ float Ps[32][128];
    __shared__ float Vs[32][64];
    int z = blockIdx.z;
    int h = z % HH;
    int seg = (z / HH) % n;
    int b = z / (HH * n);
    int off = h / gsz;
    int tid = threadIdx.x;
    int qbase = blockIdx.x * 128;
    const float* Sp = g_S + (size_t)z * 589824;
    int tx = tid & 7, ty = tid >> 3;
    int tm = ty * 4, tn = tx * 8;

    unsigned long long acc2[4][4];
    #pragma unroll
    for (int i = 0; i < 4; ++i)
        #pragma unroll
        for (int j = 0; j < 4; ++j) acc2[i][j] = 0ull;

    for (int kt = 0; kt < 24; ++kt) {
        int k0 = kt * 32;
        #pragma unroll
        for (int it = 0; it < 4; ++it) {
            int l = it * 256 + tid;
            int mm = l >> 3, k4 = (l & 7) * 4;
            float4 pv4 = *(const float4*)(Sp + (size_t)(qbase + mm) * 768 + k0 + k4);
            Ps[k4+0][mm] = pv4.x; Ps[k4+1][mm] = pv4.y; Ps[k4+2][mm] = pv4.z; Ps[k4+3][mm] = pv4.w;
        }
        #pragma unroll
        for (int it = 0; it < 2; ++it) {
            int l = it * 256 + tid;
            int kk = l >> 4, d4 = (l & 15) * 4;
            int pos = seg * w + (k0 + kk) * r + off;
            float4 vv = make_float4(0,0,0,0);
            if (pos < LV) vv = *(const float4*)(vmat + (size_t)(b * LV + pos) * EV + h * DHv + d4);
            *(float4*)&Vs[kk][d4] = vv;
        }
        __syncthreads();
        #pragma unroll
        for (int kk = 0; kk < 32; ++kk) {
            float4 a = *(const float4*)&Ps[kk][tm];
            float4 b0 = *(const float4*)&Vs[kk][tn];
            float4 b1 = *(const float4*)&Vs[kk][tn + 4];
            unsigned long long bp[4];
            bp[0] = pk2(b0.x, b0.y); bp[1] = pk2(b0.z, b0.w);
            bp[2] = pk2(b1.x, b1.y); bp[3] = pk2(b1.z, b1.w);
            float av[4] = {a.x,a.y,a.z,a.w};
            #pragma unroll
            for (int i = 0; i < 4; ++i) {
                unsigned long long ad = pk2(av[i], av[i]);
                #pragma unroll
                for (int j = 0; j < 4; ++j) ffma2(acc2[i][j], ad, bp[j]);
            }
        }
        __syncthreads();
    }

    float* Op = g_obr + (size_t)(ub + z) * 49152;
    #pragma unroll
    for (int i = 0; i < 4; ++i) {
        int rowq = qbase + tm + i;
        float o[8];
        #pragma unroll
        for (int j = 0; j < 4; ++j) upk2(acc2[i][j], o[2*j], o[2*j+1]);
        *(float4*)(Op + (size_t)rowq * 64 + tn)     = make_float4(o[0],o[1],o[2],o[3]);
        *(float4*)(Op + (size_t)rowq * 64 + tn + 4) = make_float4(o[4],o[5],o[6],o[7]);
    }
}

// ---------------- branch recombination (softmax over branch lse) -------------
__global__ void combine_kernel()
{
    int blk = blockIdx.x;
    int h = blk % HH;
    int p = (blk / HH) % LV;
    int b = blk / (HH * LV);
    int d = threadIdx.x;
    const int ws[5] = {768, 1536, 3072, 6144, 12288};
    const int rs[5] = {1, 2, 4, 8, 16};
    const int gs[5] = {12, 6, 3, 2, 1};
    const int ns[5] = {5, 3, 2, 1, 1};
    const int ub[5] = {0, 120, 192, 240, 264};
    float lses[5];
    size_t oix[5];
    bool cov[5];
    float mx = -1e30f;
    #pragma unroll
    for (int br = 0; br < 5; ++br) {
        int seg = p / ws[br];
        int jj = p - seg * ws[br];
        int off = h / gs[br];
        int rr = jj & (rs[br] - 1);
        cov[br] = (rr == off);
        if (cov[br]) {
            int j = jj / rs[br];
            int unit = ub[br] + (b * ns[br] + seg) * HH + h;
            lses[br] = g_lse[(size_t)unit * 768 + j];
            oix[br] = (size_t)unit * 49152 + (size_t)j * 64;
            mx = fmaxf(mx, lses[br]);
        }
    }
    float sw = 0.f, out = 0.f;
    #pragma unroll
    for (int br = 0; br < 5; ++br) {
        if (cov[br]) {
            float wgt = expf(lses[br] - mx);
            sw += wgt;
            out += wgt * g_obr[oix[br] + d];
        }
    }
    g_a[((size_t)(b * LV + p)) * EV + h * DHv + d] = out / sw;
}

// ---------------- classification head ----------------------------------------
__global__ void head_kernel(const float* __restrict__ hn, const float* __restrict__ W,
                            const float* __restrict__ bias, float* __restrict__ out)
{
    int nidx = blockIdx.x * blockDim.x + threadIdx.x;
    int b = blockIdx.y;
    if (nidx >= 1000) return;
    const float* row = hn + (size_t)b * LV * EV;   // token 0 (cls)
    float acc = bias[nidx];
    for (int e = 0; e < EV; ++e) acc = fmaf(row[e], W[(size_t)e * 1000 + nidx], acc);
    out[b * 1000 + nidx] = acc;
}

// ---------------- host orchestration ------------------------------------------
extern "C" void kernel_launch(void* const* d_in, const int* in_sizes, int n_in,
                              void* d_out, int out_size)
{
    (void)in_sizes; (void)n_in; (void)out_size;
    const float* x        = (const float*)d_in[0];
    const float* patch_w  = (const float*)d_in[1];
    const float* patch_b  = (const float*)d_in[2];
    const float* cls_tok  = (const float*)d_in[3];
    const float* pos_emb  = (const float*)d_in[4];
    const float* ln1_g    = (const float*)d_in[5];
    const float* ln1_b    = (const float*)d_in[6];
    const float* wq       = (const float*)d_in[7];
    const float* bq       = (const float*)d_in[8];
    const float* wk       = (const float*)d_in[9];
    const float* bk       = (const float*)d_in[10];
    const float* wv       = (const float*)d_in[11];
    const float* bv_      = (const float*)d_in[12];
    const float* wo       = (const float*)d_in[13];
    const float* bo       = (const float*)d_in[14];
    const float* ln2_g    = (const float*)d_in[15];
    const float* ln2_b    = (const float*)d_in[16];
    const float* w1       = (const float*)d_in[17];
    const float* b1       = (const float*)d_in[18];
    const float* w2       = (const float*)d_in[19];
    const float* b2       = (const float*)d_in[20];
    const float* normf_g  = (const float*)d_in[21];
    const float* normf_b  = (const float*)d_in[22];
    const float* head_w   = (const float*)d_in[23];
    const float* head_b   = (const float*)d_in[24];
    float* out = (float*)d_out;

    float *p_h, *p_hn, *p_q, *p_k, *p_v, *p_a, *p_m1, *p_col;
    cudaGetSymbolAddress((void**)&p_h, g_h);
    cudaGetSymbolAddress((void**)&p_hn, g_hn);
    cudaGetSymbolAddress((void**)&p_q, g_q);
    cudaGetSymbolAddress((void**)&p_k, g_k);
    cudaGetSymbolAddress((void**)&p_v, g_v);
    cudaGetSymbolAddress((void**)&p_a, g_a);
    cudaGetSymbolAddress((void**)&p_m1, g_m1);
    cudaGetSymbolAddress((void**)&p_col, g_col);

    const int ws[5] = {768, 1536, 3072, 6144, 12288};
    const int rs[5] = {1, 2, 4, 8, 16};
    const int gs[5] = {12, 6, 3, 2, 1};
    const int ns[5] = {5, 3, 2, 1, 1};
    const int ub[5] = {0, 120, 192, 240, 264};

    // 1) patch embed: im2col + GEMM
    im2col_kernel<<<(BV * NP * 1024 + 255) / 256, 256>>>(x);
    {
        dim3 g((BV * NP + 127) / 128, EV / 128);
        sgemm128<1,0><<<g, 256>>>(p_col, patch_w, patch_b, nullptr, p_hn, BV * NP, EV, 1024);
    }
    // 2) assemble h
    assemble_kernel<<<(int)(((size_t)ML * EV + 255) / 256), 256>>>(cls_tok, pos_emb);

    dim3 gEE((ML + 127) / 128, EV / 128);
    dim3 gE4((ML + 127) / 128, 3072 / 128);

    for (int layer = 0; layer < 2; ++layer) {
        size_t oEE = (size_t)layer * EV * EV;
        size_t oE  = (size_t)layer * EV;
        size_t oE4 = (size_t)layer * EV * 3072;
        size_t o4  = (size_t)layer * 3072;

        layernorm_kernel<<<ML, 256>>>(p_h, ln1_g + oE, ln1_b + oE, p_hn);
        sgemm128<0,0><<<gEE, 256>>>(p_hn, wq + oEE, bq + oE, nullptr, p_q, ML, EV, EV);
        sgemm128<0,0><<<gEE, 256>>>(p_hn, wk + oEE, bk + oE, nullptr, p_k, ML, EV, EV);
        sgemm128<0,0><<<gEE, 256>>>(p_hn, wv + oEE, bv_ + oE, nullptr, p_v, ML, EV, EV);

        for (int br = 0; br < 5; ++br) {
            int units = BV * ns[br] * HH;
            dim3 gsc(6, 6, units);
            scores128<<<gsc, 256>>>(p_q, p_k, ws[br], rs[br], gs[br], ns[br]);
            softmax_kernel<<<units * 768, 256>>>(ub[br]);
            dim3 gpv(6, 1, units);
            pv128<<<gpv, 256>>>(p_v, ws[br], rs[br], gs[br], ns[br], ub[br]);
        }
        combine_kernel<<<BV * LV * HH, 64>>>();

        sgemm128<0,0><<<gEE, 256>>>(p_a, wo + oEE, bo + oE, p_h, p_h, ML, EV, EV);
        layernorm_kernel<<<ML, 256>>>(p_h, ln2_g + oE, ln2_b + oE, p_hn);
        sgemm128<0,1><<<gE4, 256>>>(p_hn, w1 + oE4, b1 + o4, nullptr, p_m1, ML, 3072, EV);
        sgemm128<0,0><<<gEE, 256>>>(p_m1, w2 + oE4, b2 + oE, p_h, p_h, ML, EV, 3072);
    }

    layernorm_kernel<<<ML, 256>>>(p_h, normf_g, normf_b, p_hn);
    head_kernel<<<dim3(4, BV), 256>>>(p_hn, head_w, head_b, out);
}

// round 5
// speedup vs baseline: 2.4589x; 1.3960x over previous
#include <cuda_runtime.h>
#include <cuda_bf16.h>
#include <math.h>
#include <stdint.h>

#define BV 2
#define LV 3073
#define EV 768
#define HH 12
#define DHv 64
#define ML (BV*LV)          // 6146 rows
#define NP 3072             // patches per batch

// ---------------- scratch (device globals; no allocations allowed) ----------
__device__ float g_h  [(size_t)ML*EV];
__device__ float g_hn [(size_t)ML*EV];
__device__ float g_q  [(size_t)ML*EV];
__device__ float g_k  [(size_t)ML*EV];
__device__ float g_v  [(size_t)ML*EV];
__device__ float g_a  [(size_t)ML*EV];
__device__ float g_m1 [(size_t)ML*3072];
__device__ float g_col[(size_t)BV*NP*1024];
__device__ float g_S  [(size_t)120*768*768];
__device__ float g_obr[(size_t)288*768*64];
__device__ float g_lse[(size_t)288*768];
// bf16 split buffers
__device__ __align__(16) __nv_bfloat16 g_ah[(size_t)ML*3072];
__device__ __align__(16) __nv_bfloat16 g_al[(size_t)ML*3072];
#define WTOT 14942208
__device__ __align__(16) __nv_bfloat16 g_wh[WTOT];
__device__ __align__(16) __nv_bfloat16 g_wl[WTOT];

// ---------------- generic helpers -------------------------------------------
__device__ __forceinline__ float geluf(float v) {
    return 0.5f * v * (1.f + erff(v * 0.70710678118654752f));
}
__device__ __forceinline__ float warpMax(float v) {
    #pragma unroll
    for (int o = 16; o; o >>= 1) v = fmaxf(v, __shfl_xor_sync(0xffffffffu, v, o));
    return v;
}
__device__ __forceinline__ float warpSum(float v) {
    #pragma unroll
    for (int o = 16; o; o >>= 1) v += __shfl_xor_sync(0xffffffffu, v, o);
    return v;
}
__device__ __forceinline__ unsigned long long pk2(float lo, float hi) {
    unsigned long long r;
    asm("mov.b64 %0, {%1, %2};" : "=l"(r) : "r"(__float_as_uint(lo)), "r"(__float_as_uint(hi)));
    return r;
}
__device__ __forceinline__ void upk2(unsigned long long v, float& lo, float& hi) {
    unsigned int a, b;
    asm("mov.b64 {%0, %1}, %2;" : "=r"(a), "=r"(b) : "l"(v));
    lo = __uint_as_float(a); hi = __uint_as_float(b);
}
__device__ __forceinline__ void ffma2(unsigned long long& c, unsigned long long a, unsigned long long b) {
    asm("fma.rn.f32x2 %0, %1, %2, %0;" : "+l"(c) : "l"(a), "l"(b));
}
__device__ __forceinline__ uint32_t s2u(const void* p) {
    uint32_t a;
    asm("{ .reg .u64 t; cvta.to.shared.u64 t, %1; cvt.u32.u64 %0, t; }" : "=r"(a) : "l"(p));
    return a;
}
__device__ __forceinline__ void cpa16(uint32_t saddr, const void* g, int sz) {
    asm volatile("cp.async.cg.shared.global [%0], [%1], 16, %2;"
                 :: "r"(saddr), "l"(g), "r"(sz) : "memory");
}
__device__ __forceinline__ void mma16816(float* d, const uint32_t* a, uint32_t b0, uint32_t b1) {
    asm volatile("mma.sync.aligned.m16n8k16.row.col.f32.bf16.bf16.f32 "
                 "{%0,%1,%2,%3},{%4,%5,%6,%7},{%8,%9},{%0,%1,%2,%3};"
                 : "+f"(d[0]), "+f"(d[1]), "+f"(d[2]), "+f"(d[3])
                 : "r"(a[0]), "r"(a[1]), "r"(a[2]), "r"(a[3]), "r"(b0), "r"(b1));
}

// ---------------- split-bf16 tensor-core GEMM (mma.sync HMMA) ----------------
// C[M,N] = act(A@B^T + bias) (+res).  A: MxK bf16 hi/lo; B: NxK bf16 hi/lo.
// K % 32 == 0, N % 128 == 0.
#define HG_STRIDE 40                    // halves per smem row (32 data + 8 pad)
#define HG_MAT (128*HG_STRIDE)          // halves per matrix tile
#define HG_BUF (4*HG_MAT)               // halves per buffer (Ah|Al|Bh|Bl)
#define HG_SMEM (2*HG_BUF*2)            // bytes, double buffered

template<int ACT>
__global__ void __launch_bounds__(256, 2)
hgemm(const __nv_bfloat16* __restrict__ Ah, const __nv_bfloat16* __restrict__ Al,
      const __nv_bfloat16* __restrict__ Bh, const __nv_bfloat16* __restrict__ Bl,
      const float* __restrict__ bias, const float* __restrict__ res,
      float* __restrict__ C, int M, int N, int K)
{
    extern __shared__ __nv_bfloat16 sm[];
    const int tid = threadIdx.x, wid = tid >> 5, lane = tid & 31;
    const int m0 = blockIdx.x * 128, n0 = blockIdx.y * 128;
    const int g = lane >> 2, t = lane & 3;
    const int wm0 = (wid >> 1) * 32, wn0 = (wid & 1) * 64;
    const uint32_t smbase = s2u(sm);
    const __nv_bfloat16* srcs[4] = {Ah, Al, Bh, Bl};

    float acc[2][8][4];
    #pragma unroll
    for (int i = 0; i < 2; ++i)
        #pragma unroll
        for (int j = 0; j < 8; ++j)
            #pragma unroll
            for (int u = 0; u < 4; ++u) acc[i][j][u] = 0.f;

    const int KC = K >> 5;
    const int srow = tid >> 1;

    auto issue = [&](int c) {
        int k0 = c << 5;
        int buf = c & 1;
        #pragma unroll
        for (int mat = 0; mat < 4; ++mat) {
            #pragma unroll
            for (int j = 0; j < 2; ++j) {
                int q = (tid & 1) * 2 + j;
                int grow = (mat < 2) ? (m0 + srow) : (n0 + srow);
                bool ok = (mat >= 2) || (grow < M);
                const __nv_bfloat16* gp = ok ? (srcs[mat] + (size_t)grow * K + k0 + q * 8)
                                             : srcs[mat];
                uint32_t sa = smbase + (uint32_t)(buf * HG_BUF + mat * HG_MAT + srow * HG_STRIDE + q * 8) * 2;
                cpa16(sa, gp, ok ? 16 : 0);
            }
        }
        asm volatile("cp.async.commit_group;" ::: "memory");
    };

    issue(0);
    for (int c = 0; c < KC; ++c) {
        if (c + 1 < KC) {
            issue(c + 1);
            asm volatile("cp.async.wait_group 1;" ::: "memory");
        } else {
            asm volatile("cp.async.wait_group 0;" ::: "memory");
        }
        __syncthreads();
        const __nv_bfloat16* bb = sm + (size_t)(c & 1) * HG_BUF;
        #pragma unroll
        for (int ks = 0; ks < 32; ks += 16) {
            uint32_t afr[2][2][4];   // [variant hi/lo][mf][reg]
            #pragma unroll
            for (int v = 0; v < 2; ++v)
                #pragma unroll
                for (int mf = 0; mf < 2; ++mf) {
                    const __nv_bfloat16* pa = bb + v * HG_MAT + (wm0 + mf * 16 + g) * HG_STRIDE + ks + 2 * t;
                    afr[v][mf][0] = *(const uint32_t*)pa;
                    afr[v][mf][1] = *(const uint32_t*)(pa + 8 * HG_STRIDE);
                    afr[v][mf][2] = *(const uint32_t*)(pa + 8);
                    afr[v][mf][3] = *(const uint32_t*)(pa + 8 * HG_STRIDE + 8);
                }
            #pragma unroll
            for (int nf = 0; nf < 8; ++nf) {
                const __nv_bfloat16* pbh = bb + 2 * HG_MAT + (wn0 + nf * 8 + g) * HG_STRIDE + ks + 2 * t;
                const __nv_bfloat16* pbl = pbh + HG_MAT;
                uint32_t bh0 = *(const uint32_t*)pbh;
                uint32_t bh1 = *(const uint32_t*)(pbh + 8);
                uint32_t bl0 = *(const uint32_t*)pbl;
                uint32_t bl1 = *(const uint32_t*)(pbl + 8);
                #pragma unroll
                for (int mf = 0; mf < 2; ++mf) {
                    mma16816(acc[mf][nf], afr[0][mf], bh0, bh1);
                    mma16816(acc[mf][nf], afr[0][mf], bl0, bl1);
                    mma16816(acc[mf][nf], afr[1][mf], bh0, bh1);
                }
            }
        }
        __syncthreads();
    }

    // epilogue
    #pragma unroll
    for (int mf = 0; mf < 2; ++mf) {
        int row0 = m0 + wm0 + mf * 16 + g;
        #pragma unroll
        for (int nf = 0; nf < 8; ++nf) {
            int col = n0 + wn0 + nf * 8 + 2 * t;
            float b0v = bias[col], b1v = bias[col + 1];
            if (row0 < M) {
                float c0 = acc[mf][nf][0] + b0v;
                float c1 = acc[mf][nf][1] + b1v;
                if (ACT) { c0 = geluf(c0); c1 = geluf(c1); }
                if (res) {
                    c0 += res[(size_t)row0 * N + col];
                    c1 += res[(size_t)row0 * N + col + 1];
                }
                *(float2*)(C + (size_t)row0 * N + col) = make_float2(c0, c1);
            }
            int row1 = row0 + 8;
            if (row1 < M) {
                float c2 = acc[mf][nf][2] + b0v;
                float c3 = acc[mf][nf][3] + b1v;
                if (ACT) { c2 = geluf(c2); c3 = geluf(c3); }
                if (res) {
                    c2 += res[(size_t)row1 * N + col];
                    c3 += res[(size_t)row1 * N + col + 1];
                }
                *(float2*)(C + (size_t)row1 * N + col) = make_float2(c2, c3);
            }
        }
    }
}

// ---------------- fp32 -> bf16 hi/lo split (same layout) ---------------------
__global__ void split_copy(const float* __restrict__ s, __nv_bfloat16* __restrict__ oh,
                           __nv_bfloat16* __restrict__ ol, long n)
{
    long i = ((long)blockIdx.x * 256 + threadIdx.x) * 4;
    if (i >= n) return;
    float4 v = *(const float4*)(s + i);
    float vv[4] = {v.x, v.y, v.z, v.w};
    #pragma unroll
    for (int u = 0; u < 4; ++u) {
        __nv_bfloat16 h = __float2bfloat16(vv[u]);
        __nv_bfloat16 l = __float2bfloat16(vv[u] - __bfloat162float(h));
        oh[i + u] = h; ol[i + u] = l;
    }
}

// ---------------- fp32 (K,N) -> bf16 hi/lo transposed (N,K) ------------------
__global__ void splitT(const float* __restrict__ w, __nv_bfloat16* __restrict__ oh,
                       __nv_bfloat16* __restrict__ ol, int K, int N)
{
    __shared__ float t[32][33];
    int kb = blockIdx.x * 32, nb = blockIdx.y * 32;
    int x = threadIdx.x, y = threadIdx.y;
    #pragma unroll
    for (int i = 0; i < 32; i += 8)
        t[y + i][x] = w[(size_t)(kb + y + i) * N + nb + x];
    __syncthreads();
    #pragma unroll
    for (int i = 0; i < 32; i += 8) {
        float v = t[x][y + i];
        __nv_bfloat16 h = __float2bfloat16(v);
        __nv_bfloat16 l = __float2bfloat16(v - __bfloat162float(h));
        size_t o = (size_t)(nb + y + i) * K + kb + x;
        oh[o] = h; ol[o] = l;
    }
}

// ---------------- im2col for 3D patch embed ---------------------------------
__global__ void im2col_kernel(const float* __restrict__ x) {
    int idx = blockIdx.x * 256 + threadIdx.x;
    if (idx >= BV * NP * 1024) return;
    int kk = idx & 1023;
    int p  = (idx >> 10) % NP;
    int b  = (idx >> 10) / NP;
    int pw_ = kk & 15, ph_ = (kk >> 4) & 15, pd_ = kk >> 8;
    int bz = p & 15, by = (p >> 4) & 15, bx = p >> 8;
    g_col[idx] = x[(((size_t)b * 48 + bx * 4 + pd_) * 256 + by * 16 + ph_) * 256 + bz * 16 + pw_];
}

// ---------------- assemble h = [cls+pos0 ; tok+pos1:] ------------------------
__global__ void assemble_kernel(const float* __restrict__ cls, const float* __restrict__ pos) {
    size_t idx = (size_t)blockIdx.x * 256 + threadIdx.x;
    if (idx >= (size_t)ML * EV) return;
    int e = idx % EV;
    size_t t = idx / EV;
    int l = (int)(t % LV);
    int b = (int)(t / LV);
    float v;
    if (l == 0) v = cls[e] + pos[e];
    else        v = g_hn[((size_t)b * NP + (l - 1)) * EV + e] + pos[(size_t)l * EV + e];
    g_h[idx] = v;
}

// ---------------- layernorm ---------------------------------------------------
__global__ void layernorm_kernel(const float* __restrict__ x, const float* __restrict__ g,
                                 const float* __restrict__ bta, float* __restrict__ y)
{
    int row = blockIdx.x;
    const float* xr = x + (size_t)row * EV;
    int tid = threadIdx.x;
    float v0 = xr[tid], v1 = xr[tid + 256], v2 = xr[tid + 512];
    float s = v0 + v1 + v2;
    float s2 = v0 * v0 + v1 * v1 + v2 * v2;
    __shared__ float shA[8], shB[8];
    float ws = warpSum(s), ws2 = warpSum(s2);
    int lane = tid & 31, wid = tid >> 5;
    if (lane == 0) { shA[wid] = ws; shB[wid] = ws2; }
    __syncthreads();
    if (tid == 0) {
        float a = 0, bb = 0;
        #pragma unroll
        for (int i = 0; i < 8; ++i) { a += shA[i]; bb += shB[i]; }
        shA[0] = a; shB[0] = bb;
    }
    __syncthreads();
    float mu = shA[0] * (1.f / 768.f);
    float var = shB[0] * (1.f / 768.f) - mu * mu;
    float inv = rsqrtf(var + 1e-5f);
    float* yr = y + (size_t)row * EV;
    yr[tid      ] = (v0 - mu) * inv * g[tid      ] + bta[tid      ];
    yr[tid + 256] = (v1 - mu) * inv * g[tid + 256] + bta[tid + 256];
    yr[tid + 512] = (v2 - mu) * inv * g[tid + 512] + bta[tid + 512];
}

// ---------------- dilated attention scores: S = QK^T / 8 (128x128 tiles) -----
__global__ void __launch_bounds__(256, 2)
scores128(const float* __restrict__ q, const float* __restrict__ kmat,
          int w, int r, int gsz, int n)
{
    __shared__ float Qs[32][128];
    __shared__ float Ks[32][128];
    int z = blockIdx.z;
    int h = z % HH;
    int seg = (z / HH) % n;
    int b = z / (HH * n);
    int off = h / gsz;
    int tid = threadIdx.x;
    int m0 = blockIdx.x * 128, n0 = blockIdx.y * 128;
    int tx = tid & 15, ty = tid >> 4;
    int tm = ty * 8, tn = tx * 8;

    unsigned long long acc2[8][4];
    #pragma unroll
    for (int i = 0; i < 8; ++i)
        #pragma unroll
        for (int j = 0; j < 4; ++j) acc2[i][j] = 0ull;

    #pragma unroll
    for (int kt = 0; kt < 2; ++kt) {
        int k0 = kt * 32;
        #pragma unroll
        for (int it = 0; it < 4; ++it) {
            int l = it * 256 + tid;
            int mm = l >> 3, k4 = (l & 7) * 4;
            int posq = seg * w + (m0 + mm) * r + off;
            float4 vq = make_float4(0,0,0,0);
            if (posq < LV) vq = *(const float4*)(q + (size_t)(b * LV + posq) * EV + h * DHv + k0 + k4);
            Qs[k4+0][mm] = vq.x; Qs[k4+1][mm] = vq.y; Qs[k4+2][mm] = vq.z; Qs[k4+3][mm] = vq.w;
            int posk = seg * w + (n0 + mm) * r + off;
            float4 vk = make_float4(0,0,0,0);
            if (posk < LV) vk = *(const float4*)(kmat + (size_t)(b * LV + posk) * EV + h * DHv + k0 + k4);
            Ks[k4+0][mm] = vk.x; Ks[k4+1][mm] = vk.y; Ks[k4+2][mm] = vk.z; Ks[k4+3][mm] = vk.w;
        }
        __syncthreads();
        #pragma unroll
        for (int kk = 0; kk < 32; ++kk) {
            float4 a0 = *(const float4*)&Qs[kk][tm];
            float4 a1 = *(const float4*)&Qs[kk][tm + 4];
            float4 b0 = *(const float4*)&Ks[kk][tn];
            float4 b1 = *(const float4*)&Ks[kk][tn + 4];
            unsigned long long bp[4];
            bp[0] = pk2(b0.x, b0.y); bp[1] = pk2(b0.z, b0.w);
            bp[2] = pk2(b1.x, b1.y); bp[3] = pk2(b1.z, b1.w);
            float av[8] = {a0.x,a0.y,a0.z,a0.w,a1.x,a1.y,a1.z,a1.w};
            #pragma unroll
            for (int i = 0; i < 8; ++i) {
                unsigned long long ad = pk2(av[i], av[i]);
                #pragma unroll
                for (int j = 0; j < 4; ++j) ffma2(acc2[i][j], ad, bp[j]);
            }
        }
        __syncthreads();
    }

    float* Sp = g_S + (size_t)z * 589824;
    #pragma unroll
    for (int i = 0; i < 8; ++i) {
        int rowq = m0 + tm + i;
        float o[8];
        #pragma unroll
        for (int j = 0; j < 4; ++j) upk2(acc2[i][j], o[2*j], o[2*j+1]);
        *(float4*)(Sp + (size_t)rowq * 768 + n0 + tn) =
            make_float4(o[0]*0.125f, o[1]*0.125f, o[2]*0.125f, o[3]*0.125f);
        *(float4*)(Sp + (size_t)rowq * 768 + n0 + tn + 4) =
            make_float4(o[4]*0.125f, o[5]*0.125f, o[6]*0.125f, o[7]*0.125f);
    }
}

// ---------------- softmax over each row of S + lse ---------------------------
__global__ void softmax_kernel(int lseBase)
{
    int row = blockIdx.x;
    float* sr = g_S + (size_t)row * 768;
    int tid = threadIdx.x;
    float v0 = sr[tid], v1 = sr[tid + 256], v2 = sr[tid + 512];
    float mx = fmaxf(v0, fmaxf(v1, v2));
    __shared__ float shA[8], shB[8];
    mx = warpMax(mx);
    int lane = tid & 31, wid = tid >> 5;
    if (lane == 0) shA[wid] = mx;
    __syncthreads();
    if (tid == 0) {
        float m = shA[0];
        #pragma unroll
        for (int i = 1; i < 8; ++i) m = fmaxf(m, shA[i]);
        shA[0] = m;
    }
    __syncthreads();
    mx = shA[0];
    float e0 = expf(v0 - mx), e1 = expf(v1 - mx), e2 = expf(v2 - mx);
    float s = warpSum(e0 + e1 + e2);
    if (lane == 0) shB[wid] = s;
    __syncthreads();
    if (tid == 0) {
        float a = 0;
        #pragma unroll
        for (int i = 0; i < 8; ++i) a += shB[i];
        shB[0] = a;
    }
    __syncthreads();
    s = shB[0];
    float inv = 1.f / s;
    sr[tid] = e0 * inv; sr[tid + 256] = e1 * inv; sr[tid + 512] = e2 * inv;
    if (tid == 0) g_lse[(size_t)lseBase * 768 + row] = mx + logf(s);
}

// ---------------- O = P @ V (gathered), 128x64 tiles --------------------------
__global__ void __launch_bounds__(256, 2)
pv128(const float* __restrict__ vmat, int w, int r, int gsz, int n, int ub)
{
    __shared__ float Ps[32][128];
    __shared__ float Vs[32][64];
    int z = blockIdx.z;
    int h = z % HH;
    int seg = (z / HH) % n;
    int b = z / (HH * n);
    int off = h / gsz;
    int tid = threadIdx.x;
    int qbase = blockIdx.x * 128;
    const float* Sp = g_S + (size_t)z * 589824;
    int tx = tid & 7, ty = tid >> 3;
    int tm = ty * 4, tn = tx * 8;

    unsigned long long acc2[4][4];
    #pragma unroll
    for (int i = 0; i < 4; ++i)
        #pragma unroll
        for (int j = 0; j < 4; ++j) acc2[i][j] = 0ull;

    for (int kt = 0; kt < 24; ++kt) {
        int k0 = kt * 32;
        #pragma unroll
        for (int it = 0; it < 4; ++it) {
            int l = it * 256 + tid;
            int mm = l >> 3, k4 = (l & 7) * 4;
            float4 pv4 = *(const float4*)(Sp + (size_t)(qbase + mm) * 768 + k0 + k4);
            Ps[k4+0][mm] = pv4.x; Ps[k4+1][mm] = pv4.y; Ps[k4+2][mm] = pv4.z; Ps[k4+3][mm] = pv4.w;
        }
        #pragma unroll
        for (int it = 0; it < 2; ++it) {
            int l = it * 256 + tid;
            int kk = l >> 4, d4 = (l & 15) * 4;
            int pos = seg * w + (k0 + kk) * r + off;
            float4 vv = make_float4(0,0,0,0);
            if (pos < LV) vv = *(const float4*)(vmat + (size_t)(b * LV + pos) * EV + h * DHv + d4);
            *(float4*)&Vs[kk][d4] = vv;
        }
        __syncthreads();
        #pragma unroll
        for (int kk = 0; kk < 32; ++kk) {
            float4 a = *(const float4*)&Ps[kk][tm];
            float4 b0 = *(const float4*)&Vs[kk][tn];
            float4 b1 = *(const float4*)&Vs[kk][tn + 4];
            unsigned long long bp[4];
            bp[0] = pk2(b0.x, b0.y); bp[1] = pk2(b0.z, b0.w);
            bp[2] = pk2(b1.x, b1.y); bp[3] = pk2(b1.z, b1.w);
            float av[4] = {a.x,a.y,a.z,a.w};
            #pragma unroll
            for (int i = 0; i < 4; ++i) {
                unsigned long long ad = pk2(av[i], av[i]);
                #pragma unroll
                for (int j = 0; j < 4; ++j) ffma2(acc2[i][j], ad, bp[j]);
            }
        }
        __syncthreads();
    }

    float* Op = g_obr + (size_t)(ub + z) * 49152;
    #pragma unroll
    for (int i = 0; i < 4; ++i) {
        int rowq = qbase + tm + i;
        float o[8];
        #pragma unroll
        for (int j = 0; j < 4; ++j) upk2(acc2[i][j], o[2*j], o[2*j+1]);
        *(float4*)(Op + (size_t)rowq * 64 + tn)     = make_float4(o[0],o[1],o[2],o[3]);
        *(float4*)(Op + (size_t)rowq * 64 + tn + 4) = make_float4(o[4],o[5],o[6],o[7]);
    }
}

// ---------------- branch recombination ----------------------------------------
__global__ void combine_kernel()
{
    int blk = blockIdx.x;
    int h = blk % HH;
    int p = (blk / HH) % LV;
    int b = blk / (HH * LV);
    int d = threadIdx.x;
    const int ws[5] = {768, 1536, 3072, 6144, 12288};
    const int rs[5] = {1, 2, 4, 8, 16};
    const int gs[5] = {12, 6, 3, 2, 1};
    const int ns[5] = {5, 3, 2, 1, 1};
    const int ub[5] = {0, 120, 192, 240, 264};
    float lses[5];
    size_t oix[5];
    bool cov[5];
    float mx = -1e30f;
    #pragma unroll
    for (int br = 0; br < 5; ++br) {
        int seg = p / ws[br];
        int jj = p - seg * ws[br];
        int off = h / gs[br];
        int rr = jj & (rs[br] - 1);
        cov[br] = (rr == off);
        if (cov[br]) {
            int j = jj / rs[br];
            int unit = ub[br] + (b * ns[br] + seg) * HH + h;
            lses[br] = g_lse[(size_t)unit * 768 + j];
            oix[br] = (size_t)unit * 49152 + (size_t)j * 64;
            mx = fmaxf(mx, lses[br]);
        }
    }
    float sw = 0.f, out = 0.f;
    #pragma unroll
    for (int br = 0; br < 5; ++br) {
        if (cov[br]) {
            float wgt = expf(lses[br] - mx);
            sw += wgt;
            out += wgt * g_obr[oix[br] + d];
        }
    }
    g_a[((size_t)(b * LV + p)) * EV + h * DHv + d] = out / sw;
}

// ---------------- classification head ----------------------------------------
__global__ void head_kernel(const float* __restrict__ hn, const float* __restrict__ W,
                            const float* __restrict__ bias, float* __restrict__ out)
{
    int nidx = blockIdx.x * blockDim.x + threadIdx.x;
    int b = blockIdx.y;
    if (nidx >= 1000) return;
    const float* row = hn + (size_t)b * LV * EV;
    float acc = bias[nidx];
    for (int e = 0; e < EV; ++e) acc = fmaf(row[e], W[(size_t)e * 1000 + nidx], acc);
    out[b * 1000 + nidx] = acc;
}

// ---------------- host orchestration ------------------------------------------
static void launch_split(const float* src, __nv_bfloat16* oh, __nv_bfloat16* ol, long n) {
    long threads4 = (n + 3) / 4;
    int blocks = (int)((threads4 + 255) / 256);
    split_copy<<<blocks, 256>>>(src, oh, ol, n);
}

extern "C" void kernel_launch(void* const* d_in, const int* in_sizes, int n_in,
                              void* d_out, int out_size)
{
    (void)in_sizes; (void)n_in; (void)out_size;
    const float* x        = (const float*)d_in[0];
    const float* patch_w  = (const float*)d_in[1];
    const float* patch_b  = (const float*)d_in[2];
    const float* cls_tok  = (const float*)d_in[3];
    const float* pos_emb  = (const float*)d_in[4];
    const float* ln1_g    = (const float*)d_in[5];
    const float* ln1_b    = (const float*)d_in[6];
    const float* wq       = (const float*)d_in[7];
    const float* bq       = (const float*)d_in[8];
    const float* wk       = (const float*)d_in[9];
    const float* bk       = (const float*)d_in[10];
    const float* wv       = (const float*)d_in[11];
    const float* bv_      = (const float*)d_in[12];
    const float* wo       = (const float*)d_in[13];
    const float* bo       = (const float*)d_in[14];
    const float* ln2_g    = (const float*)d_in[15];
    const float* ln2_b    = (const float*)d_in[16];
    const float* w1       = (const float*)d_in[17];
    const float* b1       = (const float*)d_in[18];
    const float* w2       = (const float*)d_in[19];
    const float* b2       = (const float*)d_in[20];
    const float* normf_g  = (const float*)d_in[21];
    const float* normf_b  = (const float*)d_in[22];
    const float* head_w   = (const float*)d_in[23];
    const float* head_b   = (const float*)d_in[24];
    float* out = (float*)d_out;

    float *p_h, *p_hn, *p_q, *p_k, *p_v, *p_a, *p_m1, *p_col;
    __nv_bfloat16 *p_ah, *p_al, *p_wh, *p_wl;
    cudaGetSymbolAddress((void**)&p_h, g_h);
    cudaGetSymbolAddress((void**)&p_hn, g_hn);
    cudaGetSymbolAddress((void**)&p_q, g_q);
    cudaGetSymbolAddress((void**)&p_k, g_k);
    cudaGetSymbolAddress((void**)&p_v, g_v);
    cudaGetSymbolAddress((void**)&p_a, g_a);
    cudaGetSymbolAddress((void**)&p_m1, g_m1);
    cudaGetSymbolAddress((void**)&p_col, g_col);
    cudaGetSymbolAddress((void**)&p_ah, g_ah);
    cudaGetSymbolAddress((void**)&p_al, g_al);
    cudaGetSymbolAddress((void**)&p_wh, g_wh);
    cudaGetSymbolAddress((void**)&p_wl, g_wl);

    cudaFuncSetAttribute(hgemm<0>, cudaFuncAttributeMaxDynamicSharedMemorySize, HG_SMEM);
    cudaFuncSetAttribute(hgemm<1>, cudaFuncAttributeMaxDynamicSharedMemorySize, HG_SMEM);

    const int ws[5] = {768, 1536, 3072, 6144, 12288};
    const int rs[5] = {1, 2, 4, 8, 16};
    const int gs[5] = {12, 6, 3, 2, 1};
    const int ns[5] = {5, 3, 2, 1, 1};
    const int ub[5] = {0, 120, 192, 240, 264};

    // ---- weight prep: bf16 hi/lo, N x K layout --------------------------------
    const size_t OFF_PATCH = 0;
    const size_t LSZ = 7077888;
    launch_split(patch_w, p_wh + OFF_PATCH, p_wl + OFF_PATCH, 786432);   // already N x K
    for (int l = 0; l < 2; ++l) {
        size_t base = 786432 + (size_t)l * LSZ;
        size_t oEE = (size_t)l * EV * EV;
        size_t oE4 = (size_t)l * EV * 3072;
        dim3 blk(32, 8);
        splitT<<<dim3(24, 24), blk>>>(wq + oEE, p_wh + base,           p_wl + base,           768, 768);
        splitT<<<dim3(24, 24), blk>>>(wk + oEE, p_wh + base + 589824,  p_wl + base + 589824,  768, 768);
        splitT<<<dim3(24, 24), blk>>>(wv + oEE, p_wh + base + 1179648, p_wl + base + 1179648, 768, 768);
        splitT<<<dim3(24, 24), blk>>>(wo + oEE, p_wh + base + 1769472, p_wl + base + 1769472, 768, 768);
        splitT<<<dim3(24, 96), blk>>>(w1 + oE4, p_wh + base + 2359296, p_wl + base + 2359296, 768, 3072);
        splitT<<<dim3(96, 24), blk>>>(w2 + oE4, p_wh + base + 4718592, p_wl + base + 4718592, 3072, 768);
    }

    // ---- patch embed -----------------------------------------------------------
    im2col_kernel<<<(BV * NP * 1024 + 255) / 256, 256>>>(x);
    launch_split(p_col, p_ah, p_al, (long)BV * NP * 1024);
    hgemm<0><<<dim3(48, 6), 256, HG_SMEM>>>(p_ah, p_al, p_wh + OFF_PATCH, p_wl + OFF_PATCH,
                                            patch_b, nullptr, p_hn, BV * NP, EV, 1024);
    assemble_kernel<<<(int)(((size_t)ML * EV + 255) / 256), 256>>>(cls_tok, pos_emb);

    dim3 gEEt(49, 6);     // ceil(6146/128) x 768/128
    dim3 gE4t(49, 24);    // x 3072/128

    for (int layer = 0; layer < 2; ++layer) {
        size_t base = 786432 + (size_t)layer * LSZ;
        size_t oE  = (size_t)layer * EV;
        size_t o4  = (size_t)layer * 3072;

        layernorm_kernel<<<ML, 256>>>(p_h, ln1_g + oE, ln1_b + oE, p_hn);
        launch_split(p_hn, p_ah, p_al, (long)ML * EV);
        hgemm<0><<<gEEt, 256, HG_SMEM>>>(p_ah, p_al, p_wh + base,           p_wl + base,           bq + oE,  nullptr, p_q, ML, EV, EV);
        hgemm<0><<<gEEt, 256, HG_SMEM>>>(p_ah, p_al, p_wh + base + 589824,  p_wl + base + 589824,  bk + oE,  nullptr, p_k, ML, EV, EV);
        hgemm<0><<<gEEt, 256, HG_SMEM>>>(p_ah, p_al, p_wh + base + 1179648, p_wl + base + 1179648, bv_ + oE, nullptr, p_v, ML, EV, EV);

        for (int br = 0; br < 5; ++br) {
            int units = BV * ns[br] * HH;
            dim3 gsc(6, 6, units);
            scores128<<<gsc, 256>>>(p_q, p_k, ws[br], rs[br], gs[br], ns[br]);
            softmax_kernel<<<units * 768, 256>>>(ub[br]);
            dim3 gpv(6, 1, units);
            pv128<<<gpv, 256>>>(p_v, ws[br], rs[br], gs[br], ns[br], ub[br]);
        }
        combine_kernel<<<BV * LV * HH, 64>>>();

        launch_split(p_a, p_ah, p_al, (long)ML * EV);
        hgemm<0><<<gEEt, 256, HG_SMEM>>>(p_ah, p_al, p_wh + base + 1769472, p_wl + base + 1769472, bo + oE, p_h, p_h, ML, EV, EV);

        layernorm_kernel<<<ML, 256>>>(p_h, ln2_g + oE, ln2_b + oE, p_hn);
        launch_split(p_hn, p_ah, p_al, (long)ML * EV);
        hgemm<1><<<gE4t, 256, HG_SMEM>>>(p_ah, p_al, p_wh + base + 2359296, p_wl + base + 2359296, b1 + o4, nullptr, p_m1, ML, 3072, EV);
        launch_split(p_m1, p_ah, p_al, (long)ML * 3072);
        hgemm<0><<<gEEt, 256, HG_SMEM>>>(p_ah, p_al, p_wh + base + 4718592, p_wl + base + 4718592, b2 + oE, p_h, p_h, ML, EV, 3072);
    }

    layernorm_kernel<<<ML, 256>>>(p_h, normf_g, normf_b, p_hn);
    head_kernel<<<dim3(4, BV), 256>>>(p_hn, head_w, head_b, out);
}

// round 6
// speedup vs baseline: 3.6377x; 1.4794x over previous
#include <cuda_runtime.h>
#include <cuda_bf16.h>
#include <math.h>
#include <stdint.h>

#define BV 2
#define LV 3073
#define EV 768
#define HH 12
#define DHv 64
#define ML (BV*LV)          // 6146 rows
#define NP 3072             // patches per batch

typedef __nv_bfloat16 bf16;
typedef __nv_bfloat162 bf162;

// ---------------- scratch (device globals) -----------------------------------
__device__ float g_h  [(size_t)ML*EV];
__device__ float g_hn [(size_t)ML*EV];
__device__ float g_S  [(size_t)120*768*768];
__device__ float g_obr[(size_t)288*768*64];
__device__ float g_lse[(size_t)288*768];
__device__ __align__(16) bf16 g_ph[(size_t)120*768*768];
__device__ __align__(16) bf16 g_pl[(size_t)120*768*768];
__device__ __align__(16) bf16 g_colh[(size_t)BV*NP*1024];
__device__ __align__(16) bf16 g_coll[(size_t)BV*NP*1024];
__device__ __align__(16) bf16 g_qh[(size_t)ML*EV];
__device__ __align__(16) bf16 g_ql[(size_t)ML*EV];
__device__ __align__(16) bf16 g_kh[(size_t)ML*EV];
__device__ __align__(16) bf16 g_kl[(size_t)ML*EV];
__device__ __align__(16) bf16 g_vh[(size_t)ML*EV];
__device__ __align__(16) bf16 g_vl[(size_t)ML*EV];
__device__ __align__(16) bf16 g_xh[(size_t)ML*EV];
__device__ __align__(16) bf16 g_xl[(size_t)ML*EV];
__device__ __align__(16) bf16 g_m1h[(size_t)ML*3072];
__device__ __align__(16) bf16 g_m1l[(size_t)ML*3072];
__device__ __align__(16) bf16 g_oh[(size_t)ML*EV];
__device__ __align__(16) bf16 g_ol[(size_t)ML*EV];
#define WTOT 14942208
__device__ __align__(16) bf16 g_wh[WTOT];
__device__ __align__(16) bf16 g_wl[WTOT];

// ---------------- helpers -----------------------------------------------------
__device__ __forceinline__ float geluf(float v) {
    return 0.5f * v * (1.f + erff(v * 0.70710678118654752f));
}
__device__ __forceinline__ float warpMax(float v) {
    #pragma unroll
    for (int o = 16; o; o >>= 1) v = fmaxf(v, __shfl_xor_sync(0xffffffffu, v, o));
    return v;
}
__device__ __forceinline__ float warpSum(float v) {
    #pragma unroll
    for (int o = 16; o; o >>= 1) v += __shfl_xor_sync(0xffffffffu, v, o);
    return v;
}
__device__ __forceinline__ uint32_t s2u(const void* p) {
    uint32_t a;
    asm("{ .reg .u64 t; cvta.to.shared.u64 t, %1; cvt.u32.u64 %0, t; }" : "=r"(a) : "l"(p));
    return a;
}
__device__ __forceinline__ void cpa16(uint32_t saddr, const void* g, int sz) {
    asm volatile("cp.async.cg.shared.global [%0], [%1], 16, %2;"
                 :: "r"(saddr), "l"(g), "r"(sz) : "memory");
}
__device__ __forceinline__ void mma16816(float* d, const uint32_t* a, uint32_t b0, uint32_t b1) {
    asm volatile("mma.sync.aligned.m16n8k16.row.col.f32.bf16.bf16.f32 "
                 "{%0,%1,%2,%3},{%4,%5,%6,%7},{%8,%9},{%0,%1,%2,%3};"
                 : "+f"(d[0]), "+f"(d[1]), "+f"(d[2]), "+f"(d[3])
                 : "r"(a[0]), "r"(a[1]), "r"(a[2]), "r"(a[3]), "r"(b0), "r"(b1));
}
__device__ __forceinline__ bf162 split2(float c0, float c1, bf162& lo) {
    bf16 h0 = __float2bfloat16(c0);
    bf16 h1 = __float2bfloat16(c1);
    bf16 l0 = __float2bfloat16(c0 - __bfloat162float(h0));
    bf16 l1 = __float2bfloat16(c1 - __bfloat162float(h1));
    lo = __halves2bfloat162(l0, l1);
    return __halves2bfloat162(h0, h1);
}

// ---------------- split-bf16 tensor-core GEMM (mma.sync) ---------------------
#define HG_STRIDE 40
#define HG_MAT (128*HG_STRIDE)
#define HG_BUF (4*HG_MAT)
#define HG_SMEM (2*HG_BUF*2)

template<int ACT, int OSPLIT>
__global__ void __launch_bounds__(256, 2)
hgemm(const bf16* __restrict__ Ah, const bf16* __restrict__ Al,
      const bf16* __restrict__ Bh, const bf16* __restrict__ Bl,
      const float* __restrict__ bias, const float* __restrict__ res,
      float* __restrict__ C, bf16* __restrict__ Ch, bf16* __restrict__ Cl,
      int M, int N, int K)
{
    extern __shared__ bf16 sm[];
    const int tid = threadIdx.x, wid = tid >> 5, lane = tid & 31;
    const int m0 = blockIdx.x * 128, n0 = blockIdx.y * 128;
    const int g = lane >> 2, t = lane & 3;
    const int wm0 = (wid >> 1) * 32, wn0 = (wid & 1) * 64;
    const uint32_t smbase = s2u(sm);
    const bf16* srcs[4] = {Ah, Al, Bh, Bl};

    float acc[2][8][4];
    #pragma unroll
    for (int i = 0; i < 2; ++i)
        #pragma unroll
        for (int j = 0; j < 8; ++j)
            #pragma unroll
            for (int u = 0; u < 4; ++u) acc[i][j][u] = 0.f;

    const int KC = K >> 5;
    const int srow = tid >> 1;

    auto issue = [&](int c) {
        int k0 = c << 5;
        int buf = c & 1;
        #pragma unroll
        for (int mat = 0; mat < 4; ++mat) {
            #pragma unroll
            for (int j = 0; j < 2; ++j) {
                int q = (tid & 1) * 2 + j;
                int grow = (mat < 2) ? (m0 + srow) : (n0 + srow);
                bool ok = (mat >= 2) || (grow < M);
                const bf16* gp = ok ? (srcs[mat] + (size_t)grow * K + k0 + q * 8) : srcs[mat];
                uint32_t sa = smbase + (uint32_t)(buf * HG_BUF + mat * HG_MAT + srow * HG_STRIDE + q * 8) * 2;
                cpa16(sa, gp, ok ? 16 : 0);
            }
        }
        asm volatile("cp.async.commit_group;" ::: "memory");
    };

    issue(0);
    for (int c = 0; c < KC; ++c) {
        if (c + 1 < KC) {
            issue(c + 1);
            asm volatile("cp.async.wait_group 1;" ::: "memory");
        } else {
            asm volatile("cp.async.wait_group 0;" ::: "memory");
        }
        __syncthreads();
        const bf16* bb = sm + (size_t)(c & 1) * HG_BUF;
        #pragma unroll
        for (int ks = 0; ks < 32; ks += 16) {
            uint32_t afr[2][2][4];
            #pragma unroll
            for (int v = 0; v < 2; ++v)
                #pragma unroll
                for (int mf = 0; mf < 2; ++mf) {
                    const bf16* pa = bb + v * HG_MAT + (wm0 + mf * 16 + g) * HG_STRIDE + ks + 2 * t;
                    afr[v][mf][0] = *(const uint32_t*)pa;
                    afr[v][mf][1] = *(const uint32_t*)(pa + 8 * HG_STRIDE);
                    afr[v][mf][2] = *(const uint32_t*)(pa + 8);
                    afr[v][mf][3] = *(const uint32_t*)(pa + 8 * HG_STRIDE + 8);
                }
            #pragma unroll
            for (int nf = 0; nf < 8; ++nf) {
                const bf16* pbh = bb + 2 * HG_MAT + (wn0 + nf * 8 + g) * HG_STRIDE + ks + 2 * t;
                const bf16* pbl = pbh + HG_MAT;
                uint32_t bh0 = *(const uint32_t*)pbh;
                uint32_t bh1 = *(const uint32_t*)(pbh + 8);
                uint32_t bl0 = *(const uint32_t*)pbl;
                uint32_t bl1 = *(const uint32_t*)(pbl + 8);
                #pragma unroll
                for (int mf = 0; mf < 2; ++mf) {
                    mma16816(acc[mf][nf], afr[0][mf], bh0, bh1);
                    mma16816(acc[mf][nf], afr[0][mf], bl0, bl1);
                    mma16816(acc[mf][nf], afr[1][mf], bh0, bh1);
                }
            }
        }
        __syncthreads();
    }

    #pragma unroll
    for (int mf = 0; mf < 2; ++mf) {
        #pragma unroll
        for (int rr = 0; rr < 2; ++rr) {
            int row = m0 + wm0 + mf * 16 + g + rr * 8;
            if (row >= M) continue;
            #pragma unroll
            for (int nf = 0; nf < 8; ++nf) {
                int col = n0 + wn0 + nf * 8 + 2 * t;
                float c0 = acc[mf][nf][rr * 2 + 0] + bias[col];
                float c1 = acc[mf][nf][rr * 2 + 1] + bias[col + 1];
                if (ACT) { c0 = geluf(c0); c1 = geluf(c1); }
                if (OSPLIT) {
                    bf162 lo;
                    bf162 hi = split2(c0, c1, lo);
                    *(bf162*)(Ch + (size_t)row * N + col) = hi;
                    *(bf162*)(Cl + (size_t)row * N + col) = lo;
                } else {
                    if (res) {
                        c0 += res[(size_t)row * N + col];
                        c1 += res[(size_t)row * N + col + 1];
                    }
                    *(float2*)(C + (size_t)row * N + col) = make_float2(c0, c1);
                }
            }
        }
    }
}

// ---------------- attention scores via mma: S = QK^T / 8 ---------------------
#define SC_STR 72
#define SC_MAT (128*SC_STR)
#define SC_SMEM (4*SC_MAT*2)
__global__ void __launch_bounds__(256, 1)
scores_mma(const bf16* __restrict__ qh, const bf16* __restrict__ ql,
           const bf16* __restrict__ kh, const bf16* __restrict__ kl,
           int w, int r, int gsz, int n)
{
    extern __shared__ bf16 sm[];
    const int tid = threadIdx.x, wid = tid >> 5, lane = tid & 31;
    const int g = lane >> 2, t = lane & 3;
    const int wm0 = (wid >> 1) * 32, wn0 = (wid & 1) * 64;
    int z = blockIdx.z;
    int hd = z % HH;
    int seg = (z / HH) % n;
    int bb_ = z / (HH * n);
    int off = hd / gsz;
    int m0 = blockIdx.x * 128, n0 = blockIdx.y * 128;
    const uint32_t smb = s2u(sm);
    const bf16* srcs[4] = {qh, ql, kh, kl};

    #pragma unroll
    for (int it = 0; it < 16; ++it) {
        int idx = it * 256 + tid;
        int mat = idx >> 10;
        int rg = idx & 1023;
        int row = rg >> 3, q8 = rg & 7;
        int base = (mat < 2) ? m0 : n0;
        int pos = seg * w + (base + row) * r + off;
        bool ok = pos < LV;
        const bf16* gp = ok ? (srcs[mat] + ((size_t)(bb_ * LV) + pos) * EV + hd * DHv + q8 * 8)
                            : srcs[mat];
        cpa16(smb + (uint32_t)(mat * SC_MAT + row * SC_STR + q8 * 8) * 2, gp, ok ? 16 : 0);
    }
    asm volatile("cp.async.commit_group;" ::: "memory");
    asm volatile("cp.async.wait_group 0;" ::: "memory");
    __syncthreads();

    float acc[2][8][4];
    #pragma unroll
    for (int i = 0; i < 2; ++i)
        #pragma unroll
        for (int j = 0; j < 8; ++j)
            #pragma unroll
            for (int u = 0; u < 4; ++u) acc[i][j][u] = 0.f;

    #pragma unroll
    for (int ks = 0; ks < 64; ks += 16) {
        uint32_t afr[2][2][4];
        #pragma unroll
        for (int v = 0; v < 2; ++v)
            #pragma unroll
            for (int mf = 0; mf < 2; ++mf) {
                const bf16* pa = sm + v * SC_MAT + (wm0 + mf * 16 + g) * SC_STR + ks + 2 * t;
                afr[v][mf][0] = *(const uint32_t*)pa;
                afr[v][mf][1] = *(const uint32_t*)(pa + 8 * SC_STR);
                afr[v][mf][2] = *(const uint32_t*)(pa + 8);
                afr[v][mf][3] = *(const uint32_t*)(pa + 8 * SC_STR + 8);
            }
        #pragma unroll
        for (int nf = 0; nf < 8; ++nf) {
            const bf16* pbh = sm + 2 * SC_MAT + (wn0 + nf * 8 + g) * SC_STR + ks + 2 * t;
            const bf16* pbl = pbh + SC_MAT;
            uint32_t bh0 = *(const uint32_t*)pbh;
            uint32_t bh1 = *(const uint32_t*)(pbh + 8);
            uint32_t bl0 = *(const uint32_t*)pbl;
            uint32_t bl1 = *(const uint32_t*)(pbl + 8);
            #pragma unroll
            for (int mf = 0; mf < 2; ++mf) {
                mma16816(acc[mf][nf], afr[0][mf], bh0, bh1);
                mma16816(acc[mf][nf], afr[0][mf], bl0, bl1);
                mma16816(acc[mf][nf], afr[1][mf], bh0, bh1);
            }
        }
    }

    float* Sp = g_S + (size_t)z * 589824;
    #pragma unroll
    for (int mf = 0; mf < 2; ++mf)
        #pragma unroll
        for (int rr = 0; rr < 2; ++rr) {
            int row = m0 + wm0 + mf * 16 + g + rr * 8;
            #pragma unroll
            for (int nf = 0; nf < 8; ++nf) {
                int col = n0 + wn0 + nf * 8 + 2 * t;
                *(float2*)(Sp + (size_t)row * 768 + col) =
                    make_float2(acc[mf][nf][rr*2] * 0.125f, acc[mf][nf][rr*2+1] * 0.125f);
            }
        }
}

// ---------------- softmax: fp32 S -> bf16 hi/lo P + lse ----------------------
__global__ void softmax_kernel(int lseBase)
{
    int row = blockIdx.x;
    const float* sr = g_S + (size_t)row * 768;
    bf16* ph = g_ph + (size_t)row * 768;
    bf16* pl = g_pl + (size_t)row * 768;
    int tid = threadIdx.x;
    float v0 = sr[tid], v1 = sr[tid + 256], v2 = sr[tid + 512];
    float mx = fmaxf(v0, fmaxf(v1, v2));
    __shared__ float shA[8], shB[8];
    mx = warpMax(mx);
    int lane = tid & 31, wid = tid >> 5;
    if (lane == 0) shA[wid] = mx;
    __syncthreads();
    if (tid == 0) {
        float m = shA[0];
        #pragma unroll
        for (int i = 1; i < 8; ++i) m = fmaxf(m, shA[i]);
        shA[0] = m;
    }
    __syncthreads();
    mx = shA[0];
    float e0 = expf(v0 - mx), e1 = expf(v1 - mx), e2 = expf(v2 - mx);
    float s = warpSum(e0 + e1 + e2);
    if (lane == 0) shB[wid] = s;
    __syncthreads();
    if (tid == 0) {
        float a = 0;
        #pragma unroll
        for (int i = 0; i < 8; ++i) a += shB[i];
        shB[0] = a;
    }
    __syncthreads();
    s = shB[0];
    float inv = 1.f / s;
    float p[3] = {e0 * inv, e1 * inv, e2 * inv};
    #pragma unroll
    for (int u = 0; u < 3; ++u) {
        bf16 hh_ = __float2bfloat16(p[u]);
        bf16 ll_ = __float2bfloat16(p[u] - __bfloat162float(hh_));
        ph[tid + u * 256] = hh_;
        pl[tid + u * 256] = ll_;
    }
    if (tid == 0) g_lse[(size_t)lseBase * 768 + row] = mx + logf(s);
}

// ---------------- PV via mma: O = P @ V (gathered V transposed in smem) ------
#define PV_PSTR 72
#define PV_PMAT (128*PV_PSTR)
#define PV_VSTR 72
#define PV_VMAT (64*PV_VSTR)
#define PV_SMEM ((2*PV_PMAT + 2*PV_VMAT)*2)
__global__ void __launch_bounds__(256, 2)
pv_mma(const bf16* __restrict__ vh, const bf16* __restrict__ vl,
       int w, int r, int gsz, int n, int ub)
{
    extern __shared__ bf16 sm[];
    const int tid = threadIdx.x, wid = tid >> 5, lane = tid & 31;
    const int g = lane >> 2, t = lane & 3;
    const int wm0 = (wid >> 1) * 32, wn0 = (wid & 1) * 32;
    int z = blockIdx.z;
    int hd = z % HH;
    int seg = (z / HH) % n;
    int bb_ = z / (HH * n);
    int off = hd / gsz;
    int qbase = blockIdx.x * 128;
    const uint32_t smb = s2u(sm);
    const bf16* Phg = g_ph + (size_t)z * 589824;
    const bf16* Plg = g_pl + (size_t)z * 589824;
    bf16* VTH = sm + 2 * PV_PMAT;
    bf16* VTL = VTH + PV_VMAT;

    float acc[2][4][4];
    #pragma unroll
    for (int i = 0; i < 2; ++i)
        #pragma unroll
        for (int j = 0; j < 4; ++j)
            #pragma unroll
            for (int u = 0; u < 4; ++u) acc[i][j][u] = 0.f;

    const int kk = tid >> 2;          // key index within chunk
    const int d0 = (tid & 3) * 16;    // d-range start

    for (int kt = 0; kt < 12; ++kt) {
        int k0 = kt * 64;
        // P chunk via cp.async
        #pragma unroll
        for (int it = 0; it < 8; ++it) {
            int idx = it * 256 + tid;
            int mat = idx >> 10;
            int rg = idx & 1023;
            int row = rg >> 3, q8 = rg & 7;
            const bf16* gp = (mat ? Plg : Phg) + (size_t)(qbase + row) * 768 + k0 + q8 * 8;
            cpa16(smb + (uint32_t)(mat * PV_PMAT + row * PV_PSTR + q8 * 8) * 2, gp, 16);
        }
        asm volatile("cp.async.commit_group;" ::: "memory");

        // V chunk: gather rows, transpose into smem
        {
            int pos = seg * w + (k0 + kk) * r + off;
            bool ok = pos < LV;
            uint4 h0 = make_uint4(0,0,0,0), h1 = h0, l0 = h0, l1 = h0;
            if (ok) {
                const bf16* pvh = vh + ((size_t)(bb_ * LV) + pos) * EV + hd * DHv + d0;
                const bf16* pvl = vl + ((size_t)(bb_ * LV) + pos) * EV + hd * DHv + d0;
                h0 = *(const uint4*)pvh; h1 = *(const uint4*)(pvh + 8);
                l0 = *(const uint4*)pvl; l1 = *(const uint4*)(pvl + 8);
            }
            bf16 bufh[16], bufl[16];
            *(uint4*)&bufh[0] = h0; *(uint4*)&bufh[8] = h1;
            *(uint4*)&bufl[0] = l0; *(uint4*)&bufl[8] = l1;
            #pragma unroll
            for (int j = 0; j < 16; ++j) {
                int jj = (j + kk) & 15;                 // stagger to reduce conflicts
                VTH[(d0 + jj) * PV_VSTR + kk] = bufh[jj];
                VTL[(d0 + jj) * PV_VSTR + kk] = bufl[jj];
            }
        }
        asm volatile("cp.async.wait_group 0;" ::: "memory");
        __syncthreads();

        #pragma unroll
        for (int ks = 0; ks < 64; ks += 16) {
            uint32_t afr[2][2][4];
            #pragma unroll
            for (int v = 0; v < 2; ++v)
                #pragma unroll
                for (int mf = 0; mf < 2; ++mf) {
                    const bf16* pa = sm + v * PV_PMAT + (wm0 + mf * 16 + g) * PV_PSTR + ks + 2 * t;
                    afr[v][mf][0] = *(const uint32_t*)pa;
                    afr[v][mf][1] = *(const uint32_t*)(pa + 8 * PV_PSTR);
                    afr[v][mf][2] = *(const uint32_t*)(pa + 8);
                    afr[v][mf][3] = *(const uint32_t*)(pa + 8 * PV_PSTR + 8);
                }
            #pragma unroll
            for (int nf = 0; nf < 4; ++nf) {
                const bf16* pbh = VTH + (wn0 + nf * 8 + g) * PV_VSTR + ks + 2 * t;
                const bf16* pbl = VTL + (wn0 + nf * 8 + g) * PV_VSTR + ks + 2 * t;
                uint32_t bh0 = *(const uint32_t*)pbh;
                uint32_t bh1 = *(const uint32_t*)(pbh + 8);
                uint32_t bl0 = *(const uint32_t*)pbl;
                uint32_t bl1 = *(const uint32_t*)(pbl + 8);
                #pragma unroll
                for (int mf = 0; mf < 2; ++mf) {
                    mma16816(acc[mf][nf], afr[0][mf], bh0, bh1);
                    mma16816(acc[mf][nf], afr[0][mf], bl0, bl1);
                    mma16816(acc[mf][nf], afr[1][mf], bh0, bh1);
                }
            }
        }
        __syncthreads();
    }

    float* Op = g_obr + (size_t)(ub + z) * 49152;
    #pragma unroll
    for (int mf = 0; mf < 2; ++mf)
        #pragma unroll
        for (int rr = 0; rr < 2; ++rr) {
            int row = qbase + wm0 + mf * 16 + g + rr * 8;
            #pragma unroll
            for (int nf = 0; nf < 4; ++nf) {
                int col = wn0 + nf * 8 + 2 * t;
                *(float2*)(Op + (size_t)row * 64 + col) =
                    make_float2(acc[mf][nf][rr*2], acc[mf][nf][rr*2+1]);
            }
        }
}

// ---------------- misc kernels ------------------------------------------------
__global__ void im2col_split(const float* __restrict__ x) {
    int idx = blockIdx.x * 256 + threadIdx.x;
    if (idx >= BV * NP * 1024) return;
    int kk = idx & 1023;
    int p  = (idx >> 10) % NP;
    int b  = (idx >> 10) / NP;
    int pw_ = kk & 15, ph_ = (kk >> 4) & 15, pd_ = kk >> 8;
    int bz = p & 15, by = (p >> 4) & 15, bx = p >> 8;
    float v = x[(((size_t)b * 48 + bx * 4 + pd_) * 256 + by * 16 + ph_) * 256 + bz * 16 + pw_];
    bf16 h = __float2bfloat16(v);
    g_colh[idx] = h;
    g_coll[idx] = __float2bfloat16(v - __bfloat162float(h));
}

__global__ void assemble_kernel(const float* __restrict__ cls, const float* __restrict__ pos) {
    size_t idx = (size_t)blockIdx.x * 256 + threadIdx.x;
    if (idx >= (size_t)ML * EV) return;
    int e = idx % EV;
    size_t t = idx / EV;
    int l = (int)(t % LV);
    int b = (int)(t / LV);
    float v;
    if (l == 0) v = cls[e] + pos[e];
    else        v = g_hn[((size_t)b * NP + (l - 1)) * EV + e] + pos[(size_t)l * EV + e];
    g_h[idx] = v;
}

template<int SPLIT>
__global__ void layernorm_kernel(const float* __restrict__ x, const float* __restrict__ g,
                                 const float* __restrict__ bta, float* __restrict__ y,
                                 bf16* __restrict__ yh, bf16* __restrict__ yl)
{
    int row = blockIdx.x;
    const float* xr = x + (size_t)row * EV;
    int tid = threadIdx.x;
    float v0 = xr[tid], v1 = xr[tid + 256], v2 = xr[tid + 512];
    float s = v0 + v1 + v2;
    float s2 = v0 * v0 + v1 * v1 + v2 * v2;
    __shared__ float shA[8], shB[8];
    float ws = warpSum(s), ws2 = warpSum(s2);
    int lane = tid & 31, wid = tid >> 5;
    if (lane == 0) { shA[wid] = ws; shB[wid] = ws2; }
    __syncthreads();
    if (tid == 0) {
        float a = 0, bb = 0;
        #pragma unroll
        for (int i = 0; i < 8; ++i) { a += shA[i]; bb += shB[i]; }
        shA[0] = a; shB[0] = bb;
    }
    __syncthreads();
    float mu = shA[0] * (1.f / 768.f);
    float var = shB[0] * (1.f / 768.f) - mu * mu;
    float inv = rsqrtf(var + 1e-5f);
    float o[3] = {v0, v1, v2};
    #pragma unroll
    for (int u = 0; u < 3; ++u) {
        int e = tid + u * 256;
        float c = (o[u] - mu) * inv * g[e] + bta[e];
        if (SPLIT) {
            bf16 h = __float2bfloat16(c);
            yh[(size_t)row * EV + e] = h;
            yl[(size_t)row * EV + e] = __float2bfloat16(c - __bfloat162float(h));
        } else {
            y[(size_t)row * EV + e] = c;
        }
    }
}

__global__ void combine_kernel()
{
    int blk = blockIdx.x;
    int hd = blk % HH;
    int p = (blk / HH) % LV;
    int b = blk / (HH * LV);
    int d = threadIdx.x;
    const int ws[5] = {768, 1536, 3072, 6144, 12288};
    const int rs[5] = {1, 2, 4, 8, 16};
    const int gs[5] = {12, 6, 3, 2, 1};
    const int ns[5] = {5, 3, 2, 1, 1};
    const int ub[5] = {0, 120, 192, 240, 264};
    float lses[5];
    size_t oix[5];
    bool cov[5];
    float mx = -1e30f;
    #pragma unroll
    for (int br = 0; br < 5; ++br) {
        int seg = p / ws[br];
        int jj = p - seg * ws[br];
        int off = hd / gs[br];
        int rr = jj & (rs[br] - 1);
        cov[br] = (rr == off);
        if (cov[br]) {
            int j = jj / rs[br];
            int unit = ub[br] + (b * ns[br] + seg) * HH + hd;
            lses[br] = g_lse[(size_t)unit * 768 + j];
            oix[br] = (size_t)unit * 49152 + (size_t)j * 64;
            mx = fmaxf(mx, lses[br]);
        }
    }
    float sw = 0.f, out = 0.f;
    #pragma unroll
    for (int br = 0; br < 5; ++br) {
        if (cov[br]) {
            float wgt = expf(lses[br] - mx);
            sw += wgt;
            out += wgt * g_obr[oix[br] + d];
        }
    }
    float c = out / sw;
    size_t o = ((size_t)(b * LV + p)) * EV + hd * DHv + d;
    bf16 h = __float2bfloat16(c);
    g_oh[o] = h;
    g_ol[o] = __float2bfloat16(c - __bfloat162float(h));
}

__global__ void head_kernel(const float* __restrict__ hn, const float* __restrict__ W,
                            const float* __restrict__ bias, float* __restrict__ out)
{
    int nidx = blockIdx.x * blockDim.x + threadIdx.x;
    int b = blockIdx.y;
    if (nidx >= 1000) return;
    const float* row = hn + (size_t)b * LV * EV;
    float acc = bias[nidx];
    for (int e = 0; e < EV; ++e) acc = fmaf(row[e], W[(size_t)e * 1000 + nidx], acc);
    out[b * 1000 + nidx] = acc;
}

// weight transpose+split: (K,N) fp32 -> (N,K) bf16 hi/lo
__global__ void splitT(const float* __restrict__ w, bf16* __restrict__ oh,
                       bf16* __restrict__ ol, int K, int N)
{
    __shared__ float t[32][33];
    int kb = blockIdx.x * 32, nb = blockIdx.y * 32;
    int x = threadIdx.x, y = threadIdx.y;
    #pragma unroll
    for (int i = 0; i < 32; i += 8)
        t[y + i][x] = w[(size_t)(kb + y + i) * N + nb + x];
    __syncthreads();
    #pragma unroll
    for (int i = 0; i < 32; i += 8) {
        float v = t[x][y + i];
        bf16 h = __float2bfloat16(v);
        bf16 l = __float2bfloat16(v - __bfloat162float(h));
        size_t o = (size_t)(nb + y + i) * K + kb + x;
        oh[o] = h; ol[o] = l;
    }
}

__global__ void split_copy(const float* __restrict__ s, bf16* __restrict__ oh,
                           bf16* __restrict__ ol, long n)
{
    long i = ((long)blockIdx.x * 256 + threadIdx.x) * 4;
    if (i >= n) return;
    float4 v = *(const float4*)(s + i);
    float vv[4] = {v.x, v.y, v.z, v.w};
    #pragma unroll
    for (int u = 0; u < 4; ++u) {
        bf16 h = __float2bfloat16(vv[u]);
        oh[i + u] = h;
        ol[i + u] = __float2bfloat16(vv[u] - __bfloat162float(h));
    }
}

// ---------------- host orchestration ------------------------------------------
extern "C" void kernel_launch(void* const* d_in, const int* in_sizes, int n_in,
                              void* d_out, int out_size)
{
    (void)in_sizes; (void)n_in; (void)out_size;
    const float* x        = (const float*)d_in[0];
    const float* patch_w  = (const float*)d_in[1];
    const float* patch_b  = (const float*)d_in[2];
    const float* cls_tok  = (const float*)d_in[3];
    const float* pos_emb  = (const float*)d_in[4];
    const float* ln1_g    = (const float*)d_in[5];
    const float* ln1_b    = (const float*)d_in[6];
    const float* wq       = (const float*)d_in[7];
    const float* bq       = (const float*)d_in[8];
    const float* wk       = (const float*)d_in[9];
    const float* bk       = (const float*)d_in[10];
    const float* wv       = (const float*)d_in[11];
    const float* bv_      = (const float*)d_in[12];
    const float* wo       = (const float*)d_in[13];
    const float* bo       = (const float*)d_in[14];
    const float* ln2_g    = (const float*)d_in[15];
    const float* ln2_b    = (const float*)d_in[16];
    const float* w1       = (const float*)d_in[17];
    const float* b1       = (const float*)d_in[18];
    const float* w2       = (const float*)d_in[19];
    const float* b2       = (const float*)d_in[20];
    const float* normf_g  = (const float*)d_in[21];
    const float* normf_b  = (const float*)d_in[22];
    const float* head_w   = (const float*)d_in[23];
    const float* head_b   = (const float*)d_in[24];
    float* out = (float*)d_out;

    float *p_h, *p_hn;
    bf16 *p_colh, *p_coll, *p_qh, *p_ql, *p_kh, *p_kl, *p_vh, *p_vl;
    bf16 *p_xh, *p_xl, *p_m1h, *p_m1l, *p_oh, *p_ol, *p_wh, *p_wl;
    cudaGetSymbolAddress((void**)&p_h, g_h);
    cudaGetSymbolAddress((void**)&p_hn, g_hn);
    cudaGetSymbolAddress((void**)&p_colh, g_colh);
    cudaGetSymbolAddress((void**)&p_coll, g_coll);
    cudaGetSymbolAddress((void**)&p_qh, g_qh);
    cudaGetSymbolAddress((void**)&p_ql, g_ql);
    cudaGetSymbolAddress((void**)&p_kh, g_kh);
    cudaGetSymbolAddress((void**)&p_kl, g_kl);
    cudaGetSymbolAddress((void**)&p_vh, g_vh);
    cudaGetSymbolAddress((void**)&p_vl, g_vl);
    cudaGetSymbolAddress((void**)&p_xh, g_xh);
    cudaGetSymbolAddress((void**)&p_xl, g_xl);
    cudaGetSymbolAddress((void**)&p_m1h, g_m1h);
    cudaGetSymbolAddress((void**)&p_m1l, g_m1l);
    cudaGetSymbolAddress((void**)&p_oh, g_oh);
    cudaGetSymbolAddress((void**)&p_ol, g_ol);
    cudaGetSymbolAddress((void**)&p_wh, g_wh);
    cudaGetSymbolAddress((void**)&p_wl, g_wl);

    cudaFuncSetAttribute(hgemm<0,0>, cudaFuncAttributeMaxDynamicSharedMemorySize, HG_SMEM);
    cudaFuncSetAttribute(hgemm<0,1>, cudaFuncAttributeMaxDynamicSharedMemorySize, HG_SMEM);
    cudaFuncSetAttribute(hgemm<1,1>, cudaFuncAttributeMaxDynamicSharedMemorySize, HG_SMEM);
    cudaFuncSetAttribute(scores_mma, cudaFuncAttributeMaxDynamicSharedMemorySize, SC_SMEM);
    cudaFuncSetAttribute(pv_mma, cudaFuncAttributeMaxDynamicSharedMemorySize, PV_SMEM);

    const int ws[5] = {768, 1536, 3072, 6144, 12288};
    const int rs[5] = {1, 2, 4, 8, 16};
    const int gs[5] = {12, 6, 3, 2, 1};
    const int ns[5] = {5, 3, 2, 1, 1};
    const int ub[5] = {0, 120, 192, 240, 264};

    // ---- weight prep ----------------------------------------------------------
    const size_t LSZ = 7077888;
    {
        long n = 786432;
        split_copy<<<(int)((n/4 + 255) / 256), 256>>>(patch_w, p_wh, p_wl, n);
    }
    for (int l = 0; l < 2; ++l) {
        size_t base = 786432 + (size_t)l * LSZ;
        size_t oEE = (size_t)l * EV * EV;
        size_t oE4 = (size_t)l * EV * 3072;
        dim3 blk(32, 8);
        splitT<<<dim3(24, 24), blk>>>(wq + oEE, p_wh + base,           p_wl + base,           768, 768);
        splitT<<<dim3(24, 24), blk>>>(wk + oEE, p_wh + base + 589824,  p_wl + base + 589824,  768, 768);
        splitT<<<dim3(24, 24), blk>>>(wv + oEE, p_wh + base + 1179648, p_wl + base + 1179648, 768, 768);
        splitT<<<dim3(24, 24), blk>>>(wo + oEE, p_wh + base + 1769472, p_wl + base + 1769472, 768, 768);
        splitT<<<dim3(24, 96), blk>>>(w1 + oE4, p_wh + base + 2359296, p_wl + base + 2359296, 768, 3072);
        splitT<<<dim3(96, 24), blk>>>(w2 + oE4, p_wh + base + 4718592, p_wl + base + 4718592, 3072, 768);
    }

    // ---- patch embed ------------------------------------------------------------
    im2col_split<<<(BV * NP * 1024 + 255) / 256, 256>>>(x);
    hgemm<0,0><<<dim3(48, 6), 256, HG_SMEM>>>(p_colh, p_coll, p_wh, p_wl,
                                              patch_b, nullptr, p_hn, nullptr, nullptr,
                                              BV * NP, EV, 1024);
    assemble_kernel<<<(int)(((size_t)ML * EV + 255) / 256), 256>>>(cls_tok, pos_emb);

    dim3 gEEt(49, 6);
    dim3 gE4t(49, 24);

    for (int layer = 0; layer < 2; ++layer) {
        size_t base = 786432 + (size_t)layer * LSZ;
        size_t oE  = (size_t)layer * EV;
        size_t o4  = (size_t)layer * 3072;

        layernorm_kernel<1><<<ML, 256>>>(p_h, ln1_g + oE, ln1_b + oE, nullptr, p_xh, p_xl);
        hgemm<0,1><<<gEEt, 256, HG_SMEM>>>(p_xh, p_xl, p_wh + base,           p_wl + base,           bq + oE,  nullptr, nullptr, p_qh, p_ql, ML, EV, EV);
        hgemm<0,1><<<gEEt, 256, HG_SMEM>>>(p_xh, p_xl, p_wh + base + 589824,  p_wl + base + 589824,  bk + oE,  nullptr, nullptr, p_kh, p_kl, ML, EV, EV);
        hgemm<0,1><<<gEEt, 256, HG_SMEM>>>(p_xh, p_xl, p_wh + base + 1179648, p_wl + base + 1179648, bv_ + oE, nullptr, nullptr, p_vh, p_vl, ML, EV, EV);

        for (int br = 0; br < 5; ++br) {
            int units = BV * ns[br] * HH;
            dim3 gsc(6, 6, units);
            scores_mma<<<gsc, 256, SC_SMEM>>>(p_qh, p_ql, p_kh, p_kl, ws[br], rs[br], gs[br], ns[br]);
            softmax_kernel<<<units * 768, 256>>>(ub[br]);
            dim3 gpv(6, 1, units);
            pv_mma<<<gpv, 256, PV_SMEM>>>(p_vh, p_vl, ws[br], rs[br], gs[br], ns[br], ub[br]);
        }
        combine_kernel<<<BV * LV * HH, 64>>>();

        hgemm<0,0><<<gEEt, 256, HG_SMEM>>>(p_oh, p_ol, p_wh + base + 1769472, p_wl + base + 1769472, bo + oE, p_h, p_h, nullptr, nullptr, ML, EV, EV);

        layernorm_kernel<1><<<ML, 256>>>(p_h, ln2_g + oE, ln2_b + oE, nullptr, p_xh, p_xl);
        hgemm<1,1><<<gE4t, 256, HG_SMEM>>>(p_xh, p_xl, p_wh + base + 2359296, p_wl + base + 2359296, b1 + o4, nullptr, nullptr, p_m1h, p_m1l, ML, 3072, EV);
        hgemm<0,0><<<gEEt, 256, HG_SMEM>>>(p_m1h, p_m1l, p_wh + base + 4718592, p_wl + base + 4718592, b2 + oE, p_h, p_h, nullptr, nullptr, ML, EV, 3072);
    }

    layernorm_kernel<0><<<ML, 256>>>(p_h, normf_g, normf_b, p_hn, nullptr, nullptr);
    head_kernel<<<dim3(4, BV), 256>>>(p_hn, head_w, head_b, out);
}

// round 7
// speedup vs baseline: 4.4674x; 1.2281x over previous
#include <cuda_runtime.h>
#include <cuda_bf16.h>
#include <math.h>
#include <stdint.h>

#define BV 2
#define LV 3073
#define EV 768
#define HH 12
#define DHv 64
#define ML (BV*LV)          // 6146 rows
#define NP 3072             // patches per batch

typedef __nv_bfloat16 bf16;
typedef __nv_bfloat162 bf162;

// ---------------- scratch (device globals) -----------------------------------
__device__ float g_h  [(size_t)ML*EV];
__device__ float g_hn [(size_t)ML*EV];
__device__ float g_obr[(size_t)288*768*64];
__device__ float g_lse[(size_t)288*768];
__device__ __align__(16) bf16 g_colh[(size_t)BV*NP*1024];
__device__ __align__(16) bf16 g_coll[(size_t)BV*NP*1024];
__device__ __align__(16) bf16 g_qh[(size_t)ML*EV];
__device__ __align__(16) bf16 g_ql[(size_t)ML*EV];
__device__ __align__(16) bf16 g_kh[(size_t)ML*EV];
__device__ __align__(16) bf16 g_kl[(size_t)ML*EV];
__device__ __align__(16) bf16 g_vh[(size_t)ML*EV];
__device__ __align__(16) bf16 g_vl[(size_t)ML*EV];
__device__ __align__(16) bf16 g_xh[(size_t)ML*EV];
__device__ __align__(16) bf16 g_xl[(size_t)ML*EV];
__device__ __align__(16) bf16 g_m1h[(size_t)ML*3072];
__device__ __align__(16) bf16 g_m1l[(size_t)ML*3072];
__device__ __align__(16) bf16 g_oh[(size_t)ML*EV];
__device__ __align__(16) bf16 g_ol[(size_t)ML*EV];
#define WTOT 14942208
__device__ __align__(16) bf16 g_wh[WTOT];
__device__ __align__(16) bf16 g_wl[WTOT];

// ---------------- helpers -----------------------------------------------------
__device__ __forceinline__ float geluf(float v) {
    return 0.5f * v * (1.f + erff(v * 0.70710678118654752f));
}
__device__ __forceinline__ float warpSum(float v) {
    #pragma unroll
    for (int o = 16; o; o >>= 1) v += __shfl_xor_sync(0xffffffffu, v, o);
    return v;
}
__device__ __forceinline__ uint32_t s2u(const void* p) {
    uint32_t a;
    asm("{ .reg .u64 t; cvta.to.shared.u64 t, %1; cvt.u32.u64 %0, t; }" : "=r"(a) : "l"(p));
    return a;
}
__device__ __forceinline__ void cpa16(uint32_t saddr, const void* g, int sz) {
    asm volatile("cp.async.cg.shared.global [%0], [%1], 16, %2;"
                 :: "r"(saddr), "l"(g), "r"(sz) : "memory");
}
__device__ __forceinline__ void mma16816(float* d, const uint32_t* a, uint32_t b0, uint32_t b1) {
    asm volatile("mma.sync.aligned.m16n8k16.row.col.f32.bf16.bf16.f32 "
                 "{%0,%1,%2,%3},{%4,%5,%6,%7},{%8,%9},{%0,%1,%2,%3};"
                 : "+f"(d[0]), "+f"(d[1]), "+f"(d[2]), "+f"(d[3])
                 : "r"(a[0]), "r"(a[1]), "r"(a[2]), "r"(a[3]), "r"(b0), "r"(b1));
}
__device__ __forceinline__ bf162 split2(float c0, float c1, bf162& lo) {
    bf16 h0 = __float2bfloat16(c0);
    bf16 h1 = __float2bfloat16(c1);
    bf16 l0 = __float2bfloat16(c0 - __bfloat162float(h0));
    bf16 l1 = __float2bfloat16(c1 - __bfloat162float(h1));
    lo = __halves2bfloat162(l0, l1);
    return __halves2bfloat162(h0, h1);
}
__device__ __forceinline__ uint32_t pkbf(float c0, float c1, uint32_t& lo) {
    bf16 h0 = __float2bfloat16(c0);
    bf16 h1 = __float2bfloat16(c1);
    bf16 l0 = __float2bfloat16(c0 - __bfloat162float(h0));
    bf16 l1 = __float2bfloat16(c1 - __bfloat162float(h1));
    bf162 L = __halves2bfloat162(l0, l1);
    bf162 H = __halves2bfloat162(h0, h1);
    lo = *(uint32_t*)&L;
    return *(uint32_t*)&H;
}

// ---------------- split-bf16 tensor-core GEMM (mma.sync) ---------------------
#define HG_STRIDE 40
#define HG_MAT (128*HG_STRIDE)
#define HG_BUF (4*HG_MAT)
#define HG_SMEM (2*HG_BUF*2)

template<int ACT, int OSPLIT>
__global__ void __launch_bounds__(256, 2)
hgemm(const bf16* __restrict__ Ah, const bf16* __restrict__ Al,
      const bf16* __restrict__ Bh, const bf16* __restrict__ Bl,
      const float* __restrict__ bias, const float* __restrict__ res,
      float* __restrict__ C, bf16* __restrict__ Ch, bf16* __restrict__ Cl,
      int M, int N, int K)
{
    extern __shared__ bf16 sm[];
    const int tid = threadIdx.x, wid = tid >> 5, lane = tid & 31;
    const int m0 = blockIdx.x * 128, n0 = blockIdx.y * 128;
    const int g = lane >> 2, t = lane & 3;
    const int wm0 = (wid >> 1) * 32, wn0 = (wid & 1) * 64;
    const uint32_t smbase = s2u(sm);
    const bf16* srcs[4] = {Ah, Al, Bh, Bl};

    float acc[2][8][4];
    #pragma unroll
    for (int i = 0; i < 2; ++i)
        #pragma unroll
        for (int j = 0; j < 8; ++j)
            #pragma unroll
            for (int u = 0; u < 4; ++u) acc[i][j][u] = 0.f;

    const int KC = K >> 5;
    const int srow = tid >> 1;

    auto issue = [&](int c) {
        int k0 = c << 5;
        int buf = c & 1;
        #pragma unroll
        for (int mat = 0; mat < 4; ++mat) {
            #pragma unroll
            for (int j = 0; j < 2; ++j) {
                int q = (tid & 1) * 2 + j;
                int grow = (mat < 2) ? (m0 + srow) : (n0 + srow);
                bool ok = (mat >= 2) || (grow < M);
                const bf16* gp = ok ? (srcs[mat] + (size_t)grow * K + k0 + q * 8) : srcs[mat];
                uint32_t sa = smbase + (uint32_t)(buf * HG_BUF + mat * HG_MAT + srow * HG_STRIDE + q * 8) * 2;
                cpa16(sa, gp, ok ? 16 : 0);
            }
        }
        asm volatile("cp.async.commit_group;" ::: "memory");
    };

    issue(0);
    for (int c = 0; c < KC; ++c) {
        if (c + 1 < KC) {
            issue(c + 1);
            asm volatile("cp.async.wait_group 1;" ::: "memory");
        } else {
            asm volatile("cp.async.wait_group 0;" ::: "memory");
        }
        __syncthreads();
        const bf16* bb = sm + (size_t)(c & 1) * HG_BUF;
        #pragma unroll
        for (int ks = 0; ks < 32; ks += 16) {
            uint32_t afr[2][2][4];
            #pragma unroll
            for (int v = 0; v < 2; ++v)
                #pragma unroll
                for (int mf = 0; mf < 2; ++mf) {
                    const bf16* pa = bb + v * HG_MAT + (wm0 + mf * 16 + g) * HG_STRIDE + ks + 2 * t;
                    afr[v][mf][0] = *(const uint32_t*)pa;
                    afr[v][mf][1] = *(const uint32_t*)(pa + 8 * HG_STRIDE);
                    afr[v][mf][2] = *(const uint32_t*)(pa + 8);
                    afr[v][mf][3] = *(const uint32_t*)(pa + 8 * HG_STRIDE + 8);
                }
            #pragma unroll
            for (int nf = 0; nf < 8; ++nf) {
                const bf16* pbh = bb + 2 * HG_MAT + (wn0 + nf * 8 + g) * HG_STRIDE + ks + 2 * t;
                const bf16* pbl = pbh + HG_MAT;
                uint32_t bh0 = *(const uint32_t*)pbh;
                uint32_t bh1 = *(const uint32_t*)(pbh + 8);
                uint32_t bl0 = *(const uint32_t*)pbl;
                uint32_t bl1 = *(const uint32_t*)(pbl + 8);
                #pragma unroll
                for (int mf = 0; mf < 2; ++mf) {
                    mma16816(acc[mf][nf], afr[0][mf], bh0, bh1);
                    mma16816(acc[mf][nf], afr[0][mf], bl0, bl1);
                    mma16816(acc[mf][nf], afr[1][mf], bh0, bh1);
                }
            }
        }
        __syncthreads();
    }

    #pragma unroll
    for (int mf = 0; mf < 2; ++mf) {
        #pragma unroll
        for (int rr = 0; rr < 2; ++rr) {
            int row = m0 + wm0 + mf * 16 + g + rr * 8;
            if (row >= M) continue;
            #pragma unroll
            for (int nf = 0; nf < 8; ++nf) {
                int col = n0 + wn0 + nf * 8 + 2 * t;
                float c0 = acc[mf][nf][rr * 2 + 0] + bias[col];
                float c1 = acc[mf][nf][rr * 2 + 1] + bias[col + 1];
                if (ACT) { c0 = geluf(c0); c1 = geluf(c1); }
                if (OSPLIT) {
                    bf162 lo;
                    bf162 hi = split2(c0, c1, lo);
                    *(bf162*)(Ch + (size_t)row * N + col) = hi;
                    *(bf162*)(Cl + (size_t)row * N + col) = lo;
                } else {
                    if (res) {
                        c0 += res[(size_t)row * N + col];
                        c1 += res[(size_t)row * N + col + 1];
                    }
                    *(float2*)(C + (size_t)row * N + col) = make_float2(c0, c1);
                }
            }
        }
    }
}

// ---------------- fused flash attention (per unit, 128-q tile) ---------------
// smem layout (halves): QH[128*72] QL KH[128*72] KL VTH[64*136] VTL
#define FA_QSTR 72
#define FA_VSTR 136
#define FA_QH 0
#define FA_QL 9216
#define FA_KH 18432
#define FA_KL 27648
#define FA_VTH 36864
#define FA_VTL 45568
#define FA_SMEM (54272*2)

__global__ void __launch_bounds__(256, 1)
fattn(const bf16* __restrict__ qh, const bf16* __restrict__ ql,
      const bf16* __restrict__ kh, const bf16* __restrict__ kl,
      const bf16* __restrict__ vh, const bf16* __restrict__ vl,
      int w, int r, int gsz, int n, int ub)
{
    extern __shared__ bf16 sm[];
    const int tid = threadIdx.x, wid = tid >> 5, lane = tid & 31;
    const int g = lane >> 2, t = lane & 3;
    int z = blockIdx.z;
    int hd = z % HH;
    int seg = (z / HH) % n;
    int bb_ = z / (HH * n);
    int off = hd / gsz;
    int m0 = blockIdx.x * 128;
    const uint32_t smb = s2u(sm);

    // ---- load Q tile (gathered, hi/lo) ----
    {
        const bf16* srcs[2] = {qh, ql};
        #pragma unroll
        for (int it = 0; it < 8; ++it) {
            int idx = it * 256 + tid;
            int mat = idx >> 10;
            int rg = idx & 1023;
            int row = rg >> 3, q8 = rg & 7;
            int pos = seg * w + (m0 + row) * r + off;
            bool ok = pos < LV;
            const bf16* gp = ok ? (srcs[mat] + ((size_t)(bb_ * LV) + pos) * EV + hd * DHv + q8 * 8)
                                : srcs[mat];
            cpa16(smb + (uint32_t)((mat ? FA_QL : FA_QH) + row * FA_QSTR + q8 * 8) * 2, gp, ok ? 16 : 0);
        }
        asm volatile("cp.async.commit_group;" ::: "memory");
        asm volatile("cp.async.wait_group 0;" ::: "memory");
        __syncthreads();
    }

    // ---- Q fragments into registers (rows wid*16 .. +16) ----
    uint32_t qfr[2][4][4];
    #pragma unroll
    for (int v = 0; v < 2; ++v)
        #pragma unroll
        for (int k4 = 0; k4 < 4; ++k4) {
            const bf16* pa = sm + (v ? FA_QL : FA_QH) + (wid * 16 + g) * FA_QSTR + k4 * 16 + 2 * t;
            qfr[v][k4][0] = *(const uint32_t*)pa;
            qfr[v][k4][1] = *(const uint32_t*)(pa + 8 * FA_QSTR);
            qfr[v][k4][2] = *(const uint32_t*)(pa + 8);
            qfr[v][k4][3] = *(const uint32_t*)(pa + 8 * FA_QSTR + 8);
        }

    float m_[2] = {-1e30f, -1e30f};
    float l_[2] = {0.f, 0.f};
    float acco[8][4];
    #pragma unroll
    for (int j = 0; j < 8; ++j)
        #pragma unroll
        for (int u = 0; u < 4; ++u) acco[j][u] = 0.f;

    const int kkey = tid >> 1;             // key within chunk (0..127)
    const int dbase = (tid & 1) * 32;      // dh range for V transpose

    for (int kt = 0; kt < 6; ++kt) {
        int n0 = kt * 128;
        __syncthreads();   // previous chunk's smem reads done

        // K chunk (gathered, hi/lo)
        {
            const bf16* srcs[2] = {kh, kl};
            #pragma unroll
            for (int it = 0; it < 8; ++it) {
                int idx = it * 256 + tid;
                int mat = idx >> 10;
                int rg = idx & 1023;
                int row = rg >> 3, q8 = rg & 7;
                int pos = seg * w + (n0 + row) * r + off;
                bool ok = pos < LV;
                const bf16* gp = ok ? (srcs[mat] + ((size_t)(bb_ * LV) + pos) * EV + hd * DHv + q8 * 8)
                                    : srcs[mat];
                cpa16(smb + (uint32_t)((mat ? FA_KL : FA_KH) + row * FA_QSTR + q8 * 8) * 2, gp, ok ? 16 : 0);
            }
            asm volatile("cp.async.commit_group;" ::: "memory");
        }
        // V chunk gathered + transposed (dh x key)
        {
            int pos = seg * w + (n0 + kkey) * r + off;
            bool ok = pos < LV;
            bf16 bufh[32], bufl[32];
            if (ok) {
                const bf16* pvh = vh + ((size_t)(bb_ * LV) + pos) * EV + hd * DHv + dbase;
                const bf16* pvl = vl + ((size_t)(bb_ * LV) + pos) * EV + hd * DHv + dbase;
                #pragma unroll
                for (int q = 0; q < 4; ++q) {
                    *(uint4*)&bufh[q * 8] = *(const uint4*)(pvh + q * 8);
                    *(uint4*)&bufl[q * 8] = *(const uint4*)(pvl + q * 8);
                }
            } else {
                #pragma unroll
                for (int q = 0; q < 4; ++q) {
                    *(uint4*)&bufh[q * 8] = make_uint4(0, 0, 0, 0);
                    *(uint4*)&bufl[q * 8] = make_uint4(0, 0, 0, 0);
                }
            }
            #pragma unroll
            for (int j = 0; j < 32; ++j) {
                int jj = (j + kkey) & 31;
                sm[FA_VTH + (dbase + jj) * FA_VSTR + kkey] = bufh[jj];
                sm[FA_VTL + (dbase + jj) * FA_VSTR + kkey] = bufl[jj];
            }
        }
        asm volatile("cp.async.wait_group 0;" ::: "memory");
        __syncthreads();

        // ---- S = Q K^T (3-pass), 16 rows x 128 keys per warp ----
        float accs[16][4];
        #pragma unroll
        for (int j = 0; j < 16; ++j)
            #pragma unroll
            for (int u = 0; u < 4; ++u) accs[j][u] = 0.f;
        #pragma unroll
        for (int k4 = 0; k4 < 4; ++k4) {
            int ks = k4 * 16;
            #pragma unroll
            for (int nf = 0; nf < 16; ++nf) {
                const bf16* pbh = sm + FA_KH + (nf * 8 + g) * FA_QSTR + ks + 2 * t;
                const bf16* pbl = sm + FA_KL + (nf * 8 + g) * FA_QSTR + ks + 2 * t;
                uint32_t bh0 = *(const uint32_t*)pbh;
                uint32_t bh1 = *(const uint32_t*)(pbh + 8);
                uint32_t bl0 = *(const uint32_t*)pbl;
                uint32_t bl1 = *(const uint32_t*)(pbl + 8);
                mma16816(accs[nf], qfr[0][k4], bh0, bh1);
                mma16816(accs[nf], qfr[0][k4], bl0, bl1);
                mma16816(accs[nf], qfr[1][k4], bh0, bh1);
            }
        }

        // ---- online softmax ----
        float mx0 = -1e30f, mx1 = -1e30f;
        #pragma unroll
        for (int nf = 0; nf < 16; ++nf) {
            #pragma unroll
            for (int u = 0; u < 4; ++u) accs[nf][u] *= 0.125f;
            mx0 = fmaxf(mx0, fmaxf(accs[nf][0], accs[nf][1]));
            mx1 = fmaxf(mx1, fmaxf(accs[nf][2], accs[nf][3]));
        }
        mx0 = fmaxf(mx0, __shfl_xor_sync(0xffffffffu, mx0, 1));
        mx0 = fmaxf(mx0, __shfl_xor_sync(0xffffffffu, mx0, 2));
        mx1 = fmaxf(mx1, __shfl_xor_sync(0xffffffffu, mx1, 1));
        mx1 = fmaxf(mx1, __shfl_xor_sync(0xffffffffu, mx1, 2));
        float mn0 = fmaxf(m_[0], mx0), mn1 = fmaxf(m_[1], mx1);
        float sc0 = expf(m_[0] - mn0), sc1 = expf(m_[1] - mn1);
        float sum0 = 0.f, sum1 = 0.f;
        #pragma unroll
        for (int nf = 0; nf < 16; ++nf) {
            accs[nf][0] = expf(accs[nf][0] - mn0);
            accs[nf][1] = expf(accs[nf][1] - mn0);
            accs[nf][2] = expf(accs[nf][2] - mn1);
            accs[nf][3] = expf(accs[nf][3] - mn1);
            sum0 += accs[nf][0] + accs[nf][1];
            sum1 += accs[nf][2] + accs[nf][3];
        }
        sum0 += __shfl_xor_sync(0xffffffffu, sum0, 1);
        sum0 += __shfl_xor_sync(0xffffffffu, sum0, 2);
        sum1 += __shfl_xor_sync(0xffffffffu, sum1, 1);
        sum1 += __shfl_xor_sync(0xffffffffu, sum1, 2);
        l_[0] = l_[0] * sc0 + sum0;
        l_[1] = l_[1] * sc1 + sum1;
        m_[0] = mn0; m_[1] = mn1;
        #pragma unroll
        for (int nf = 0; nf < 8; ++nf) {
            acco[nf][0] *= sc0; acco[nf][1] *= sc0;
            acco[nf][2] *= sc1; acco[nf][3] *= sc1;
        }

        // ---- O += P V (3-pass); S frags ARE the PV A-frags ----
        #pragma unroll
        for (int kb = 0; kb < 8; ++kb) {
            uint32_t ah[4], al[4];
            ah[0] = pkbf(accs[2*kb][0],   accs[2*kb][1],   al[0]);
            ah[1] = pkbf(accs[2*kb][2],   accs[2*kb][3],   al[1]);
            ah[2] = pkbf(accs[2*kb+1][0], accs[2*kb+1][1], al[2]);
            ah[3] = pkbf(accs[2*kb+1][2], accs[2*kb+1][3], al[3]);
            #pragma unroll
            for (int nf = 0; nf < 8; ++nf) {
                const bf16* pbh = sm + FA_VTH + (nf * 8 + g) * FA_VSTR + kb * 16 + 2 * t;
                const bf16* pbl = sm + FA_VTL + (nf * 8 + g) * FA_VSTR + kb * 16 + 2 * t;
                uint32_t bh0 = *(const uint32_t*)pbh;
                uint32_t bh1 = *(const uint32_t*)(pbh + 8);
                uint32_t bl0 = *(const uint32_t*)pbl;
                uint32_t bl1 = *(const uint32_t*)(pbl + 8);
                mma16816(acco[nf], ah, bh0, bh1);
                mma16816(acco[nf], ah, bl0, bl1);
                mma16816(acco[nf], al, bh0, bh1);
            }
        }
    }

    // ---- epilogue ----
    float inv0 = 1.f / l_[0], inv1 = 1.f / l_[1];
    int row0 = m0 + wid * 16 + g;
    int row1 = row0 + 8;
    float* Op = g_obr + (size_t)(ub + z) * 49152;
    #pragma unroll
    for (int nf = 0; nf < 8; ++nf) {
        int col = nf * 8 + 2 * t;
        *(float2*)(Op + (size_t)row0 * 64 + col) = make_float2(acco[nf][0] * inv0, acco[nf][1] * inv0);
        *(float2*)(Op + (size_t)row1 * 64 + col) = make_float2(acco[nf][2] * inv1, acco[nf][3] * inv1);
    }
    if (t == 0) {
        g_lse[(size_t)(ub + z) * 768 + row0] = m_[0] + logf(l_[0]);
        g_lse[(size_t)(ub + z) * 768 + row1] = m_[1] + logf(l_[1]);
    }
}

// ---------------- misc kernels ------------------------------------------------
__global__ void im2col_split(const float* __restrict__ x) {
    int idx = blockIdx.x * 256 + threadIdx.x;
    if (idx >= BV * NP * 1024) return;
    int kk = idx & 1023;
    int p  = (idx >> 10) % NP;
    int b  = (idx >> 10) / NP;
    int pw_ = kk & 15, ph_ = (kk >> 4) & 15, pd_ = kk >> 8;
    int bz = p & 15, by = (p >> 4) & 15, bx = p >> 8;
    float v = x[(((size_t)b * 48 + bx * 4 + pd_) * 256 + by * 16 + ph_) * 256 + bz * 16 + pw_];
    bf16 h = __float2bfloat16(v);
    g_colh[idx] = h;
    g_coll[idx] = __float2bfloat16(v - __bfloat162float(h));
}

__global__ void assemble_kernel(const float* __restrict__ cls, const float* __restrict__ pos) {
    size_t idx = (size_t)blockIdx.x * 256 + threadIdx.x;
    if (idx >= (size_t)ML * EV) return;
    int e = idx % EV;
    size_t t = idx / EV;
    int l = (int)(t % LV);
    int b = (int)(t / LV);
    float v;
    if (l == 0) v = cls[e] + pos[e];
    else        v = g_hn[((size_t)b * NP + (l - 1)) * EV + e] + pos[(size_t)l * EV + e];
    g_h[idx] = v;
}

template<int SPLIT>
__global__ void layernorm_kernel(const float* __restrict__ x, const float* __restrict__ g,
                                 const float* __restrict__ bta, float* __restrict__ y,
                                 bf16* __restrict__ yh, bf16* __restrict__ yl)
{
    int row = blockIdx.x;
    const float* xr = x + (size_t)row * EV;
    int tid = threadIdx.x;
    float v0 = xr[tid], v1 = xr[tid + 256], v2 = xr[tid + 512];
    float s = v0 + v1 + v2;
    float s2 = v0 * v0 + v1 * v1 + v2 * v2;
    __shared__ float shA[8], shB[8];
    float ws = warpSum(s), ws2 = warpSum(s2);
    int lane = tid & 31, wid = tid >> 5;
    if (lane == 0) { shA[wid] = ws; shB[wid] = ws2; }
    __syncthreads();
    if (tid == 0) {
        float a = 0, bb = 0;
        #pragma unroll
        for (int i = 0; i < 8; ++i) { a += shA[i]; bb += shB[i]; }
        shA[0] = a; shB[0] = bb;
    }
    __syncthreads();
    float mu = shA[0] * (1.f / 768.f);
    float var = shB[0] * (1.f / 768.f) - mu * mu;
    float inv = rsqrtf(var + 1e-5f);
    float o[3] = {v0, v1, v2};
    #pragma unroll
    for (int u = 0; u < 3; ++u) {
        int e = tid + u * 256;
        float c = (o[u] - mu) * inv * g[e] + bta[e];
        if (SPLIT) {
            bf16 h = __float2bfloat16(c);
            yh[(size_t)row * EV + e] = h;
            yl[(size_t)row * EV + e] = __float2bfloat16(c - __bfloat162float(h));
        } else {
            y[(size_t)row * EV + e] = c;
        }
    }
}

__global__ void combine_kernel()
{
    int blk = blockIdx.x;
    int hd = blk % HH;
    int p = (blk / HH) % LV;
    int b = blk / (HH * LV);
    int d = threadIdx.x;
    const int ws[5] = {768, 1536, 3072, 6144, 12288};
    const int rs[5] = {1, 2, 4, 8, 16};
    const int gs[5] = {12, 6, 3, 2, 1};
    const int ns[5] = {5, 3, 2, 1, 1};
    const int ub[5] = {0, 120, 192, 240, 264};
    float lses[5];
    size_t oix[5];
    bool cov[5];
    float mx = -1e30f;
    #pragma unroll
    for (int br = 0; br < 5; ++br) {
        int seg = p / ws[br];
        int jj = p - seg * ws[br];
        int off = hd / gs[br];
        int rr = jj & (rs[br] - 1);
        cov[br] = (rr == off);
        if (cov[br]) {
            int j = jj / rs[br];
            int unit = ub[br] + (b * ns[br] + seg) * HH + hd;
            lses[br] = g_lse[(size_t)unit * 768 + j];
            oix[br] = (size_t)unit * 49152 + (size_t)j * 64;
            mx = fmaxf(mx, lses[br]);
        }
    }
    float sw = 0.f, out = 0.f;
    #pragma unroll
    for (int br = 0; br < 5; ++br) {
        if (cov[br]) {
            float wgt = expf(lses[br] - mx);
            sw += wgt;
            out += wgt * g_obr[oix[br] + d];
        }
    }
    float c = out / sw;
    size_t o = ((size_t)(b * LV + p)) * EV + hd * DHv + d;
    bf16 h = __float2bfloat16(c);
    g_oh[o] = h;
    g_ol[o] = __float2bfloat16(c - __bfloat162float(h));
}

__global__ void head_kernel(const float* __restrict__ hn, const float* __restrict__ W,
                            const float* __restrict__ bias, float* __restrict__ out)
{
    int nidx = blockIdx.x * blockDim.x + threadIdx.x;
    int b = blockIdx.y;
    if (nidx >= 1000) return;
    const float* row = hn + (size_t)b * LV * EV;
    float acc = bias[nidx];
    for (int e = 0; e < EV; ++e) acc = fmaf(row[e], W[(size_t)e * 1000 + nidx], acc);
    out[b * 1000 + nidx] = acc;
}

__global__ void splitT(const float* __restrict__ w, bf16* __restrict__ oh,
                       bf16* __restrict__ ol, int K, int N)
{
    __shared__ float t[32][33];
    int kb = blockIdx.x * 32, nb = blockIdx.y * 32;
    int x = threadIdx.x, y = threadIdx.y;
    #pragma unroll
    for (int i = 0; i < 32; i += 8)
        t[y + i][x] = w[(size_t)(kb + y + i) * N + nb + x];
    __syncthreads();
    #pragma unroll
    for (int i = 0; i < 32; i += 8) {
        float v = t[x][y + i];
        bf16 h = __float2bfloat16(v);
        bf16 l = __float2bfloat16(v - __bfloat162float(h));
        size_t o = (size_t)(nb + y + i) * K + kb + x;
        oh[o] = h; ol[o] = l;
    }
}

__global__ void split_copy(const float* __restrict__ s, bf16* __restrict__ oh,
                           bf16* __restrict__ ol, long n)
{
    long i = ((long)blockIdx.x * 256 + threadIdx.x) * 4;
    if (i >= n) return;
    float4 v = *(const float4*)(s + i);
    float vv[4] = {v.x, v.y, v.z, v.w};
    #pragma unroll
    for (int u = 0; u < 4; ++u) {
        bf16 h = __float2bfloat16(vv[u]);
        oh[i + u] = h;
        ol[i + u] = __float2bfloat16(vv[u] - __bfloat162float(h));
    }
}

// ---------------- host orchestration ------------------------------------------
extern "C" void kernel_launch(void* const* d_in, const int* in_sizes, int n_in,
                              void* d_out, int out_size)
{
    (void)in_sizes; (void)n_in; (void)out_size;
    const float* x        = (const float*)d_in[0];
    const float* patch_w  = (const float*)d_in[1];
    const float* patch_b  = (const float*)d_in[2];
    const float* cls_tok  = (const float*)d_in[3];
    const float* pos_emb  = (const float*)d_in[4];
    const float* ln1_g    = (const float*)d_in[5];
    const float* ln1_b    = (const float*)d_in[6];
    const float* wq       = (const float*)d_in[7];
    const float* bq       = (const float*)d_in[8];
    const float* wk       = (const float*)d_in[9];
    const float* bk       = (const float*)d_in[10];
    const float* wv       = (const float*)d_in[11];
    const float* bv_      = (const float*)d_in[12];
    const float* wo       = (const float*)d_in[13];
    const float* bo       = (const float*)d_in[14];
    const float* ln2_g    = (const float*)d_in[15];
    const float* ln2_b    = (const float*)d_in[16];
    const float* w1       = (const float*)d_in[17];
    const float* b1       = (const float*)d_in[18];
    const float* w2       = (const float*)d_in[19];
    const float* b2       = (const float*)d_in[20];
    const float* normf_g  = (const float*)d_in[21];
    const float* normf_b  = (const float*)d_in[22];
    const float* head_w   = (const float*)d_in[23];
    const float* head_b   = (const float*)d_in[24];
    float* out = (float*)d_out;

    float *p_h, *p_hn;
    bf16 *p_colh, *p_coll, *p_qh, *p_ql, *p_kh, *p_kl, *p_vh, *p_vl;
    bf16 *p_xh, *p_xl, *p_m1h, *p_m1l, *p_oh, *p_ol, *p_wh, *p_wl;
    cudaGetSymbolAddress((void**)&p_h, g_h);
    cudaGetSymbolAddress((void**)&p_hn, g_hn);
    cudaGetSymbolAddress((void**)&p_colh, g_colh);
    cudaGetSymbolAddress((void**)&p_coll, g_coll);
    cudaGetSymbolAddress((void**)&p_qh, g_qh);
    cudaGetSymbolAddress((void**)&p_ql, g_ql);
    cudaGetSymbolAddress((void**)&p_kh, g_kh);
    cudaGetSymbolAddress((void**)&p_kl, g_kl);
    cudaGetSymbolAddress((void**)&p_vh, g_vh);
    cudaGetSymbolAddress((void**)&p_vl, g_vl);
    cudaGetSymbolAddress((void**)&p_xh, g_xh);
    cudaGetSymbolAddress((void**)&p_xl, g_xl);
    cudaGetSymbolAddress((void**)&p_m1h, g_m1h);
    cudaGetSymbolAddress((void**)&p_m1l, g_m1l);
    cudaGetSymbolAddress((void**)&p_oh, g_oh);
    cudaGetSymbolAddress((void**)&p_ol, g_ol);
    cudaGetSymbolAddress((void**)&p_wh, g_wh);
    cudaGetSymbolAddress((void**)&p_wl, g_wl);

    cudaFuncSetAttribute(hgemm<0,0>, cudaFuncAttributeMaxDynamicSharedMemorySize, HG_SMEM);
    cudaFuncSetAttribute(hgemm<0,1>, cudaFuncAttributeMaxDynamicSharedMemorySize, HG_SMEM);
    cudaFuncSetAttribute(hgemm<1,1>, cudaFuncAttributeMaxDynamicSharedMemorySize, HG_SMEM);
    cudaFuncSetAttribute(fattn, cudaFuncAttributeMaxDynamicSharedMemorySize, FA_SMEM);

    const int ws[5] = {768, 1536, 3072, 6144, 12288};
    const int rs[5] = {1, 2, 4, 8, 16};
    const int gs[5] = {12, 6, 3, 2, 1};
    const int ns[5] = {5, 3, 2, 1, 1};
    const int ub[5] = {0, 120, 192, 240, 264};

    // ---- weight prep ----------------------------------------------------------
    const size_t LSZ = 7077888;
    {
        long n = 786432;
        split_copy<<<(int)((n/4 + 255) / 256), 256>>>(patch_w, p_wh, p_wl, n);
    }
    for (int l = 0; l < 2; ++l) {
        size_t base = 786432 + (size_t)l * LSZ;
        size_t oEE = (size_t)l * EV * EV;
        size_t oE4 = (size_t)l * EV * 3072;
        dim3 blk(32, 8);
        splitT<<<dim3(24, 24), blk>>>(wq + oEE, p_wh + base,           p_wl + base,           768, 768);
        splitT<<<dim3(24, 24), blk>>>(wk + oEE, p_wh + base + 589824,  p_wl + base + 589824,  768, 768);
        splitT<<<dim3(24, 24), blk>>>(wv + oEE, p_wh + base + 1179648, p_wl + base + 1179648, 768, 768);
        splitT<<<dim3(24, 24), blk>>>(wo + oEE, p_wh + base + 1769472, p_wl + base + 1769472, 768, 768);
        splitT<<<dim3(24, 96), blk>>>(w1 + oE4, p_wh + base + 2359296, p_wl + base + 2359296, 768, 3072);
        splitT<<<dim3(96, 24), blk>>>(w2 + oE4, p_wh + base + 4718592, p_wl + base + 4718592, 3072, 768);
    }

    // ---- patch embed ------------------------------------------------------------
    im2col_split<<<(BV * NP * 1024 + 255) / 256, 256>>>(x);
    hgemm<0,0><<<dim3(48, 6), 256, HG_SMEM>>>(p_colh, p_coll, p_wh, p_wl,
                                              patch_b, nullptr, p_hn, nullptr, nullptr,
                                              BV * NP, EV, 1024);
    assemble_kernel<<<(int)(((size_t)ML * EV + 255) / 256), 256>>>(cls_tok, pos_emb);

    dim3 gEEt(49, 6);
    dim3 gE4t(49, 24);

    for (int layer = 0; layer < 2; ++layer) {
        size_t base = 786432 + (size_t)layer * LSZ;
        size_t oE  = (size_t)layer * EV;
        size_t o4  = (size_t)layer * 3072;

        layernorm_kernel<1><<<ML, 256>>>(p_h, ln1_g + oE, ln1_b + oE, nullptr, p_xh, p_xl);
        hgemm<0,1><<<gEEt, 256, HG_SMEM>>>(p_xh, p_xl, p_wh + base,           p_wl + base,           bq + oE,  nullptr, nullptr, p_qh, p_ql, ML, EV, EV);
        hgemm<0,1><<<gEEt, 256, HG_SMEM>>>(p_xh, p_xl, p_wh + base + 589824,  p_wl + base + 589824,  bk + oE,  nullptr, nullptr, p_kh, p_kl, ML, EV, EV);
        hgemm<0,1><<<gEEt, 256, HG_SMEM>>>(p_xh, p_xl, p_wh + base + 1179648, p_wl + base + 1179648, bv_ + oE, nullptr, nullptr, p_vh, p_vl, ML, EV, EV);

        for (int br = 0; br < 5; ++br) {
            int units = BV * ns[br] * HH;
            dim3 gfa(6, 1, units);
            fattn<<<gfa, 256, FA_SMEM>>>(p_qh, p_ql, p_kh, p_kl, p_vh, p_vl,
                                         ws[br], rs[br], gs[br], ns[br], ub[br]);
        }
        combine_kernel<<<BV * LV * HH, 64>>>();

        hgemm<0,0><<<gEEt, 256, HG_SMEM>>>(p_oh, p_ol, p_wh + base + 1769472, p_wl + base + 1769472, bo + oE, p_h, p_h, nullptr, nullptr, ML, EV, EV);

        layernorm_kernel<1><<<ML, 256>>>(p_h, ln2_g + oE, ln2_b + oE, nullptr, p_xh, p_xl);
        hgemm<1,1><<<gE4t, 256, HG_SMEM>>>(p_xh, p_xl, p_wh + base + 2359296, p_wl + base + 2359296, b1 + o4, nullptr, nullptr, p_m1h, p_m1l, ML, 3072, EV);
        hgemm<0,0><<<gEEt, 256, HG_SMEM>>>(p_m1h, p_m1l, p_wh + base + 4718592, p_wl + base + 4718592, b2 + oE, p_h, p_h, nullptr, nullptr, ML, EV, 3072);
    }

    layernorm_kernel<0><<<ML, 256>>>(p_h, normf_g, normf_b, p_hn, nullptr, nullptr);
    head_kernel<<<dim3(4, BV), 256>>>(p_hn, head_w, head_b, out);
}

// round 8
// speedup vs baseline: 7.1797x; 1.6071x over previous
#include <cuda_runtime.h>
#include <cuda_fp16.h>
#include <math.h>
#include <stdint.h>

#define BV 2
#define LV 3073
#define EV 768
#define HH 12
#define DHv 64
#define ML (BV*LV)          // 6146 rows
#define NP 3072             // patches per batch

typedef __half fp16;

// ---------------- scratch (device globals) -----------------------------------
__device__ float g_h  [(size_t)ML*EV];
__device__ float g_hn [(size_t)ML*EV];
__device__ float g_obr[(size_t)288*768*64];
__device__ float g_lse[(size_t)288*768];
__device__ __align__(16) fp16 g_col[(size_t)BV*NP*1024];
__device__ __align__(16) fp16 g_x  [(size_t)ML*EV];
__device__ __align__(16) fp16 g_q  [(size_t)ML*EV];
__device__ __align__(16) fp16 g_k  [(size_t)ML*EV];
__device__ __align__(16) fp16 g_v  [(size_t)ML*EV];
__device__ __align__(16) fp16 g_m1 [(size_t)ML*3072];
__device__ __align__(16) fp16 g_o  [(size_t)ML*EV];
#define WTOT 14942208
__device__ __align__(16) fp16 g_wh[WTOT];
__device__ __align__(16) fp16 g_wl[WTOT];

// ---------------- helpers -----------------------------------------------------
__device__ __forceinline__ float geluf(float v) {
    return 0.5f * v * (1.f + erff(v * 0.70710678118654752f));
}
__device__ __forceinline__ float warpSum(float v) {
    #pragma unroll
    for (int o = 16; o; o >>= 1) v += __shfl_xor_sync(0xffffffffu, v, o);
    return v;
}
__device__ __forceinline__ uint32_t s2u(const void* p) {
    uint32_t a;
    asm("{ .reg .u64 t; cvta.to.shared.u64 t, %1; cvt.u32.u64 %0, t; }" : "=r"(a) : "l"(p));
    return a;
}
__device__ __forceinline__ void cpa16(uint32_t saddr, const void* g, int sz) {
    asm volatile("cp.async.cg.shared.global [%0], [%1], 16, %2;"
                 :: "r"(saddr), "l"(g), "r"(sz) : "memory");
}
__device__ __forceinline__ void mma16816(float* d, const uint32_t* a, uint32_t b0, uint32_t b1) {
    asm volatile("mma.sync.aligned.m16n8k16.row.col.f32.f16.f16.f32 "
                 "{%0,%1,%2,%3},{%4,%5,%6,%7},{%8,%9},{%0,%1,%2,%3};"
                 : "+f"(d[0]), "+f"(d[1]), "+f"(d[2]), "+f"(d[3])
                 : "r"(a[0]), "r"(a[1]), "r"(a[2]), "r"(a[3]), "r"(b0), "r"(b1));
}
__device__ __forceinline__ uint32_t h2u(float c0, float c1) {
    __half2 h = __floats2half2_rn(c0, c1);
    return *(uint32_t*)&h;
}

// ---------------- fp16 tensor-core GEMM (mma.sync) ----------------------------
// C = act(A@B^T + bias) (+res).  A: MxK fp16 single; B: NxK fp16 hi(/lo).
// NPASS=2: a*bh + a*bl (weights exact). NPASS=1: a*bh only.
// OUT=0: fp32 C (+res). OUT=1: fp16 Cf.
#define HG_STRIDE 40
#define HG_MAT (128*HG_STRIDE)

template<int ACT, int OUT, int NPASS>
__global__ void __launch_bounds__(256, 2)
hgemm(const fp16* __restrict__ A, const fp16* __restrict__ Bh, const fp16* __restrict__ Bl,
      const float* __restrict__ bias, const float* __restrict__ res,
      float* __restrict__ C, fp16* __restrict__ Cf, int M, int N, int K)
{
    constexpr int NMAT = 1 + NPASS;
    constexpr int BUFH = NMAT * HG_MAT;
    extern __shared__ fp16 sm[];
    const int tid = threadIdx.x, wid = tid >> 5, lane = tid & 31;
    const int m0 = blockIdx.x * 128, n0 = blockIdx.y * 128;
    const int g = lane >> 2, t = lane & 3;
    const int wm0 = (wid >> 1) * 32, wn0 = (wid & 1) * 64;
    const uint32_t smbase = s2u(sm);
    const fp16* srcs[3] = {A, Bh, Bl};

    float acc[2][8][4];
    #pragma unroll
    for (int i = 0; i < 2; ++i)
        #pragma unroll
        for (int j = 0; j < 8; ++j)
            #pragma unroll
            for (int u = 0; u < 4; ++u) acc[i][j][u] = 0.f;

    const int KC = K >> 5;
    const int srow = tid >> 1;

    auto issue = [&](int c) {
        int k0 = c << 5;
        int buf = c & 1;
        #pragma unroll
        for (int mat = 0; mat < NMAT; ++mat) {
            #pragma unroll
            for (int j = 0; j < 2; ++j) {
                int q = (tid & 1) * 2 + j;
                int grow = (mat == 0) ? (m0 + srow) : (n0 + srow);
                bool ok = (mat > 0) || (grow < M);
                const fp16* gp = ok ? (srcs[mat] + (size_t)grow * K + k0 + q * 8) : srcs[mat];
                uint32_t sa = smbase + (uint32_t)(buf * BUFH + mat * HG_MAT + srow * HG_STRIDE + q * 8) * 2;
                cpa16(sa, gp, ok ? 16 : 0);
            }
        }
        asm volatile("cp.async.commit_group;" ::: "memory");
    };

    issue(0);
    for (int c = 0; c < KC; ++c) {
        if (c + 1 < KC) {
            issue(c + 1);
            asm volatile("cp.async.wait_group 1;" ::: "memory");
        } else {
            asm volatile("cp.async.wait_group 0;" ::: "memory");
        }
        __syncthreads();
        const fp16* bb = sm + (size_t)(c & 1) * BUFH;
        #pragma unroll
        for (int ks = 0; ks < 32; ks += 16) {
            uint32_t afr[2][4];
            #pragma unroll
            for (int mf = 0; mf < 2; ++mf) {
                const fp16* pa = bb + (wm0 + mf * 16 + g) * HG_STRIDE + ks + 2 * t;
                afr[mf][0] = *(const uint32_t*)pa;
                afr[mf][1] = *(const uint32_t*)(pa + 8 * HG_STRIDE);
                afr[mf][2] = *(const uint32_t*)(pa + 8);
                afr[mf][3] = *(const uint32_t*)(pa + 8 * HG_STRIDE + 8);
            }
            #pragma unroll
            for (int nf = 0; nf < 8; ++nf) {
                const fp16* pbh = bb + HG_MAT + (wn0 + nf * 8 + g) * HG_STRIDE + ks + 2 * t;
                uint32_t bh0 = *(const uint32_t*)pbh;
                uint32_t bh1 = *(const uint32_t*)(pbh + 8);
                #pragma unroll
                for (int mf = 0; mf < 2; ++mf) mma16816(acc[mf][nf], afr[mf], bh0, bh1);
                if (NPASS == 2) {
                    const fp16* pbl = pbh + HG_MAT;
                    uint32_t bl0 = *(const uint32_t*)pbl;
                    uint32_t bl1 = *(const uint32_t*)(pbl + 8);
                    #pragma unroll
                    for (int mf = 0; mf < 2; ++mf) mma16816(acc[mf][nf], afr[mf], bl0, bl1);
                }
            }
        }
        __syncthreads();
    }

    #pragma unroll
    for (int mf = 0; mf < 2; ++mf) {
        #pragma unroll
        for (int rr = 0; rr < 2; ++rr) {
            int row = m0 + wm0 + mf * 16 + g + rr * 8;
            if (row >= M) continue;
            #pragma unroll
            for (int nf = 0; nf < 8; ++nf) {
                int col = n0 + wn0 + nf * 8 + 2 * t;
                float c0 = acc[mf][nf][rr * 2 + 0] + bias[col];
                float c1 = acc[mf][nf][rr * 2 + 1] + bias[col + 1];
                if (ACT) { c0 = geluf(c0); c1 = geluf(c1); }
                if (OUT == 1) {
                    __half2 h = __floats2half2_rn(c0, c1);
                    *(__half2*)(Cf + (size_t)row * N + col) = h;
                } else {
                    if (res) {
                        c0 += res[(size_t)row * N + col];
                        c1 += res[(size_t)row * N + col + 1];
                    }
                    *(float2*)(C + (size_t)row * N + col) = make_float2(c0, c1);
                }
            }
        }
    }
}

// ---------------- fused flash attention (1-pass fp16, double-buffered) -------
#define FA_QSTR 72
#define FA_VSTR 136
#define FA_Q 0
#define FA_K(b)  (9216 + (b)*9216)
#define FA_VT(b) (27648 + (b)*8704)
#define FA_SMEM (45056*2)

__global__ void __launch_bounds__(256, 1)
fattn(const fp16* __restrict__ q, const fp16* __restrict__ k, const fp16* __restrict__ v,
      int w, int r, int gsz, int n, int ub)
{
    extern __shared__ fp16 sm[];
    const int tid = threadIdx.x, wid = tid >> 5, lane = tid & 31;
    const int g = lane >> 2, t = lane & 3;
    int z = blockIdx.z;
    int hd = z % HH;
    int seg = (z / HH) % n;
    int bb_ = z / (HH * n);
    int off = hd / gsz;
    int m0 = blockIdx.x * 128;
    const uint32_t smb = s2u(sm);
    const int kkey = tid >> 1;
    const int dbase = (tid & 1) * 32;

    auto k_issue = [&](int kt, int buf) {
        int n0 = kt * 128;
        #pragma unroll
        for (int it = 0; it < 4; ++it) {
            int idx = it * 256 + tid;
            int row = idx >> 3, q8 = idx & 7;
            int pos = seg * w + (n0 + row) * r + off;
            bool ok = pos < LV;
            const fp16* gp = ok ? (k + ((size_t)(bb_ * LV) + pos) * EV + hd * DHv + q8 * 8) : k;
            cpa16(smb + (uint32_t)(FA_K(buf) + row * FA_QSTR + q8 * 8) * 2, gp, ok ? 16 : 0);
        }
        asm volatile("cp.async.commit_group;" ::: "memory");
    };
    auto v_ldg = [&](int kt, uint4* vr) {
        int pos = seg * w + (kt * 128 + kkey) * r + off;
        if (pos < LV) {
            const fp16* pv = v + ((size_t)(bb_ * LV) + pos) * EV + hd * DHv + dbase;
            vr[0] = *(const uint4*)pv;        vr[1] = *(const uint4*)(pv + 8);
            vr[2] = *(const uint4*)(pv + 16); vr[3] = *(const uint4*)(pv + 24);
        } else {
            vr[0] = vr[1] = vr[2] = vr[3] = make_uint4(0, 0, 0, 0);
        }
    };
    auto v_sts = [&](const uint4* vr, int buf) {
        fp16 bufh[32];
        *(uint4*)&bufh[0] = vr[0];  *(uint4*)&bufh[8] = vr[1];
        *(uint4*)&bufh[16] = vr[2]; *(uint4*)&bufh[24] = vr[3];
        #pragma unroll
        for (int j = 0; j < 32; ++j) {
            int jj = (j + kkey) & 31;
            sm[FA_VT(buf) + (dbase + jj) * FA_VSTR + kkey] = bufh[jj];
        }
    };

    // Q issue
    #pragma unroll
    for (int it = 0; it < 4; ++it) {
        int idx = it * 256 + tid;
        int row = idx >> 3, q8 = idx & 7;
        int pos = seg * w + (m0 + row) * r + off;
        bool ok = pos < LV;
        const fp16* gp = ok ? (q + ((size_t)(bb_ * LV) + pos) * EV + hd * DHv + q8 * 8) : q;
        cpa16(smb + (uint32_t)(FA_Q + row * FA_QSTR + q8 * 8) * 2, gp, ok ? 16 : 0);
    }
    asm volatile("cp.async.commit_group;" ::: "memory");

    uint4 vr[4];
    v_ldg(0, vr);
    k_issue(0, 0);
    asm volatile("cp.async.wait_group 0;" ::: "memory");
    __syncthreads();
    v_sts(vr, 0);

    uint32_t qfr[4][4];
    #pragma unroll
    for (int k4 = 0; k4 < 4; ++k4) {
        const fp16* pa = sm + FA_Q + (wid * 16 + g) * FA_QSTR + k4 * 16 + 2 * t;
        qfr[k4][0] = *(const uint32_t*)pa;
        qfr[k4][1] = *(const uint32_t*)(pa + 8 * FA_QSTR);
        qfr[k4][2] = *(const uint32_t*)(pa + 8);
        qfr[k4][3] = *(const uint32_t*)(pa + 8 * FA_QSTR + 8);
    }

    float m_[2] = {-1e30f, -1e30f};
    float l_[2] = {0.f, 0.f};
    float acco[8][4];
    #pragma unroll
    for (int j = 0; j < 8; ++j)
        #pragma unroll
        for (int u = 0; u < 4; ++u) acco[j][u] = 0.f;

    for (int kt = 0; kt < 6; ++kt) {
        int buf = kt & 1;
        if (kt < 5) v_ldg(kt + 1, vr);
        if (kt > 0) asm volatile("cp.async.wait_group 0;" ::: "memory");
        __syncthreads();
        if (kt < 5) {
            k_issue(kt + 1, buf ^ 1);
            v_sts(vr, buf ^ 1);
        }

        const fp16* Kb = sm + FA_K(buf);
        const fp16* Vb = sm + FA_VT(buf);

        // S = Q K^T (1-pass fp16)
        float accs[16][4];
        #pragma unroll
        for (int j = 0; j < 16; ++j)
            #pragma unroll
            for (int u = 0; u < 4; ++u) accs[j][u] = 0.f;
        #pragma unroll
        for (int k4 = 0; k4 < 4; ++k4) {
            #pragma unroll
            for (int nf = 0; nf < 16; ++nf) {
                const fp16* pb = Kb + (nf * 8 + g) * FA_QSTR + k4 * 16 + 2 * t;
                mma16816(accs[nf], qfr[k4], *(const uint32_t*)pb, *(const uint32_t*)(pb + 8));
            }
        }

        // online softmax
        float mx0 = -1e30f, mx1 = -1e30f;
        #pragma unroll
        for (int nf = 0; nf < 16; ++nf) {
            #pragma unroll
            for (int u = 0; u < 4; ++u) accs[nf][u] *= 0.125f;
            mx0 = fmaxf(mx0, fmaxf(accs[nf][0], accs[nf][1]));
            mx1 = fmaxf(mx1, fmaxf(accs[nf][2], accs[nf][3]));
        }
        mx0 = fmaxf(mx0, __shfl_xor_sync(0xffffffffu, mx0, 1));
        mx0 = fmaxf(mx0, __shfl_xor_sync(0xffffffffu, mx0, 2));
        mx1 = fmaxf(mx1, __shfl_xor_sync(0xffffffffu, mx1, 1));
        mx1 = fmaxf(mx1, __shfl_xor_sync(0xffffffffu, mx1, 2));
        float mn0 = fmaxf(m_[0], mx0), mn1 = fmaxf(m_[1], mx1);
        float sc0 = expf(m_[0] - mn0), sc1 = expf(m_[1] - mn1);
        float sum0 = 0.f, sum1 = 0.f;
        #pragma unroll
        for (int nf = 0; nf < 16; ++nf) {
            accs[nf][0] = expf(accs[nf][0] - mn0);
            accs[nf][1] = expf(accs[nf][1] - mn0);
            accs[nf][2] = expf(accs[nf][2] - mn1);
            accs[nf][3] = expf(accs[nf][3] - mn1);
            sum0 += accs[nf][0] + accs[nf][1];
            sum1 += accs[nf][2] + accs[nf][3];
        }
        sum0 += __shfl_xor_sync(0xffffffffu, sum0, 1);
        sum0 += __shfl_xor_sync(0xffffffffu, sum0, 2);
        sum1 += __shfl_xor_sync(0xffffffffu, sum1, 1);
        sum1 += __shfl_xor_sync(0xffffffffu, sum1, 2);
        l_[0] = l_[0] * sc0 + sum0;
        l_[1] = l_[1] * sc1 + sum1;
        m_[0] = mn0; m_[1] = mn1;
        #pragma unroll
        for (int nf = 0; nf < 8; ++nf) {
            acco[nf][0] *= sc0; acco[nf][1] *= sc0;
            acco[nf][2] *= sc1; acco[nf][3] *= sc1;
        }

        // O += P V (1-pass fp16)
        #pragma unroll
        for (int kb = 0; kb < 8; ++kb) {
            uint32_t a[4];
            a[0] = h2u(accs[2*kb][0],   accs[2*kb][1]);
            a[1] = h2u(accs[2*kb][2],   accs[2*kb][3]);
            a[2] = h2u(accs[2*kb+1][0], accs[2*kb+1][1]);
            a[3] = h2u(accs[2*kb+1][2], accs[2*kb+1][3]);
            #pragma unroll
            for (int nf = 0; nf < 8; ++nf) {
                const fp16* pb = Vb + (nf * 8 + g) * FA_VSTR + kb * 16 + 2 * t;
                mma16816(acco[nf], a, *(const uint32_t*)pb, *(const uint32_t*)(pb + 8));
            }
        }
    }

    float inv0 = 1.f / l_[0], inv1 = 1.f / l_[1];
    int row0 = m0 + wid * 16 + g;
    int row1 = row0 + 8;
    float* Op = g_obr + (size_t)(ub + z) * 49152;
    #pragma unroll
    for (int nf = 0; nf < 8; ++nf) {
        int col = nf * 8 + 2 * t;
        *(float2*)(Op + (size_t)row0 * 64 + col) = make_float2(acco[nf][0] * inv0, acco[nf][1] * inv0);
        *(float2*)(Op + (size_t)row1 * 64 + col) = make_float2(acco[nf][2] * inv1, acco[nf][3] * inv1);
    }
    if (t == 0) {
        g_lse[(size_t)(ub + z) * 768 + row0] = m_[0] + logf(l_[0]);
        g_lse[(size_t)(ub + z) * 768 + row1] = m_[1] + logf(l_[1]);
    }
}

// ---------------- misc kernels ------------------------------------------------
__global__ void im2col_half(const float* __restrict__ x) {
    int idx = blockIdx.x * 256 + threadIdx.x;
    if (idx >= BV * NP * 1024) return;
    int kk = idx & 1023;
    int p  = (idx >> 10) % NP;
    int b  = (idx >> 10) / NP;
    int pw_ = kk & 15, ph_ = (kk >> 4) & 15, pd_ = kk >> 8;
    int bz = p & 15, by = (p >> 4) & 15, bx = p >> 8;
    float v = x[(((size_t)b * 48 + bx * 4 + pd_) * 256 + by * 16 + ph_) * 256 + bz * 16 + pw_];
    g_col[idx] = __float2half_rn(v);
}

__global__ void assemble_kernel(const float* __restrict__ cls, const float* __restrict__ pos) {
    size_t idx = (size_t)blockIdx.x * 256 + threadIdx.x;
    if (idx >= (size_t)ML * EV) return;
    int e = idx % EV;
    size_t t = idx / EV;
    int l = (int)(t % LV);
    int b = (int)(t / LV);
    float v;
    if (l == 0) v = cls[e] + pos[e];
    else        v = g_hn[((size_t)b * NP + (l - 1)) * EV + e] + pos[(size_t)l * EV + e];
    g_h[idx] = v;
}

template<int HOUT>
__global__ void layernorm_kernel(const float* __restrict__ x, const float* __restrict__ g,
                                 const float* __restrict__ bta, float* __restrict__ y,
                                 fp16* __restrict__ yf)
{
    int row = blockIdx.x;
    const float* xr = x + (size_t)row * EV;
    int tid = threadIdx.x;
    float v0 = xr[tid], v1 = xr[tid + 256], v2 = xr[tid + 512];
    float s = v0 + v1 + v2;
    float s2 = v0 * v0 + v1 * v1 + v2 * v2;
    __shared__ float shA[8], shB[8];
    float ws = warpSum(s), ws2 = warpSum(s2);
    int lane = tid & 31, wid = tid >> 5;
    if (lane == 0) { shA[wid] = ws; shB[wid] = ws2; }
    __syncthreads();
    if (tid == 0) {
        float a = 0, bb = 0;
        #pragma unroll
        for (int i = 0; i < 8; ++i) { a += shA[i]; bb += shB[i]; }
        shA[0] = a; shB[0] = bb;
    }
    __syncthreads();
    float mu = shA[0] * (1.f / 768.f);
    float var = shB[0] * (1.f / 768.f) - mu * mu;
    float inv = rsqrtf(var + 1e-5f);
    float o[3] = {v0, v1, v2};
    #pragma unroll
    for (int u = 0; u < 3; ++u) {
        int e = tid + u * 256;
        float c = (o[u] - mu) * inv * g[e] + bta[e];
        if (HOUT) yf[(size_t)row * EV + e] = __float2half_rn(c);
        else      y[(size_t)row * EV + e] = c;
    }
}

__global__ void combine_kernel()
{
    int blk = blockIdx.x;
    int hd = blk % HH;
    int p = (blk / HH) % LV;
    int b = blk / (HH * LV);
    int d = threadIdx.x;
    const int ws[5] = {768, 1536, 3072, 6144, 12288};
    const int rs[5] = {1, 2, 4, 8, 16};
    const int gs[5] = {12, 6, 3, 2, 1};
    const int ns[5] = {5, 3, 2, 1, 1};
    const int ub[5] = {0, 120, 192, 240, 264};
    float lses[5];
    size_t oix[5];
    bool cov[5];
    float mx = -1e30f;
    #pragma unroll
    for (int br = 0; br < 5; ++br) {
        int seg = p / ws[br];
        int jj = p - seg * ws[br];
        int off = hd / gs[br];
        int rr = jj & (rs[br] - 1);
        cov[br] = (rr == off);
        if (cov[br]) {
            int j = jj / rs[br];
            int unit = ub[br] + (b * ns[br] + seg) * HH + hd;
            lses[br] = g_lse[(size_t)unit * 768 + j];
            oix[br] = (size_t)unit * 49152 + (size_t)j * 64;
            mx = fmaxf(mx, lses[br]);
        }
    }
    float sw = 0.f, out = 0.f;
    #pragma unroll
    for (int br = 0; br < 5; ++br) {
        if (cov[br]) {
            float wgt = expf(lses[br] - mx);
            sw += wgt;
            out += wgt * g_obr[oix[br] + d];
        }
    }
    g_o[((size_t)(b * LV + p)) * EV + hd * DHv + d] = __float2half_rn(out / sw);
}

__global__ void head_kernel(const float* __restrict__ hn, const float* __restrict__ W,
                            const float* __restrict__ bias, float* __restrict__ out)
{
    int nidx = blockIdx.x * blockDim.x + threadIdx.x;
    int b = blockIdx.y;
    if (nidx >= 1000) return;
    const float* row = hn + (size_t)b * LV * EV;
    float acc = bias[nidx];
    for (int e = 0; e < EV; ++e) acc = fmaf(row[e], W[(size_t)e * 1000 + nidx], acc);
    out[b * 1000 + nidx] = acc;
}

// weight transpose+split: (K,N) fp32 -> (N,K) fp16 hi/lo
__global__ void splitT(const float* __restrict__ w, fp16* __restrict__ oh,
                       fp16* __restrict__ ol, int K, int N)
{
    __shared__ float t[32][33];
    int kb = blockIdx.x * 32, nb = blockIdx.y * 32;
    int x = threadIdx.x, y = threadIdx.y;
    #pragma unroll
    for (int i = 0; i < 32; i += 8)
        t[y + i][x] = w[(size_t)(kb + y + i) * N + nb + x];
    __syncthreads();
    #pragma unroll
    for (int i = 0; i < 32; i += 8) {
        float v = t[x][y + i];
        fp16 h = __float2half_rn(v);
        fp16 l = __float2half_rn(v - __half2float(h));
        size_t o = (size_t)(nb + y + i) * K + kb + x;
        oh[o] = h; ol[o] = l;
    }
}

__global__ void split_copy(const float* __restrict__ s, fp16* __restrict__ oh,
                           fp16* __restrict__ ol, long n)
{
    long i = ((long)blockIdx.x * 256 + threadIdx.x) * 4;
    if (i >= n) return;
    float4 v = *(const float4*)(s + i);
    float vv[4] = {v.x, v.y, v.z, v.w};
    #pragma unroll
    for (int u = 0; u < 4; ++u) {
        fp16 h = __float2half_rn(vv[u]);
        oh[i + u] = h;
        ol[i + u] = __float2half_rn(vv[u] - __half2float(h));
    }
}

// ---------------- host orchestration ------------------------------------------
extern "C" void kernel_launch(void* const* d_in, const int* in_sizes, int n_in,
                              void* d_out, int out_size)
{
    (void)in_sizes; (void)n_in; (void)out_size;
    const float* x        = (const float*)d_in[0];
    const float* patch_w  = (const float*)d_in[1];
    const float* patch_b  = (const float*)d_in[2];
    const float* cls_tok  = (const float*)d_in[3];
    const float* pos_emb  = (const float*)d_in[4];
    const float* ln1_g    = (const float*)d_in[5];
    const float* ln1_b    = (const float*)d_in[6];
    const float* wq       = (const float*)d_in[7];
    const float* bq       = (const float*)d_in[8];
    const float* wk       = (const float*)d_in[9];
    const float* bk       = (const float*)d_in[10];
    const float* wv       = (const float*)d_in[11];
    const float* bv_      = (const float*)d_in[12];
    const float* wo       = (const float*)d_in[13];
    const float* bo       = (const float*)d_in[14];
    const float* ln2_g    = (const float*)d_in[15];
    const float* ln2_b    = (const float*)d_in[16];
    const float* w1       = (const float*)d_in[17];
    const float* b1       = (const float*)d_in[18];
    const float* w2       = (const float*)d_in[19];
    const float* b2       = (const float*)d_in[20];
    const float* normf_g  = (const float*)d_in[21];
    const float* normf_b  = (const float*)d_in[22];
    const float* head_w   = (const float*)d_in[23];
    const float* head_b   = (const float*)d_in[24];
    float* out = (float*)d_out;

    float *p_h, *p_hn;
    fp16 *p_col, *p_x, *p_q, *p_k, *p_v, *p_m1, *p_o, *p_wh, *p_wl;
    cudaGetSymbolAddress((void**)&p_h, g_h);
    cudaGetSymbolAddress((void**)&p_hn, g_hn);
    cudaGetSymbolAddress((void**)&p_col, g_col);
    cudaGetSymbolAddress((void**)&p_x, g_x);
    cudaGetSymbolAddress((void**)&p_q, g_q);
    cudaGetSymbolAddress((void**)&p_k, g_k);
    cudaGetSymbolAddress((void**)&p_v, g_v);
    cudaGetSymbolAddress((void**)&p_m1, g_m1);
    cudaGetSymbolAddress((void**)&p_o, g_o);
    cudaGetSymbolAddress((void**)&p_wh, g_wh);
    cudaGetSymbolAddress((void**)&p_wl, g_wl);

    const int HG_SMEM2 = 2 * 3 * HG_MAT * 2;
    const int HG_SMEM1 = 2 * 2 * HG_MAT * 2;
    cudaFuncSetAttribute(hgemm<0,0,2>, cudaFuncAttributeMaxDynamicSharedMemorySize, HG_SMEM2);
    cudaFuncSetAttribute(hgemm<1,1,2>, cudaFuncAttributeMaxDynamicSharedMemorySize, HG_SMEM2);
    cudaFuncSetAttribute(hgemm<0,1,1>, cudaFuncAttributeMaxDynamicSharedMemorySize, HG_SMEM1);
    cudaFuncSetAttribute(hgemm<0,0,1>, cudaFuncAttributeMaxDynamicSharedMemorySize, HG_SMEM1);
    cudaFuncSetAttribute(fattn, cudaFuncAttributeMaxDynamicSharedMemorySize, FA_SMEM);

    const int ws[5] = {768, 1536, 3072, 6144, 12288};
    const int rs[5] = {1, 2, 4, 8, 16};
    const int gs[5] = {12, 6, 3, 2, 1};
    const int ns[5] = {5, 3, 2, 1, 1};
    const int ub[5] = {0, 120, 192, 240, 264};

    // ---- weight prep: fp16 hi/lo, N x K layout --------------------------------
    const size_t LSZ = 7077888;
    {
        long n = 786432;
        split_copy<<<(int)((n/4 + 255) / 256), 256>>>(patch_w, p_wh, p_wl, n);
    }
    for (int l = 0; l < 2; ++l) {
        size_t base = 786432 + (size_t)l * LSZ;
        size_t oEE = (size_t)l * EV * EV;
        size_t oE4 = (size_t)l * EV * 3072;
        dim3 blk(32, 8);
        splitT<<<dim3(24, 24), blk>>>(wq + oEE, p_wh + base,           p_wl + base,           768, 768);
        splitT<<<dim3(24, 24), blk>>>(wk + oEE, p_wh + base + 589824,  p_wl + base + 589824,  768, 768);
        splitT<<<dim3(24, 24), blk>>>(wv + oEE, p_wh + base + 1179648, p_wl + base + 1179648, 768, 768);
        splitT<<<dim3(24, 24), blk>>>(wo + oEE, p_wh + base + 1769472, p_wl + base + 1769472, 768, 768);
        splitT<<<dim3(24, 96), blk>>>(w1 + oE4, p_wh + base + 2359296, p_wl + base + 2359296, 768, 3072);
        splitT<<<dim3(96, 24), blk>>>(w2 + oE4, p_wh + base + 4718592, p_wl + base + 4718592, 3072, 768);
    }

    // ---- patch embed (2-pass) ---------------------------------------------------
    im2col_half<<<(BV * NP * 1024 + 255) / 256, 256>>>(x);
    hgemm<0,0,2><<<dim3(48, 6), 256, HG_SMEM2>>>(p_col, p_wh, p_wl,
                                                 patch_b, nullptr, p_hn, nullptr,
                                                 BV * NP, EV, 1024);
    assemble_kernel<<<(int)(((size_t)ML * EV + 255) / 256), 256>>>(cls_tok, pos_emb);

    dim3 gEEt(49, 6);
    dim3 gE4t(49, 24);

    for (int layer = 0; layer < 2; ++layer) {
        size_t base = 786432 + (size_t)layer * LSZ;
        size_t oE  = (size_t)layer * EV;
        size_t o4  = (size_t)layer * 3072;

        layernorm_kernel<1><<<ML, 256>>>(p_h, ln1_g + oE, ln1_b + oE, nullptr, p_x);
        hgemm<0,1,1><<<gEEt, 256, HG_SMEM1>>>(p_x, p_wh + base,           p_wl, bq + oE,  nullptr, nullptr, p_q, ML, EV, EV);
        hgemm<0,1,1><<<gEEt, 256, HG_SMEM1>>>(p_x, p_wh + base + 589824,  p_wl, bk + oE,  nullptr, nullptr, p_k, ML, EV, EV);
        hgemm<0,1,1><<<gEEt, 256, HG_SMEM1>>>(p_x, p_wh + base + 1179648, p_wl, bv_ + oE, nullptr, nullptr, p_v, ML, EV, EV);

        for (int br = 0; br < 5; ++br) {
            int units = BV * ns[br] * HH;
            dim3 gfa(6, 1, units);
            fattn<<<gfa, 256, FA_SMEM>>>(p_q, p_k, p_v, ws[br], rs[br], gs[br], ns[br], ub[br]);
        }
        combine_kernel<<<BV * LV * HH, 64>>>();

        hgemm<0,0,1><<<gEEt, 256, HG_SMEM1>>>(p_o, p_wh + base + 1769472, p_wl, bo + oE, p_h, p_h, nullptr, ML, EV, EV);

        layernorm_kernel<1><<<ML, 256>>>(p_h, ln2_g + oE, ln2_b + oE, nullptr, p_x);
        hgemm<1,1,2><<<gE4t, 256, HG_SMEM2>>>(p_x, p_wh + base + 2359296, p_wl + base + 2359296, b1 + o4, nullptr, nullptr, p_m1, ML, 3072, EV);
        hgemm<0,0,2><<<gEEt, 256, HG_SMEM2>>>(p_m1, p_wh + base + 4718592, p_wl + base + 4718592, b2 + oE, p_h, p_h, nullptr, ML, EV, 3072);
    }

    layernorm_kernel<0><<<ML, 256>>>(p_h, normf_g, normf_b, p_hn, nullptr);
    head_kernel<<<dim3(4, BV), 256>>>(p_hn, head_w, head_b, out);
}

// round 9
// speedup vs baseline: 7.2640x; 1.0117x over previous
#include <cuda_runtime.h>
#include <cuda_fp16.h>
#include <math.h>
#include <stdint.h>

#define BV 2
#define LV 3073
#define EV 768
#define HH 12
#define DHv 64
#define ML (BV*LV)          // 6146 rows
#define NP 3072             // patches per batch
#define QKVS 2304           // fused qkv row stride

typedef __half fp16;

// ---------------- scratch (device globals) -----------------------------------
__device__ float g_h  [(size_t)ML*EV];
__device__ float g_hn [(size_t)ML*EV];
__device__ float g_obr[(size_t)288*768*64];
__device__ float g_lse[(size_t)288*768];
__device__ float g_bqkv[2*QKVS];
__device__ __align__(16) fp16 g_col[(size_t)BV*NP*1024];
__device__ __align__(16) fp16 g_x  [(size_t)ML*EV];
__device__ __align__(16) fp16 g_qkv[(size_t)ML*QKVS];
__device__ __align__(16) fp16 g_m1 [(size_t)ML*3072];
__device__ __align__(16) fp16 g_o  [(size_t)ML*EV];
#define WTOT 14942208
__device__ __align__(16) fp16 g_wh[WTOT];
__device__ __align__(16) fp16 g_wl[WTOT];

// ---------------- helpers -----------------------------------------------------
__device__ __forceinline__ float geluf(float v) {
    return 0.5f * v * (1.f + erff(v * 0.70710678118654752f));
}
__device__ __forceinline__ float warpSum(float v) {
    #pragma unroll
    for (int o = 16; o; o >>= 1) v += __shfl_xor_sync(0xffffffffu, v, o);
    return v;
}
__device__ __forceinline__ uint32_t s2u(const void* p) {
    uint32_t a;
    asm("{ .reg .u64 t; cvta.to.shared.u64 t, %1; cvt.u32.u64 %0, t; }" : "=r"(a) : "l"(p));
    return a;
}
__device__ __forceinline__ void cpa16(uint32_t saddr, const void* g, int sz) {
    asm volatile("cp.async.cg.shared.global [%0], [%1], 16, %2;"
                 :: "r"(saddr), "l"(g), "r"(sz) : "memory");
}
__device__ __forceinline__ void mma16816(float* d, const uint32_t* a, uint32_t b0, uint32_t b1) {
    asm volatile("mma.sync.aligned.m16n8k16.row.col.f32.f16.f16.f32 "
                 "{%0,%1,%2,%3},{%4,%5,%6,%7},{%8,%9},{%0,%1,%2,%3};"
                 : "+f"(d[0]), "+f"(d[1]), "+f"(d[2]), "+f"(d[3])
                 : "r"(a[0]), "r"(a[1]), "r"(a[2]), "r"(a[3]), "r"(b0), "r"(b1));
}
__device__ __forceinline__ uint32_t h2u(float c0, float c1) {
    __half2 h = __floats2half2_rn(c0, c1);
    return *(uint32_t*)&h;
}

// ---------------- fp16 tensor-core GEMM (mma.sync) ----------------------------
#define HG_STRIDE 40
#define HG_MAT (128*HG_STRIDE)

template<int ACT, int OUT, int NPASS>
__global__ void __launch_bounds__(256, 2)
hgemm(const fp16* __restrict__ A, const fp16* __restrict__ Bh, const fp16* __restrict__ Bl,
      const float* __restrict__ bias, const float* __restrict__ res,
      float* __restrict__ C, fp16* __restrict__ Cf, int M, int N, int K)
{
    constexpr int NMAT = 1 + NPASS;
    constexpr int BUFH = NMAT * HG_MAT;
    extern __shared__ fp16 sm[];
    const int tid = threadIdx.x, wid = tid >> 5, lane = tid & 31;
    const int m0 = blockIdx.x * 128, n0 = blockIdx.y * 128;
    const int g = lane >> 2, t = lane & 3;
    const int wm0 = (wid >> 1) * 32, wn0 = (wid & 1) * 64;
    const uint32_t smbase = s2u(sm);
    const fp16* srcs[3] = {A, Bh, Bl};

    float acc[2][8][4];
    #pragma unroll
    for (int i = 0; i < 2; ++i)
        #pragma unroll
        for (int j = 0; j < 8; ++j)
            #pragma unroll
            for (int u = 0; u < 4; ++u) acc[i][j][u] = 0.f;

    const int KC = K >> 5;
    const int srow = tid >> 1;

    auto issue = [&](int c) {
        int k0 = c << 5;
        int buf = c & 1;
        #pragma unroll
        for (int mat = 0; mat < NMAT; ++mat) {
            #pragma unroll
            for (int j = 0; j < 2; ++j) {
                int q = (tid & 1) * 2 + j;
                int grow = (mat == 0) ? (m0 + srow) : (n0 + srow);
                bool ok = (mat > 0) || (grow < M);
                const fp16* gp = ok ? (srcs[mat] + (size_t)grow * K + k0 + q * 8) : srcs[mat];
                uint32_t sa = smbase + (uint32_t)(buf * BUFH + mat * HG_MAT + srow * HG_STRIDE + q * 8) * 2;
                cpa16(sa, gp, ok ? 16 : 0);
            }
        }
        asm volatile("cp.async.commit_group;" ::: "memory");
    };

    issue(0);
    for (int c = 0; c < KC; ++c) {
        if (c + 1 < KC) {
            issue(c + 1);
            asm volatile("cp.async.wait_group 1;" ::: "memory");
        } else {
            asm volatile("cp.async.wait_group 0;" ::: "memory");
        }
        __syncthreads();
        const fp16* bb = sm + (size_t)(c & 1) * BUFH;
        #pragma unroll
        for (int ks = 0; ks < 32; ks += 16) {
            uint32_t afr[2][4];
            #pragma unroll
            for (int mf = 0; mf < 2; ++mf) {
                const fp16* pa = bb + (wm0 + mf * 16 + g) * HG_STRIDE + ks + 2 * t;
                afr[mf][0] = *(const uint32_t*)pa;
                afr[mf][1] = *(const uint32_t*)(pa + 8 * HG_STRIDE);
                afr[mf][2] = *(const uint32_t*)(pa + 8);
                afr[mf][3] = *(const uint32_t*)(pa + 8 * HG_STRIDE + 8);
            }
            #pragma unroll
            for (int nf = 0; nf < 8; ++nf) {
                const fp16* pbh = bb + HG_MAT + (wn0 + nf * 8 + g) * HG_STRIDE + ks + 2 * t;
                uint32_t bh0 = *(const uint32_t*)pbh;
                uint32_t bh1 = *(const uint32_t*)(pbh + 8);
                #pragma unroll
                for (int mf = 0; mf < 2; ++mf) mma16816(acc[mf][nf], afr[mf], bh0, bh1);
                if (NPASS == 2) {
                    const fp16* pbl = pbh + HG_MAT;
                    uint32_t bl0 = *(const uint32_t*)pbl;
                    uint32_t bl1 = *(const uint32_t*)(pbl + 8);
                    #pragma unroll
                    for (int mf = 0; mf < 2; ++mf) mma16816(acc[mf][nf], afr[mf], bl0, bl1);
                }
            }
        }
        __syncthreads();
    }

    #pragma unroll
    for (int mf = 0; mf < 2; ++mf) {
        #pragma unroll
        for (int rr = 0; rr < 2; ++rr) {
            int row = m0 + wm0 + mf * 16 + g + rr * 8;
            if (row >= M) continue;
            #pragma unroll
            for (int nf = 0; nf < 8; ++nf) {
                int col = n0 + wn0 + nf * 8 + 2 * t;
                float c0 = acc[mf][nf][rr * 2 + 0] + bias[col];
                float c1 = acc[mf][nf][rr * 2 + 1] + bias[col + 1];
                if (ACT) { c0 = geluf(c0); c1 = geluf(c1); }
                if (OUT == 1) {
                    __half2 h = __floats2half2_rn(c0, c1);
                    *(__half2*)(Cf + (size_t)row * N + col) = h;
                } else {
                    if (res) {
                        c0 += res[(size_t)row * N + col];
                        c1 += res[(size_t)row * N + col + 1];
                    }
                    *(float2*)(C + (size_t)row * N + col) = make_float2(c0, c1);
                }
            }
        }
    }
}

// ---------------- fused flash attention — ALL branches, one launch -----------
#define FA_QSTR 72
#define FA_VSTR 136
#define FA_Q 0
#define FA_K(b)  (9216 + (b)*9216)
#define FA_VT(b) (27648 + (b)*8704)
#define FA_SMEM (45056*2)

__global__ void __launch_bounds__(256, 1)
fattn(const fp16* __restrict__ qkv, int layer_unused)
{
    const int wsA[5] = {768, 1536, 3072, 6144, 12288};
    const int rsA[5] = {1, 2, 4, 8, 16};
    const int gsA[5] = {12, 6, 3, 2, 1};
    const int nsA[5] = {5, 3, 2, 1, 1};
    const int ubA[5] = {0, 120, 192, 240, 264};

    extern __shared__ fp16 sm[];
    const int tid = threadIdx.x, wid = tid >> 5, lane = tid & 31;
    const int g = lane >> 2, t = lane & 3;
    int gu = blockIdx.y;
    int br = (gu >= 264) ? 4 : (gu >= 240) ? 3 : (gu >= 192) ? 2 : (gu >= 120) ? 1 : 0;
    int z = gu - ubA[br];
    int w = wsA[br], r = rsA[br], gsz = gsA[br], n = nsA[br];
    int hd = z % HH;
    int seg = (z / HH) % n;
    int bb_ = z / (HH * n);
    int off = hd / gsz;
    int m0 = blockIdx.x * 128;
    const uint32_t smb = s2u(sm);
    const int kkey = tid >> 1;
    const int dbase = (tid & 1) * 32;
    const fp16* q = qkv;
    const fp16* k = qkv + 768;
    const fp16* v = qkv + 1536;

    auto k_issue = [&](int kt, int buf) {
        int n0 = kt * 128;
        #pragma unroll
        for (int it = 0; it < 4; ++it) {
            int idx = it * 256 + tid;
            int row = idx >> 3, q8 = idx & 7;
            int pos = seg * w + (n0 + row) * r + off;
            bool ok = pos < LV;
            const fp16* gp = ok ? (k + ((size_t)(bb_ * LV) + pos) * QKVS + hd * DHv + q8 * 8) : k;
            cpa16(smb + (uint32_t)(FA_K(buf) + row * FA_QSTR + q8 * 8) * 2, gp, ok ? 16 : 0);
        }
        asm volatile("cp.async.commit_group;" ::: "memory");
    };
    auto v_ldg = [&](int kt, uint4* vr) {
        int pos = seg * w + (kt * 128 + kkey) * r + off;
        if (pos < LV) {
            const fp16* pv = v + ((size_t)(bb_ * LV) + pos) * QKVS + hd * DHv + dbase;
            vr[0] = *(const uint4*)pv;        vr[1] = *(const uint4*)(pv + 8);
            vr[2] = *(const uint4*)(pv + 16); vr[3] = *(const uint4*)(pv + 24);
        } else {
            vr[0] = vr[1] = vr[2] = vr[3] = make_uint4(0, 0, 0, 0);
        }
    };
    auto v_sts = [&](const uint4* vr, int buf) {
        fp16 bufh[32];
        *(uint4*)&bufh[0] = vr[0];  *(uint4*)&bufh[8] = vr[1];
        *(uint4*)&bufh[16] = vr[2]; *(uint4*)&bufh[24] = vr[3];
        #pragma unroll
        for (int j = 0; j < 32; ++j) {
            int jj = (j + kkey) & 31;
            sm[FA_VT(buf) + (dbase + jj) * FA_VSTR + kkey] = bufh[jj];
        }
    };

    // Q issue
    #pragma unroll
    for (int it = 0; it < 4; ++it) {
        int idx = it * 256 + tid;
        int row = idx >> 3, q8 = idx & 7;
        int pos = seg * w + (m0 + row) * r + off;
        bool ok = pos < LV;
        const fp16* gp = ok ? (q + ((size_t)(bb_ * LV) + pos) * QKVS + hd * DHv + q8 * 8) : q;
        cpa16(smb + (uint32_t)(FA_Q + row * FA_QSTR + q8 * 8) * 2, gp, ok ? 16 : 0);
    }
    asm volatile("cp.async.commit_group;" ::: "memory");

    uint4 vr[4];
    v_ldg(0, vr);
    k_issue(0, 0);
    asm volatile("cp.async.wait_group 0;" ::: "memory");
    __syncthreads();
    v_sts(vr, 0);

    uint32_t qfr[4][4];
    #pragma unroll
    for (int k4 = 0; k4 < 4; ++k4) {
        const fp16* pa = sm + FA_Q + (wid * 16 + g) * FA_QSTR + k4 * 16 + 2 * t;
        qfr[k4][0] = *(const uint32_t*)pa;
        qfr[k4][1] = *(const uint32_t*)(pa + 8 * FA_QSTR);
        qfr[k4][2] = *(const uint32_t*)(pa + 8);
        qfr[k4][3] = *(const uint32_t*)(pa + 8 * FA_QSTR + 8);
    }

    float m_[2] = {-1e30f, -1e30f};
    float l_[2] = {0.f, 0.f};
    float acco[8][4];
    #pragma unroll
    for (int j = 0; j < 8; ++j)
        #pragma unroll
        for (int u = 0; u < 4; ++u) acco[j][u] = 0.f;

    for (int kt = 0; kt < 6; ++kt) {
        int buf = kt & 1;
        if (kt < 5) v_ldg(kt + 1, vr);
        if (kt > 0) asm volatile("cp.async.wait_group 0;" ::: "memory");
        __syncthreads();
        if (kt < 5) {
            k_issue(kt + 1, buf ^ 1);
            v_sts(vr, buf ^ 1);
        }

        const fp16* Kb = sm + FA_K(buf);
        const fp16* Vb = sm + FA_VT(buf);

        float accs[16][4];
        #pragma unroll
        for (int j = 0; j < 16; ++j)
            #pragma unroll
            for (int u = 0; u < 4; ++u) accs[j][u] = 0.f;
        #pragma unroll
        for (int k4 = 0; k4 < 4; ++k4) {
            #pragma unroll
            for (int nf = 0; nf < 16; ++nf) {
                const fp16* pb = Kb + (nf * 8 + g) * FA_QSTR + k4 * 16 + 2 * t;
                mma16816(accs[nf], qfr[k4], *(const uint32_t*)pb, *(const uint32_t*)(pb + 8));
            }
        }

        float mx0 = -1e30f, mx1 = -1e30f;
        #pragma unroll
        for (int nf = 0; nf < 16; ++nf) {
            #pragma unroll
            for (int u = 0; u < 4; ++u) accs[nf][u] *= 0.125f;
            mx0 = fmaxf(mx0, fmaxf(accs[nf][0], accs[nf][1]));
            mx1 = fmaxf(mx1, fmaxf(accs[nf][2], accs[nf][3]));
        }
        mx0 = fmaxf(mx0, __shfl_xor_sync(0xffffffffu, mx0, 1));
        mx0 = fmaxf(mx0, __shfl_xor_sync(0xffffffffu, mx0, 2));
        mx1 = fmaxf(mx1, __shfl_xor_sync(0xffffffffu, mx1, 1));
        mx1 = fmaxf(mx1, __shfl_xor_sync(0xffffffffu, mx1, 2));
        float mn0 = fmaxf(m_[0], mx0), mn1 = fmaxf(m_[1], mx1);
        float sc0 = expf(m_[0] - mn0), sc1 = expf(m_[1] - mn1);
        float sum0 = 0.f, sum1 = 0.f;
        #pragma unroll
        for (int nf = 0; nf < 16; ++nf) {
            accs[nf][0] = expf(accs[nf][0] - mn0);
            accs[nf][1] = expf(accs[nf][1] - mn0);
            accs[nf][2] = expf(accs[nf][2] - mn1);
            accs[nf][3] = expf(accs[nf][3] - mn1);
            sum0 += accs[nf][0] + accs[nf][1];
            sum1 += accs[nf][2] + accs[nf][3];
        }
        sum0 += __shfl_xor_sync(0xffffffffu, sum0, 1);
        sum0 += __shfl_xor_sync(0xffffffffu, sum0, 2);
        sum1 += __shfl_xor_sync(0xffffffffu, sum1, 1);
        sum1 += __shfl_xor_sync(0xffffffffu, sum1, 2);
        l_[0] = l_[0] * sc0 + sum0;
        l_[1] = l_[1] * sc1 + sum1;
        m_[0] = mn0; m_[1] = mn1;
        #pragma unroll
        for (int nf = 0; nf < 8; ++nf) {
            acco[nf][0] *= sc0; acco[nf][1] *= sc0;
            acco[nf][2] *= sc1; acco[nf][3] *= sc1;
        }

        #pragma unroll
        for (int kb = 0; kb < 8; ++kb) {
            uint32_t a[4];
            a[0] = h2u(accs[2*kb][0],   accs[2*kb][1]);
            a[1] = h2u(accs[2*kb][2],   accs[2*kb][3]);
            a[2] = h2u(accs[2*kb+1][0], accs[2*kb+1][1]);
            a[3] = h2u(accs[2*kb+1][2], accs[2*kb+1][3]);
            #pragma unroll
            for (int nf = 0; nf < 8; ++nf) {
                const fp16* pb = Vb + (nf * 8 + g) * FA_VSTR + kb * 16 + 2 * t;
                mma16816(acco[nf], a, *(const uint32_t*)pb, *(const uint32_t*)(pb + 8));
            }
        }
    }

    float inv0 = 1.f / l_[0], inv1 = 1.f / l_[1];
    int row0 = m0 + wid * 16 + g;
    int row1 = row0 + 8;
    float* Op = g_obr + (size_t)gu * 49152;
    #pragma unroll
    for (int nf = 0; nf < 8; ++nf) {
        int col = nf * 8 + 2 * t;
        *(float2*)(Op + (size_t)row0 * 64 + col) = make_float2(acco[nf][0] * inv0, acco[nf][1] * inv0);
        *(float2*)(Op + (size_t)row1 * 64 + col) = make_float2(acco[nf][2] * inv1, acco[nf][3] * inv1);
    }
    if (t == 0) {
        g_lse[(size_t)gu * 768 + row0] = m_[0] + logf(l_[0]);
        g_lse[(size_t)gu * 768 + row1] = m_[1] + logf(l_[1]);
    }
}

// ---------------- misc kernels ------------------------------------------------
__global__ void im2col_half(const float* __restrict__ x) {
    int idx = blockIdx.x * 256 + threadIdx.x;
    if (idx >= BV * NP * 1024) return;
    int kk = idx & 1023;
    int p  = (idx >> 10) % NP;
    int b  = (idx >> 10) / NP;
    int pw_ = kk & 15, ph_ = (kk >> 4) & 15, pd_ = kk >> 8;
    int bz = p & 15, by = (p >> 4) & 15, bx = p >> 8;
    float v = x[(((size_t)b * 48 + bx * 4 + pd_) * 256 + by * 16 + ph_) * 256 + bz * 16 + pw_];
    g_col[idx] = __float2half_rn(v);
}

__global__ void assemble_kernel(const float* __restrict__ cls, const float* __restrict__ pos) {
    size_t idx = (size_t)blockIdx.x * 256 + threadIdx.x;
    if (idx >= (size_t)ML * EV) return;
    int e = idx % EV;
    size_t t = idx / EV;
    int l = (int)(t % LV);
    int b = (int)(t / LV);
    float v;
    if (l == 0) v = cls[e] + pos[e];
    else        v = g_hn[((size_t)b * NP + (l - 1)) * EV + e] + pos[(size_t)l * EV + e];
    g_h[idx] = v;
}

template<int HOUT>
__global__ void layernorm_kernel(const float* __restrict__ x, const float* __restrict__ g,
                                 const float* __restrict__ bta, float* __restrict__ y,
                                 fp16* __restrict__ yf)
{
    int row = blockIdx.x;
    const float* xr = x + (size_t)row * EV;
    int tid = threadIdx.x;
    float v0 = xr[tid], v1 = xr[tid + 256], v2 = xr[tid + 512];
    float s = v0 + v1 + v2;
    float s2 = v0 * v0 + v1 * v1 + v2 * v2;
    __shared__ float shA[8], shB[8];
    float ws = warpSum(s), ws2 = warpSum(s2);
    int lane = tid & 31, wid = tid >> 5;
    if (lane == 0) { shA[wid] = ws; shB[wid] = ws2; }
    __syncthreads();
    if (tid == 0) {
        float a = 0, bb = 0;
        #pragma unroll
        for (int i = 0; i < 8; ++i) { a += shA[i]; bb += shB[i]; }
        shA[0] = a; shB[0] = bb;
    }
    __syncthreads();
    float mu = shA[0] * (1.f / 768.f);
    float var = shB[0] * (1.f / 768.f) - mu * mu;
    float inv = rsqrtf(var + 1e-5f);
    float o[3] = {v0, v1, v2};
    #pragma unroll
    for (int u = 0; u < 3; ++u) {
        int e = tid + u * 256;
        float c = (o[u] - mu) * inv * g[e] + bta[e];
        if (HOUT) yf[(size_t)row * EV + e] = __float2half_rn(c);
        else      y[(size_t)row * EV + e] = c;
    }
}

__global__ void combine_kernel()
{
    int idx = blockIdx.x * 4 + (threadIdx.x >> 6);     // (b,p,hd) unit
    int d = threadIdx.x & 63;
    int hd = idx % HH;
    int p = (idx / HH) % LV;
    int b = idx / (HH * LV);
    if (b >= BV) return;
    const int ws[5] = {768, 1536, 3072, 6144, 12288};
    const int rs[5] = {1, 2, 4, 8, 16};
    const int gs[5] = {12, 6, 3, 2, 1};
    const int ns[5] = {5, 3, 2, 1, 1};
    const int ub[5] = {0, 120, 192, 240, 264};
    float lses[5];
    size_t oix[5];
    bool cov[5];
    float mx = -1e30f;
    #pragma unroll
    for (int br = 0; br < 5; ++br) {
        int seg = p / ws[br];
        int jj = p - seg * ws[br];
        int off = hd / gs[br];
        int rr = jj & (rs[br] - 1);
        cov[br] = (rr == off);
        if (cov[br]) {
            int j = jj / rs[br];
            int unit = ub[br] + (b * ns[br] + seg) * HH + hd;
            lses[br] = g_lse[(size_t)unit * 768 + j];
            oix[br] = (size_t)unit * 49152 + (size_t)j * 64;
            mx = fmaxf(mx, lses[br]);
        }
    }
    float sw = 0.f, out = 0.f;
    #pragma unroll
    for (int br = 0; br < 5; ++br) {
        if (cov[br]) {
            float wgt = expf(lses[br] - mx);
            sw += wgt;
            out += wgt * g_obr[oix[br] + d];
        }
    }
    g_o[((size_t)(b * LV + p)) * EV + hd * DHv + d] = __float2half_rn(out / sw);
}

__global__ void head_kernel(const float* __restrict__ hn, const float* __restrict__ W,
                            const float* __restrict__ bias, float* __restrict__ out)
{
    int nidx = blockIdx.x * blockDim.x + threadIdx.x;
    int b = blockIdx.y;
    if (nidx >= 1000) return;
    const float* row = hn + (size_t)b * LV * EV;
    float acc = bias[nidx];
    for (int e = 0; e < EV; ++e) acc = fmaf(row[e], W[(size_t)e * 1000 + nidx], acc);
    out[b * 1000 + nidx] = acc;
}

__global__ void splitT(const float* __restrict__ w, fp16* __restrict__ oh,
                       fp16* __restrict__ ol, int K, int N)
{
    __shared__ float t[32][33];
    int kb = blockIdx.x * 32, nb = blockIdx.y * 32;
    int x = threadIdx.x, y = threadIdx.y;
    #pragma unroll
    for (int i = 0; i < 32; i += 8)
        t[y + i][x] = w[(size_t)(kb + y + i) * N + nb + x];
    __syncthreads();
    #pragma unroll
    for (int i = 0; i < 32; i += 8) {
        float v = t[x][y + i];
        fp16 h = __float2half_rn(v);
        fp16 l = __float2half_rn(v - __half2float(h));
        size_t o = (size_t)(nb + y + i) * K + kb + x;
        oh[o] = h; ol[o] = l;
    }
}

__global__ void split_copy(const float* __restrict__ s, fp16* __restrict__ oh,
                           fp16* __restrict__ ol, long n)
{
    long i = ((long)blockIdx.x * 256 + threadIdx.x) * 4;
    if (i >= n) return;
    float4 v = *(const float4*)(s + i);
    float vv[4] = {v.x, v.y, v.z, v.w};
    #pragma unroll
    for (int u = 0; u < 4; ++u) {
        fp16 h = __float2half_rn(vv[u]);
        oh[i + u] = h;
        ol[i + u] = __float2half_rn(vv[u] - __half2float(h));
    }
}

__global__ void pack_bias(const float* __restrict__ bq, const float* __restrict__ bk,
                          const float* __restrict__ bv)
{
    int i = blockIdx.x * 256 + threadIdx.x;
    if (i >= 2 * QKVS) return;
    int l = i / QKVS, e = i % QKVS;
    float v;
    if (e < 768)       v = bq[l * EV + e];
    else if (e < 1536) v = bk[l * EV + e - 768];
    else               v = bv[l * EV + e - 1536];
    g_bqkv[i] = v;
}

// ---------------- host orchestration ------------------------------------------
extern "C" void kernel_launch(void* const* d_in, const int* in_sizes, int n_in,
                              void* d_out, int out_size)
{
    (void)in_sizes; (void)n_in; (void)out_size;
    const float* x        = (const float*)d_in[0];
    const float* patch_w  = (const float*)d_in[1];
    const float* patch_b  = (const float*)d_in[2];
    const float* cls_tok  = (const float*)d_in[3];
    const float* pos_emb  = (const float*)d_in[4];
    const float* ln1_g    = (const float*)d_in[5];
    const float* ln1_b    = (const float*)d_in[6];
    const float* wq       = (const float*)d_in[7];
    const float* bq       = (const float*)d_in[8];
    const float* wk       = (const float*)d_in[9];
    const float* bk       = (const float*)d_in[10];
    const float* wv       = (const float*)d_in[11];
    const float* bv_      = (const float*)d_in[12];
    const float* wo       = (const float*)d_in[13];
    const float* bo       = (const float*)d_in[14];
    const float* ln2_g    = (const float*)d_in[15];
    const float* ln2_b    = (const float*)d_in[16];
    const float* w1       = (const float*)d_in[17];
    const float* b1       = (const float*)d_in[18];
    const float* w2       = (const float*)d_in[19];
    const float* b2       = (const float*)d_in[20];
    const float* normf_g  = (const float*)d_in[21];
    const float* normf_b  = (const float*)d_in[22];
    const float* head_w   = (const float*)d_in[23];
    const float* head_b   = (const float*)d_in[24];
    float* out = (float*)d_out;

    float *p_h, *p_hn, *p_bqkv;
    fp16 *p_col, *p_x, *p_qkv, *p_m1, *p_o, *p_wh, *p_wl;
    cudaGetSymbolAddress((void**)&p_h, g_h);
    cudaGetSymbolAddress((void**)&p_hn, g_hn);
    cudaGetSymbolAddress((void**)&p_bqkv, g_bqkv);
    cudaGetSymbolAddress((void**)&p_col, g_col);
    cudaGetSymbolAddress((void**)&p_x, g_x);
    cudaGetSymbolAddress((void**)&p_qkv, g_qkv);
    cudaGetSymbolAddress((void**)&p_m1, g_m1);
    cudaGetSymbolAddress((void**)&p_o, g_o);
    cudaGetSymbolAddress((void**)&p_wh, g_wh);
    cudaGetSymbolAddress((void**)&p_wl, g_wl);

    const int HG_SMEM2 = 2 * 3 * HG_MAT * 2;
    const int HG_SMEM1 = 2 * 2 * HG_MAT * 2;
    cudaFuncSetAttribute(hgemm<0,0,2>, cudaFuncAttributeMaxDynamicSharedMemorySize, HG_SMEM2);
    cudaFuncSetAttribute(hgemm<1,1,2>, cudaFuncAttributeMaxDynamicSharedMemorySize, HG_SMEM2);
    cudaFuncSetAttribute(hgemm<0,1,1>, cudaFuncAttributeMaxDynamicSharedMemorySize, HG_SMEM1);
    cudaFuncSetAttribute(hgemm<0,0,1>, cudaFuncAttributeMaxDynamicSharedMemorySize, HG_SMEM1);
    cudaFuncSetAttribute(fattn, cudaFuncAttributeMaxDynamicSharedMemorySize, FA_SMEM);

    // ---- weight prep: fp16 hi/lo, N x K layout --------------------------------
    const size_t LSZ = 7077888;
    {
        long n = 786432;
        split_copy<<<(int)((n/4 + 255) / 256), 256>>>(patch_w, p_wh, p_wl, n);
    }
    pack_bias<<<(2 * QKVS + 255) / 256, 256>>>(bq, bk, bv_);
    for (int l = 0; l < 2; ++l) {
        size_t base = 786432 + (size_t)l * LSZ;
        size_t oEE = (size_t)l * EV * EV;
        size_t oE4 = (size_t)l * EV * 3072;
        dim3 blk(32, 8);
        splitT<<<dim3(24, 24), blk>>>(wq + oEE, p_wh + base,           p_wl + base,           768, 768);
        splitT<<<dim3(24, 24), blk>>>(wk + oEE, p_wh + base + 589824,  p_wl + base + 589824,  768, 768);
        splitT<<<dim3(24, 24), blk>>>(wv + oEE, p_wh + base + 1179648, p_wl + base + 1179648, 768, 768);
        splitT<<<dim3(24, 24), blk>>>(wo + oEE, p_wh + base + 1769472, p_wl + base + 1769472, 768, 768);
        splitT<<<dim3(24, 96), blk>>>(w1 + oE4, p_wh + base + 2359296, p_wl + base + 2359296, 768, 3072);
        splitT<<<dim3(96, 24), blk>>>(w2 + oE4, p_wh + base + 4718592, p_wl + base + 4718592, 3072, 768);
    }

    // ---- patch embed (2-pass) ---------------------------------------------------
    im2col_half<<<(BV * NP * 1024 + 255) / 256, 256>>>(x);
    hgemm<0,0,2><<<dim3(48, 6), 256, HG_SMEM2>>>(p_col, p_wh, p_wl,
                                                 patch_b, nullptr, p_hn, nullptr,
                                                 BV * NP, EV, 1024);
    assemble_kernel<<<(int)(((size_t)ML * EV + 255) / 256), 256>>>(cls_tok, pos_emb);

    dim3 gEEt(49, 6);
    dim3 gQKV(49, 18);
    dim3 gE4t(49, 24);

    for (int layer = 0; layer < 2; ++layer) {
        size_t base = 786432 + (size_t)layer * LSZ;
        size_t oE  = (size_t)layer * EV;
        size_t o4  = (size_t)layer * 3072;

        layernorm_kernel<1><<<ML, 256>>>(p_h, ln1_g + oE, ln1_b + oE, nullptr, p_x);
        hgemm<0,1,1><<<gQKV, 256, HG_SMEM1>>>(p_x, p_wh + base, p_wl,
                                              p_bqkv + layer * QKVS, nullptr, nullptr, p_qkv,
                                              ML, QKVS, EV);

        fattn<<<dim3(6, 288), 256, FA_SMEM>>>(p_qkv, layer);
        combine_kernel<<<(BV * LV * HH + 3) / 4, 256>>>();

        hgemm<0,0,1><<<gEEt, 256, HG_SMEM1>>>(p_o, p_wh + base + 1769472, p_wl, bo + oE, p_h, p_h, nullptr, ML, EV, EV);

        layernorm_kernel<1><<<ML, 256>>>(p_h, ln2_g + oE, ln2_b + oE, nullptr, p_x);
        hgemm<1,1,2><<<gE4t, 256, HG_SMEM2>>>(p_x, p_wh + base + 2359296, p_wl + base + 2359296, b1 + o4, nullptr, nullptr, p_m1, ML, 3072, EV);
        hgemm<0,0,2><<<gEEt, 256, HG_SMEM2>>>(p_m1, p_wh + base + 4718592, p_wl + base + 4718592, b2 + oE, p_h, p_h, nullptr, ML, EV, 3072);
    }

    layernorm_kernel<0><<<ML, 256>>>(p_h, normf_g, normf_b, p_hn, nullptr);
    head_kernel<<<dim3(4, BV), 256>>>(p_hn, head_w, head_b, out);
}

// round 10
// speedup vs baseline: 7.4870x; 1.0307x over previous
#include <cuda_runtime.h>
#include <cuda_fp16.h>
#include <math.h>
#include <stdint.h>

#define BV 2
#define LV 3073
#define EV 768
#define HH 12
#define DHv 64
#define ML (BV*LV)          // 6146 rows
#define NP 3072             // patches per batch
#define QKVS 2304           // fused qkv row stride

typedef __half fp16;

// ---------------- scratch (device globals) -----------------------------------
__device__ float g_h  [(size_t)ML*EV];
__device__ float g_hn [(size_t)ML*EV];
__device__ float g_obr[(size_t)288*768*64];
__device__ float g_lse[(size_t)288*768];
__device__ float g_bqkv[2*QKVS];
__device__ __align__(16) fp16 g_col[(size_t)BV*NP*1024];
__device__ __align__(16) fp16 g_x  [(size_t)ML*EV];
__device__ __align__(16) fp16 g_qkv[(size_t)ML*QKVS];
__device__ __align__(16) fp16 g_m1 [(size_t)ML*3072];
__device__ __align__(16) fp16 g_o  [(size_t)ML*EV];
#define WTOT 14942208
__device__ __align__(16) fp16 g_wh[WTOT];
__device__ __align__(16) fp16 g_wl[WTOT];

// ---------------- helpers -----------------------------------------------------
__device__ __forceinline__ float geluf(float v) {
    return 0.5f * v * (1.f + erff(v * 0.70710678118654752f));
}
__device__ __forceinline__ float warpSum(float v) {
    #pragma unroll
    for (int o = 16; o; o >>= 1) v += __shfl_xor_sync(0xffffffffu, v, o);
    return v;
}
__device__ __forceinline__ uint32_t s2u(const void* p) {
    uint32_t a;
    asm("{ .reg .u64 t; cvta.to.shared.u64 t, %1; cvt.u32.u64 %0, t; }" : "=r"(a) : "l"(p));
    return a;
}
__device__ __forceinline__ void cpa16(uint32_t saddr, const void* g, int sz) {
    asm volatile("cp.async.cg.shared.global [%0], [%1], 16, %2;"
                 :: "r"(saddr), "l"(g), "r"(sz) : "memory");
}
__device__ __forceinline__ void mma16816(float* d, const uint32_t* a, uint32_t b0, uint32_t b1) {
    asm volatile("mma.sync.aligned.m16n8k16.row.col.f32.f16.f16.f32 "
                 "{%0,%1,%2,%3},{%4,%5,%6,%7},{%8,%9},{%0,%1,%2,%3};"
                 : "+f"(d[0]), "+f"(d[1]), "+f"(d[2]), "+f"(d[3])
                 : "r"(a[0]), "r"(a[1]), "r"(a[2]), "r"(a[3]), "r"(b0), "r"(b1));
}
__device__ __forceinline__ void ldsm4(uint32_t& r0, uint32_t& r1, uint32_t& r2, uint32_t& r3,
                                      uint32_t saddr) {
    asm volatile("ldmatrix.sync.aligned.m8n8.x4.shared.b16 {%0,%1,%2,%3}, [%4];"
                 : "=r"(r0), "=r"(r1), "=r"(r2), "=r"(r3) : "r"(saddr));
}
__device__ __forceinline__ uint32_t h2u(float c0, float c1) {
    __half2 h = __floats2half2_rn(c0, c1);
    return *(uint32_t*)&h;
}

// ---------------- fp16 tensor-core GEMM (mma.sync + ldmatrix) -----------------
#define HG_STRIDE 40
#define HG_MAT (128*HG_STRIDE)

template<int ACT, int OUT, int NPASS>
__global__ void __launch_bounds__(256, 2)
hgemm(const fp16* __restrict__ A, const fp16* __restrict__ Bh, const fp16* __restrict__ Bl,
      const float* __restrict__ bias, const float* __restrict__ res,
      float* __restrict__ C, fp16* __restrict__ Cf, int M, int N, int K)
{
    constexpr int NMAT = 1 + NPASS;
    constexpr int BUFH = NMAT * HG_MAT;
    extern __shared__ fp16 sm[];
    const int tid = threadIdx.x, wid = tid >> 5, lane = tid & 31;
    const int m0 = blockIdx.x * 128, n0 = blockIdx.y * 128;
    const int g = lane >> 2, t = lane & 3;
    const int wm0 = (wid >> 1) * 32, wn0 = (wid & 1) * 64;
    const uint32_t smbase = s2u(sm);
    const fp16* srcs[3] = {A, Bh, Bl};
    // ldmatrix lane patterns
    const int arow8 = ((lane >> 3) & 1) * 8 + (lane & 7);   // A: m0/m1 rows, m2/m3 cols+8
    const int acol8 = (lane >> 4) * 8;
    const int bnf   = lane >> 4;                             // B: 2 nf per x4
    const int brow  = lane & 7;
    const int bcol8 = ((lane >> 3) & 1) * 8;

    float acc[2][8][4];
    #pragma unroll
    for (int i = 0; i < 2; ++i)
        #pragma unroll
        for (int j = 0; j < 8; ++j)
            #pragma unroll
            for (int u = 0; u < 4; ++u) acc[i][j][u] = 0.f;

    const int KC = K >> 5;
    const int srow = tid >> 1;

    auto issue = [&](int c) {
        int k0 = c << 5;
        int buf = c & 1;
        #pragma unroll
        for (int mat = 0; mat < NMAT; ++mat) {
            #pragma unroll
            for (int j = 0; j < 2; ++j) {
                int q = (tid & 1) * 2 + j;
                int grow = (mat == 0) ? (m0 + srow) : (n0 + srow);
                bool ok = (mat > 0) || (grow < M);
                const fp16* gp = ok ? (srcs[mat] + (size_t)grow * K + k0 + q * 8) : srcs[mat];
                uint32_t sa = smbase + (uint32_t)(buf * BUFH + mat * HG_MAT + srow * HG_STRIDE + q * 8) * 2;
                cpa16(sa, gp, ok ? 16 : 0);
            }
        }
        asm volatile("cp.async.commit_group;" ::: "memory");
    };

    issue(0);
    for (int c = 0; c < KC; ++c) {
        if (c + 1 < KC) {
            issue(c + 1);
            asm volatile("cp.async.wait_group 1;" ::: "memory");
        } else {
            asm volatile("cp.async.wait_group 0;" ::: "memory");
        }
        __syncthreads();
        const uint32_t bufoff = (uint32_t)(c & 1) * BUFH;
        #pragma unroll
        for (int ks = 0; ks < 32; ks += 16) {
            uint32_t afr[2][4];
            #pragma unroll
            for (int mf = 0; mf < 2; ++mf) {
                uint32_t addr = smbase + (bufoff + (uint32_t)((wm0 + mf * 16 + arow8) * HG_STRIDE + ks + acol8)) * 2;
                ldsm4(afr[mf][0], afr[mf][1], afr[mf][2], afr[mf][3], addr);
            }
            #pragma unroll
            for (int p = 0; p < 8; p += 2) {
                uint32_t b0, b1, b2, b3;
                uint32_t baddr = smbase + (bufoff + (uint32_t)(HG_MAT + (wn0 + (p + bnf) * 8 + brow) * HG_STRIDE + ks + bcol8)) * 2;
                ldsm4(b0, b1, b2, b3, baddr);
                #pragma unroll
                for (int mf = 0; mf < 2; ++mf) {
                    mma16816(acc[mf][p],     afr[mf], b0, b1);
                    mma16816(acc[mf][p + 1], afr[mf], b2, b3);
                }
                if (NPASS == 2) {
                    uint32_t l0, l1, l2, l3;
                    ldsm4(l0, l1, l2, l3, baddr + HG_MAT * 2);
                    #pragma unroll
                    for (int mf = 0; mf < 2; ++mf) {
                        mma16816(acc[mf][p],     afr[mf], l0, l1);
                        mma16816(acc[mf][p + 1], afr[mf], l2, l3);
                    }
                }
            }
        }
        __syncthreads();
    }

    #pragma unroll
    for (int mf = 0; mf < 2; ++mf) {
        #pragma unroll
        for (int rr = 0; rr < 2; ++rr) {
            int row = m0 + wm0 + mf * 16 + g + rr * 8;
            if (row >= M) continue;
            #pragma unroll
            for (int nf = 0; nf < 8; ++nf) {
                int col = n0 + wn0 + nf * 8 + 2 * t;
                float c0 = acc[mf][nf][rr * 2 + 0] + bias[col];
                float c1 = acc[mf][nf][rr * 2 + 1] + bias[col + 1];
                if (ACT) { c0 = geluf(c0); c1 = geluf(c1); }
                if (OUT == 1) {
                    __half2 h = __floats2half2_rn(c0, c1);
                    *(__half2*)(Cf + (size_t)row * N + col) = h;
                } else {
                    if (res) {
                        c0 += res[(size_t)row * N + col];
                        c1 += res[(size_t)row * N + col + 1];
                    }
                    *(float2*)(C + (size_t)row * N + col) = make_float2(c0, c1);
                }
            }
        }
    }
}

// ---------------- fused flash attention — ALL branches, one launch -----------
#define FA_QSTR 72
#define FA_VSTR 136
#define FA_Q 0
#define FA_K(b)  (9216 + (b)*9216)
#define FA_VT(b) (27648 + (b)*8704)
#define FA_SMEM (45056*2)

__global__ void __launch_bounds__(256, 1)
fattn(const fp16* __restrict__ qkv, int layer_unused)
{
    const int wsA[5] = {768, 1536, 3072, 6144, 12288};
    const int rsA[5] = {1, 2, 4, 8, 16};
    const int gsA[5] = {12, 6, 3, 2, 1};
    const int nsA[5] = {5, 3, 2, 1, 1};
    const int ubA[5] = {0, 120, 192, 240, 264};

    extern __shared__ fp16 sm[];
    const int tid = threadIdx.x, wid = tid >> 5, lane = tid & 31;
    const int g = lane >> 2, t = lane & 3;
    int gu = blockIdx.y;
    int br = (gu >= 264) ? 4 : (gu >= 240) ? 3 : (gu >= 192) ? 2 : (gu >= 120) ? 1 : 0;
    int z = gu - ubA[br];
    int w = wsA[br], r = rsA[br], gsz = gsA[br], n = nsA[br];
    int hd = z % HH;
    int seg = (z / HH) % n;
    int bb_ = z / (HH * n);
    int off = hd / gsz;
    int m0 = blockIdx.x * 128;
    const uint32_t smb = s2u(sm);
    const int kkey = tid >> 1;
    const int dbase = (tid & 1) * 32;
    const int arow8 = ((lane >> 3) & 1) * 8 + (lane & 7);
    const int acol8 = (lane >> 4) * 8;
    const int bnf   = lane >> 4;
    const int brow  = lane & 7;
    const int bcol8 = ((lane >> 3) & 1) * 8;
    const fp16* q = qkv;
    const fp16* k = qkv + 768;
    const fp16* v = qkv + 1536;

    auto k_issue = [&](int kt, int buf) {
        int n0 = kt * 128;
        #pragma unroll
        for (int it = 0; it < 4; ++it) {
            int idx = it * 256 + tid;
            int row = idx >> 3, q8 = idx & 7;
            int pos = seg * w + (n0 + row) * r + off;
            bool ok = pos < LV;
            const fp16* gp = ok ? (k + ((size_t)(bb_ * LV) + pos) * QKVS + hd * DHv + q8 * 8) : k;
            cpa16(smb + (uint32_t)(FA_K(buf) + row * FA_QSTR + q8 * 8) * 2, gp, ok ? 16 : 0);
        }
        asm volatile("cp.async.commit_group;" ::: "memory");
    };
    auto v_ldg = [&](int kt, uint4* vr) {
        int pos = seg * w + (kt * 128 + kkey) * r + off;
        if (pos < LV) {
            const fp16* pv = v + ((size_t)(bb_ * LV) + pos) * QKVS + hd * DHv + dbase;
            vr[0] = *(const uint4*)pv;        vr[1] = *(const uint4*)(pv + 8);
            vr[2] = *(const uint4*)(pv + 16); vr[3] = *(const uint4*)(pv + 24);
        } else {
            vr[0] = vr[1] = vr[2] = vr[3] = make_uint4(0, 0, 0, 0);
        }
    };
    auto v_sts = [&](const uint4* vr, int buf) {
        fp16 bufh[32];
        *(uint4*)&bufh[0] = vr[0];  *(uint4*)&bufh[8] = vr[1];
        *(uint4*)&bufh[16] = vr[2]; *(uint4*)&bufh[24] = vr[3];
        #pragma unroll
        for (int j = 0; j < 32; ++j) {
            int jj = (j + kkey) & 31;
            sm[FA_VT(buf) + (dbase + jj) * FA_VSTR + kkey] = bufh[jj];
        }
    };

    // Q issue
    #pragma unroll
    for (int it = 0; it < 4; ++it) {
        int idx = it * 256 + tid;
        int row = idx >> 3, q8 = idx & 7;
        int pos = seg * w + (m0 + row) * r + off;
        bool ok = pos < LV;
        const fp16* gp = ok ? (q + ((size_t)(bb_ * LV) + pos) * QKVS + hd * DHv + q8 * 8) : q;
        cpa16(smb + (uint32_t)(FA_Q + row * FA_QSTR + q8 * 8) * 2, gp, ok ? 16 : 0);
    }
    asm volatile("cp.async.commit_group;" ::: "memory");

    uint4 vr[4];
    v_ldg(0, vr);
    k_issue(0, 0);
    asm volatile("cp.async.wait_group 0;" ::: "memory");
    __syncthreads();
    v_sts(vr, 0);

    uint32_t qfr[4][4];
    #pragma unroll
    for (int k4 = 0; k4 < 4; ++k4) {
        uint32_t addr = smb + (uint32_t)(FA_Q + (wid * 16 + arow8) * FA_QSTR + k4 * 16 + acol8) * 2;
        ldsm4(qfr[k4][0], qfr[k4][1], qfr[k4][2], qfr[k4][3], addr);
    }

    float m_[2] = {-1e30f, -1e30f};
    float l_[2] = {0.f, 0.f};
    float acco[8][4];
    #pragma unroll
    for (int j = 0; j < 8; ++j)
        #pragma unroll
        for (int u = 0; u < 4; ++u) acco[j][u] = 0.f;

    for (int kt = 0; kt < 6; ++kt) {
        int buf = kt & 1;
        if (kt < 5) v_ldg(kt + 1, vr);
        if (kt > 0) asm volatile("cp.async.wait_group 0;" ::: "memory");
        __syncthreads();
        if (kt < 5) {
            k_issue(kt + 1, buf ^ 1);
            v_sts(vr, buf ^ 1);
        }

        // S = Q K^T (ldmatrix B)
        float accs[16][4];
        #pragma unroll
        for (int j = 0; j < 16; ++j)
            #pragma unroll
            for (int u = 0; u < 4; ++u) accs[j][u] = 0.f;
        #pragma unroll
        for (int k4 = 0; k4 < 4; ++k4) {
            #pragma unroll
            for (int p = 0; p < 16; p += 2) {
                uint32_t b0, b1, b2, b3;
                uint32_t addr = smb + (uint32_t)(FA_K(buf) + ((p + bnf) * 8 + brow) * FA_QSTR + k4 * 16 + bcol8) * 2;
                ldsm4(b0, b1, b2, b3, addr);
                mma16816(accs[p],     qfr[k4], b0, b1);
                mma16816(accs[p + 1], qfr[k4], b2, b3);
            }
        }

        // online softmax
        float mx0 = -1e30f, mx1 = -1e30f;
        #pragma unroll
        for (int nf = 0; nf < 16; ++nf) {
            #pragma unroll
            for (int u = 0; u < 4; ++u) accs[nf][u] *= 0.125f;
            mx0 = fmaxf(mx0, fmaxf(accs[nf][0], accs[nf][1]));
            mx1 = fmaxf(mx1, fmaxf(accs[nf][2], accs[nf][3]));
        }
        mx0 = fmaxf(mx0, __shfl_xor_sync(0xffffffffu, mx0, 1));
        mx0 = fmaxf(mx0, __shfl_xor_sync(0xffffffffu, mx0, 2));
        mx1 = fmaxf(mx1, __shfl_xor_sync(0xffffffffu, mx1, 1));
        mx1 = fmaxf(mx1, __shfl_xor_sync(0xffffffffu, mx1, 2));
        float mn0 = fmaxf(m_[0], mx0), mn1 = fmaxf(m_[1], mx1);
        float sc0 = expf(m_[0] - mn0), sc1 = expf(m_[1] - mn1);
        float sum0 = 0.f, sum1 = 0.f;
        #pragma unroll
        for (int nf = 0; nf < 16; ++nf) {
            accs[nf][0] = expf(accs[nf][0] - mn0);
            accs[nf][1] = expf(accs[nf][1] - mn0);
            accs[nf][2] = expf(accs[nf][2] - mn1);
            accs[nf][3] = expf(accs[nf][3] - mn1);
            sum0 += accs[nf][0] + accs[nf][1];
            sum1 += accs[nf][2] + accs[nf][3];
        }
        sum0 += __shfl_xor_sync(0xffffffffu, sum0, 1);
        sum0 += __shfl_xor_sync(0xffffffffu, sum0, 2);
        sum1 += __shfl_xor_sync(0xffffffffu, sum1, 1);
        sum1 += __shfl_xor_sync(0xffffffffu, sum1, 2);
        l_[0] = l_[0] * sc0 + sum0;
        l_[1] = l_[1] * sc1 + sum1;
        m_[0] = mn0; m_[1] = mn1;
        #pragma unroll
        for (int nf = 0; nf < 8; ++nf) {
            acco[nf][0] *= sc0; acco[nf][1] *= sc0;
            acco[nf][2] *= sc1; acco[nf][3] *= sc1;
        }

        // O += P V (ldmatrix V)
        #pragma unroll
        for (int kb = 0; kb < 8; ++kb) {
            uint32_t a[4];
            a[0] = h2u(accs[2*kb][0],   accs[2*kb][1]);
            a[1] = h2u(accs[2*kb][2],   accs[2*kb][3]);
            a[2] = h2u(accs[2*kb+1][0], accs[2*kb+1][1]);
            a[3] = h2u(accs[2*kb+1][2], accs[2*kb+1][3]);
            #pragma unroll
            for (int p = 0; p < 8; p += 2) {
                uint32_t b0, b1, b2, b3;
                uint32_t addr = smb + (uint32_t)(FA_VT(buf) + ((p + bnf) * 8 + brow) * FA_VSTR + kb * 16 + bcol8) * 2;
                ldsm4(b0, b1, b2, b3, addr);
                mma16816(acco[p],     a, b0, b1);
                mma16816(acco[p + 1], a, b2, b3);
            }
        }
    }

    float inv0 = 1.f / l_[0], inv1 = 1.f / l_[1];
    int row0 = m0 + wid * 16 + g;
    int row1 = row0 + 8;
    float* Op = g_obr + (size_t)gu * 49152;
    #pragma unroll
    for (int nf = 0; nf < 8; ++nf) {
        int col = nf * 8 + 2 * t;
        *(float2*)(Op + (size_t)row0 * 64 + col) = make_float2(acco[nf][0] * inv0, acco[nf][1] * inv0);
        *(float2*)(Op + (size_t)row1 * 64 + col) = make_float2(acco[nf][2] * inv1, acco[nf][3] * inv1);
    }
    if (t == 0) {
        g_lse[(size_t)gu * 768 + row0] = m_[0] + logf(l_[0]);
        g_lse[(size_t)gu * 768 + row1] = m_[1] + logf(l_[1]);
    }
}

// ---------------- misc kernels ------------------------------------------------
__global__ void im2col_half(const float* __restrict__ x) {
    int idx = blockIdx.x * 256 + threadIdx.x;
    if (idx >= BV * NP * 1024) return;
    int kk = idx & 1023;
    int p  = (idx >> 10) % NP;
    int b  = (idx >> 10) / NP;
    int pw_ = kk & 15, ph_ = (kk >> 4) & 15, pd_ = kk >> 8;
    int bz = p & 15, by = (p >> 4) & 15, bx = p >> 8;
    float v = x[(((size_t)b * 48 + bx * 4 + pd_) * 256 + by * 16 + ph_) * 256 + bz * 16 + pw_];
    g_col[idx] = __float2half_rn(v);
}

__global__ void assemble_kernel(const float* __restrict__ cls, const float* __restrict__ pos) {
    size_t idx = (size_t)blockIdx.x * 256 + threadIdx.x;
    if (idx >= (size_t)ML * EV) return;
    int e = idx % EV;
    size_t t = idx / EV;
    int l = (int)(t % LV);
    int b = (int)(t / LV);
    float v;
    if (l == 0) v = cls[e] + pos[e];
    else        v = g_hn[((size_t)b * NP + (l - 1)) * EV + e] + pos[(size_t)l * EV + e];
    g_h[idx] = v;
}

template<int HOUT>
__global__ void layernorm_kernel(const float* __restrict__ x, const float* __restrict__ g,
                                 const float* __restrict__ bta, float* __restrict__ y,
                                 fp16* __restrict__ yf)
{
    int row = blockIdx.x;
    const float* xr = x + (size_t)row * EV;
    int tid = threadIdx.x;
    float v0 = xr[tid], v1 = xr[tid + 256], v2 = xr[tid + 512];
    float s = v0 + v1 + v2;
    float s2 = v0 * v0 + v1 * v1 + v2 * v2;
    __shared__ float shA[8], shB[8];
    float ws = warpSum(s), ws2 = warpSum(s2);
    int lane = tid & 31, wid = tid >> 5;
    if (lane == 0) { shA[wid] = ws; shB[wid] = ws2; }
    __syncthreads();
    if (tid == 0) {
        float a = 0, bb = 0;
        #pragma unroll
        for (int i = 0; i < 8; ++i) { a += shA[i]; bb += shB[i]; }
        shA[0] = a; shB[0] = bb;
    }
    __syncthreads();
    float mu = shA[0] * (1.f / 768.f);
    float var = shB[0] * (1.f / 768.f) - mu * mu;
    float inv = rsqrtf(var + 1e-5f);
    float o[3] = {v0, v1, v2};
    #pragma unroll
    for (int u = 0; u < 3; ++u) {
        int e = tid + u * 256;
        float c = (o[u] - mu) * inv * g[e] + bta[e];
        if (HOUT) yf[(size_t)row * EV + e] = __float2half_rn(c);
        else      y[(size_t)row * EV + e] = c;
    }
}

__global__ void combine_kernel()
{
    int idx = blockIdx.x * 4 + (threadIdx.x >> 6);
    int d = threadIdx.x & 63;
    int hd = idx % HH;
    int p = (idx / HH) % LV;
    int b = idx / (HH * LV);
    if (b >= BV) return;
    const int ws[5] = {768, 1536, 3072, 6144, 12288};
    const int rs[5] = {1, 2, 4, 8, 16};
    const int gs[5] = {12, 6, 3, 2, 1};
    const int ns[5] = {5, 3, 2, 1, 1};
    const int ub[5] = {0, 120, 192, 240, 264};
    float lses[5];
    size_t oix[5];
    bool cov[5];
    float mx = -1e30f;
    #pragma unroll
    for (int br = 0; br < 5; ++br) {
        int seg = p / ws[br];
        int jj = p - seg * ws[br];
        int off = hd / gs[br];
        int rr = jj & (rs[br] - 1);
        cov[br] = (rr == off);
        if (cov[br]) {
            int j = jj / rs[br];
            int unit = ub[br] + (b * ns[br] + seg) * HH + hd;
            lses[br] = g_lse[(size_t)unit * 768 + j];
            oix[br] = (size_t)unit * 49152 + (size_t)j * 64;
            mx = fmaxf(mx, lses[br]);
        }
    }
    float sw = 0.f, out = 0.f;
    #pragma unroll
    for (int br = 0; br < 5; ++br) {
        if (cov[br]) {
            float wgt = expf(lses[br] - mx);
            sw += wgt;
            out += wgt * g_obr[oix[br] + d];
        }
    }
    g_o[((size_t)(b * LV + p)) * EV + hd * DHv + d] = __float2half_rn(out / sw);
}

__global__ void head_kernel(const float* __restrict__ hn, const float* __restrict__ W,
                            const float* __restrict__ bias, float* __restrict__ out)
{
    int nidx = blockIdx.x * blockDim.x + threadIdx.x;
    int b = blockIdx.y;
    if (nidx >= 1000) return;
    const float* row = hn + (size_t)b * LV * EV;
    float acc = bias[nidx];
    for (int e = 0; e < EV; ++e) acc = fmaf(row[e], W[(size_t)e * 1000 + nidx], acc);
    out[b * 1000 + nidx] = acc;
}

__global__ void splitT(const float* __restrict__ w, fp16* __restrict__ oh,
                       fp16* __restrict__ ol, int K, int N)
{
    __shared__ float t[32][33];
    int kb = blockIdx.x * 32, nb = blockIdx.y * 32;
    int x = threadIdx.x, y = threadIdx.y;
    #pragma unroll
    for (int i = 0; i < 32; i += 8)
        t[y + i][x] = w[(size_t)(kb + y + i) * N + nb + x];
    __syncthreads();
    #pragma unroll
    for (int i = 0; i < 32; i += 8) {
        float v = t[x][y + i];
        fp16 h = __float2half_rn(v);
        fp16 l = __float2half_rn(v - __half2float(h));
        size_t o = (size_t)(nb + y + i) * K + kb + x;
        oh[o] = h; ol[o] = l;
    }
}

__global__ void split_copy(const float* __restrict__ s, fp16* __restrict__ oh,
                           fp16* __restrict__ ol, long n)
{
    long i = ((long)blockIdx.x * 256 + threadIdx.x) * 4;
    if (i >= n) return;
    float4 v = *(const float4*)(s + i);
    float vv[4] = {v.x, v.y, v.z, v.w};
    #pragma unroll
    for (int u = 0; u < 4; ++u) {
        fp16 h = __float2half_rn(vv[u]);
        oh[i + u] = h;
        ol[i + u] = __float2half_rn(vv[u] - __half2float(h));
    }
}

__global__ void pack_bias(const float* __restrict__ bq, const float* __restrict__ bk,
                          const float* __restrict__ bv)
{
    int i = blockIdx.x * 256 + threadIdx.x;
    if (i >= 2 * QKVS) return;
    int l = i / QKVS, e = i % QKVS;
    float v;
    if (e < 768)       v = bq[l * EV + e];
    else if (e < 1536) v = bk[l * EV + e - 768];
    else               v = bv[l * EV + e - 1536];
    g_bqkv[i] = v;
}

// ---------------- host orchestration ------------------------------------------
extern "C" void kernel_launch(void* const* d_in, const int* in_sizes, int n_in,
                              void* d_out, int out_size)
{
    (void)in_sizes; (void)n_in; (void)out_size;
    const float* x        = (const float*)d_in[0];
    const float* patch_w  = (const float*)d_in[1];
    const float* patch_b  = (const float*)d_in[2];
    const float* cls_tok  = (const float*)d_in[3];
    const float* pos_emb  = (const float*)d_in[4];
    const float* ln1_g    = (const float*)d_in[5];
    const float* ln1_b    = (const float*)d_in[6];
    const float* wq       = (const float*)d_in[7];
    const float* bq       = (const float*)d_in[8];
    const float* wk       = (const float*)d_in[9];
    const float* bk       = (const float*)d_in[10];
    const float* wv       = (const float*)d_in[11];
    const float* bv_      = (const float*)d_in[12];
    const float* wo       = (const float*)d_in[13];
    const float* bo       = (const float*)d_in[14];
    const float* ln2_g    = (const float*)d_in[15];
    const float* ln2_b    = (const float*)d_in[16];
    const float* w1       = (const float*)d_in[17];
    const float* b1       = (const float*)d_in[18];
    const float* w2       = (const float*)d_in[19];
    const float* b2       = (const float*)d_in[20];
    const float* normf_g  = (const float*)d_in[21];
    const float* normf_b  = (const float*)d_in[22];
    const float* head_w   = (const float*)d_in[23];
    const float* head_b   = (const float*)d_in[24];
    float* out = (float*)d_out;

    float *p_h, *p_hn, *p_bqkv;
    fp16 *p_col, *p_x, *p_qkv, *p_m1, *p_o, *p_wh, *p_wl;
    cudaGetSymbolAddress((void**)&p_h, g_h);
    cudaGetSymbolAddress((void**)&p_hn, g_hn);
    cudaGetSymbolAddress((void**)&p_bqkv, g_bqkv);
    cudaGetSymbolAddress((void**)&p_col, g_col);
    cudaGetSymbolAddress((void**)&p_x, g_x);
    cudaGetSymbolAddress((void**)&p_qkv, g_qkv);
    cudaGetSymbolAddress((void**)&p_m1, g_m1);
    cudaGetSymbolAddress((void**)&p_o, g_o);
    cudaGetSymbolAddress((void**)&p_wh, g_wh);
    cudaGetSymbolAddress((void**)&p_wl, g_wl);

    const int HG_SMEM2 = 2 * 3 * HG_MAT * 2;
    const int HG_SMEM1 = 2 * 2 * HG_MAT * 2;
    cudaFuncSetAttribute(hgemm<0,0,2>, cudaFuncAttributeMaxDynamicSharedMemorySize, HG_SMEM2);
    cudaFuncSetAttribute(hgemm<1,1,2>, cudaFuncAttributeMaxDynamicSharedMemorySize, HG_SMEM2);
    cudaFuncSetAttribute(hgemm<0,1,1>, cudaFuncAttributeMaxDynamicSharedMemorySize, HG_SMEM1);
    cudaFuncSetAttribute(hgemm<0,0,1>, cudaFuncAttributeMaxDynamicSharedMemorySize, HG_SMEM1);
    cudaFuncSetAttribute(fattn, cudaFuncAttributeMaxDynamicSharedMemorySize, FA_SMEM);

    // ---- weight prep: fp16 hi/lo, N x K layout --------------------------------
    const size_t LSZ = 7077888;
    {
        long n = 786432;
        split_copy<<<(int)((n/4 + 255) / 256), 256>>>(patch_w, p_wh, p_wl, n);
    }
    pack_bias<<<(2 * QKVS + 255) / 256, 256>>>(bq, bk, bv_);
    for (int l = 0; l < 2; ++l) {
        size_t base = 786432 + (size_t)l * LSZ;
        size_t oEE = (size_t)l * EV * EV;
        size_t oE4 = (size_t)l * EV * 3072;
        dim3 blk(32, 8);
        splitT<<<dim3(24, 24), blk>>>(wq + oEE, p_wh + base,           p_wl + base,           768, 768);
        splitT<<<dim3(24, 24), blk>>>(wk + oEE, p_wh + base + 589824,  p_wl + base + 589824,  768, 768);
        splitT<<<dim3(24, 24), blk>>>(wv + oEE, p_wh + base + 1179648, p_wl + base + 1179648, 768, 768);
        splitT<<<dim3(24, 24), blk>>>(wo + oEE, p_wh + base + 1769472, p_wl + base + 1769472, 768, 768);
        splitT<<<dim3(24, 96), blk>>>(w1 + oE4, p_wh + base + 2359296, p_wl + base + 2359296, 768, 3072);
        splitT<<<dim3(96, 24), blk>>>(w2 + oE4, p_wh + base + 4718592, p_wl + base + 4718592, 3072, 768);
    }

    // ---- patch embed (2-pass) ---------------------------------------------------
    im2col_half<<<(BV * NP * 1024 + 255) / 256, 256>>>(x);
    hgemm<0,0,2><<<dim3(48, 6), 256, HG_SMEM2>>>(p_col, p_wh, p_wl,
                                                 patch_b, nullptr, p_hn, nullptr,
                                                 BV * NP, EV, 1024);
    assemble_kernel<<<(int)(((size_t)ML * EV + 255) / 256), 256>>>(cls_tok, pos_emb);

    dim3 gEEt(49, 6);
    dim3 gQKV(49, 18);
    dim3 gE4t(49, 24);

    for (int layer = 0; layer < 2; ++layer) {
        size_t base = 786432 + (size_t)layer * LSZ;
        size_t oE  = (size_t)layer * EV;
        size_t o4  = (size_t)layer * 3072;

        layernorm_kernel<1><<<ML, 256>>>(p_h, ln1_g + oE, ln1_b + oE, nullptr, p_x);
        hgemm<0,1,1><<<gQKV, 256, HG_SMEM1>>>(p_x, p_wh + base, p_wl,
                                              p_bqkv + layer * QKVS, nullptr, nullptr, p_qkv,
                                              ML, QKVS, EV);

        fattn<<<dim3(6, 288), 256, FA_SMEM>>>(p_qkv, layer);
        combine_kernel<<<(BV * LV * HH + 3) / 4, 256>>>();

        hgemm<0,0,1><<<gEEt, 256, HG_SMEM1>>>(p_o, p_wh + base + 1769472, p_wl, bo + oE, p_h, p_h, nullptr, ML, EV, EV);

        layernorm_kernel<1><<<ML, 256>>>(p_h, ln2_g + oE, ln2_b + oE, nullptr, p_x);
        hgemm<1,1,2><<<gE4t, 256, HG_SMEM2>>>(p_x, p_wh + base + 2359296, p_wl + base + 2359296, b1 + o4, nullptr, nullptr, p_m1, ML, 3072, EV);
        hgemm<0,0,2><<<gEEt, 256, HG_SMEM2>>>(p_m1, p_wh + base + 4718592, p_wl + base + 4718592, b2 + oE, p_h, p_h, nullptr, ML, EV, 3072);
    }

    layernorm_kernel<0><<<ML, 256>>>(p_h, normf_g, normf_b, p_hn, nullptr);
    head_kernel<<<dim3(4, BV), 256>>>(p_hn, head_w, head_b, out);
}

// round 11
// speedup vs baseline: 8.4019x; 1.1222x over previous
#include <cuda_runtime.h>
#include <cuda_fp16.h>
#include <math.h>
#include <stdint.h>

#define BV 2
#define LV 3073
#define EV 768
#define HH 12
#define DHv 64
#define ML (BV*LV)          // 6146 rows
#define NP 3072             // patches per batch
#define QKVS 2304           // fused qkv row stride

typedef __half fp16;

// ---------------- scratch (device globals) -----------------------------------
__device__ float g_h  [(size_t)ML*EV];
__device__ float g_hn [(size_t)ML*EV];
__device__ float g_obr[(size_t)288*768*64];
__device__ float g_lse[(size_t)288*768];
__device__ float g_bqkv[2*QKVS];
__device__ __align__(16) fp16 g_col[(size_t)BV*NP*1024];
__device__ __align__(16) fp16 g_x  [(size_t)ML*EV];
__device__ __align__(16) fp16 g_qkv[(size_t)ML*QKVS];
__device__ __align__(16) fp16 g_m1 [(size_t)ML*3072];
__device__ __align__(16) fp16 g_o  [(size_t)ML*EV];
#define WTOT 14942208
__device__ __align__(16) fp16 g_wh[WTOT];
__device__ __align__(16) fp16 g_wl[WTOT];

// ---------------- helpers -----------------------------------------------------
__device__ __forceinline__ float geluf(float v) {
    return 0.5f * v * (1.f + erff(v * 0.70710678118654752f));
}
__device__ __forceinline__ float warpSum(float v) {
    #pragma unroll
    for (int o = 16; o; o >>= 1) v += __shfl_xor_sync(0xffffffffu, v, o);
    return v;
}
__device__ __forceinline__ uint32_t s2u(const void* p) {
    uint32_t a;
    asm("{ .reg .u64 t; cvta.to.shared.u64 t, %1; cvt.u32.u64 %0, t; }" : "=r"(a) : "l"(p));
    return a;
}
__device__ __forceinline__ void cpa16(uint32_t saddr, const void* g, int sz) {
    asm volatile("cp.async.cg.shared.global [%0], [%1], 16, %2;"
                 :: "r"(saddr), "l"(g), "r"(sz) : "memory");
}
__device__ __forceinline__ void mma16816(float* d, const uint32_t* a, uint32_t b0, uint32_t b1) {
    asm volatile("mma.sync.aligned.m16n8k16.row.col.f32.f16.f16.f32 "
                 "{%0,%1,%2,%3},{%4,%5,%6,%7},{%8,%9},{%0,%1,%2,%3};"
                 : "+f"(d[0]), "+f"(d[1]), "+f"(d[2]), "+f"(d[3])
                 : "r"(a[0]), "r"(a[1]), "r"(a[2]), "r"(a[3]), "r"(b0), "r"(b1));
}
__device__ __forceinline__ void ldsm4(uint32_t& r0, uint32_t& r1, uint32_t& r2, uint32_t& r3,
                                      uint32_t saddr) {
    asm volatile("ldmatrix.sync.aligned.m8n8.x4.shared.b16 {%0,%1,%2,%3}, [%4];"
                 : "=r"(r0), "=r"(r1), "=r"(r2), "=r"(r3) : "r"(saddr));
}
__device__ __forceinline__ uint32_t h2u(float c0, float c1) {
    __half2 h = __floats2half2_rn(c0, c1);
    return *(uint32_t*)&h;
}

// ---------------- fp16 tensor-core GEMM (mma.sync + ldmatrix) -----------------
// NPASS==1 uses K-chunk 64 (fewer barriers); NPASS==2 uses K-chunk 32.
template<int NPASS> struct HGC {
    static constexpr int KCH  = (NPASS == 1) ? 64 : 32;
    static constexpr int STR  = KCH + 8;
    static constexpr int MATH = 128 * STR;          // halves per matrix tile
    static constexpr int BUFH = (1 + NPASS) * MATH; // halves per buffer
    static constexpr int SMEM = 2 * BUFH * 2;       // bytes
};

template<int ACT, int OUT, int NPASS, int QSCALE>
__global__ void __launch_bounds__(256, 2)
hgemm(const fp16* __restrict__ A, const fp16* __restrict__ Bh, const fp16* __restrict__ Bl,
      const float* __restrict__ bias, const float* __restrict__ res,
      float* __restrict__ C, fp16* __restrict__ Cf, int M, int N, int K)
{
    constexpr int NMAT = 1 + NPASS;
    constexpr int KCH  = HGC<NPASS>::KCH;
    constexpr int STR  = HGC<NPASS>::STR;
    constexpr int MATH = HGC<NPASS>::MATH;
    constexpr int BUFH = HGC<NPASS>::BUFH;
    constexpr int GPR  = KCH / 8;          // 16B groups per row
    constexpr int ITER = 128 * GPR / 256;  // staging iters per mat
    extern __shared__ fp16 sm[];
    const int tid = threadIdx.x, wid = tid >> 5, lane = tid & 31;
    const int m0 = blockIdx.x * 128, n0 = blockIdx.y * 128;
    const int g = lane >> 2, t = lane & 3;
    const int wm0 = (wid >> 1) * 32, wn0 = (wid & 1) * 64;
    const uint32_t smbase = s2u(sm);
    const fp16* srcs[3] = {A, Bh, Bl};
    const int arow8 = ((lane >> 3) & 1) * 8 + (lane & 7);
    const int acol8 = (lane >> 4) * 8;
    const int bnf   = lane >> 4;
    const int brow  = lane & 7;
    const int bcol8 = ((lane >> 3) & 1) * 8;

    float acc[2][8][4];
    #pragma unroll
    for (int i = 0; i < 2; ++i)
        #pragma unroll
        for (int j = 0; j < 8; ++j)
            #pragma unroll
            for (int u = 0; u < 4; ++u) acc[i][j][u] = 0.f;

    const int KC = K / KCH;

    auto issue = [&](int c) {
        int k0 = c * KCH;
        int buf = c & 1;
        #pragma unroll
        for (int mat = 0; mat < NMAT; ++mat) {
            #pragma unroll
            for (int it = 0; it < ITER; ++it) {
                int idx = it * 256 + tid;
                int row = idx / GPR, q8 = idx % GPR;
                int grow = (mat == 0) ? (m0 + row) : (n0 + row);
                bool ok = (mat > 0) || (grow < M);
                const fp16* gp = ok ? (srcs[mat] + (size_t)grow * K + k0 + q8 * 8) : srcs[mat];
                uint32_t sa = smbase + (uint32_t)(buf * BUFH + mat * MATH + row * STR + q8 * 8) * 2;
                cpa16(sa, gp, ok ? 16 : 0);
            }
        }
        asm volatile("cp.async.commit_group;" ::: "memory");
    };

    issue(0);
    for (int c = 0; c < KC; ++c) {
        if (c + 1 < KC) {
            issue(c + 1);
            asm volatile("cp.async.wait_group 1;" ::: "memory");
        } else {
            asm volatile("cp.async.wait_group 0;" ::: "memory");
        }
        __syncthreads();
        const uint32_t bufoff = (uint32_t)(c & 1) * BUFH;
        #pragma unroll
        for (int ks = 0; ks < KCH; ks += 16) {
            uint32_t afr[2][4];
            #pragma unroll
            for (int mf = 0; mf < 2; ++mf) {
                uint32_t addr = smbase + (bufoff + (uint32_t)((wm0 + mf * 16 + arow8) * STR + ks + acol8)) * 2;
                ldsm4(afr[mf][0], afr[mf][1], afr[mf][2], afr[mf][3], addr);
            }
            #pragma unroll
            for (int p = 0; p < 8; p += 2) {
                uint32_t b0, b1, b2, b3;
                uint32_t baddr = smbase + (bufoff + (uint32_t)(MATH + (wn0 + (p + bnf) * 8 + brow) * STR + ks + bcol8)) * 2;
                ldsm4(b0, b1, b2, b3, baddr);
                #pragma unroll
                for (int mf = 0; mf < 2; ++mf) {
                    mma16816(acc[mf][p],     afr[mf], b0, b1);
                    mma16816(acc[mf][p + 1], afr[mf], b2, b3);
                }
                if (NPASS == 2) {
                    uint32_t l0, l1, l2, l3;
                    ldsm4(l0, l1, l2, l3, baddr + MATH * 2);
                    #pragma unroll
                    for (int mf = 0; mf < 2; ++mf) {
                        mma16816(acc[mf][p],     afr[mf], l0, l1);
                        mma16816(acc[mf][p + 1], afr[mf], l2, l3);
                    }
                }
            }
        }
        __syncthreads();
    }

    #pragma unroll
    for (int mf = 0; mf < 2; ++mf) {
        #pragma unroll
        for (int rr = 0; rr < 2; ++rr) {
            int row = m0 + wm0 + mf * 16 + g + rr * 8;
            if (row >= M) continue;
            #pragma unroll
            for (int nf = 0; nf < 8; ++nf) {
                int col = n0 + wn0 + nf * 8 + 2 * t;
                float c0 = acc[mf][nf][rr * 2 + 0] + bias[col];
                float c1 = acc[mf][nf][rr * 2 + 1] + bias[col + 1];
                if (ACT) { c0 = geluf(c0); c1 = geluf(c1); }
                if (QSCALE && col < 768) { c0 *= 0.125f; c1 *= 0.125f; }
                if (OUT == 1) {
                    __half2 h = __floats2half2_rn(c0, c1);
                    *(__half2*)(Cf + (size_t)row * N + col) = h;
                } else {
                    if (res) {
                        c0 += res[(size_t)row * N + col];
                        c1 += res[(size_t)row * N + col + 1];
                    }
                    *(float2*)(C + (size_t)row * N + col) = make_float2(c0, c1);
                }
            }
        }
    }
}

// ---------------- fused flash attention — ALL branches, one launch -----------
#define FA_QSTR 72
#define FA_VSTR 136
#define FA_Q 0
#define FA_K(b)  (9216 + (b)*9216)
#define FA_VT(b) (27648 + (b)*8704)
#define FA_SMEM (45056*2)

__global__ void __launch_bounds__(256, 1)
fattn(const fp16* __restrict__ qkv, int layer_unused)
{
    const int wsA[5] = {768, 1536, 3072, 6144, 12288};
    const int rsA[5] = {1, 2, 4, 8, 16};
    const int gsA[5] = {12, 6, 3, 2, 1};
    const int nsA[5] = {5, 3, 2, 1, 1};
    const int ubA[5] = {0, 120, 192, 240, 264};

    extern __shared__ fp16 sm[];
    const int tid = threadIdx.x, wid = tid >> 5, lane = tid & 31;
    const int g = lane >> 2, t = lane & 3;
    int gu = blockIdx.y;
    int br = (gu >= 264) ? 4 : (gu >= 240) ? 3 : (gu >= 192) ? 2 : (gu >= 120) ? 1 : 0;
    int z = gu - ubA[br];
    int w = wsA[br], r = rsA[br], gsz = gsA[br], n = nsA[br];
    int hd = z % HH;
    int seg = (z / HH) % n;
    int bb_ = z / (HH * n);
    int off = hd / gsz;
    int m0 = blockIdx.x * 128;
    const uint32_t smb = s2u(sm);
    const int kkey = tid >> 1;
    const int dbase = (tid & 1) * 32;
    const int arow8 = ((lane >> 3) & 1) * 8 + (lane & 7);
    const int acol8 = (lane >> 4) * 8;
    const int bnf   = lane >> 4;
    const int brow  = lane & 7;
    const int bcol8 = ((lane >> 3) & 1) * 8;
    const fp16* q = qkv;
    const fp16* k = qkv + 768;
    const fp16* v = qkv + 1536;

    auto k_issue = [&](int kt, int buf) {
        int n0 = kt * 128;
        #pragma unroll
        for (int it = 0; it < 4; ++it) {
            int idx = it * 256 + tid;
            int row = idx >> 3, q8 = idx & 7;
            int pos = seg * w + (n0 + row) * r + off;
            bool ok = pos < LV;
            const fp16* gp = ok ? (k + ((size_t)(bb_ * LV) + pos) * QKVS + hd * DHv + q8 * 8) : k;
            cpa16(smb + (uint32_t)(FA_K(buf) + row * FA_QSTR + q8 * 8) * 2, gp, ok ? 16 : 0);
        }
        asm volatile("cp.async.commit_group;" ::: "memory");
    };
    auto v_ldg = [&](int kt, uint4* vr) {
        int pos = seg * w + (kt * 128 + kkey) * r + off;
        if (pos < LV) {
            const fp16* pv = v + ((size_t)(bb_ * LV) + pos) * QKVS + hd * DHv + dbase;
            vr[0] = *(const uint4*)pv;        vr[1] = *(const uint4*)(pv + 8);
            vr[2] = *(const uint4*)(pv + 16); vr[3] = *(const uint4*)(pv + 24);
        } else {
            vr[0] = vr[1] = vr[2] = vr[3] = make_uint4(0, 0, 0, 0);
        }
    };
    auto v_sts = [&](const uint4* vr, int buf) {
        fp16 bufh[32];
        *(uint4*)&bufh[0] = vr[0];  *(uint4*)&bufh[8] = vr[1];
        *(uint4*)&bufh[16] = vr[2]; *(uint4*)&bufh[24] = vr[3];
        #pragma unroll
        for (int j = 0; j < 32; ++j) {
            int jj = (j + kkey) & 31;
            sm[FA_VT(buf) + (dbase + jj) * FA_VSTR + kkey] = bufh[jj];
        }
    };

    // Q issue
    #pragma unroll
    for (int it = 0; it < 4; ++it) {
        int idx = it * 256 + tid;
        int row = idx >> 3, q8 = idx & 7;
        int pos = seg * w + (m0 + row) * r + off;
        bool ok = pos < LV;
        const fp16* gp = ok ? (q + ((size_t)(bb_ * LV) + pos) * QKVS + hd * DHv + q8 * 8) : q;
        cpa16(smb + (uint32_t)(FA_Q + row * FA_QSTR + q8 * 8) * 2, gp, ok ? 16 : 0);
    }
    asm volatile("cp.async.commit_group;" ::: "memory");

    uint4 vr[4];
    v_ldg(0, vr);
    k_issue(0, 0);
    asm volatile("cp.async.wait_group 0;" ::: "memory");
    __syncthreads();
    v_sts(vr, 0);

    uint32_t qfr[4][4];
    #pragma unroll
    for (int k4 = 0; k4 < 4; ++k4) {
        uint32_t addr = smb + (uint32_t)(FA_Q + (wid * 16 + arow8) * FA_QSTR + k4 * 16 + acol8) * 2;
        ldsm4(qfr[k4][0], qfr[k4][1], qfr[k4][2], qfr[k4][3], addr);
    }

    float m_[2] = {-1e30f, -1e30f};
    float l_[2] = {0.f, 0.f};
    float acco[8][4];
    #pragma unroll
    for (int j = 0; j < 8; ++j)
        #pragma unroll
        for (int u = 0; u < 4; ++u) acco[j][u] = 0.f;

    for (int kt = 0; kt < 6; ++kt) {
        int buf = kt & 1;
        if (kt < 5) v_ldg(kt + 1, vr);
        if (kt > 0) asm volatile("cp.async.wait_group 0;" ::: "memory");
        __syncthreads();
        if (kt < 5) {
            k_issue(kt + 1, buf ^ 1);
            v_sts(vr, buf ^ 1);
        }

        // S = Q K^T  (q pre-scaled by 1/8 in QKV epilogue)
        float accs[16][4];
        #pragma unroll
        for (int j = 0; j < 16; ++j)
            #pragma unroll
            for (int u = 0; u < 4; ++u) accs[j][u] = 0.f;
        #pragma unroll
        for (int k4 = 0; k4 < 4; ++k4) {
            #pragma unroll
            for (int p = 0; p < 16; p += 2) {
                uint32_t b0, b1, b2, b3;
                uint32_t addr = smb + (uint32_t)(FA_K(buf) + ((p + bnf) * 8 + brow) * FA_QSTR + k4 * 16 + bcol8) * 2;
                ldsm4(b0, b1, b2, b3, addr);
                mma16816(accs[p],     qfr[k4], b0, b1);
                mma16816(accs[p + 1], qfr[k4], b2, b3);
            }
        }

        // online softmax (fast exp)
        float mx0 = -1e30f, mx1 = -1e30f;
        #pragma unroll
        for (int nf = 0; nf < 16; ++nf) {
            mx0 = fmaxf(mx0, fmaxf(accs[nf][0], accs[nf][1]));
            mx1 = fmaxf(mx1, fmaxf(accs[nf][2], accs[nf][3]));
        }
        mx0 = fmaxf(mx0, __shfl_xor_sync(0xffffffffu, mx0, 1));
        mx0 = fmaxf(mx0, __shfl_xor_sync(0xffffffffu, mx0, 2));
        mx1 = fmaxf(mx1, __shfl_xor_sync(0xffffffffu, mx1, 1));
        mx1 = fmaxf(mx1, __shfl_xor_sync(0xffffffffu, mx1, 2));
        float mn0 = fmaxf(m_[0], mx0), mn1 = fmaxf(m_[1], mx1);
        float sc0 = __expf(m_[0] - mn0), sc1 = __expf(m_[1] - mn1);
        float sum0 = 0.f, sum1 = 0.f;
        #pragma unroll
        for (int nf = 0; nf < 16; ++nf) {
            accs[nf][0] = __expf(accs[nf][0] - mn0);
            accs[nf][1] = __expf(accs[nf][1] - mn0);
            accs[nf][2] = __expf(accs[nf][2] - mn1);
            accs[nf][3] = __expf(accs[nf][3] - mn1);
            sum0 += accs[nf][0] + accs[nf][1];
            sum1 += accs[nf][2] + accs[nf][3];
        }
        sum0 += __shfl_xor_sync(0xffffffffu, sum0, 1);
        sum0 += __shfl_xor_sync(0xffffffffu, sum0, 2);
        sum1 += __shfl_xor_sync(0xffffffffu, sum1, 1);
        sum1 += __shfl_xor_sync(0xffffffffu, sum1, 2);
        l_[0] = l_[0] * sc0 + sum0;
        l_[1] = l_[1] * sc1 + sum1;
        m_[0] = mn0; m_[1] = mn1;
        #pragma unroll
        for (int nf = 0; nf < 8; ++nf) {
            acco[nf][0] *= sc0; acco[nf][1] *= sc0;
            acco[nf][2] *= sc1; acco[nf][3] *= sc1;
        }

        // O += P V
        #pragma unroll
        for (int kb = 0; kb < 8; ++kb) {
            uint32_t a[4];
            a[0] = h2u(accs[2*kb][0],   accs[2*kb][1]);
            a[1] = h2u(accs[2*kb][2],   accs[2*kb][3]);
            a[2] = h2u(accs[2*kb+1][0], accs[2*kb+1][1]);
            a[3] = h2u(accs[2*kb+1][2], accs[2*kb+1][3]);
            #pragma unroll
            for (int p = 0; p < 8; p += 2) {
                uint32_t b0, b1, b2, b3;
                uint32_t addr = smb + (uint32_t)(FA_VT(buf) + ((p + bnf) * 8 + brow) * FA_VSTR + kb * 16 + bcol8) * 2;
                ldsm4(b0, b1, b2, b3, addr);
                mma16816(acco[p],     a, b0, b1);
                mma16816(acco[p + 1], a, b2, b3);
            }
        }
    }

    float inv0 = 1.f / l_[0], inv1 = 1.f / l_[1];
    int row0 = m0 + wid * 16 + g;
    int row1 = row0 + 8;
    float* Op = g_obr + (size_t)gu * 49152;
    #pragma unroll
    for (int nf = 0; nf < 8; ++nf) {
        int col = nf * 8 + 2 * t;
        *(float2*)(Op + (size_t)row0 * 64 + col) = make_float2(acco[nf][0] * inv0, acco[nf][1] * inv0);
        *(float2*)(Op + (size_t)row1 * 64 + col) = make_float2(acco[nf][2] * inv1, acco[nf][3] * inv1);
    }
    if (t == 0) {
        g_lse[(size_t)gu * 768 + row0] = m_[0] + logf(l_[0]);
        g_lse[(size_t)gu * 768 + row1] = m_[1] + logf(l_[1]);
    }
}

// ---------------- misc kernels ------------------------------------------------
__global__ void im2col_half(const float* __restrict__ x) {
    int idx = blockIdx.x * 256 + threadIdx.x;
    if (idx >= BV * NP * 1024) return;
    int kk = idx & 1023;
    int p  = (idx >> 10) % NP;
    int b  = (idx >> 10) / NP;
    int pw_ = kk & 15, ph_ = (kk >> 4) & 15, pd_ = kk >> 8;
    int bz = p & 15, by = (p >> 4) & 15, bx = p >> 8;
    float v = x[(((size_t)b * 48 + bx * 4 + pd_) * 256 + by * 16 + ph_) * 256 + bz * 16 + pw_];
    g_col[idx] = __float2half_rn(v);
}

__global__ void assemble_kernel(const float* __restrict__ cls, const float* __restrict__ pos) {
    size_t idx = (size_t)blockIdx.x * 256 + threadIdx.x;
    if (idx >= (size_t)ML * EV) return;
    int e = idx % EV;
    size_t t = idx / EV;
    int l = (int)(t % LV);
    int b = (int)(t / LV);
    float v;
    if (l == 0) v = cls[e] + pos[e];
    else        v = g_hn[((size_t)b * NP + (l - 1)) * EV + e] + pos[(size_t)l * EV + e];
    g_h[idx] = v;
}

template<int HOUT>
__global__ void layernorm_kernel(const float* __restrict__ x, const float* __restrict__ g,
                                 const float* __restrict__ bta, float* __restrict__ y,
                                 fp16* __restrict__ yf)
{
    int row = blockIdx.x;
    const float* xr = x + (size_t)row * EV;
    int tid = threadIdx.x;
    float v0 = xr[tid], v1 = xr[tid + 256], v2 = xr[tid + 512];
    float s = v0 + v1 + v2;
    float s2 = v0 * v0 + v1 * v1 + v2 * v2;
    __shared__ float shA[8], shB[8];
    float ws = warpSum(s), ws2 = warpSum(s2);
    int lane = tid & 31, wid = tid >> 5;
    if (lane == 0) { shA[wid] = ws; shB[wid] = ws2; }
    __syncthreads();
    if (tid == 0) {
        float a = 0, bb = 0;
        #pragma unroll
        for (int i = 0; i < 8; ++i) { a += shA[i]; bb += shB[i]; }
        shA[0] = a; shB[0] = bb;
    }
    __syncthreads();
    float mu = shA[0] * (1.f / 768.f);
    float var = shB[0] * (1.f / 768.f) - mu * mu;
    float inv = rsqrtf(var + 1e-5f);
    float o[3] = {v0, v1, v2};
    #pragma unroll
    for (int u = 0; u < 3; ++u) {
        int e = tid + u * 256;
        float c = (o[u] - mu) * inv * g[e] + bta[e];
        if (HOUT) yf[(size_t)row * EV + e] = __float2half_rn(c);
        else      y[(size_t)row * EV + e] = c;
    }
}

__global__ void combine_kernel()
{
    int idx = blockIdx.x * 4 + (threadIdx.x >> 6);
    int d = threadIdx.x & 63;
    int hd = idx % HH;
    int p = (idx / HH) % LV;
    int b = idx / (HH * LV);
    if (b >= BV) return;
    const int ws[5] = {768, 1536, 3072, 6144, 12288};
    const int rs[5] = {1, 2, 4, 8, 16};
    const int gs[5] = {12, 6, 3, 2, 1};
    const int ns[5] = {5, 3, 2, 1, 1};
    const int ub[5] = {0, 120, 192, 240, 264};
    float lses[5];
    size_t oix[5];
    bool cov[5];
    float mx = -1e30f;
    #pragma unroll
    for (int br = 0; br < 5; ++br) {
        int seg = p / ws[br];
        int jj = p - seg * ws[br];
        int off = hd / gs[br];
        int rr = jj & (rs[br] - 1);
        cov[br] = (rr == off);
        if (cov[br]) {
            int j = jj / rs[br];
            int unit = ub[br] + (b * ns[br] + seg) * HH + hd;
            lses[br] = g_lse[(size_t)unit * 768 + j];
            oix[br] = (size_t)unit * 49152 + (size_t)j * 64;
            mx = fmaxf(mx, lses[br]);
        }
    }
    float sw = 0.f, out = 0.f;
    #pragma unroll
    for (int br = 0; br < 5; ++br) {
        if (cov[br]) {
            float wgt = __expf(lses[br] - mx);
            sw += wgt;
            out += wgt * g_obr[oix[br] + d];
        }
    }
    g_o[((size_t)(b * LV + p)) * EV + hd * DHv + d] = __float2half_rn(out / sw);
}

__global__ void head_kernel(const float* __restrict__ hn, const float* __restrict__ W,
                            const float* __restrict__ bias, float* __restrict__ out)
{
    int nidx = blockIdx.x * blockDim.x + threadIdx.x;
    int b = blockIdx.y;
    if (nidx >= 1000) return;
    const float* row = hn + (size_t)b * LV * EV;
    float acc = bias[nidx];
    for (int e = 0; e < EV; ++e) acc = fmaf(row[e], W[(size_t)e * 1000 + nidx], acc);
    out[b * 1000 + nidx] = acc;
}

__global__ void splitT(const float* __restrict__ w, fp16* __restrict__ oh,
                       fp16* __restrict__ ol, int K, int N)
{
    __shared__ float t[32][33];
    int kb = blockIdx.x * 32, nb = blockIdx.y * 32;
    int x = threadIdx.x, y = threadIdx.y;
    #pragma unroll
    for (int i = 0; i < 32; i += 8)
        t[y + i][x] = w[(size_t)(kb + y + i) * N + nb + x];
    __syncthreads();
    #pragma unroll
    for (int i = 0; i < 32; i += 8) {
        float v = t[x][y + i];
        fp16 h = __float2half_rn(v);
        fp16 l = __float2half_rn(v - __half2float(h));
        size_t o = (size_t)(nb + y + i) * K + kb + x;
        oh[o] = h; ol[o] = l;
    }
}

__global__ void split_copy(const float* __restrict__ s, fp16* __restrict__ oh,
                           fp16* __restrict__ ol, long n)
{
    long i = ((long)blockIdx.x * 256 + threadIdx.x) * 4;
    if (i >= n) return;
    float4 v = *(const float4*)(s + i);
    float vv[4] = {v.x, v.y, v.z, v.w};
    #pragma unroll
    for (int u = 0; u < 4; ++u) {
        fp16 h = __float2half_rn(vv[u]);
        oh[i + u] = h;
        ol[i + u] = __float2half_rn(vv[u] - __half2float(h));
    }
}

__global__ void pack_bias(const float* __restrict__ bq, const float* __restrict__ bk,
                          const float* __restrict__ bv)
{
    int i = blockIdx.x * 256 + threadIdx.x;
    if (i >= 2 * QKVS) return;
    int l = i / QKVS, e = i % QKVS;
    float v;
    if (e < 768)       v = bq[l * EV + e];
    else if (e < 1536) v = bk[l * EV + e - 768];
    else               v = bv[l * EV + e - 1536];
    g_bqkv[i] = v;
}

// ---------------- host orchestration ------------------------------------------
extern "C" void kernel_launch(void* const* d_in, const int* in_sizes, int n_in,
                              void* d_out, int out_size)
{
    (void)in_sizes; (void)n_in; (void)out_size;
    const float* x        = (const float*)d_in[0];
    const float* patch_w  = (const float*)d_in[1];
    const float* patch_b  = (const float*)d_in[2];
    const float* cls_tok  = (const float*)d_in[3];
    const float* pos_emb  = (const float*)d_in[4];
    const float* ln1_g    = (const float*)d_in[5];
    const float* ln1_b    = (const float*)d_in[6];
    const float* wq       = (const float*)d_in[7];
    const float* bq       = (const float*)d_in[8];
    const float* wk       = (const float*)d_in[9];
    const float* bk       = (const float*)d_in[10];
    const float* wv       = (const float*)d_in[11];
    const float* bv_      = (const float*)d_in[12];
    const float* wo       = (const float*)d_in[13];
    const float* bo       = (const float*)d_in[14];
    const float* ln2_g    = (const float*)d_in[15];
    const float* ln2_b    = (const float*)d_in[16];
    const float* w1       = (const float*)d_in[17];
    const float* b1       = (const float*)d_in[18];
    const float* w2       = (const float*)d_in[19];
    const float* b2       = (const float*)d_in[20];
    const float* normf_g  = (const float*)d_in[21];
    const float* normf_b  = (const float*)d_in[22];
    const float* head_w   = (const float*)d_in[23];
    const float* head_b   = (const float*)d_in[24];
    float* out = (float*)d_out;

    float *p_h, *p_hn, *p_bqkv;
    fp16 *p_col, *p_x, *p_qkv, *p_m1, *p_o, *p_wh, *p_wl;
    cudaGetSymbolAddress((void**)&p_h, g_h);
    cudaGetSymbolAddress((void**)&p_hn, g_hn);
    cudaGetSymbolAddress((void**)&p_bqkv, g_bqkv);
    cudaGetSymbolAddress((void**)&p_col, g_col);
    cudaGetSymbolAddress((void**)&p_x, g_x);
    cudaGetSymbolAddress((void**)&p_qkv, g_qkv);
    cudaGetSymbolAddress((void**)&p_m1, g_m1);
    cudaGetSymbolAddress((void**)&p_o, g_o);
    cudaGetSymbolAddress((void**)&p_wh, g_wh);
    cudaGetSymbolAddress((void**)&p_wl, g_wl);

    const int SM2 = HGC<2>::SMEM;
    const int SM1 = HGC<1>::SMEM;
    cudaFuncSetAttribute(hgemm<0,0,2,0>, cudaFuncAttributeMaxDynamicSharedMemorySize, SM2);
    cudaFuncSetAttribute(hgemm<1,1,2,0>, cudaFuncAttributeMaxDynamicSharedMemorySize, SM2);
    cudaFuncSetAttribute(hgemm<0,1,1,1>, cudaFuncAttributeMaxDynamicSharedMemorySize, SM1);
    cudaFuncSetAttribute(hgemm<0,0,1,0>, cudaFuncAttributeMaxDynamicSharedMemorySize, SM1);
    cudaFuncSetAttribute(fattn, cudaFuncAttributeMaxDynamicSharedMemorySize, FA_SMEM);

    // ---- prep, ordered so launch #6 (ncu -s 5 -c 1) is the patch hgemm --------
    const size_t LSZ = 7077888;
    {
        long n = 786432;
        split_copy<<<(int)((n/4 + 255) / 256), 256>>>(patch_w, p_wh, p_wl, n);   // 1
    }
    im2col_half<<<(BV * NP * 1024 + 255) / 256, 256>>>(x);                       // 2
    pack_bias<<<(2 * QKVS + 255) / 256, 256>>>(bq, bk, bv_);                     // 3
    dim3 blk(32, 8);
    splitT<<<dim3(24, 24), blk>>>(wq, p_wh + 786432, p_wl + 786432, 768, 768);   // 4
    splitT<<<dim3(24, 24), blk>>>(wk, p_wh + 786432 + 589824, p_wl + 786432 + 589824, 768, 768); // 5
    hgemm<0,0,2,0><<<dim3(48, 6), 256, SM2>>>(p_col, p_wh, p_wl,
                                              patch_b, nullptr, p_hn, nullptr,
                                              BV * NP, EV, 1024);                // 6 <- profiled
    for (int l = 0; l < 2; ++l) {
        size_t base = 786432 + (size_t)l * LSZ;
        size_t oEE = (size_t)l * EV * EV;
        size_t oE4 = (size_t)l * EV * 3072;
        if (l == 1) {
            splitT<<<dim3(24, 24), blk>>>(wq + oEE, p_wh + base,          p_wl + base,          768, 768);
            splitT<<<dim3(24, 24), blk>>>(wk + oEE, p_wh + base + 589824, p_wl + base + 589824, 768, 768);
        }
        splitT<<<dim3(24, 24), blk>>>(wv + oEE, p_wh + base + 1179648, p_wl + base + 1179648, 768, 768);
        splitT<<<dim3(24, 24), blk>>>(wo + oEE, p_wh + base + 1769472, p_wl + base + 1769472, 768, 768);
        splitT<<<dim3(24, 96), blk>>>(w1 + oE4, p_wh + base + 2359296, p_wl + base + 2359296, 768, 3072);
        splitT<<<dim3(96, 24), blk>>>(w2 + oE4, p_wh + base + 4718592, p_wl + base + 4718592, 3072, 768);
    }

    assemble_kernel<<<(int)(((size_t)ML * EV + 255) / 256), 256>>>(cls_tok, pos_emb);

    dim3 gEEt(49, 6);
    dim3 gQKV(49, 18);
    dim3 gE4t(49, 24);

    for (int layer = 0; layer < 2; ++layer) {
        size_t base = 786432 + (size_t)layer * LSZ;
        size_t oE  = (size_t)layer * EV;
        size_t o4  = (size_t)layer * 3072;

        layernorm_kernel<1><<<ML, 256>>>(p_h, ln1_g + oE, ln1_b + oE, nullptr, p_x);
        hgemm<0,1,1,1><<<gQKV, 256, SM1>>>(p_x, p_wh + base, p_wl,
                                           p_bqkv + layer * QKVS, nullptr, nullptr, p_qkv,
                                           ML, QKVS, EV);

        fattn<<<dim3(6, 288), 256, FA_SMEM>>>(p_qkv, layer);
        combine_kernel<<<(BV * LV * HH + 3) / 4, 256>>>();

        hgemm<0,0,1,0><<<gEEt, 256, SM1>>>(p_o, p_wh + base + 1769472, p_wl, bo + oE, p_h, p_h, nullptr, ML, EV, EV);

        layernorm_kernel<1><<<ML, 256>>>(p_h, ln2_g + oE, ln2_b + oE, nullptr, p_x);
        hgemm<1,1,2,0><<<gE4t, 256, SM2>>>(p_x, p_wh + base + 2359296, p_wl + base + 2359296, b1 + o4, nullptr, nullptr, p_m1, ML, 3072, EV);
        hgemm<0,0,2,0><<<gEEt, 256, SM2>>>(p_m1, p_wh + base + 4718592, p_wl + base + 4718592, b2 + oE, p_h, p_h, nullptr, ML, EV, 3072);
    }

    layernorm_kernel<0><<<ML, 256>>>(p_h, normf_g, normf_b, p_hn, nullptr);
    head_kernel<<<dim3(4, BV), 256>>>(p_hn, head_w, head_b, out);
}

// round 12
// speedup vs baseline: 10.3282x; 1.2293x over previous
#include <cuda_runtime.h>
#include <cuda_fp16.h>
#include <math.h>
#include <stdint.h>

#define BV 2
#define LV 3073
#define EV 768
#define HH 12
#define DHv 64
#define ML (BV*LV)          // 6146 rows
#define NP 3072             // patches per batch
#define QKVS 2304           // fused qkv row stride
#define LOG2E 1.4426950408889634f

typedef __half fp16;

// ---------------- scratch (device globals) -----------------------------------
__device__ float g_h  [(size_t)ML*EV];
__device__ float g_hn [(size_t)ML*EV];
__device__ float g_obr[(size_t)288*768*64];
__device__ float g_lse[(size_t)288*768];
__device__ float g_bqkv[2*QKVS];
__device__ __align__(16) fp16 g_col[(size_t)BV*NP*1024];
__device__ __align__(16) fp16 g_x  [(size_t)ML*EV];
__device__ __align__(16) fp16 g_qkv[(size_t)ML*QKVS];
__device__ __align__(16) fp16 g_m1 [(size_t)ML*3072];
__device__ __align__(16) fp16 g_o  [(size_t)ML*EV];
#define WTOT 14942208
__device__ __align__(16) fp16 g_wh[WTOT];
__device__ __align__(16) fp16 g_wl[WTOT];

// ---------------- helpers -----------------------------------------------------
__device__ __forceinline__ float geluf(float v) {
    return 0.5f * v * (1.f + erff(v * 0.70710678118654752f));
}
__device__ __forceinline__ float warpSum(float v) {
    #pragma unroll
    for (int o = 16; o; o >>= 1) v += __shfl_xor_sync(0xffffffffu, v, o);
    return v;
}
__device__ __forceinline__ uint32_t s2u(const void* p) {
    uint32_t a;
    asm("{ .reg .u64 t; cvta.to.shared.u64 t, %1; cvt.u32.u64 %0, t; }" : "=r"(a) : "l"(p));
    return a;
}
__device__ __forceinline__ void cpa16(uint32_t saddr, const void* g, int sz) {
    asm volatile("cp.async.cg.shared.global [%0], [%1], 16, %2;"
                 :: "r"(saddr), "l"(g), "r"(sz) : "memory");
}
__device__ __forceinline__ void mma16816(float* d, const uint32_t* a, uint32_t b0, uint32_t b1) {
    asm volatile("mma.sync.aligned.m16n8k16.row.col.f32.f16.f16.f32 "
                 "{%0,%1,%2,%3},{%4,%5,%6,%7},{%8,%9},{%0,%1,%2,%3};"
                 : "+f"(d[0]), "+f"(d[1]), "+f"(d[2]), "+f"(d[3])
                 : "r"(a[0]), "r"(a[1]), "r"(a[2]), "r"(a[3]), "r"(b0), "r"(b1));
}
__device__ __forceinline__ void ldsm4(uint32_t& r0, uint32_t& r1, uint32_t& r2, uint32_t& r3,
                                      uint32_t saddr) {
    asm volatile("ldmatrix.sync.aligned.m8n8.x4.shared.b16 {%0,%1,%2,%3}, [%4];"
                 : "=r"(r0), "=r"(r1), "=r"(r2), "=r"(r3) : "r"(saddr));
}
__device__ __forceinline__ uint32_t h2u(float c0, float c1) {
    __half2 h = __floats2half2_rn(c0, c1);
    return *(uint32_t*)&h;
}
__device__ __forceinline__ uint32_t ex2h2(float c0, float c1) {
    uint32_t x = h2u(c0, c1), r;
    asm("ex2.approx.f16x2 %0, %1;" : "=r"(r) : "r"(x));
    return r;
}

// ---------------- fp16 tensor-core GEMM (mma.sync + ldmatrix) -----------------
template<int NPASS> struct HGC {
    static constexpr int KCH  = (NPASS == 1) ? 64 : 32;
    static constexpr int STR  = KCH + 8;
    static constexpr int MATH = 128 * STR;
    static constexpr int BUFH = (1 + NPASS) * MATH;
    static constexpr int SMEM = 2 * BUFH * 2;
};

template<int ACT, int OUT, int NPASS, int QSCALE>
__global__ void __launch_bounds__(256, 2)
hgemm(const fp16* __restrict__ A, const fp16* __restrict__ Bh, const fp16* __restrict__ Bl,
      const float* __restrict__ bias, const float* __restrict__ res,
      float* __restrict__ C, fp16* __restrict__ Cf, int M, int N, int K)
{
    constexpr int NMAT = 1 + NPASS;
    constexpr int KCH  = HGC<NPASS>::KCH;
    constexpr int STR  = HGC<NPASS>::STR;
    constexpr int MATH = HGC<NPASS>::MATH;
    constexpr int BUFH = HGC<NPASS>::BUFH;
    constexpr int GPR  = KCH / 8;
    constexpr int ITER = 128 * GPR / 256;
    extern __shared__ fp16 sm[];
    const int tid = threadIdx.x, wid = tid >> 5, lane = tid & 31;
    const int m0 = blockIdx.x * 128, n0 = blockIdx.y * 128;
    const int g = lane >> 2, t = lane & 3;
    const int wm0 = (wid >> 1) * 32, wn0 = (wid & 1) * 64;
    const uint32_t smbase = s2u(sm);
    const fp16* srcs[3] = {A, Bh, Bl};
    const int arow8 = ((lane >> 3) & 1) * 8 + (lane & 7);
    const int acol8 = (lane >> 4) * 8;
    const int bnf   = lane >> 4;
    const int brow  = lane & 7;
    const int bcol8 = ((lane >> 3) & 1) * 8;

    float acc[2][8][4];
    #pragma unroll
    for (int i = 0; i < 2; ++i)
        #pragma unroll
        for (int j = 0; j < 8; ++j)
            #pragma unroll
            for (int u = 0; u < 4; ++u) acc[i][j][u] = 0.f;

    const int KC = K / KCH;

    auto issue = [&](int c) {
        int k0 = c * KCH;
        int buf = c & 1;
        #pragma unroll
        for (int mat = 0; mat < NMAT; ++mat) {
            #pragma unroll
            for (int it = 0; it < ITER; ++it) {
                int idx = it * 256 + tid;
                int row = idx / GPR, q8 = idx % GPR;
                int grow = (mat == 0) ? (m0 + row) : (n0 + row);
                bool ok = (mat > 0) || (grow < M);
                const fp16* gp = ok ? (srcs[mat] + (size_t)grow * K + k0 + q8 * 8) : srcs[mat];
                uint32_t sa = smbase + (uint32_t)(buf * BUFH + mat * MATH + row * STR + q8 * 8) * 2;
                cpa16(sa, gp, ok ? 16 : 0);
            }
        }
        asm volatile("cp.async.commit_group;" ::: "memory");
    };

    issue(0);
    for (int c = 0; c < KC; ++c) {
        if (c + 1 < KC) {
            issue(c + 1);
            asm volatile("cp.async.wait_group 1;" ::: "memory");
        } else {
            asm volatile("cp.async.wait_group 0;" ::: "memory");
        }
        __syncthreads();
        const uint32_t bufoff = (uint32_t)(c & 1) * BUFH;
        #pragma unroll
        for (int ks = 0; ks < KCH; ks += 16) {
            uint32_t afr[2][4];
            #pragma unroll
            for (int mf = 0; mf < 2; ++mf) {
                uint32_t addr = smbase + (bufoff + (uint32_t)((wm0 + mf * 16 + arow8) * STR + ks + acol8)) * 2;
                ldsm4(afr[mf][0], afr[mf][1], afr[mf][2], afr[mf][3], addr);
            }
            #pragma unroll
            for (int p = 0; p < 8; p += 2) {
                uint32_t b0, b1, b2, b3;
                uint32_t baddr = smbase + (bufoff + (uint32_t)(MATH + (wn0 + (p + bnf) * 8 + brow) * STR + ks + bcol8)) * 2;
                ldsm4(b0, b1, b2, b3, baddr);
                #pragma unroll
                for (int mf = 0; mf < 2; ++mf) {
                    mma16816(acc[mf][p],     afr[mf], b0, b1);
                    mma16816(acc[mf][p + 1], afr[mf], b2, b3);
                }
                if (NPASS == 2) {
                    uint32_t l0, l1, l2, l3;
                    ldsm4(l0, l1, l2, l3, baddr + MATH * 2);
                    #pragma unroll
                    for (int mf = 0; mf < 2; ++mf) {
                        mma16816(acc[mf][p],     afr[mf], l0, l1);
                        mma16816(acc[mf][p + 1], afr[mf], l2, l3);
                    }
                }
            }
        }
        __syncthreads();
    }

    #pragma unroll
    for (int mf = 0; mf < 2; ++mf) {
        #pragma unroll
        for (int rr = 0; rr < 2; ++rr) {
            int row = m0 + wm0 + mf * 16 + g + rr * 8;
            if (row >= M) continue;
            #pragma unroll
            for (int nf = 0; nf < 8; ++nf) {
                int col = n0 + wn0 + nf * 8 + 2 * t;
                float c0 = acc[mf][nf][rr * 2 + 0] + bias[col];
                float c1 = acc[mf][nf][rr * 2 + 1] + bias[col + 1];
                if (ACT) { c0 = geluf(c0); c1 = geluf(c1); }
                if (QSCALE && col < 768) { c0 *= 0.125f; c1 *= 0.125f; }
                if (OUT == 1) {
                    __half2 h = __floats2half2_rn(c0, c1);
                    *(__half2*)(Cf + (size_t)row * N + col) = h;
                } else {
                    if (res) {
                        c0 += res[(size_t)row * N + col];
                        c1 += res[(size_t)row * N + col + 1];
                    }
                    *(float2*)(C + (size_t)row * N + col) = make_float2(c0, c1);
                }
            }
        }
    }
}

// ---------------- fused flash attention — ALL branches, one launch -----------
#define FA_QSTR 72
#define FA_VSTR 136
#define FA_Q 0
#define FA_K(b)  (9216 + (b)*9216)
#define FA_VT(b) (27648 + (b)*8704)
#define FA_SMEM (45056*2)

__global__ void __launch_bounds__(256, 1)
fattn(const fp16* __restrict__ qkv, int layer_unused)
{
    const int wsA[5] = {768, 1536, 3072, 6144, 12288};
    const int rsA[5] = {1, 2, 4, 8, 16};
    const int gsA[5] = {12, 6, 3, 2, 1};
    const int nsA[5] = {5, 3, 2, 1, 1};
    const int ubA[5] = {0, 120, 192, 240, 264};

    extern __shared__ fp16 sm[];
    const int tid = threadIdx.x, wid = tid >> 5, lane = tid & 31;
    const int g = lane >> 2, t = lane & 3;
    int gu = blockIdx.y;
    int br = (gu >= 264) ? 4 : (gu >= 240) ? 3 : (gu >= 192) ? 2 : (gu >= 120) ? 1 : 0;
    int z = gu - ubA[br];
    int w = wsA[br], r = rsA[br], gsz = gsA[br], n = nsA[br];
    int hd = z % HH;
    int seg = (z / HH) % n;
    int bb_ = z / (HH * n);
    int off = hd / gsz;
    int m0 = blockIdx.x * 128;
    const uint32_t smb = s2u(sm);
    const int kkey = tid >> 1;
    const int dbase = (tid & 1) * 32;
    const int arow8 = ((lane >> 3) & 1) * 8 + (lane & 7);
    const int acol8 = (lane >> 4) * 8;
    const int bnf   = lane >> 4;
    const int brow  = lane & 7;
    const int bcol8 = ((lane >> 3) & 1) * 8;
    const fp16* q = qkv;
    const fp16* k = qkv + 768;
    const fp16* v = qkv + 1536;

    auto k_issue = [&](int kt, int buf) {
        int n0 = kt * 128;
        #pragma unroll
        for (int it = 0; it < 4; ++it) {
            int idx = it * 256 + tid;
            int row = idx >> 3, q8 = idx & 7;
            int pos = seg * w + (n0 + row) * r + off;
            bool ok = pos < LV;
            const fp16* gp = ok ? (k + ((size_t)(bb_ * LV) + pos) * QKVS + hd * DHv + q8 * 8) : k;
            cpa16(smb + (uint32_t)(FA_K(buf) + row * FA_QSTR + q8 * 8) * 2, gp, ok ? 16 : 0);
        }
        asm volatile("cp.async.commit_group;" ::: "memory");
    };
    auto v_ldg = [&](int kt, uint4* vr) {
        int pos = seg * w + (kt * 128 + kkey) * r + off;
        if (pos < LV) {
            const fp16* pv = v + ((size_t)(bb_ * LV) + pos) * QKVS + hd * DHv + dbase;
            vr[0] = *(const uint4*)pv;        vr[1] = *(const uint4*)(pv + 8);
            vr[2] = *(const uint4*)(pv + 16); vr[3] = *(const uint4*)(pv + 24);
        } else {
            vr[0] = vr[1] = vr[2] = vr[3] = make_uint4(0, 0, 0, 0);
        }
    };
    auto v_sts = [&](const uint4* vr, int buf) {
        fp16 bufh[32];
        *(uint4*)&bufh[0] = vr[0];  *(uint4*)&bufh[8] = vr[1];
        *(uint4*)&bufh[16] = vr[2]; *(uint4*)&bufh[24] = vr[3];
        #pragma unroll
        for (int j = 0; j < 32; ++j) {
            int jj = (j + kkey) & 31;
            sm[FA_VT(buf) + (dbase + jj) * FA_VSTR + kkey] = bufh[jj];
        }
    };

    // Q issue
    #pragma unroll
    for (int it = 0; it < 4; ++it) {
        int idx = it * 256 + tid;
        int row = idx >> 3, q8 = idx & 7;
        int pos = seg * w + (m0 + row) * r + off;
        bool ok = pos < LV;
        const fp16* gp = ok ? (q + ((size_t)(bb_ * LV) + pos) * QKVS + hd * DHv + q8 * 8) : q;
        cpa16(smb + (uint32_t)(FA_Q + row * FA_QSTR + q8 * 8) * 2, gp, ok ? 16 : 0);
    }
    asm volatile("cp.async.commit_group;" ::: "memory");

    uint4 vr[4];
    v_ldg(0, vr);
    k_issue(0, 0);
    asm volatile("cp.async.wait_group 0;" ::: "memory");
    __syncthreads();
    v_sts(vr, 0);

    uint32_t qfr[4][4];
    #pragma unroll
    for (int k4 = 0; k4 < 4; ++k4) {
        uint32_t addr = smb + (uint32_t)(FA_Q + (wid * 16 + arow8) * FA_QSTR + k4 * 16 + acol8) * 2;
        ldsm4(qfr[k4][0], qfr[k4][1], qfr[k4][2], qfr[k4][3], addr);
    }

    float m_[2] = {-1e30f, -1e30f};
    float l_[2] = {0.f, 0.f};
    float acco[8][4];
    #pragma unroll
    for (int j = 0; j < 8; ++j)
        #pragma unroll
        for (int u = 0; u < 4; ++u) acco[j][u] = 0.f;

    for (int kt = 0; kt < 6; ++kt) {
        int buf = kt & 1;
        if (kt < 5) v_ldg(kt + 1, vr);
        if (kt > 0) asm volatile("cp.async.wait_group 0;" ::: "memory");
        __syncthreads();
        if (kt < 5) {
            k_issue(kt + 1, buf ^ 1);
            v_sts(vr, buf ^ 1);
        }

        // S = Q K^T  (q pre-scaled by 1/8 in QKV epilogue)
        float accs[16][4];
        #pragma unroll
        for (int j = 0; j < 16; ++j)
            #pragma unroll
            for (int u = 0; u < 4; ++u) accs[j][u] = 0.f;
        #pragma unroll
        for (int k4 = 0; k4 < 4; ++k4) {
            #pragma unroll
            for (int p = 0; p < 16; p += 2) {
                uint32_t b0, b1, b2, b3;
                uint32_t addr = smb + (uint32_t)(FA_K(buf) + ((p + bnf) * 8 + brow) * FA_QSTR + k4 * 16 + bcol8) * 2;
                ldsm4(b0, b1, b2, b3, addr);
                mma16816(accs[p],     qfr[k4], b0, b1);
                mma16816(accs[p + 1], qfr[k4], b2, b3);
            }
        }

        // online softmax: P = 2^((s - m) * log2e), computed in fp16x2 via MUFU
        float mx0 = -1e30f, mx1 = -1e30f;
        #pragma unroll
        for (int nf = 0; nf < 16; ++nf) {
            mx0 = fmaxf(mx0, fmaxf(accs[nf][0], accs[nf][1]));
            mx1 = fmaxf(mx1, fmaxf(accs[nf][2], accs[nf][3]));
        }
        mx0 = fmaxf(mx0, __shfl_xor_sync(0xffffffffu, mx0, 1));
        mx0 = fmaxf(mx0, __shfl_xor_sync(0xffffffffu, mx0, 2));
        mx1 = fmaxf(mx1, __shfl_xor_sync(0xffffffffu, mx1, 1));
        mx1 = fmaxf(mx1, __shfl_xor_sync(0xffffffffu, mx1, 2));
        float mn0 = fmaxf(m_[0], mx0), mn1 = fmaxf(m_[1], mx1);
        float mnl0 = mn0 * LOG2E, mnl1 = mn1 * LOG2E;
        uint32_t pfr[16][2];
        float sum0 = 0.f, sum1 = 0.f;
        #pragma unroll
        for (int nf = 0; nf < 16; ++nf) {
            float t0 = fmaf(accs[nf][0], LOG2E, -mnl0);
            float t1 = fmaf(accs[nf][1], LOG2E, -mnl0);
            float t2 = fmaf(accs[nf][2], LOG2E, -mnl1);
            float t3 = fmaf(accs[nf][3], LOG2E, -mnl1);
            pfr[nf][0] = ex2h2(t0, t1);
            pfr[nf][1] = ex2h2(t2, t3);
            float2 f0 = __half22float2(*(__half2*)&pfr[nf][0]);
            float2 f1 = __half22float2(*(__half2*)&pfr[nf][1]);
            sum0 += f0.x + f0.y;
            sum1 += f1.x + f1.y;
        }
        sum0 += __shfl_xor_sync(0xffffffffu, sum0, 1);
        sum0 += __shfl_xor_sync(0xffffffffu, sum0, 2);
        sum1 += __shfl_xor_sync(0xffffffffu, sum1, 1);
        sum1 += __shfl_xor_sync(0xffffffffu, sum1, 2);
        float sc0 = __expf(m_[0] - mn0), sc1 = __expf(m_[1] - mn1);
        l_[0] = l_[0] * sc0 + sum0;
        l_[1] = l_[1] * sc1 + sum1;
        m_[0] = mn0; m_[1] = mn1;
        #pragma unroll
        for (int nf = 0; nf < 8; ++nf) {
            acco[nf][0] *= sc0; acco[nf][1] *= sc0;
            acco[nf][2] *= sc1; acco[nf][3] *= sc1;
        }

        // O += P V — pfr pairs ARE the A-fragment registers
        #pragma unroll
        for (int kb = 0; kb < 8; ++kb) {
            uint32_t a[4] = {pfr[2*kb][0], pfr[2*kb][1], pfr[2*kb+1][0], pfr[2*kb+1][1]};
            #pragma unroll
            for (int p = 0; p < 8; p += 2) {
                uint32_t b0, b1, b2, b3;
                uint32_t addr = smb + (uint32_t)(FA_VT(buf) + ((p + bnf) * 8 + brow) * FA_VSTR + kb * 16 + bcol8) * 2;
                ldsm4(b0, b1, b2, b3, addr);
                mma16816(acco[p],     a, b0, b1);
                mma16816(acco[p + 1], a, b2, b3);
            }
        }
    }

    float inv0 = 1.f / l_[0], inv1 = 1.f / l_[1];
    int row0 = m0 + wid * 16 + g;
    int row1 = row0 + 8;
    float* Op = g_obr + (size_t)gu * 49152;
    #pragma unroll
    for (int nf = 0; nf < 8; ++nf) {
        int col = nf * 8 + 2 * t;
        *(float2*)(Op + (size_t)row0 * 64 + col) = make_float2(acco[nf][0] * inv0, acco[nf][1] * inv0);
        *(float2*)(Op + (size_t)row1 * 64 + col) = make_float2(acco[nf][2] * inv1, acco[nf][3] * inv1);
    }
    if (t == 0) {
        g_lse[(size_t)gu * 768 + row0] = m_[0] + logf(l_[0]);
        g_lse[(size_t)gu * 768 + row1] = m_[1] + logf(l_[1]);
    }
}

// ---------------- misc kernels ------------------------------------------------
__global__ void im2col_half(const float* __restrict__ x) {
    int idx = blockIdx.x * 256 + threadIdx.x;
    if (idx >= BV * NP * 1024) return;
    int kk = idx & 1023;
    int p  = (idx >> 10) % NP;
    int b  = (idx >> 10) / NP;
    int pw_ = kk & 15, ph_ = (kk >> 4) & 15, pd_ = kk >> 8;
    int bz = p & 15, by = (p >> 4) & 15, bx = p >> 8;
    float v = x[(((size_t)b * 48 + bx * 4 + pd_) * 256 + by * 16 + ph_) * 256 + bz * 16 + pw_];
    g_col[idx] = __float2half_rn(v);
}

__global__ void assemble_kernel(const float* __restrict__ cls, const float* __restrict__ pos) {
    size_t idx = (size_t)blockIdx.x * 256 + threadIdx.x;
    if (idx >= (size_t)ML * EV) return;
    int e = idx % EV;
    size_t t = idx / EV;
    int l = (int)(t % LV);
    int b = (int)(t / LV);
    float v;
    if (l == 0) v = cls[e] + pos[e];
    else        v = g_hn[((size_t)b * NP + (l - 1)) * EV + e] + pos[(size_t)l * EV + e];
    g_h[idx] = v;
}

template<int HOUT>
__global__ void layernorm_kernel(const float* __restrict__ x, const float* __restrict__ g,
                                 const float* __restrict__ bta, float* __restrict__ y,
                                 fp16* __restrict__ yf)
{
    int row = blockIdx.x;
    const float* xr = x + (size_t)row * EV;
    int tid = threadIdx.x;
    float v0 = xr[tid], v1 = xr[tid + 256], v2 = xr[tid + 512];
    float s = v0 + v1 + v2;
    float s2 = v0 * v0 + v1 * v1 + v2 * v2;
    __shared__ float shA[8], shB[8];
    float ws = warpSum(s), ws2 = warpSum(s2);
    int lane = tid & 31, wid = tid >> 5;
    if (lane == 0) { shA[wid] = ws; shB[wid] = ws2; }
    __syncthreads();
    if (tid == 0) {
        float a = 0, bb = 0;
        #pragma unroll
        for (int i = 0; i < 8; ++i) { a += shA[i]; bb += shB[i]; }
        shA[0] = a; shB[0] = bb;
    }
    __syncthreads();
    float mu = shA[0] * (1.f / 768.f);
    float var = shB[0] * (1.f / 768.f) - mu * mu;
    float inv = rsqrtf(var + 1e-5f);
    float o[3] = {v0, v1, v2};
    #pragma unroll
    for (int u = 0; u < 3; ++u) {
        int e = tid + u * 256;
        float c = (o[u] - mu) * inv * g[e] + bta[e];
        if (HOUT) yf[(size_t)row * EV + e] = __float2half_rn(c);
        else      y[(size_t)row * EV + e] = c;
    }
}

__global__ void combine_kernel()
{
    int idx = blockIdx.x * 4 + (threadIdx.x >> 6);
    int d = threadIdx.x & 63;
    int hd = idx % HH;
    int p = (idx / HH) % LV;
    int b = idx / (HH * LV);
    if (b >= BV) return;
    const int ws[5] = {768, 1536, 3072, 6144, 12288};
    const int rs[5] = {1, 2, 4, 8, 16};
    const int gs[5] = {12, 6, 3, 2, 1};
    const int ns[5] = {5, 3, 2, 1, 1};
    const int ub[5] = {0, 120, 192, 240, 264};
    float lses[5];
    size_t oix[5];
    bool cov[5];
    float mx = -1e30f;
    #pragma unroll
    for (int br = 0; br < 5; ++br) {
        int seg = p / ws[br];
        int jj = p - seg * ws[br];
        int off = hd / gs[br];
        int rr = jj & (rs[br] - 1);
        cov[br] = (rr == off);
        if (cov[br]) {
            int j = jj / rs[br];
            int unit = ub[br] + (b * ns[br] + seg) * HH + hd;
            lses[br] = g_lse[(size_t)unit * 768 + j];
            oix[br] = (size_t)unit * 49152 + (size_t)j * 64;
            mx = fmaxf(mx, lses[br]);
        }
    }
    float sw = 0.f, out = 0.f;
    #pragma unroll
    for (int br = 0; br < 5; ++br) {
        if (cov[br]) {
            float wgt = __expf(lses[br] - mx);
            sw += wgt;
            out += wgt * g_obr[oix[br] + d];
        }
    }
    g_o[((size_t)(b * LV + p)) * EV + hd * DHv + d] = __float2half_rn(out / sw);
}

__global__ void head_kernel(const float* __restrict__ hn, const float* __restrict__ W,
                            const float* __restrict__ bias, float* __restrict__ out)
{
    int nidx = blockIdx.x * blockDim.x + threadIdx.x;
    int b = blockIdx.y;
    if (nidx >= 1000) return;
    const float* row = hn + (size_t)b * LV * EV;
    float acc = bias[nidx];
    for (int e = 0; e < EV; ++e) acc = fmaf(row[e], W[(size_t)e * 1000 + nidx], acc);
    out[b * 1000 + nidx] = acc;
}

__global__ void splitT(const float* __restrict__ w, fp16* __restrict__ oh,
                       fp16* __restrict__ ol, int K, int N)
{
    __shared__ float t[32][33];
    int kb = blockIdx.x * 32, nb = blockIdx.y * 32;
    int x = threadIdx.x, y = threadIdx.y;
    #pragma unroll
    for (int i = 0; i < 32; i += 8)
        t[y + i][x] = w[(size_t)(kb + y + i) * N + nb + x];
    __syncthreads();
    #pragma unroll
    for (int i = 0; i < 32; i += 8) {
        float v = t[x][y + i];
        fp16 h = __float2half_rn(v);
        fp16 l = __float2half_rn(v - __half2float(h));
        size_t o = (size_t)(nb + y + i) * K + kb + x;
        oh[o] = h; ol[o] = l;
    }
}

__global__ void split_copy(const float* __restrict__ s, fp16* __restrict__ oh,
                           fp16* __restrict__ ol, long n)
{
    long i = ((long)blockIdx.x * 256 + threadIdx.x) * 4;
    if (i >= n) return;
    float4 v = *(const float4*)(s + i);
    float vv[4] = {v.x, v.y, v.z, v.w};
    #pragma unroll
    for (int u = 0; u < 4; ++u) {
        fp16 h = __float2half_rn(vv[u]);
        oh[i + u] = h;
        ol[i + u] = __float2half_rn(vv[u] - __half2float(h));
    }
}

__global__ void pack_bias(const float* __restrict__ bq, const float* __restrict__ bk,
                          const float* __restrict__ bv)
{
    int i = blockIdx.x * 256 + threadIdx.x;
    if (i >= 2 * QKVS) return;
    int l = i / QKVS, e = i % QKVS;
    float v;
    if (e < 768)       v = bq[l * EV + e];
    else if (e < 1536) v = bk[l * EV + e - 768];
    else               v = bv[l * EV + e - 1536];
    g_bqkv[i] = v;
}

// ---------------- host orchestration ------------------------------------------
extern "C" void kernel_launch(void* const* d_in, const int* in_sizes, int n_in,
                              void* d_out, int out_size)
{
    (void)in_sizes; (void)n_in; (void)out_size;
    const float* x        = (const float*)d_in[0];
    const float* patch_w  = (const float*)d_in[1];
    const float* patch_b  = (const float*)d_in[2];
    const float* cls_tok  = (const float*)d_in[3];
    const float* pos_emb  = (const float*)d_in[4];
    const float* ln1_g    = (const float*)d_in[5];
    const float* ln1_b    = (const float*)d_in[6];
    const float* wq       = (const float*)d_in[7];
    const float* bq       = (const float*)d_in[8];
    const float* wk       = (const float*)d_in[9];
    const float* bk       = (const float*)d_in[10];
    const float* wv       = (const float*)d_in[11];
    const float* bv_      = (const float*)d_in[12];
    const float* wo       = (const float*)d_in[13];
    const float* bo       = (const float*)d_in[14];
    const float* ln2_g    = (const float*)d_in[15];
    const float* ln2_b    = (const float*)d_in[16];
    const float* w1       = (const float*)d_in[17];
    const float* b1       = (const float*)d_in[18];
    const float* w2       = (const float*)d_in[19];
    const float* b2       = (const float*)d_in[20];
    const float* normf_g  = (const float*)d_in[21];
    const float* normf_b  = (const float*)d_in[22];
    const float* head_w   = (const float*)d_in[23];
    const float* head_b   = (const float*)d_in[24];
    float* out = (float*)d_out;

    float *p_h, *p_hn, *p_bqkv;
    fp16 *p_col, *p_x, *p_qkv, *p_m1, *p_o, *p_wh, *p_wl;
    cudaGetSymbolAddress((void**)&p_h, g_h);
    cudaGetSymbolAddress((void**)&p_hn, g_hn);
    cudaGetSymbolAddress((void**)&p_bqkv, g_bqkv);
    cudaGetSymbolAddress((void**)&p_col, g_col);
    cudaGetSymbolAddress((void**)&p_x, g_x);
    cudaGetSymbolAddress((void**)&p_qkv, g_qkv);
    cudaGetSymbolAddress((void**)&p_m1, g_m1);
    cudaGetSymbolAddress((void**)&p_o, g_o);
    cudaGetSymbolAddress((void**)&p_wh, g_wh);
    cudaGetSymbolAddress((void**)&p_wl, g_wl);

    const int SM2 = HGC<2>::SMEM;
    const int SM1 = HGC<1>::SMEM;
    cudaFuncSetAttribute(hgemm<0,0,2,0>, cudaFuncAttributeMaxDynamicSharedMemorySize, SM2);
    cudaFuncSetAttribute(hgemm<0,1,1,1>, cudaFuncAttributeMaxDynamicSharedMemorySize, SM1);
    cudaFuncSetAttribute(hgemm<0,0,1,0>, cudaFuncAttributeMaxDynamicSharedMemorySize, SM1);
    cudaFuncSetAttribute(hgemm<1,1,1,0>, cudaFuncAttributeMaxDynamicSharedMemorySize, SM1);
    cudaFuncSetAttribute(fattn, cudaFuncAttributeMaxDynamicSharedMemorySize, FA_SMEM);

    // ---- prep (patch hgemm is our 5th launch for ncu capture) ------------------
    const size_t LSZ = 7077888;
    {
        long n = 786432;
        split_copy<<<(int)((n/4 + 255) / 256), 256>>>(patch_w, p_wh, p_wl, n);   // 1
    }
    im2col_half<<<(BV * NP * 1024 + 255) / 256, 256>>>(x);                       // 2
    pack_bias<<<(2 * QKVS + 255) / 256, 256>>>(bq, bk, bv_);                     // 3
    dim3 blk(32, 8);
    splitT<<<dim3(24, 24), blk>>>(wq, p_wh + 786432, p_wl + 786432, 768, 768);   // 4
    hgemm<0,0,2,0><<<dim3(48, 6), 256, SM2>>>(p_col, p_wh, p_wl,
                                              patch_b, nullptr, p_hn, nullptr,
                                              BV * NP, EV, 1024);                // 5 <- profiled
    for (int l = 0; l < 2; ++l) {
        size_t base = 786432 + (size_t)l * LSZ;
        size_t oEE = (size_t)l * EV * EV;
        size_t oE4 = (size_t)l * EV * 3072;
        if (l == 1)
            splitT<<<dim3(24, 24), blk>>>(wq + oEE, p_wh + base, p_wl + base, 768, 768);
        splitT<<<dim3(24, 24), blk>>>(wk + oEE, p_wh + base + 589824,  p_wl + base + 589824,  768, 768);
        splitT<<<dim3(24, 24), blk>>>(wv + oEE, p_wh + base + 1179648, p_wl + base + 1179648, 768, 768);
        splitT<<<dim3(24, 24), blk>>>(wo + oEE, p_wh + base + 1769472, p_wl + base + 1769472, 768, 768);
        splitT<<<dim3(24, 96), blk>>>(w1 + oE4, p_wh + base + 2359296, p_wl + base + 2359296, 768, 3072);
        splitT<<<dim3(96, 24), blk>>>(w2 + oE4, p_wh + base + 4718592, p_wl + base + 4718592, 3072, 768);
    }

    assemble_kernel<<<(int)(((size_t)ML * EV + 255) / 256), 256>>>(cls_tok, pos_emb);

    dim3 gEEt(49, 6);
    dim3 gQKV(49, 18);
    dim3 gE4t(49, 24);

    for (int layer = 0; layer < 2; ++layer) {
        size_t base = 786432 + (size_t)layer * LSZ;
        size_t oE  = (size_t)layer * EV;
        size_t o4  = (size_t)layer * 3072;

        layernorm_kernel<1><<<ML, 256>>>(p_h, ln1_g + oE, ln1_b + oE, nullptr, p_x);
        hgemm<0,1,1,1><<<gQKV, 256, SM1>>>(p_x, p_wh + base, p_wl,
                                           p_bqkv + layer * QKVS, nullptr, nullptr, p_qkv,
                                           ML, QKVS, EV);

        fattn<<<dim3(6, 288), 256, FA_SMEM>>>(p_qkv, layer);
        combine_kernel<<<(BV * LV * HH + 3) / 4, 256>>>();

        hgemm<0,0,1,0><<<gEEt, 256, SM1>>>(p_o, p_wh + base + 1769472, p_wl, bo + oE, p_h, p_h, nullptr, ML, EV, EV);

        layernorm_kernel<1><<<ML, 256>>>(p_h, ln2_g + oE, ln2_b + oE, nullptr, p_x);
        hgemm<1,1,1,0><<<gE4t, 256, SM1>>>(p_x, p_wh + base + 2359296, p_wl, b1 + o4, nullptr, nullptr, p_m1, ML, 3072, EV);
        hgemm<0,0,1,0><<<gEEt, 256, SM1>>>(p_m1, p_wh + base + 4718592, p_wl, b2 + oE, p_h, p_h, nullptr, ML, EV, 3072);
    }

    layernorm_kernel<0><<<ML, 256>>>(p_h, normf_g, normf_b, p_hn, nullptr);
    head_kernel<<<dim3(4, BV), 256>>>(p_hn, head_w, head_b, out);
}

// round 13
// speedup vs baseline: 11.8202x; 1.1445x over previous
#include <cuda_runtime.h>
#include <cuda_fp16.h>
#include <math.h>
#include <stdint.h>

#define BV 2
#define LV 3073
#define EV 768
#define HH 12
#define DHv 64
#define ML (BV*LV)          // 6146 rows
#define NP 3072             // patches per batch
#define QKVS 2304           // fused qkv row stride
#define LOG2E 1.4426950408889634f

typedef __half fp16;

// ---------------- scratch (device globals) -----------------------------------
__device__ float g_h  [(size_t)ML*EV];
__device__ float g_hn [(size_t)ML*EV];
__device__ __align__(16) fp16 g_obr[(size_t)288*768*64];
__device__ float g_lse[(size_t)288*768];
__device__ float g_bqkv[2*QKVS];
__device__ __align__(16) fp16 g_col[(size_t)BV*NP*1024];
__device__ __align__(16) fp16 g_x  [(size_t)ML*EV];
__device__ __align__(16) fp16 g_qkv[(size_t)ML*QKVS];
__device__ __align__(16) fp16 g_m1 [(size_t)ML*3072];
__device__ __align__(16) fp16 g_o  [(size_t)ML*EV];
#define WTOT 14942208
__device__ __align__(16) fp16 g_wh[WTOT];
__device__ __align__(16) fp16 g_wl[WTOT];   // only patch region used (2-pass)

// ---------------- helpers -----------------------------------------------------
__device__ __forceinline__ float geluf(float v) {
    return 0.5f * v * (1.f + erff(v * 0.70710678118654752f));
}
__device__ __forceinline__ float warpSum(float v) {
    #pragma unroll
    for (int o = 16; o; o >>= 1) v += __shfl_xor_sync(0xffffffffu, v, o);
    return v;
}
__device__ __forceinline__ uint32_t s2u(const void* p) {
    uint32_t a;
    asm("{ .reg .u64 t; cvta.to.shared.u64 t, %1; cvt.u32.u64 %0, t; }" : "=r"(a) : "l"(p));
    return a;
}
__device__ __forceinline__ void cpa16(uint32_t saddr, const void* g, int sz) {
    asm volatile("cp.async.cg.shared.global [%0], [%1], 16, %2;"
                 :: "r"(saddr), "l"(g), "r"(sz) : "memory");
}
__device__ __forceinline__ void mma16816(float* d, const uint32_t* a, uint32_t b0, uint32_t b1) {
    asm volatile("mma.sync.aligned.m16n8k16.row.col.f32.f16.f16.f32 "
                 "{%0,%1,%2,%3},{%4,%5,%6,%7},{%8,%9},{%0,%1,%2,%3};"
                 : "+f"(d[0]), "+f"(d[1]), "+f"(d[2]), "+f"(d[3])
                 : "r"(a[0]), "r"(a[1]), "r"(a[2]), "r"(a[3]), "r"(b0), "r"(b1));
}
__device__ __forceinline__ void ldsm4(uint32_t& r0, uint32_t& r1, uint32_t& r2, uint32_t& r3,
                                      uint32_t saddr) {
    asm volatile("ldmatrix.sync.aligned.m8n8.x4.shared.b16 {%0,%1,%2,%3}, [%4];"
                 : "=r"(r0), "=r"(r1), "=r"(r2), "=r"(r3) : "r"(saddr));
}
__device__ __forceinline__ void ldsm4t(uint32_t& r0, uint32_t& r1, uint32_t& r2, uint32_t& r3,
                                       uint32_t saddr) {
    asm volatile("ldmatrix.sync.aligned.m8n8.x4.trans.shared.b16 {%0,%1,%2,%3}, [%4];"
                 : "=r"(r0), "=r"(r1), "=r"(r2), "=r"(r3) : "r"(saddr));
}
__device__ __forceinline__ uint32_t h2u(float c0, float c1) {
    __half2 h = __floats2half2_rn(c0, c1);
    return *(uint32_t*)&h;
}
__device__ __forceinline__ uint32_t ex2h2(float c0, float c1) {
    uint32_t x = h2u(c0, c1), r;
    asm("ex2.approx.f16x2 %0, %1;" : "=r"(r) : "r"(x));
    return r;
}

// ---------------- fp16 tensor-core GEMM (mma.sync + ldmatrix) -----------------
template<int NPASS> struct HGC {
    static constexpr int KCH  = (NPASS == 1) ? 64 : 32;
    static constexpr int STR  = KCH + 8;
    static constexpr int MATH = 128 * STR;
    static constexpr int BUFH = (1 + NPASS) * MATH;
    static constexpr int SMEM = 2 * BUFH * 2;
};

template<int ACT, int OUT, int NPASS, int QSCALE>
__global__ void __launch_bounds__(256, 2)
hgemm(const fp16* __restrict__ A, const fp16* __restrict__ Bh, const fp16* __restrict__ Bl,
      const float* __restrict__ bias, const float* __restrict__ res,
      float* __restrict__ C, fp16* __restrict__ Cf, int M, int N, int K)
{
    constexpr int NMAT = 1 + NPASS;
    constexpr int KCH  = HGC<NPASS>::KCH;
    constexpr int STR  = HGC<NPASS>::STR;
    constexpr int MATH = HGC<NPASS>::MATH;
    constexpr int BUFH = HGC<NPASS>::BUFH;
    constexpr int GPR  = KCH / 8;
    constexpr int ITER = 128 * GPR / 256;
    extern __shared__ fp16 sm[];
    const int tid = threadIdx.x, wid = tid >> 5, lane = tid & 31;
    const int m0 = blockIdx.x * 128, n0 = blockIdx.y * 128;
    const int g = lane >> 2, t = lane & 3;
    const int wm0 = (wid >> 1) * 32, wn0 = (wid & 1) * 64;
    const uint32_t smbase = s2u(sm);
    const fp16* srcs[3] = {A, Bh, Bl};
    const int arow8 = ((lane >> 3) & 1) * 8 + (lane & 7);
    const int acol8 = (lane >> 4) * 8;
    const int bnf   = lane >> 4;
    const int brow  = lane & 7;
    const int bcol8 = ((lane >> 3) & 1) * 8;

    float acc[2][8][4];
    #pragma unroll
    for (int i = 0; i < 2; ++i)
        #pragma unroll
        for (int j = 0; j < 8; ++j)
            #pragma unroll
            for (int u = 0; u < 4; ++u) acc[i][j][u] = 0.f;

    const int KC = K / KCH;

    auto issue = [&](int c) {
        int k0 = c * KCH;
        int buf = c & 1;
        #pragma unroll
        for (int mat = 0; mat < NMAT; ++mat) {
            #pragma unroll
            for (int it = 0; it < ITER; ++it) {
                int idx = it * 256 + tid;
                int row = idx / GPR, q8 = idx % GPR;
                int grow = (mat == 0) ? (m0 + row) : (n0 + row);
                bool ok = (mat > 0) || (grow < M);
                const fp16* gp = ok ? (srcs[mat] + (size_t)grow * K + k0 + q8 * 8) : srcs[mat];
                uint32_t sa = smbase + (uint32_t)(buf * BUFH + mat * MATH + row * STR + q8 * 8) * 2;
                cpa16(sa, gp, ok ? 16 : 0);
            }
        }
        asm volatile("cp.async.commit_group;" ::: "memory");
    };

    issue(0);
    for (int c = 0; c < KC; ++c) {
        if (c + 1 < KC) {
            issue(c + 1);
            asm volatile("cp.async.wait_group 1;" ::: "memory");
        } else {
            asm volatile("cp.async.wait_group 0;" ::: "memory");
        }
        __syncthreads();
        const uint32_t bufoff = (uint32_t)(c & 1) * BUFH;
        #pragma unroll
        for (int ks = 0; ks < KCH; ks += 16) {
            uint32_t afr[2][4];
            #pragma unroll
            for (int mf = 0; mf < 2; ++mf) {
                uint32_t addr = smbase + (bufoff + (uint32_t)((wm0 + mf * 16 + arow8) * STR + ks + acol8)) * 2;
                ldsm4(afr[mf][0], afr[mf][1], afr[mf][2], afr[mf][3], addr);
            }
            #pragma unroll
            for (int p = 0; p < 8; p += 2) {
                uint32_t b0, b1, b2, b3;
                uint32_t baddr = smbase + (bufoff + (uint32_t)(MATH + (wn0 + (p + bnf) * 8 + brow) * STR + ks + bcol8)) * 2;
                ldsm4(b0, b1, b2, b3, baddr);
                #pragma unroll
                for (int mf = 0; mf < 2; ++mf) {
                    mma16816(acc[mf][p],     afr[mf], b0, b1);
                    mma16816(acc[mf][p + 1], afr[mf], b2, b3);
                }
                if (NPASS == 2) {
                    uint32_t l0, l1, l2, l3;
                    ldsm4(l0, l1, l2, l3, baddr + MATH * 2);
                    #pragma unroll
                    for (int mf = 0; mf < 2; ++mf) {
                        mma16816(acc[mf][p],     afr[mf], l0, l1);
                        mma16816(acc[mf][p + 1], afr[mf], l2, l3);
                    }
                }
            }
        }
        __syncthreads();
    }

    #pragma unroll
    for (int mf = 0; mf < 2; ++mf) {
        #pragma unroll
        for (int rr = 0; rr < 2; ++rr) {
            int row = m0 + wm0 + mf * 16 + g + rr * 8;
            if (row >= M) continue;
            #pragma unroll
            for (int nf = 0; nf < 8; ++nf) {
                int col = n0 + wn0 + nf * 8 + 2 * t;
                float c0 = acc[mf][nf][rr * 2 + 0] + bias[col];
                float c1 = acc[mf][nf][rr * 2 + 1] + bias[col + 1];
                if (ACT) { c0 = geluf(c0); c1 = geluf(c1); }
                if (QSCALE && col < 768) { c0 *= 0.125f; c1 *= 0.125f; }
                if (OUT == 1) {
                    __half2 h = __floats2half2_rn(c0, c1);
                    *(__half2*)(Cf + (size_t)row * N + col) = h;
                } else {
                    if (res) {
                        c0 += res[(size_t)row * N + col];
                        c1 += res[(size_t)row * N + col + 1];
                    }
                    *(float2*)(C + (size_t)row * N + col) = make_float2(c0, c1);
                }
            }
        }
    }
}

// ---------------- fused flash attention — ALL branches, one launch -----------
// smem (halves): Q[128*72] K0 K1 V0 V1 (each 128*72)
#define FA_STR 72
#define FA_Q 0
#define FA_K(b)  (9216 + (b)*9216)
#define FA_V(b)  (27648 + (b)*9216)
#define FA_SMEM (46080*2)

__global__ void __launch_bounds__(256, 1)
fattn(const fp16* __restrict__ qkv, int layer_unused)
{
    const int wsA[5] = {768, 1536, 3072, 6144, 12288};
    const int rsA[5] = {1, 2, 4, 8, 16};
    const int gsA[5] = {12, 6, 3, 2, 1};
    const int nsA[5] = {5, 3, 2, 1, 1};
    const int ubA[5] = {0, 120, 192, 240, 264};

    extern __shared__ fp16 sm[];
    const int tid = threadIdx.x, wid = tid >> 5, lane = tid & 31;
    const int g = lane >> 2, t = lane & 3;
    int gu = blockIdx.y;
    int br = (gu >= 264) ? 4 : (gu >= 240) ? 3 : (gu >= 192) ? 2 : (gu >= 120) ? 1 : 0;
    int z = gu - ubA[br];
    int w = wsA[br], r = rsA[br], gsz = gsA[br], n = nsA[br];
    int hd = z % HH;
    int seg = (z / HH) % n;
    int bb_ = z / (HH * n);
    int off = hd / gsz;
    int m0 = blockIdx.x * 128;
    const uint32_t smb = s2u(sm);
    const int arow8 = ((lane >> 3) & 1) * 8 + (lane & 7);
    const int acol8 = (lane >> 4) * 8;
    const int bnf   = lane >> 4;
    const int brow  = lane & 7;
    const int bcol8 = ((lane >> 3) & 1) * 8;
    const int vrow  = lane & 15;          // trans-ldsm row within 16-key block
    const int vcol  = lane >> 4;          // trans-ldsm dh-group selector
    const fp16* q = qkv;
    const fp16* k = qkv + 768;
    const fp16* v = qkv + 1536;

    auto kv_issue = [&](int kt, int buf) {
        int n0 = kt * 128;
        #pragma unroll
        for (int it = 0; it < 4; ++it) {
            int idx = it * 256 + tid;
            int row = idx >> 3, q8 = idx & 7;
            int pos = seg * w + (n0 + row) * r + off;
            bool ok = pos < LV;
            const fp16* gpk = ok ? (k + ((size_t)(bb_ * LV) + pos) * QKVS + hd * DHv + q8 * 8) : k;
            cpa16(smb + (uint32_t)(FA_K(buf) + row * FA_STR + q8 * 8) * 2, gpk, ok ? 16 : 0);
            const fp16* gpv = ok ? (v + ((size_t)(bb_ * LV) + pos) * QKVS + hd * DHv + q8 * 8) : v;
            cpa16(smb + (uint32_t)(FA_V(buf) + row * FA_STR + q8 * 8) * 2, gpv, ok ? 16 : 0);
        }
        asm volatile("cp.async.commit_group;" ::: "memory");
    };

    // prologue: Q + chunk 0
    #pragma unroll
    for (int it = 0; it < 4; ++it) {
        int idx = it * 256 + tid;
        int row = idx >> 3, q8 = idx & 7;
        int pos = seg * w + (m0 + row) * r + off;
        bool ok = pos < LV;
        const fp16* gp = ok ? (q + ((size_t)(bb_ * LV) + pos) * QKVS + hd * DHv + q8 * 8) : q;
        cpa16(smb + (uint32_t)(FA_Q + row * FA_STR + q8 * 8) * 2, gp, ok ? 16 : 0);
    }
    kv_issue(0, 0);
    asm volatile("cp.async.wait_group 0;" ::: "memory");
    __syncthreads();

    uint32_t qfr[4][4];
    #pragma unroll
    for (int k4 = 0; k4 < 4; ++k4) {
        uint32_t addr = smb + (uint32_t)(FA_Q + (wid * 16 + arow8) * FA_STR + k4 * 16 + acol8) * 2;
        ldsm4(qfr[k4][0], qfr[k4][1], qfr[k4][2], qfr[k4][3], addr);
    }

    float m_[2] = {-1e30f, -1e30f};
    float l_[2] = {0.f, 0.f};
    float acco[8][4];
    #pragma unroll
    for (int j = 0; j < 8; ++j)
        #pragma unroll
        for (int u = 0; u < 4; ++u) acco[j][u] = 0.f;

    for (int kt = 0; kt < 6; ++kt) {
        int buf = kt & 1;
        if (kt < 5) kv_issue(kt + 1, buf ^ 1);

        // S = Q K^T  (q pre-scaled by 1/8 in QKV epilogue)
        float accs[16][4];
        #pragma unroll
        for (int j = 0; j < 16; ++j)
            #pragma unroll
            for (int u = 0; u < 4; ++u) accs[j][u] = 0.f;
        #pragma unroll
        for (int k4 = 0; k4 < 4; ++k4) {
            #pragma unroll
            for (int p = 0; p < 16; p += 2) {
                uint32_t b0, b1, b2, b3;
                uint32_t addr = smb + (uint32_t)(FA_K(buf) + ((p + bnf) * 8 + brow) * FA_STR + k4 * 16 + bcol8) * 2;
                ldsm4(b0, b1, b2, b3, addr);
                mma16816(accs[p],     qfr[k4], b0, b1);
                mma16816(accs[p + 1], qfr[k4], b2, b3);
            }
        }

        // online softmax: P = 2^((s-m)*log2e) in fp16x2 via MUFU
        float mx0 = -1e30f, mx1 = -1e30f;
        #pragma unroll
        for (int nf = 0; nf < 16; ++nf) {
            mx0 = fmaxf(mx0, fmaxf(accs[nf][0], accs[nf][1]));
            mx1 = fmaxf(mx1, fmaxf(accs[nf][2], accs[nf][3]));
        }
        mx0 = fmaxf(mx0, __shfl_xor_sync(0xffffffffu, mx0, 1));
        mx0 = fmaxf(mx0, __shfl_xor_sync(0xffffffffu, mx0, 2));
        mx1 = fmaxf(mx1, __shfl_xor_sync(0xffffffffu, mx1, 1));
        mx1 = fmaxf(mx1, __shfl_xor_sync(0xffffffffu, mx1, 2));
        float mn0 = fmaxf(m_[0], mx0), mn1 = fmaxf(m_[1], mx1);
        float mnl0 = mn0 * LOG2E, mnl1 = mn1 * LOG2E;
        uint32_t pfr[16][2];
        float sum0 = 0.f, sum1 = 0.f;
        #pragma unroll
        for (int nf = 0; nf < 16; ++nf) {
            float t0 = fmaf(accs[nf][0], LOG2E, -mnl0);
            float t1 = fmaf(accs[nf][1], LOG2E, -mnl0);
            float t2 = fmaf(accs[nf][2], LOG2E, -mnl1);
            float t3 = fmaf(accs[nf][3], LOG2E, -mnl1);
            pfr[nf][0] = ex2h2(t0, t1);
            pfr[nf][1] = ex2h2(t2, t3);
            float2 f0 = __half22float2(*(__half2*)&pfr[nf][0]);
            float2 f1 = __half22float2(*(__half2*)&pfr[nf][1]);
            sum0 += f0.x + f0.y;
            sum1 += f1.x + f1.y;
        }
        sum0 += __shfl_xor_sync(0xffffffffu, sum0, 1);
        sum0 += __shfl_xor_sync(0xffffffffu, sum0, 2);
        sum1 += __shfl_xor_sync(0xffffffffu, sum1, 1);
        sum1 += __shfl_xor_sync(0xffffffffu, sum1, 2);
        float sc0 = __expf(m_[0] - mn0), sc1 = __expf(m_[1] - mn1);
        l_[0] = l_[0] * sc0 + sum0;
        l_[1] = l_[1] * sc1 + sum1;
        m_[0] = mn0; m_[1] = mn1;
        #pragma unroll
        for (int nf = 0; nf < 8; ++nf) {
            acco[nf][0] *= sc0; acco[nf][1] *= sc0;
            acco[nf][2] *= sc1; acco[nf][3] *= sc1;
        }

        // O += P V — V row-major, fragments via ldmatrix.trans
        #pragma unroll
        for (int kb = 0; kb < 8; ++kb) {
            uint32_t a[4] = {pfr[2*kb][0], pfr[2*kb][1], pfr[2*kb+1][0], pfr[2*kb+1][1]};
            #pragma unroll
            for (int p = 0; p < 8; p += 2) {
                uint32_t b0, b1, b2, b3;
                uint32_t addr = smb + (uint32_t)(FA_V(buf) + (kb * 16 + vrow) * FA_STR + (p + vcol) * 8) * 2;
                ldsm4t(b0, b1, b2, b3, addr);
                mma16816(acco[p],     a, b0, b1);
                mma16816(acco[p + 1], a, b2, b3);
            }
        }

        if (kt < 5) {
            asm volatile("cp.async.wait_group 0;" ::: "memory");
            __syncthreads();
        }
    }

    float inv0 = 1.f / l_[0], inv1 = 1.f / l_[1];
    int row0 = m0 + wid * 16 + g;
    int row1 = row0 + 8;
    fp16* Op = g_obr + (size_t)gu * 49152;
    #pragma unroll
    for (int nf = 0; nf < 8; ++nf) {
        int col = nf * 8 + 2 * t;
        *(__half2*)(Op + (size_t)row0 * 64 + col) = __floats2half2_rn(acco[nf][0] * inv0, acco[nf][1] * inv0);
        *(__half2*)(Op + (size_t)row1 * 64 + col) = __floats2half2_rn(acco[nf][2] * inv1, acco[nf][3] * inv1);
    }
    if (t == 0) {
        g_lse[(size_t)gu * 768 + row0] = m_[0] + logf(l_[0]);
        g_lse[(size_t)gu * 768 + row1] = m_[1] + logf(l_[1]);
    }
}

// ---------------- misc kernels ------------------------------------------------
__global__ void im2col_half(const float* __restrict__ x) {
    int idx = blockIdx.x * 256 + threadIdx.x;
    if (idx >= BV * NP * 1024) return;
    int kk = idx & 1023;
    int p  = (idx >> 10) % NP;
    int b  = (idx >> 10) / NP;
    int pw_ = kk & 15, ph_ = (kk >> 4) & 15, pd_ = kk >> 8;
    int bz = p & 15, by = (p >> 4) & 15, bx = p >> 8;
    float v = x[(((size_t)b * 48 + bx * 4 + pd_) * 256 + by * 16 + ph_) * 256 + bz * 16 + pw_];
    g_col[idx] = __float2half_rn(v);
}

__global__ void assemble_kernel(const float* __restrict__ cls, const float* __restrict__ pos) {
    size_t idx = (size_t)blockIdx.x * 256 + threadIdx.x;
    if (idx >= (size_t)ML * EV) return;
    int e = idx % EV;
    size_t t = idx / EV;
    int l = (int)(t % LV);
    int b = (int)(t / LV);
    float v;
    if (l == 0) v = cls[e] + pos[e];
    else        v = g_hn[((size_t)b * NP + (l - 1)) * EV + e] + pos[(size_t)l * EV + e];
    g_h[idx] = v;
}

template<int HOUT>
__global__ void layernorm_kernel(const float* __restrict__ x, const float* __restrict__ g,
                                 const float* __restrict__ bta, float* __restrict__ y,
                                 fp16* __restrict__ yf)
{
    int row = blockIdx.x;
    const float* xr = x + (size_t)row * EV;
    int tid = threadIdx.x;
    float v0 = xr[tid], v1 = xr[tid + 256], v2 = xr[tid + 512];
    float s = v0 + v1 + v2;
    float s2 = v0 * v0 + v1 * v1 + v2 * v2;
    __shared__ float shA[8], shB[8];
    float ws = warpSum(s), ws2 = warpSum(s2);
    int lane = tid & 31, wid = tid >> 5;
    if (lane == 0) { shA[wid] = ws; shB[wid] = ws2; }
    __syncthreads();
    if (tid == 0) {
        float a = 0, bb = 0;
        #pragma unroll
        for (int i = 0; i < 8; ++i) { a += shA[i]; bb += shB[i]; }
        shA[0] = a; shB[0] = bb;
    }
    __syncthreads();
    float mu = shA[0] * (1.f / 768.f);
    float var = shB[0] * (1.f / 768.f) - mu * mu;
    float inv = rsqrtf(var + 1e-5f);
    float o[3] = {v0, v1, v2};
    #pragma unroll
    for (int u = 0; u < 3; ++u) {
        int e = tid + u * 256;
        float c = (o[u] - mu) * inv * g[e] + bta[e];
        if (HOUT) yf[(size_t)row * EV + e] = __float2half_rn(c);
        else      y[(size_t)row * EV + e] = c;
    }
}

__global__ void combine_kernel()
{
    int idx = blockIdx.x * 4 + (threadIdx.x >> 6);
    int d = threadIdx.x & 63;
    int hd = idx % HH;
    int p = (idx / HH) % LV;
    int b = idx / (HH * LV);
    if (b >= BV) return;
    const int ws[5] = {768, 1536, 3072, 6144, 12288};
    const int rs[5] = {1, 2, 4, 8, 16};
    const int gs[5] = {12, 6, 3, 2, 1};
    const int ns[5] = {5, 3, 2, 1, 1};
    const int ub[5] = {0, 120, 192, 240, 264};
    float lses[5];
    size_t oix[5];
    bool cov[5];
    float mx = -1e30f;
    #pragma unroll
    for (int br = 0; br < 5; ++br) {
        int seg = p / ws[br];
        int jj = p - seg * ws[br];
        int off = hd / gs[br];
        int rr = jj & (rs[br] - 1);
        cov[br] = (rr == off);
        if (cov[br]) {
            int j = jj / rs[br];
            int unit = ub[br] + (b * ns[br] + seg) * HH + hd;
            lses[br] = g_lse[(size_t)unit * 768 + j];
            oix[br] = (size_t)unit * 49152 + (size_t)j * 64;
            mx = fmaxf(mx, lses[br]);
        }
    }
    float sw = 0.f, out = 0.f;
    #pragma unroll
    for (int br = 0; br < 5; ++br) {
        if (cov[br]) {
            float wgt = __expf(lses[br] - mx);
            sw += wgt;
            out += wgt * __half2float(g_obr[oix[br] + d]);
        }
    }
    g_o[((size_t)(b * LV + p)) * EV + hd * DHv + d] = __float2half_rn(out / sw);
}

__global__ void head_kernel(const float* __restrict__ hn, const float* __restrict__ W,
                            const float* __restrict__ bias, float* __restrict__ out)
{
    int nidx = blockIdx.x * blockDim.x + threadIdx.x;
    int b = blockIdx.y;
    if (nidx >= 1000) return;
    const float* row = hn + (size_t)b * LV * EV;
    float acc = bias[nidx];
    for (int e = 0; e < EV; ++e) acc = fmaf(row[e], W[(size_t)e * 1000 + nidx], acc);
    out[b * 1000 + nidx] = acc;
}

// transpose all of one layer's 1-pass weights (hi only): 6912 tiles of 32x32
__global__ void transT_all(const float* __restrict__ wq, const float* __restrict__ wk,
                           const float* __restrict__ wv, const float* __restrict__ wo,
                           const float* __restrict__ w1, const float* __restrict__ w2,
                           fp16* __restrict__ dst)
{
    int tile = blockIdx.x;
    const float* src;
    int K, N, kb, nb;
    size_t doff;
    if (tile < 2304) {
        int wsel = tile / 576, tt = tile % 576;
        src = (wsel == 0) ? wq : (wsel == 1) ? wk : (wsel == 2) ? wv : wo;
        K = 768; N = 768; doff = (size_t)wsel * 589824;
        kb = (tt % 24) * 32; nb = (tt / 24) * 32;
    } else if (tile < 4608) {
        int tt = tile - 2304;
        src = w1; K = 768; N = 3072; doff = 2359296;
        kb = (tt % 24) * 32; nb = (tt / 24) * 32;
    } else {
        int tt = tile - 4608;
        src = w2; K = 3072; N = 768; doff = 4718592;
        kb = (tt % 96) * 32; nb = (tt / 96) * 32;
    }
    __shared__ float t[32][33];
    int x = threadIdx.x, y = threadIdx.y;
    #pragma unroll
    for (int i = 0; i < 32; i += 8)
        t[y + i][x] = src[(size_t)(kb + y + i) * N + nb + x];
    __syncthreads();
    #pragma unroll
    for (int i = 0; i < 32; i += 8)
        dst[doff + (size_t)(nb + y + i) * K + kb + x] = __float2half_rn(t[x][y + i]);
}

__global__ void split_copy(const float* __restrict__ s, fp16* __restrict__ oh,
                           fp16* __restrict__ ol, long n)
{
    long i = ((long)blockIdx.x * 256 + threadIdx.x) * 4;
    if (i >= n) return;
    float4 v = *(const float4*)(s + i);
    float vv[4] = {v.x, v.y, v.z, v.w};
    #pragma unroll
    for (int u = 0; u < 4; ++u) {
        fp16 h = __float2half_rn(vv[u]);
        oh[i + u] = h;
        ol[i + u] = __float2half_rn(vv[u] - __half2float(h));
    }
}

__global__ void pack_bias(const float* __restrict__ bq, const float* __restrict__ bk,
                          const float* __restrict__ bv)
{
    int i = blockIdx.x * 256 + threadIdx.x;
    if (i >= 2 * QKVS) return;
    int l = i / QKVS, e = i % QKVS;
    float v;
    if (e < 768)       v = bq[l * EV + e];
    else if (e < 1536) v = bk[l * EV + e - 768];
    else               v = bv[l * EV + e - 1536];
    g_bqkv[i] = v;
}

// ---------------- host orchestration ------------------------------------------
extern "C" void kernel_launch(void* const* d_in, const int* in_sizes, int n_in,
                              void* d_out, int out_size)
{
    (void)in_sizes; (void)n_in; (void)out_size;
    const float* x        = (const float*)d_in[0];
    const float* patch_w  = (const float*)d_in[1];
    const float* patch_b  = (const float*)d_in[2];
    const float* cls_tok  = (const float*)d_in[3];
    const float* pos_emb  = (const float*)d_in[4];
    const float* ln1_g    = (const float*)d_in[5];
    const float* ln1_b    = (const float*)d_in[6];
    const float* wq       = (const float*)d_in[7];
    const float* bq       = (const float*)d_in[8];
    const float* wk       = (const float*)d_in[9];
    const float* bk       = (const float*)d_in[10];
    const float* wv       = (const float*)d_in[11];
    const float* bv_      = (const float*)d_in[12];
    const float* wo       = (const float*)d_in[13];
    const float* bo       = (const float*)d_in[14];
    const float* ln2_g    = (const float*)d_in[15];
    const float* ln2_b    = (const float*)d_in[16];
    const float* w1       = (const float*)d_in[17];
    const float* b1       = (const float*)d_in[18];
    const float* w2       = (const float*)d_in[19];
    const float* b2       = (const float*)d_in[20];
    const float* normf_g  = (const float*)d_in[21];
    const float* normf_b  = (const float*)d_in[22];
    const float* head_w   = (const float*)d_in[23];
    const float* head_b   = (const float*)d_in[24];
    float* out = (float*)d_out;

    float *p_h, *p_hn, *p_bqkv;
    fp16 *p_col, *p_x, *p_qkv, *p_m1, *p_o, *p_wh, *p_wl;
    cudaGetSymbolAddress((void**)&p_h, g_h);
    cudaGetSymbolAddress((void**)&p_hn, g_hn);
    cudaGetSymbolAddress((void**)&p_bqkv, g_bqkv);
    cudaGetSymbolAddress((void**)&p_col, g_col);
    cudaGetSymbolAddress((void**)&p_x, g_x);
    cudaGetSymbolAddress((void**)&p_qkv, g_qkv);
    cudaGetSymbolAddress((void**)&p_m1, g_m1);
    cudaGetSymbolAddress((void**)&p_o, g_o);
    cudaGetSymbolAddress((void**)&p_wh, g_wh);
    cudaGetSymbolAddress((void**)&p_wl, g_wl);

    const int SM2 = HGC<2>::SMEM;
    const int SM1 = HGC<1>::SMEM;
    cudaFuncSetAttribute(hgemm<0,0,2,0>, cudaFuncAttributeMaxDynamicSharedMemorySize, SM2);
    cudaFuncSetAttribute(hgemm<0,1,1,1>, cudaFuncAttributeMaxDynamicSharedMemorySize, SM1);
    cudaFuncSetAttribute(hgemm<0,0,1,0>, cudaFuncAttributeMaxDynamicSharedMemorySize, SM1);
    cudaFuncSetAttribute(hgemm<1,1,1,0>, cudaFuncAttributeMaxDynamicSharedMemorySize, SM1);
    cudaFuncSetAttribute(fattn, cudaFuncAttributeMaxDynamicSharedMemorySize, FA_SMEM);

    // ---- prep (launch #6 = patch hgemm, for ncu -s 5 -c 1 capture) -------------
    const size_t LSZ = 7077888;
    dim3 blk(32, 8);
    {
        long n = 786432;
        split_copy<<<(int)((n/4 + 255) / 256), 256>>>(patch_w, p_wh, p_wl, n);       // 1
    }
    im2col_half<<<(BV * NP * 1024 + 255) / 256, 256>>>(x);                           // 2
    pack_bias<<<(2 * QKVS + 255) / 256, 256>>>(bq, bk, bv_);                         // 3
    transT_all<<<6912, blk>>>(wq, wk, wv, wo, w1, w2, p_wh + 786432);                // 4
    transT_all<<<6912, blk>>>(wq + 589824, wk + 589824, wv + 589824, wo + 589824,
                              w1 + 2359296, w2 + 2359296, p_wh + 786432 + LSZ);      // 5
    hgemm<0,0,2,0><<<dim3(48, 6), 256, SM2>>>(p_col, p_wh, p_wl,
                                              patch_b, nullptr, p_hn, nullptr,
                                              BV * NP, EV, 1024);                    // 6 <- profiled
    assemble_kernel<<<(int)(((size_t)ML * EV + 255) / 256), 256>>>(cls_tok, pos_emb);

    dim3 gEEt(49, 6);
    dim3 gQKV(49, 18);
    dim3 gE4t(49, 24);

    for (int layer = 0; layer < 2; ++layer) {
        size_t base = 786432 + (size_t)layer * LSZ;
        size_t oE  = (size_t)layer * EV;
        size_t o4  = (size_t)layer * 3072;

        layernorm_kernel<1><<<ML, 256>>>(p_h, ln1_g + oE, ln1_b + oE, nullptr, p_x);
        hgemm<0,1,1,1><<<gQKV, 256, SM1>>>(p_x, p_wh + base, p_wl,
                                           p_bqkv + layer * QKVS, nullptr, nullptr, p_qkv,
                                           ML, QKVS, EV);

        fattn<<<dim3(6, 288), 256, FA_SMEM>>>(p_qkv, layer);
        combine_kernel<<<(BV * LV * HH + 3) / 4, 256>>>();

        hgemm<0,0,1,0><<<gEEt, 256, SM1>>>(p_o, p_wh + base + 1769472, p_wl, bo + oE, p_h, p_h, nullptr, ML, EV, EV);

        layernorm_kernel<1><<<ML, 256>>>(p_h, ln2_g + oE, ln2_b + oE, nullptr, p_x);
        hgemm<1,1,1,0><<<gE4t, 256, SM1>>>(p_x, p_wh + base + 2359296, p_wl, b1 + o4, nullptr, nullptr, p_m1, ML, 3072, EV);
        hgemm<0,0,1,0><<<gEEt, 256, SM1>>>(p_m1, p_wh + base + 4718592, p_wl, b2 + oE, p_h, p_h, nullptr, ML, EV, 3072);
    }

    layernorm_kernel<0><<<ML, 256>>>(p_h, normf_g, normf_b, p_hn, nullptr);
    head_kernel<<<dim3(4, BV), 256>>>(p_hn, head_w, head_b, out);
}

// round 14
// speedup vs baseline: 12.1104x; 1.0245x over previous
#include <cuda_runtime.h>
#include <cuda_fp16.h>
#include <math.h>
#include <stdint.h>

#define BV 2
#define LV 3073
#define EV 768
#define HH 12
#define DHv 64
#define ML (BV*LV)          // 6146 rows
#define NP 3072             // patches per batch
#define QKVS 2304           // fused qkv row stride
#define LOG2E 1.4426950408889634f

typedef __half fp16;

// ---------------- scratch (device globals) -----------------------------------
__device__ float g_h  [(size_t)ML*EV];
__device__ float g_hn [(size_t)ML*EV];
__device__ __align__(16) fp16 g_obr[(size_t)288*768*64];
__device__ float g_lse[(size_t)288*768];
__device__ float g_bqkv[2*QKVS];
__device__ __align__(16) fp16 g_col[(size_t)BV*NP*1024];
__device__ __align__(16) fp16 g_x  [(size_t)ML*EV];
__device__ __align__(16) fp16 g_qkv[(size_t)ML*QKVS];
__device__ __align__(16) fp16 g_m1 [(size_t)ML*3072];
__device__ __align__(16) fp16 g_o  [(size_t)ML*EV];
#define WTOT 14942208
__device__ __align__(16) fp16 g_wh[WTOT];
__device__ __align__(16) fp16 g_wl[WTOT];   // only patch region used (2-pass)

// ---------------- helpers -----------------------------------------------------
__device__ __forceinline__ float geluf(float v) {
    return 0.5f * v * (1.f + erff(v * 0.70710678118654752f));
}
__device__ __forceinline__ float warpSum(float v) {
    #pragma unroll
    for (int o = 16; o; o >>= 1) v += __shfl_xor_sync(0xffffffffu, v, o);
    return v;
}
__device__ __forceinline__ uint32_t s2u(const void* p) {
    uint32_t a;
    asm("{ .reg .u64 t; cvta.to.shared.u64 t, %1; cvt.u32.u64 %0, t; }" : "=r"(a) : "l"(p));
    return a;
}
__device__ __forceinline__ void cpa16(uint32_t saddr, const void* g, int sz) {
    asm volatile("cp.async.cg.shared.global [%0], [%1], 16, %2;"
                 :: "r"(saddr), "l"(g), "r"(sz) : "memory");
}
__device__ __forceinline__ void mma16816(float* d, const uint32_t* a, uint32_t b0, uint32_t b1) {
    asm volatile("mma.sync.aligned.m16n8k16.row.col.f32.f16.f16.f32 "
                 "{%0,%1,%2,%3},{%4,%5,%6,%7},{%8,%9},{%0,%1,%2,%3};"
                 : "+f"(d[0]), "+f"(d[1]), "+f"(d[2]), "+f"(d[3])
                 : "r"(a[0]), "r"(a[1]), "r"(a[2]), "r"(a[3]), "r"(b0), "r"(b1));
}
__device__ __forceinline__ void ldsm4(uint32_t& r0, uint32_t& r1, uint32_t& r2, uint32_t& r3,
                                      uint32_t saddr) {
    asm volatile("ldmatrix.sync.aligned.m8n8.x4.shared.b16 {%0,%1,%2,%3}, [%4];"
                 : "=r"(r0), "=r"(r1), "=r"(r2), "=r"(r3) : "r"(saddr));
}
__device__ __forceinline__ void ldsm4t(uint32_t& r0, uint32_t& r1, uint32_t& r2, uint32_t& r3,
                                       uint32_t saddr) {
    asm volatile("ldmatrix.sync.aligned.m8n8.x4.trans.shared.b16 {%0,%1,%2,%3}, [%4];"
                 : "=r"(r0), "=r"(r1), "=r"(r2), "=r"(r3) : "r"(saddr));
}
__device__ __forceinline__ uint32_t h2u(float c0, float c1) {
    __half2 h = __floats2half2_rn(c0, c1);
    return *(uint32_t*)&h;
}
__device__ __forceinline__ uint32_t ex2h2(float c0, float c1) {
    uint32_t x = h2u(c0, c1), r;
    asm("ex2.approx.f16x2 %0, %1;" : "=r"(r) : "r"(x));
    return r;
}

// ---------------- fp16 tensor-core GEMM (mma.sync + ldmatrix) -----------------
template<int NPASS> struct HGC {
    static constexpr int KCH  = (NPASS == 1) ? 64 : 32;
    static constexpr int STR  = KCH + 8;
    static constexpr int MATH = 128 * STR;
    static constexpr int BUFH = (1 + NPASS) * MATH;
    static constexpr int SMEM = 2 * BUFH * 2;
};

template<int ACT, int OUT, int NPASS, int QSCALE>
__global__ void __launch_bounds__(256, 2)
hgemm(const fp16* __restrict__ A, const fp16* __restrict__ Bh, const fp16* __restrict__ Bl,
      const float* __restrict__ bias, const float* __restrict__ res,
      float* __restrict__ C, fp16* __restrict__ Cf, int M, int N, int K)
{
    constexpr int NMAT = 1 + NPASS;
    constexpr int KCH  = HGC<NPASS>::KCH;
    constexpr int STR  = HGC<NPASS>::STR;
    constexpr int MATH = HGC<NPASS>::MATH;
    constexpr int BUFH = HGC<NPASS>::BUFH;
    constexpr int GPR  = KCH / 8;
    constexpr int ITER = 128 * GPR / 256;
    extern __shared__ fp16 sm[];
    const int tid = threadIdx.x, wid = tid >> 5, lane = tid & 31;
    const int m0 = blockIdx.x * 128, n0 = blockIdx.y * 128;
    const int g = lane >> 2, t = lane & 3;
    const int wm0 = (wid >> 1) * 32, wn0 = (wid & 1) * 64;
    const uint32_t smbase = s2u(sm);
    const fp16* srcs[3] = {A, Bh, Bl};
    const int arow8 = ((lane >> 3) & 1) * 8 + (lane & 7);
    const int acol8 = (lane >> 4) * 8;
    const int bnf   = lane >> 4;
    const int brow  = lane & 7;
    const int bcol8 = ((lane >> 3) & 1) * 8;

    float acc[2][8][4];
    #pragma unroll
    for (int i = 0; i < 2; ++i)
        #pragma unroll
        for (int j = 0; j < 8; ++j)
            #pragma unroll
            for (int u = 0; u < 4; ++u) acc[i][j][u] = 0.f;

    const int KC = K / KCH;

    auto issue = [&](int c) {
        int k0 = c * KCH;
        int buf = c & 1;
        #pragma unroll
        for (int mat = 0; mat < NMAT; ++mat) {
            #pragma unroll
            for (int it = 0; it < ITER; ++it) {
                int idx = it * 256 + tid;
                int row = idx / GPR, q8 = idx % GPR;
                int grow = (mat == 0) ? (m0 + row) : (n0 + row);
                bool ok = (mat > 0) || (grow < M);
                const fp16* gp = ok ? (srcs[mat] + (size_t)grow * K + k0 + q8 * 8) : srcs[mat];
                uint32_t sa = smbase + (uint32_t)(buf * BUFH + mat * MATH + row * STR + q8 * 8) * 2;
                cpa16(sa, gp, ok ? 16 : 0);
            }
        }
        asm volatile("cp.async.commit_group;" ::: "memory");
    };

    issue(0);
    for (int c = 0; c < KC; ++c) {
        if (c + 1 < KC) {
            issue(c + 1);
            asm volatile("cp.async.wait_group 1;" ::: "memory");
        } else {
            asm volatile("cp.async.wait_group 0;" ::: "memory");
        }
        __syncthreads();
        const uint32_t bufoff = (uint32_t)(c & 1) * BUFH;
        #pragma unroll
        for (int ks = 0; ks < KCH; ks += 16) {
            uint32_t afr[2][4];
            #pragma unroll
            for (int mf = 0; mf < 2; ++mf) {
                uint32_t addr = smbase + (bufoff + (uint32_t)((wm0 + mf * 16 + arow8) * STR + ks + acol8)) * 2;
                ldsm4(afr[mf][0], afr[mf][1], afr[mf][2], afr[mf][3], addr);
            }
            #pragma unroll
            for (int p = 0; p < 8; p += 2) {
                uint32_t b0, b1, b2, b3;
                uint32_t baddr = smbase + (bufoff + (uint32_t)(MATH + (wn0 + (p + bnf) * 8 + brow) * STR + ks + bcol8)) * 2;
                ldsm4(b0, b1, b2, b3, baddr);
                #pragma unroll
                for (int mf = 0; mf < 2; ++mf) {
                    mma16816(acc[mf][p],     afr[mf], b0, b1);
                    mma16816(acc[mf][p + 1], afr[mf], b2, b3);
                }
                if (NPASS == 2) {
                    uint32_t l0, l1, l2, l3;
                    ldsm4(l0, l1, l2, l3, baddr + MATH * 2);
                    #pragma unroll
                    for (int mf = 0; mf < 2; ++mf) {
                        mma16816(acc[mf][p],     afr[mf], l0, l1);
                        mma16816(acc[mf][p + 1], afr[mf], l2, l3);
                    }
                }
            }
        }
        __syncthreads();
    }

    #pragma unroll
    for (int mf = 0; mf < 2; ++mf) {
        #pragma unroll
        for (int rr = 0; rr < 2; ++rr) {
            int row = m0 + wm0 + mf * 16 + g + rr * 8;
            if (row >= M) continue;
            #pragma unroll
            for (int nf = 0; nf < 8; ++nf) {
                int col = n0 + wn0 + nf * 8 + 2 * t;
                float c0 = acc[mf][nf][rr * 2 + 0] + bias[col];
                float c1 = acc[mf][nf][rr * 2 + 1] + bias[col + 1];
                if (ACT) { c0 = geluf(c0); c1 = geluf(c1); }
                if (QSCALE && col < 768) { c0 *= 0.125f; c1 *= 0.125f; }
                if (OUT == 1) {
                    __half2 h = __floats2half2_rn(c0, c1);
                    *(__half2*)(Cf + (size_t)row * N + col) = h;
                } else {
                    if (res) {
                        c0 += res[(size_t)row * N + col];
                        c1 += res[(size_t)row * N + col + 1];
                    }
                    *(float2*)(C + (size_t)row * N + col) = make_float2(c0, c1);
                }
            }
        }
    }
}

// ---------------- fused flash attention — 64-key chunks, occupancy 2 ---------
// smem (halves): Q[128*72]=9216, K0 K1 V0 V1 (each 64*72=4608) -> 27648 h = 55296 B
#define FA_STR 72
#define FA_Q 0
#define FA_K(b)  (9216 + (b)*4608)
#define FA_V(b)  (18432 + (b)*4608)
#define FA_SMEM (27648*2)

__global__ void __launch_bounds__(256, 2)
fattn(const fp16* __restrict__ qkv, int layer_unused)
{
    const int wsA[5] = {768, 1536, 3072, 6144, 12288};
    const int rsA[5] = {1, 2, 4, 8, 16};
    const int gsA[5] = {12, 6, 3, 2, 1};
    const int nsA[5] = {5, 3, 2, 1, 1};
    const int ubA[5] = {0, 120, 192, 240, 264};

    extern __shared__ fp16 sm[];
    const int tid = threadIdx.x, wid = tid >> 5, lane = tid & 31;
    const int g = lane >> 2, t = lane & 3;
    int gu = blockIdx.y;
    int br = (gu >= 264) ? 4 : (gu >= 240) ? 3 : (gu >= 192) ? 2 : (gu >= 120) ? 1 : 0;
    int z = gu - ubA[br];
    int w = wsA[br], r = rsA[br], gsz = gsA[br], n = nsA[br];
    int hd = z % HH;
    int seg = (z / HH) % n;
    int bb_ = z / (HH * n);
    int off = hd / gsz;
    int m0 = blockIdx.x * 128;
    const uint32_t smb = s2u(sm);
    const int arow8 = ((lane >> 3) & 1) * 8 + (lane & 7);
    const int acol8 = (lane >> 4) * 8;
    const int bnf   = lane >> 4;
    const int brow  = lane & 7;
    const int bcol8 = ((lane >> 3) & 1) * 8;
    const int vrow  = lane & 15;
    const int vcol  = lane >> 4;
    const fp16* q = qkv;
    const fp16* k = qkv + 768;
    const fp16* v = qkv + 1536;

    // K+V 64-key chunk: 64 rows x 8 groups x 2 mats = 1024 cp / 256 thr = 4
    auto kv_issue = [&](int kt, int buf) {
        int n0 = kt * 64;
        #pragma unroll
        for (int it = 0; it < 2; ++it) {
            int idx = it * 256 + tid;
            int row = idx >> 3, q8 = idx & 7;
            int pos = seg * w + (n0 + row) * r + off;
            bool ok = pos < LV;
            const fp16* gpk = ok ? (k + ((size_t)(bb_ * LV) + pos) * QKVS + hd * DHv + q8 * 8) : k;
            cpa16(smb + (uint32_t)(FA_K(buf) + row * FA_STR + q8 * 8) * 2, gpk, ok ? 16 : 0);
            const fp16* gpv = ok ? (v + ((size_t)(bb_ * LV) + pos) * QKVS + hd * DHv + q8 * 8) : v;
            cpa16(smb + (uint32_t)(FA_V(buf) + row * FA_STR + q8 * 8) * 2, gpv, ok ? 16 : 0);
        }
        asm volatile("cp.async.commit_group;" ::: "memory");
    };

    // prologue: Q + chunk 0
    #pragma unroll
    for (int it = 0; it < 4; ++it) {
        int idx = it * 256 + tid;
        int row = idx >> 3, q8 = idx & 7;
        int pos = seg * w + (m0 + row) * r + off;
        bool ok = pos < LV;
        const fp16* gp = ok ? (q + ((size_t)(bb_ * LV) + pos) * QKVS + hd * DHv + q8 * 8) : q;
        cpa16(smb + (uint32_t)(FA_Q + row * FA_STR + q8 * 8) * 2, gp, ok ? 16 : 0);
    }
    kv_issue(0, 0);
    asm volatile("cp.async.wait_group 0;" ::: "memory");
    __syncthreads();

    uint32_t qfr[4][4];
    #pragma unroll
    for (int k4 = 0; k4 < 4; ++k4) {
        uint32_t addr = smb + (uint32_t)(FA_Q + (wid * 16 + arow8) * FA_STR + k4 * 16 + acol8) * 2;
        ldsm4(qfr[k4][0], qfr[k4][1], qfr[k4][2], qfr[k4][3], addr);
    }

    float m_[2] = {-1e30f, -1e30f};
    float l_[2] = {0.f, 0.f};
    float acco[8][4];
    #pragma unroll
    for (int j = 0; j < 8; ++j)
        #pragma unroll
        for (int u = 0; u < 4; ++u) acco[j][u] = 0.f;

    for (int kt = 0; kt < 12; ++kt) {
        int buf = kt & 1;
        if (kt < 11) kv_issue(kt + 1, buf ^ 1);

        // S = Q K^T over 64 keys
        float accs[8][4];
        #pragma unroll
        for (int j = 0; j < 8; ++j)
            #pragma unroll
            for (int u = 0; u < 4; ++u) accs[j][u] = 0.f;
        #pragma unroll
        for (int k4 = 0; k4 < 4; ++k4) {
            #pragma unroll
            for (int p = 0; p < 8; p += 2) {
                uint32_t b0, b1, b2, b3;
                uint32_t addr = smb + (uint32_t)(FA_K(buf) + ((p + bnf) * 8 + brow) * FA_STR + k4 * 16 + bcol8) * 2;
                ldsm4(b0, b1, b2, b3, addr);
                mma16816(accs[p],     qfr[k4], b0, b1);
                mma16816(accs[p + 1], qfr[k4], b2, b3);
            }
        }

        // online softmax: P = 2^((s-m)*log2e) in fp16x2 via MUFU
        float mx0 = -1e30f, mx1 = -1e30f;
        #pragma unroll
        for (int nf = 0; nf < 8; ++nf) {
            mx0 = fmaxf(mx0, fmaxf(accs[nf][0], accs[nf][1]));
            mx1 = fmaxf(mx1, fmaxf(accs[nf][2], accs[nf][3]));
        }
        mx0 = fmaxf(mx0, __shfl_xor_sync(0xffffffffu, mx0, 1));
        mx0 = fmaxf(mx0, __shfl_xor_sync(0xffffffffu, mx0, 2));
        mx1 = fmaxf(mx1, __shfl_xor_sync(0xffffffffu, mx1, 1));
        mx1 = fmaxf(mx1, __shfl_xor_sync(0xffffffffu, mx1, 2));
        float mn0 = fmaxf(m_[0], mx0), mn1 = fmaxf(m_[1], mx1);
        float mnl0 = mn0 * LOG2E, mnl1 = mn1 * LOG2E;
        uint32_t pfr[8][2];
        float sum0 = 0.f, sum1 = 0.f;
        #pragma unroll
        for (int nf = 0; nf < 8; ++nf) {
            float t0 = fmaf(accs[nf][0], LOG2E, -mnl0);
            float t1 = fmaf(accs[nf][1], LOG2E, -mnl0);
            float t2 = fmaf(accs[nf][2], LOG2E, -mnl1);
            float t3 = fmaf(accs[nf][3], LOG2E, -mnl1);
            pfr[nf][0] = ex2h2(t0, t1);
            pfr[nf][1] = ex2h2(t2, t3);
            float2 f0 = __half22float2(*(__half2*)&pfr[nf][0]);
            float2 f1 = __half22float2(*(__half2*)&pfr[nf][1]);
            sum0 += f0.x + f0.y;
            sum1 += f1.x + f1.y;
        }
        sum0 += __shfl_xor_sync(0xffffffffu, sum0, 1);
        sum0 += __shfl_xor_sync(0xffffffffu, sum0, 2);
        sum1 += __shfl_xor_sync(0xffffffffu, sum1, 1);
        sum1 += __shfl_xor_sync(0xffffffffu, sum1, 2);
        float sc0 = __expf(m_[0] - mn0), sc1 = __expf(m_[1] - mn1);
        l_[0] = l_[0] * sc0 + sum0;
        l_[1] = l_[1] * sc1 + sum1;
        m_[0] = mn0; m_[1] = mn1;
        #pragma unroll
        for (int nf = 0; nf < 8; ++nf) {
            acco[nf][0] *= sc0; acco[nf][1] *= sc0;
            acco[nf][2] *= sc1; acco[nf][3] *= sc1;
        }

        // O += P V — V row-major, fragments via ldmatrix.trans (4 kb of 16 keys)
        #pragma unroll
        for (int kb = 0; kb < 4; ++kb) {
            uint32_t a[4] = {pfr[2*kb][0], pfr[2*kb][1], pfr[2*kb+1][0], pfr[2*kb+1][1]};
            #pragma unroll
            for (int p = 0; p < 8; p += 2) {
                uint32_t b0, b1, b2, b3;
                uint32_t addr = smb + (uint32_t)(FA_V(buf) + (kb * 16 + vrow) * FA_STR + (p + vcol) * 8) * 2;
                ldsm4t(b0, b1, b2, b3, addr);
                mma16816(acco[p],     a, b0, b1);
                mma16816(acco[p + 1], a, b2, b3);
            }
        }

        if (kt < 11) {
            asm volatile("cp.async.wait_group 0;" ::: "memory");
            __syncthreads();
        }
    }

    float inv0 = 1.f / l_[0], inv1 = 1.f / l_[1];
    int row0 = m0 + wid * 16 + g;
    int row1 = row0 + 8;
    fp16* Op = g_obr + (size_t)gu * 49152;
    #pragma unroll
    for (int nf = 0; nf < 8; ++nf) {
        int col = nf * 8 + 2 * t;
        *(__half2*)(Op + (size_t)row0 * 64 + col) = __floats2half2_rn(acco[nf][0] * inv0, acco[nf][1] * inv0);
        *(__half2*)(Op + (size_t)row1 * 64 + col) = __floats2half2_rn(acco[nf][2] * inv1, acco[nf][3] * inv1);
    }
    if (t == 0) {
        g_lse[(size_t)gu * 768 + row0] = m_[0] + logf(l_[0]);
        g_lse[(size_t)gu * 768 + row1] = m_[1] + logf(l_[1]);
    }
}

// ---------------- misc kernels ------------------------------------------------
__global__ void im2col_half(const float* __restrict__ x) {
    int idx = blockIdx.x * 256 + threadIdx.x;
    if (idx >= BV * NP * 1024) return;
    int kk = idx & 1023;
    int p  = (idx >> 10) % NP;
    int b  = (idx >> 10) / NP;
    int pw_ = kk & 15, ph_ = (kk >> 4) & 15, pd_ = kk >> 8;
    int bz = p & 15, by = (p >> 4) & 15, bx = p >> 8;
    float v = x[(((size_t)b * 48 + bx * 4 + pd_) * 256 + by * 16 + ph_) * 256 + bz * 16 + pw_];
    g_col[idx] = __float2half_rn(v);
}

__global__ void assemble_kernel(const float* __restrict__ cls, const float* __restrict__ pos) {
    size_t idx = (size_t)blockIdx.x * 256 + threadIdx.x;
    if (idx >= (size_t)ML * EV) return;
    int e = idx % EV;
    size_t t = idx / EV;
    int l = (int)(t % LV);
    int b = (int)(t / LV);
    float v;
    if (l == 0) v = cls[e] + pos[e];
    else        v = g_hn[((size_t)b * NP + (l - 1)) * EV + e] + pos[(size_t)l * EV + e];
    g_h[idx] = v;
}

template<int HOUT>
__global__ void layernorm_kernel(const float* __restrict__ x, const float* __restrict__ g,
                                 const float* __restrict__ bta, float* __restrict__ y,
                                 fp16* __restrict__ yf)
{
    int row = blockIdx.x;
    const float* xr = x + (size_t)row * EV;
    int tid = threadIdx.x;
    float v0 = xr[tid], v1 = xr[tid + 256], v2 = xr[tid + 512];
    float s = v0 + v1 + v2;
    float s2 = v0 * v0 + v1 * v1 + v2 * v2;
    __shared__ float shA[8], shB[8];
    float ws = warpSum(s), ws2 = warpSum(s2);
    int lane = tid & 31, wid = tid >> 5;
    if (lane == 0) { shA[wid] = ws; shB[wid] = ws2; }
    __syncthreads();
    if (tid == 0) {
        float a = 0, bb = 0;
        #pragma unroll
        for (int i = 0; i < 8; ++i) { a += shA[i]; bb += shB[i]; }
        shA[0] = a; shB[0] = bb;
    }
    __syncthreads();
    float mu = shA[0] * (1.f / 768.f);
    float var = shB[0] * (1.f / 768.f) - mu * mu;
    float inv = rsqrtf(var + 1e-5f);
    float o[3] = {v0, v1, v2};
    #pragma unroll
    for (int u = 0; u < 3; ++u) {
        int e = tid + u * 256;
        float c = (o[u] - mu) * inv * g[e] + bta[e];
        if (HOUT) yf[(size_t)row * EV + e] = __float2half_rn(c);
        else      y[(size_t)row * EV + e] = c;
    }
}

__global__ void combine_kernel()
{
    int idx = blockIdx.x * 4 + (threadIdx.x >> 6);
    int d = threadIdx.x & 63;
    int hd = idx % HH;
    int p = (idx / HH) % LV;
    int b = idx / (HH * LV);
    if (b >= BV) return;
    const int ws[5] = {768, 1536, 3072, 6144, 12288};
    const int rs[5] = {1, 2, 4, 8, 16};
    const int gs[5] = {12, 6, 3, 2, 1};
    const int ns[5] = {5, 3, 2, 1, 1};
    const int ub[5] = {0, 120, 192, 240, 264};
    float lses[5];
    size_t oix[5];
    bool cov[5];
    float mx = -1e30f;
    #pragma unroll
    for (int br = 0; br < 5; ++br) {
        int seg = p / ws[br];
        int jj = p - seg * ws[br];
        int off = hd / gs[br];
        int rr = jj & (rs[br] - 1);
        cov[br] = (rr == off);
        if (cov[br]) {
            int j = jj / rs[br];
            int unit = ub[br] + (b * ns[br] + seg) * HH + hd;
            lses[br] = g_lse[(size_t)unit * 768 + j];
            oix[br] = (size_t)unit * 49152 + (size_t)j * 64;
            mx = fmaxf(mx, lses[br]);
        }
    }
    float sw = 0.f, out = 0.f;
    #pragma unroll
    for (int br = 0; br < 5; ++br) {
        if (cov[br]) {
            float wgt = __expf(lses[br] - mx);
            sw += wgt;
            out += wgt * __half2float(g_obr[oix[br] + d]);
        }
    }
    g_o[((size_t)(b * LV + p)) * EV + hd * DHv + d] = __float2half_rn(out / sw);
}

__global__ void head_kernel(const float* __restrict__ hn, const float* __restrict__ W,
                            const float* __restrict__ bias, float* __restrict__ out)
{
    int nidx = blockIdx.x * blockDim.x + threadIdx.x;
    int b = blockIdx.y;
    if (nidx >= 1000) return;
    const float* row = hn + (size_t)b * LV * EV;
    float acc = bias[nidx];
    for (int e = 0; e < EV; ++e) acc = fmaf(row[e], W[(size_t)e * 1000 + nidx], acc);
    out[b * 1000 + nidx] = acc;
}

// transpose all of one layer's 1-pass weights (hi only): 6912 tiles of 32x32
__global__ void transT_all(const float* __restrict__ wq, const float* __restrict__ wk,
                           const float* __restrict__ wv, const float* __restrict__ wo,
                           const float* __restrict__ w1, const float* __restrict__ w2,
                           fp16* __restrict__ dst)
{
    int tile = blockIdx.x;
    const float* src;
    int K, N, kb, nb;
    size_t doff;
    if (tile < 2304) {
        int wsel = tile / 576, tt = tile % 576;
        src = (wsel == 0) ? wq : (wsel == 1) ? wk : (wsel == 2) ? wv : wo;
        K = 768; N = 768; doff = (size_t)wsel * 589824;
        kb = (tt % 24) * 32; nb = (tt / 24) * 32;
    } else if (tile < 4608) {
        int tt = tile - 2304;
        src = w1; K = 768; N = 3072; doff = 2359296;
        kb = (tt % 24) * 32; nb = (tt / 24) * 32;
    } else {
        int tt = tile - 4608;
        src = w2; K = 3072; N = 768; doff = 4718592;
        kb = (tt % 96) * 32; nb = (tt / 96) * 32;
    }
    __shared__ float t[32][33];
    int x = threadIdx.x, y = threadIdx.y;
    #pragma unroll
    for (int i = 0; i < 32; i += 8)
        t[y + i][x] = src[(size_t)(kb + y + i) * N + nb + x];
    __syncthreads();
    #pragma unroll
    for (int i = 0; i < 32; i += 8)
        dst[doff + (size_t)(nb + y + i) * K + kb + x] = __float2half_rn(t[x][y + i]);
}

__global__ void split_copy(const float* __restrict__ s, fp16* __restrict__ oh,
                           fp16* __restrict__ ol, long n)
{
    long i = ((long)blockIdx.x * 256 + threadIdx.x) * 4;
    if (i >= n) return;
    float4 v = *(const float4*)(s + i);
    float vv[4] = {v.x, v.y, v.z, v.w};
    #pragma unroll
    for (int u = 0; u < 4; ++u) {
        fp16 h = __float2half_rn(vv[u]);
        oh[i + u] = h;
        ol[i + u] = __float2half_rn(vv[u] - __half2float(h));
    }
}

__global__ void pack_bias(const float* __restrict__ bq, const float* __restrict__ bk,
                          const float* __restrict__ bv)
{
    int i = blockIdx.x * 256 + threadIdx.x;
    if (i >= 2 * QKVS) return;
    int l = i / QKVS, e = i % QKVS;
    float v;
    if (e < 768)       v = bq[l * EV + e];
    else if (e < 1536) v = bk[l * EV + e - 768];
    else               v = bv[l * EV + e - 1536];
    g_bqkv[i] = v;
}

// ---------------- host orchestration ------------------------------------------
extern "C" void kernel_launch(void* const* d_in, const int* in_sizes, int n_in,
                              void* d_out, int out_size)
{
    (void)in_sizes; (void)n_in; (void)out_size;
    const float* x        = (const float*)d_in[0];
    const float* patch_w  = (const float*)d_in[1];
    const float* patch_b  = (const float*)d_in[2];
    const float* cls_tok  = (const float*)d_in[3];
    const float* pos_emb  = (const float*)d_in[4];
    const float* ln1_g    = (const float*)d_in[5];
    const float* ln1_b    = (const float*)d_in[6];
    const float* wq       = (const float*)d_in[7];
    const float* bq       = (const float*)d_in[8];
    const float* wk       = (const float*)d_in[9];
    const float* bk       = (const float*)d_in[10];
    const float* wv       = (const float*)d_in[11];
    const float* bv_      = (const float*)d_in[12];
    const float* wo       = (const float*)d_in[13];
    const float* bo       = (const float*)d_in[14];
    const float* ln2_g    = (const float*)d_in[15];
    const float* ln2_b    = (const float*)d_in[16];
    const float* w1       = (const float*)d_in[17];
    const float* b1       = (const float*)d_in[18];
    const float* w2       = (const float*)d_in[19];
    const float* b2       = (const float*)d_in[20];
    const float* normf_g  = (const float*)d_in[21];
    const float* normf_b  = (const float*)d_in[22];
    const float* head_w   = (const float*)d_in[23];
    const float* head_b   = (const float*)d_in[24];
    float* out = (float*)d_out;

    float *p_h, *p_hn, *p_bqkv;
    fp16 *p_col, *p_x, *p_qkv, *p_m1, *p_o, *p_wh, *p_wl;
    cudaGetSymbolAddress((void**)&p_h, g_h);
    cudaGetSymbolAddress((void**)&p_hn, g_hn);
    cudaGetSymbolAddress((void**)&p_bqkv, g_bqkv);
    cudaGetSymbolAddress((void**)&p_col, g_col);
    cudaGetSymbolAddress((void**)&p_x, g_x);
    cudaGetSymbolAddress((void**)&p_qkv, g_qkv);
    cudaGetSymbolAddress((void**)&p_m1, g_m1);
    cudaGetSymbolAddress((void**)&p_o, g_o);
    cudaGetSymbolAddress((void**)&p_wh, g_wh);
    cudaGetSymbolAddress((void**)&p_wl, g_wl);

    const int SM2 = HGC<2>::SMEM;
    const int SM1 = HGC<1>::SMEM;
    cudaFuncSetAttribute(hgemm<0,0,2,0>, cudaFuncAttributeMaxDynamicSharedMemorySize, SM2);
    cudaFuncSetAttribute(hgemm<0,1,1,1>, cudaFuncAttributeMaxDynamicSharedMemorySize, SM1);
    cudaFuncSetAttribute(hgemm<0,0,1,0>, cudaFuncAttributeMaxDynamicSharedMemorySize, SM1);
    cudaFuncSetAttribute(hgemm<1,1,1,0>, cudaFuncAttributeMaxDynamicSharedMemorySize, SM1);
    cudaFuncSetAttribute(fattn, cudaFuncAttributeMaxDynamicSharedMemorySize, FA_SMEM);

    // ---- prep (launch #5 = patch hgemm, for ncu capture) -----------------------
    const size_t LSZ = 7077888;
    dim3 blk(32, 8);
    {
        long n = 786432;
        split_copy<<<(int)((n/4 + 255) / 256), 256>>>(patch_w, p_wh, p_wl, n);       // 1
    }
    im2col_half<<<(BV * NP * 1024 + 255) / 256, 256>>>(x);                           // 2
    pack_bias<<<(2 * QKVS + 255) / 256, 256>>>(bq, bk, bv_);                         // 3
    transT_all<<<6912, blk>>>(wq, wk, wv, wo, w1, w2, p_wh + 786432);                // 4
    hgemm<0,0,2,0><<<dim3(48, 6), 256, SM2>>>(p_col, p_wh, p_wl,
                                              patch_b, nullptr, p_hn, nullptr,
                                              BV * NP, EV, 1024);                    // 5 <- profiled
    transT_all<<<6912, blk>>>(wq + 589824, wk + 589824, wv + 589824, wo + 589824,
                              w1 + 2359296, w2 + 2359296, p_wh + 786432 + LSZ);      // 6
    assemble_kernel<<<(int)(((size_t)ML * EV + 255) / 256), 256>>>(cls_tok, pos_emb);

    dim3 gEEt(49, 6);
    dim3 gQKV(49, 18);
    dim3 gE4t(49, 24);

    for (int layer = 0; layer < 2; ++layer) {
        size_t base = 786432 + (size_t)layer * LSZ;
        size_t oE  = (size_t)layer * EV;
        size_t o4  = (size_t)layer * 3072;

        layernorm_kernel<1><<<ML, 256>>>(p_h, ln1_g + oE, ln1_b + oE, nullptr, p_x);
        hgemm<0,1,1,1><<<gQKV, 256, SM1>>>(p_x, p_wh + base, p_wl,
                                           p_bqkv + layer * QKVS, nullptr, nullptr, p_qkv,
                                           ML, QKVS, EV);

        fattn<<<dim3(6, 288), 256, FA_SMEM>>>(p_qkv, layer);
        combine_kernel<<<(BV * LV * HH + 3) / 4, 256>>>();

        hgemm<0,0,1,0><<<gEEt, 256, SM1>>>(p_o, p_wh + base + 1769472, p_wl, bo + oE, p_h, p_h, nullptr, ML, EV, EV);

        layernorm_kernel<1><<<ML, 256>>>(p_h, ln2_g + oE, ln2_b + oE, nullptr, p_x);
        hgemm<1,1,1,0><<<gE4t, 256, SM1>>>(p_x, p_wh + base + 2359296, p_wl, b1 + o4, nullptr, nullptr, p_m1, ML, 3072, EV);
        hgemm<0,0,1,0><<<gEEt, 256, SM1>>>(p_m1, p_wh + base + 4718592, p_wl, b2 + oE, p_h, p_h, nullptr, ML, EV, 3072);
    }

    layernorm_kernel<0><<<ML, 256>>>(p_h, normf_g, normf_b, p_hn, nullptr);
    head_kernel<<<dim3(4, BV), 256>>>(p_hn, head_w, head_b, out);
}

// round 15
// speedup vs baseline: 12.2827x; 1.0142x over previous
#include <cuda_runtime.h>
#include <cuda_fp16.h>
#include <math.h>
#include <stdint.h>

#define BV 2
#define LV 3073
#define EV 768
#define HH 12
#define DHv 64
#define ML (BV*LV)          // 6146 rows
#define NP 3072             // patches per batch
#define QKVS 2304           // fused qkv row stride
#define LOG2E 1.4426950408889634f

typedef __half fp16;

// ---------------- scratch (device globals) -----------------------------------
__device__ float g_h  [(size_t)ML*EV];
__device__ float g_hn [(size_t)ML*EV];
__device__ __align__(16) fp16 g_obr[(size_t)288*768*64];
__device__ float g_lse[(size_t)288*768];
__device__ float g_bqkv[2*QKVS];
__device__ __align__(16) fp16 g_col[(size_t)BV*NP*1024];
__device__ __align__(16) fp16 g_x  [(size_t)ML*EV];
__device__ __align__(16) fp16 g_qkv[(size_t)ML*QKVS];
__device__ __align__(16) fp16 g_m1 [(size_t)ML*3072];
__device__ __align__(16) fp16 g_o  [(size_t)ML*EV];
#define WTOT 14942208
__device__ __align__(16) fp16 g_wh[WTOT];
__device__ __align__(16) fp16 g_wl[WTOT];   // only patch region used (2-pass)

// ---------------- helpers -----------------------------------------------------
__device__ __forceinline__ float geluf(float v) {
    return 0.5f * v * (1.f + erff(v * 0.70710678118654752f));
}
__device__ __forceinline__ uint32_t s2u(const void* p) {
    uint32_t a;
    asm("{ .reg .u64 t; cvta.to.shared.u64 t, %1; cvt.u32.u64 %0, t; }" : "=r"(a) : "l"(p));
    return a;
}
__device__ __forceinline__ void cpa16(uint32_t saddr, const void* g, int sz) {
    asm volatile("cp.async.cg.shared.global [%0], [%1], 16, %2;"
                 :: "r"(saddr), "l"(g), "r"(sz) : "memory");
}
__device__ __forceinline__ void mma16816(float* d, const uint32_t* a, uint32_t b0, uint32_t b1) {
    asm volatile("mma.sync.aligned.m16n8k16.row.col.f32.f16.f16.f32 "
                 "{%0,%1,%2,%3},{%4,%5,%6,%7},{%8,%9},{%0,%1,%2,%3};"
                 : "+f"(d[0]), "+f"(d[1]), "+f"(d[2]), "+f"(d[3])
                 : "r"(a[0]), "r"(a[1]), "r"(a[2]), "r"(a[3]), "r"(b0), "r"(b1));
}
__device__ __forceinline__ void ldsm4(uint32_t& r0, uint32_t& r1, uint32_t& r2, uint32_t& r3,
                                      uint32_t saddr) {
    asm volatile("ldmatrix.sync.aligned.m8n8.x4.shared.b16 {%0,%1,%2,%3}, [%4];"
                 : "=r"(r0), "=r"(r1), "=r"(r2), "=r"(r3) : "r"(saddr));
}
__device__ __forceinline__ void ldsm4t(uint32_t& r0, uint32_t& r1, uint32_t& r2, uint32_t& r3,
                                       uint32_t saddr) {
    asm volatile("ldmatrix.sync.aligned.m8n8.x4.trans.shared.b16 {%0,%1,%2,%3}, [%4];"
                 : "=r"(r0), "=r"(r1), "=r"(r2), "=r"(r3) : "r"(saddr));
}
__device__ __forceinline__ uint32_t h2u(float c0, float c1) {
    __half2 h = __floats2half2_rn(c0, c1);
    return *(uint32_t*)&h;
}
__device__ __forceinline__ uint32_t ex2h2(float c0, float c1) {
    uint32_t x = h2u(c0, c1), r;
    asm("ex2.approx.f16x2 %0, %1;" : "=r"(r) : "r"(x));
    return r;
}

// ---------------- fp16 tensor-core GEMM (mma.sync + ldmatrix) -----------------
// NPASS==1: K-chunk 64, 3-stage pipeline. NPASS==2: K-chunk 32, 2-stage.
template<int NPASS> struct HGC {
    static constexpr int KCH  = (NPASS == 1) ? 64 : 32;
    static constexpr int STR  = KCH + 8;
    static constexpr int MATH = 128 * STR;
    static constexpr int BUFH = (1 + NPASS) * MATH;
    static constexpr int NST  = (NPASS == 1) ? 3 : 2;
    static constexpr int SMEM = NST * BUFH * 2;
};

template<int ACT, int OUT, int NPASS, int QSCALE, int POSE>
__global__ void __launch_bounds__(256, 2)
hgemm(const fp16* __restrict__ A, const fp16* __restrict__ Bh, const fp16* __restrict__ Bl,
      const float* __restrict__ bias, const float* __restrict__ res,
      float* __restrict__ C, fp16* __restrict__ Cf, int M, int N, int K)
{
    constexpr int NMAT = 1 + NPASS;
    constexpr int KCH  = HGC<NPASS>::KCH;
    constexpr int STR  = HGC<NPASS>::STR;
    constexpr int MATH = HGC<NPASS>::MATH;
    constexpr int BUFH = HGC<NPASS>::BUFH;
    constexpr int NST  = HGC<NPASS>::NST;
    constexpr int GPR  = KCH / 8;
    constexpr int ITER = 128 * GPR / 256;
    extern __shared__ fp16 sm[];
    const int tid = threadIdx.x, wid = tid >> 5, lane = tid & 31;
    const int m0 = blockIdx.x * 128, n0 = blockIdx.y * 128;
    const int g = lane >> 2, t = lane & 3;
    const int wm0 = (wid >> 1) * 32, wn0 = (wid & 1) * 64;
    const uint32_t smbase = s2u(sm);
    const fp16* srcs[3] = {A, Bh, Bl};
    const int arow8 = ((lane >> 3) & 1) * 8 + (lane & 7);
    const int acol8 = (lane >> 4) * 8;
    const int bnf   = lane >> 4;
    const int brow  = lane & 7;
    const int bcol8 = ((lane >> 3) & 1) * 8;

    float acc[2][8][4];
    #pragma unroll
    for (int i = 0; i < 2; ++i)
        #pragma unroll
        for (int j = 0; j < 8; ++j)
            #pragma unroll
            for (int u = 0; u < 4; ++u) acc[i][j][u] = 0.f;

    const int KC = K / KCH;

    auto issue = [&](int c, int buf) {
        int k0 = c * KCH;
        #pragma unroll
        for (int mat = 0; mat < NMAT; ++mat) {
            #pragma unroll
            for (int it = 0; it < ITER; ++it) {
                int idx = it * 256 + tid;
                int row = idx / GPR, q8 = idx % GPR;
                int grow = (mat == 0) ? (m0 + row) : (n0 + row);
                bool ok = (mat > 0) || (grow < M);
                const fp16* gp = ok ? (srcs[mat] + (size_t)grow * K + k0 + q8 * 8) : srcs[mat];
                uint32_t sa = smbase + (uint32_t)(buf * BUFH + mat * MATH + row * STR + q8 * 8) * 2;
                cpa16(sa, gp, ok ? 16 : 0);
            }
        }
        asm volatile("cp.async.commit_group;" ::: "memory");
    };

    issue(0, 0);
    if (NST == 3 && KC > 1) issue(1, 1);
    int bufc = 0;
    for (int c = 0; c < KC; ++c) {
        if (NST == 3) {
            if (c + 2 < KC) {
                int nb = bufc + 2; if (nb >= 3) nb -= 3;
                issue(c + 2, nb);
                asm volatile("cp.async.wait_group 2;" ::: "memory");
            } else if (c + 1 < KC) {
                asm volatile("cp.async.wait_group 1;" ::: "memory");
            } else {
                asm volatile("cp.async.wait_group 0;" ::: "memory");
            }
        } else {
            if (c + 1 < KC) {
                issue(c + 1, bufc ^ 1);
                asm volatile("cp.async.wait_group 1;" ::: "memory");
            } else {
                asm volatile("cp.async.wait_group 0;" ::: "memory");
            }
        }
        __syncthreads();
        const uint32_t bufoff = (uint32_t)bufc * BUFH;
        #pragma unroll
        for (int ks = 0; ks < KCH; ks += 16) {
            uint32_t afr[2][4];
            #pragma unroll
            for (int mf = 0; mf < 2; ++mf) {
                uint32_t addr = smbase + (bufoff + (uint32_t)((wm0 + mf * 16 + arow8) * STR + ks + acol8)) * 2;
                ldsm4(afr[mf][0], afr[mf][1], afr[mf][2], afr[mf][3], addr);
            }
            #pragma unroll
            for (int p = 0; p < 8; p += 2) {
                uint32_t b0, b1, b2, b3;
                uint32_t baddr = smbase + (bufoff + (uint32_t)(MATH + (wn0 + (p + bnf) * 8 + brow) * STR + ks + bcol8)) * 2;
                ldsm4(b0, b1, b2, b3, baddr);
                #pragma unroll
                for (int mf = 0; mf < 2; ++mf) {
                    mma16816(acc[mf][p],     afr[mf], b0, b1);
                    mma16816(acc[mf][p + 1], afr[mf], b2, b3);
                }
                if (NPASS == 2) {
                    uint32_t l0, l1, l2, l3;
                    ldsm4(l0, l1, l2, l3, baddr + MATH * 2);
                    #pragma unroll
                    for (int mf = 0; mf < 2; ++mf) {
                        mma16816(acc[mf][p],     afr[mf], l0, l1);
                        mma16816(acc[mf][p + 1], afr[mf], l2, l3);
                    }
                }
            }
        }
        bufc = (bufc + 1 == NST) ? 0 : bufc + 1;
        __syncthreads();
    }

    #pragma unroll
    for (int mf = 0; mf < 2; ++mf) {
        #pragma unroll
        for (int rr = 0; rr < 2; ++rr) {
            int row = m0 + wm0 + mf * 16 + g + rr * 8;
            if (row >= M) continue;
            #pragma unroll
            for (int nf = 0; nf < 8; ++nf) {
                int col = n0 + wn0 + nf * 8 + 2 * t;
                float c0 = acc[mf][nf][rr * 2 + 0] + bias[col];
                float c1 = acc[mf][nf][rr * 2 + 1] + bias[col + 1];
                if (ACT) { c0 = geluf(c0); c1 = geluf(c1); }
                if (QSCALE && col < 768) { c0 *= 0.125f; c1 *= 0.125f; }
                if (OUT == 1) {
                    __half2 h = __floats2half2_rn(c0, c1);
                    *(__half2*)(Cf + (size_t)row * N + col) = h;
                } else if (POSE) {
                    // res = pos_embed base; row remap (b,p) -> b*LV + 1 + p
                    int bI = row / NP, pI = row - bI * NP;
                    size_t hrow = (size_t)bI * LV + 1 + pI;
                    c0 += res[(size_t)(1 + pI) * EV + col];
                    c1 += res[(size_t)(1 + pI) * EV + col + 1];
                    *(float2*)(C + hrow * EV + col) = make_float2(c0, c1);
                } else {
                    if (res) {
                        c0 += res[(size_t)row * N + col];
                        c1 += res[(size_t)row * N + col + 1];
                    }
                    *(float2*)(C + (size_t)row * N + col) = make_float2(c0, c1);
                }
            }
        }
    }
}

// ---------------- fused flash attention — 64-key chunks, occupancy 2 ---------
#define FA_STR 72
#define FA_Q 0
#define FA_K(b)  (9216 + (b)*4608)
#define FA_V(b)  (18432 + (b)*4608)
#define FA_SMEM (27648*2)

__global__ void __launch_bounds__(256, 2)
fattn(const fp16* __restrict__ qkv, int layer_unused)
{
    const int wsA[5] = {768, 1536, 3072, 6144, 12288};
    const int rsA[5] = {1, 2, 4, 8, 16};
    const int gsA[5] = {12, 6, 3, 2, 1};
    const int nsA[5] = {5, 3, 2, 1, 1};
    const int ubA[5] = {0, 120, 192, 240, 264};

    extern __shared__ fp16 sm[];
    const int tid = threadIdx.x, wid = tid >> 5, lane = tid & 31;
    const int g = lane >> 2, t = lane & 3;
    int gu = blockIdx.y;
    int br = (gu >= 264) ? 4 : (gu >= 240) ? 3 : (gu >= 192) ? 2 : (gu >= 120) ? 1 : 0;
    int z = gu - ubA[br];
    int w = wsA[br], r = rsA[br], gsz = gsA[br], n = nsA[br];
    int hd = z % HH;
    int seg = (z / HH) % n;
    int bb_ = z / (HH * n);
    int off = hd / gsz;
    int m0 = blockIdx.x * 128;
    const uint32_t smb = s2u(sm);
    const int arow8 = ((lane >> 3) & 1) * 8 + (lane & 7);
    const int acol8 = (lane >> 4) * 8;
    const int bnf   = lane >> 4;
    const int brow  = lane & 7;
    const int bcol8 = ((lane >> 3) & 1) * 8;
    const int vrow  = lane & 15;
    const int vcol  = lane >> 4;
    const fp16* q = qkv;
    const fp16* k = qkv + 768;
    const fp16* v = qkv + 1536;

    auto kv_issue = [&](int kt, int buf) {
        int n0 = kt * 64;
        #pragma unroll
        for (int it = 0; it < 2; ++it) {
            int idx = it * 256 + tid;
            int row = idx >> 3, q8 = idx & 7;
            int pos = seg * w + (n0 + row) * r + off;
            bool ok = pos < LV;
            const fp16* gpk = ok ? (k + ((size_t)(bb_ * LV) + pos) * QKVS + hd * DHv + q8 * 8) : k;
            cpa16(smb + (uint32_t)(FA_K(buf) + row * FA_STR + q8 * 8) * 2, gpk, ok ? 16 : 0);
            const fp16* gpv = ok ? (v + ((size_t)(bb_ * LV) + pos) * QKVS + hd * DHv + q8 * 8) : v;
            cpa16(smb + (uint32_t)(FA_V(buf) + row * FA_STR + q8 * 8) * 2, gpv, ok ? 16 : 0);
        }
        asm volatile("cp.async.commit_group;" ::: "memory");
    };

    // prologue: Q + chunk 0
    #pragma unroll
    for (int it = 0; it < 4; ++it) {
        int idx = it * 256 + tid;
        int row = idx >> 3, q8 = idx & 7;
        int pos = seg * w + (m0 + row) * r + off;
        bool ok = pos < LV;
        const fp16* gp = ok ? (q + ((size_t)(bb_ * LV) + pos) * QKVS + hd * DHv + q8 * 8) : q;
        cpa16(smb + (uint32_t)(FA_Q + row * FA_STR + q8 * 8) * 2, gp, ok ? 16 : 0);
    }
    kv_issue(0, 0);
    asm volatile("cp.async.wait_group 0;" ::: "memory");
    __syncthreads();

    uint32_t qfr[4][4];
    #pragma unroll
    for (int k4 = 0; k4 < 4; ++k4) {
        uint32_t addr = smb + (uint32_t)(FA_Q + (wid * 16 + arow8) * FA_STR + k4 * 16 + acol8) * 2;
        ldsm4(qfr[k4][0], qfr[k4][1], qfr[k4][2], qfr[k4][3], addr);
    }

    float m_[2] = {-1e30f, -1e30f};
    float l_[2] = {0.f, 0.f};
    float acco[8][4];
    #pragma unroll
    for (int j = 0; j < 8; ++j)
        #pragma unroll
        for (int u = 0; u < 4; ++u) acco[j][u] = 0.f;

    for (int kt = 0; kt < 12; ++kt) {
        int buf = kt & 1;
        if (kt < 11) kv_issue(kt + 1, buf ^ 1);

        // S = Q K^T over 64 keys
        float accs[8][4];
        #pragma unroll
        for (int j = 0; j < 8; ++j)
            #pragma unroll
            for (int u = 0; u < 4; ++u) accs[j][u] = 0.f;
        #pragma unroll
        for (int k4 = 0; k4 < 4; ++k4) {
            #pragma unroll
            for (int p = 0; p < 8; p += 2) {
                uint32_t b0, b1, b2, b3;
                uint32_t addr = smb + (uint32_t)(FA_K(buf) + ((p + bnf) * 8 + brow) * FA_STR + k4 * 16 + bcol8) * 2;
                ldsm4(b0, b1, b2, b3, addr);
                mma16816(accs[p],     qfr[k4], b0, b1);
                mma16816(accs[p + 1], qfr[k4], b2, b3);
            }
        }

        // online softmax (fp16x2 MUFU exp)
        float mx0 = -1e30f, mx1 = -1e30f;
        #pragma unroll
        for (int nf = 0; nf < 8; ++nf) {
            mx0 = fmaxf(mx0, fmaxf(accs[nf][0], accs[nf][1]));
            mx1 = fmaxf(mx1, fmaxf(accs[nf][2], accs[nf][3]));
        }
        mx0 = fmaxf(mx0, __shfl_xor_sync(0xffffffffu, mx0, 1));
        mx0 = fmaxf(mx0, __shfl_xor_sync(0xffffffffu, mx0, 2));
        mx1 = fmaxf(mx1, __shfl_xor_sync(0xffffffffu, mx1, 1));
        mx1 = fmaxf(mx1, __shfl_xor_sync(0xffffffffu, mx1, 2));
        float mn0 = fmaxf(m_[0], mx0), mn1 = fmaxf(m_[1], mx1);
        float mnl0 = mn0 * LOG2E, mnl1 = mn1 * LOG2E;
        uint32_t pfr[8][2];
        float sum0 = 0.f, sum1 = 0.f;
        #pragma unroll
        for (int nf = 0; nf < 8; ++nf) {
            float t0 = fmaf(accs[nf][0], LOG2E, -mnl0);
            float t1 = fmaf(accs[nf][1], LOG2E, -mnl0);
            float t2 = fmaf(accs[nf][2], LOG2E, -mnl1);
            float t3 = fmaf(accs[nf][3], LOG2E, -mnl1);
            pfr[nf][0] = ex2h2(t0, t1);
            pfr[nf][1] = ex2h2(t2, t3);
            float2 f0 = __half22float2(*(__half2*)&pfr[nf][0]);
            float2 f1 = __half22float2(*(__half2*)&pfr[nf][1]);
            sum0 += f0.x + f0.y;
            sum1 += f1.x + f1.y;
        }
        sum0 += __shfl_xor_sync(0xffffffffu, sum0, 1);
        sum0 += __shfl_xor_sync(0xffffffffu, sum0, 2);
        sum1 += __shfl_xor_sync(0xffffffffu, sum1, 1);
        sum1 += __shfl_xor_sync(0xffffffffu, sum1, 2);
        float sc0 = __expf(m_[0] - mn0), sc1 = __expf(m_[1] - mn1);
        l_[0] = l_[0] * sc0 + sum0;
        l_[1] = l_[1] * sc1 + sum1;
        m_[0] = mn0; m_[1] = mn1;
        #pragma unroll
        for (int nf = 0; nf < 8; ++nf) {
            acco[nf][0] *= sc0; acco[nf][1] *= sc0;
            acco[nf][2] *= sc1; acco[nf][3] *= sc1;
        }

        // O += P V (ldmatrix.trans on row-major V)
        #pragma unroll
        for (int kb = 0; kb < 4; ++kb) {
            uint32_t a[4] = {pfr[2*kb][0], pfr[2*kb][1], pfr[2*kb+1][0], pfr[2*kb+1][1]};
            #pragma unroll
            for (int p = 0; p < 8; p += 2) {
                uint32_t b0, b1, b2, b3;
                uint32_t addr = smb + (uint32_t)(FA_V(buf) + (kb * 16 + vrow) * FA_STR + (p + vcol) * 8) * 2;
                ldsm4t(b0, b1, b2, b3, addr);
                mma16816(acco[p],     a, b0, b1);
                mma16816(acco[p + 1], a, b2, b3);
            }
        }

        if (kt < 11) {
            asm volatile("cp.async.wait_group 0;" ::: "memory");
            __syncthreads();
        }
    }

    float inv0 = 1.f / l_[0], inv1 = 1.f / l_[1];
    int row0 = m0 + wid * 16 + g;
    int row1 = row0 + 8;
    fp16* Op = g_obr + (size_t)gu * 49152;
    #pragma unroll
    for (int nf = 0; nf < 8; ++nf) {
        int col = nf * 8 + 2 * t;
        *(__half2*)(Op + (size_t)row0 * 64 + col) = __floats2half2_rn(acco[nf][0] * inv0, acco[nf][1] * inv0);
        *(__half2*)(Op + (size_t)row1 * 64 + col) = __floats2half2_rn(acco[nf][2] * inv1, acco[nf][3] * inv1);
    }
    if (t == 0) {
        g_lse[(size_t)gu * 768 + row0] = m_[0] + logf(l_[0]);
        g_lse[(size_t)gu * 768 + row1] = m_[1] + logf(l_[1]);
    }
}

// ---------------- misc kernels ------------------------------------------------
__global__ void im2col_half(const float* __restrict__ x) {
    int idx = blockIdx.x * 256 + threadIdx.x;
    if (idx >= BV * NP * 1024) return;
    int kk = idx & 1023;
    int p  = (idx >> 10) % NP;
    int b  = (idx >> 10) / NP;
    int pw_ = kk & 15, ph_ = (kk >> 4) & 15, pd_ = kk >> 8;
    int bz = p & 15, by = (p >> 4) & 15, bx = p >> 8;
    float v = x[(((size_t)b * 48 + bx * 4 + pd_) * 256 + by * 16 + ph_) * 256 + bz * 16 + pw_];
    g_col[idx] = __float2half_rn(v);
}

__global__ void cls_kernel(const float* __restrict__ cls, const float* __restrict__ pos) {
    int e = blockIdx.x * 256 + threadIdx.x;
    if (e >= EV) return;
    float v = cls[e] + pos[e];
    g_h[e] = v;
    g_h[(size_t)LV * EV + e] = v;
}

// warp-per-row layernorm: 8 rows per 256-thread block, shuffle-only reduction
template<int HOUT>
__global__ void layernorm_kernel(const float* __restrict__ x, const float* __restrict__ g,
                                 const float* __restrict__ bta, float* __restrict__ y,
                                 fp16* __restrict__ yf)
{
    int row = blockIdx.x * 8 + (threadIdx.x >> 5);
    if (row >= ML) return;
    int lane = threadIdx.x & 31;
    const float4* xr = (const float4*)(x + (size_t)row * EV);
    float4 v[6];
    float s = 0.f, s2 = 0.f;
    #pragma unroll
    for (int i = 0; i < 6; ++i) {
        v[i] = xr[lane + 32 * i];
        s  += v[i].x + v[i].y + v[i].z + v[i].w;
        s2 += v[i].x*v[i].x + v[i].y*v[i].y + v[i].z*v[i].z + v[i].w*v[i].w;
    }
    #pragma unroll
    for (int o = 16; o; o >>= 1) {
        s  += __shfl_xor_sync(0xffffffffu, s, o);
        s2 += __shfl_xor_sync(0xffffffffu, s2, o);
    }
    float mu = s * (1.f / 768.f);
    float var = s2 * (1.f / 768.f) - mu * mu;
    float inv = rsqrtf(var + 1e-5f);
    #pragma unroll
    for (int i = 0; i < 6; ++i) {
        int j = lane + 32 * i;
        float4 gg = ((const float4*)g)[j];
        float4 bb = ((const float4*)bta)[j];
        float c0 = (v[i].x - mu) * inv * gg.x + bb.x;
        float c1 = (v[i].y - mu) * inv * gg.y + bb.y;
        float c2 = (v[i].z - mu) * inv * gg.z + bb.z;
        float c3 = (v[i].w - mu) * inv * gg.w + bb.w;
        if (HOUT) {
            __half2* yp = (__half2*)(yf + (size_t)row * EV + 4 * j);
            yp[0] = __floats2half2_rn(c0, c1);
            yp[1] = __floats2half2_rn(c2, c3);
        } else {
            ((float4*)(y + (size_t)row * EV))[j] = make_float4(c0, c1, c2, c3);
        }
    }
}

__global__ void combine_kernel()
{
    int idx = blockIdx.x * 4 + (threadIdx.x >> 6);
    int d = threadIdx.x & 63;
    int hd = idx % HH;
    int p = (idx / HH) % LV;
    int b = idx / (HH * LV);
    if (b >= BV) return;
    const int ws[5] = {768, 1536, 3072, 6144, 12288};
    const int rs[5] = {1, 2, 4, 8, 16};
    const int gs[5] = {12, 6, 3, 2, 1};
    const int ns[5] = {5, 3, 2, 1, 1};
    const int ub[5] = {0, 120, 192, 240, 264};
    float lses[5];
    size_t oix[5];
    bool cov[5];
    float mx = -1e30f;
    #pragma unroll
    for (int br = 0; br < 5; ++br) {
        int seg = p / ws[br];
        int jj = p - seg * ws[br];
        int off = hd / gs[br];
        int rr = jj & (rs[br] - 1);
        cov[br] = (rr == off);
        if (cov[br]) {
            int j = jj / rs[br];
            int unit = ub[br] + (b * ns[br] + seg) * HH + hd;
            lses[br] = g_lse[(size_t)unit * 768 + j];
            oix[br] = (size_t)unit * 49152 + (size_t)j * 64;
            mx = fmaxf(mx, lses[br]);
        }
    }
    float sw = 0.f, out = 0.f;
    #pragma unroll
    for (int br = 0; br < 5; ++br) {
        if (cov[br]) {
            float wgt = __expf(lses[br] - mx);
            sw += wgt;
            out += wgt * __half2float(g_obr[oix[br] + d]);
        }
    }
    g_o[((size_t)(b * LV + p)) * EV + hd * DHv + d] = __float2half_rn(out / sw);
}

__global__ void head_kernel(const float* __restrict__ hn, const float* __restrict__ W,
                            const float* __restrict__ bias, float* __restrict__ out)
{
    int nidx = blockIdx.x * blockDim.x + threadIdx.x;
    int b = blockIdx.y;
    if (nidx >= 1000) return;
    const float* row = hn + (size_t)b * LV * EV;
    float acc = bias[nidx];
    for (int e = 0; e < EV; ++e) acc = fmaf(row[e], W[(size_t)e * 1000 + nidx], acc);
    out[b * 1000 + nidx] = acc;
}

// transpose all of one layer's 1-pass weights (hi only): 6912 tiles of 32x32
__global__ void transT_all(const float* __restrict__ wq, const float* __restrict__ wk,
                           const float* __restrict__ wv, const float* __restrict__ wo,
                           const float* __restrict__ w1, const float* __restrict__ w2,
                           fp16* __restrict__ dst)
{
    int tile = blockIdx.x;
    const float* src;
    int K, N, kb, nb;
    size_t doff;
    if (tile < 2304) {
        int wsel = tile / 576, tt = tile % 576;
        src = (wsel == 0) ? wq : (wsel == 1) ? wk : (wsel == 2) ? wv : wo;
        K = 768; N = 768; doff = (size_t)wsel * 589824;
        kb = (tt % 24) * 32; nb = (tt / 24) * 32;
    } else if (tile < 4608) {
        int tt = tile - 2304;
        src = w1; K = 768; N = 3072; doff = 2359296;
        kb = (tt % 24) * 32; nb = (tt / 24) * 32;
    } else {
        int tt = tile - 4608;
        src = w2; K = 3072; N = 768; doff = 4718592;
        kb = (tt % 96) * 32; nb = (tt / 96) * 32;
    }
    __shared__ float t[32][33];
    int x = threadIdx.x, y = threadIdx.y;
    #pragma unroll
    for (int i = 0; i < 32; i += 8)
        t[y + i][x] = src[(size_t)(kb + y + i) * N + nb + x];
    __syncthreads();
    #pragma unroll
    for (int i = 0; i < 32; i += 8)
        dst[doff + (size_t)(nb + y + i) * K + kb + x] = __float2half_rn(t[x][y + i]);
}

__global__ void split_copy(const float* __restrict__ s, fp16* __restrict__ oh,
                           fp16* __restrict__ ol, long n)
{
    long i = ((long)blockIdx.x * 256 + threadIdx.x) * 4;
    if (i >= n) return;
    float4 v = *(const float4*)(s + i);
    float vv[4] = {v.x, v.y, v.z, v.w};
    #pragma unroll
    for (int u = 0; u < 4; ++u) {
        fp16 h = __float2half_rn(vv[u]);
        oh[i + u] = h;
        ol[i + u] = __float2half_rn(vv[u] - __half2float(h));
    }
}

__global__ void pack_bias(const float* __restrict__ bq, const float* __restrict__ bk,
                          const float* __restrict__ bv)
{
    int i = blockIdx.x * 256 + threadIdx.x;
    if (i >= 2 * QKVS) return;
    int l = i / QKVS, e = i % QKVS;
    float v;
    if (e < 768)       v = bq[l * EV + e];
    else if (e < 1536) v = bk[l * EV + e - 768];
    else               v = bv[l * EV + e - 1536];
    g_bqkv[i] = v;
}

// ---------------- host orchestration ------------------------------------------
extern "C" void kernel_launch(void* const* d_in, const int* in_sizes, int n_in,
                              void* d_out, int out_size)
{
    (void)in_sizes; (void)n_in; (void)out_size;
    const float* x        = (const float*)d_in[0];
    const float* patch_w  = (const float*)d_in[1];
    const float* patch_b  = (const float*)d_in[2];
    const float* cls_tok  = (const float*)d_in[3];
    const float* pos_emb  = (const float*)d_in[4];
    const float* ln1_g    = (const float*)d_in[5];
    const float* ln1_b    = (const float*)d_in[6];
    const float* wq       = (const float*)d_in[7];
    const float* bq       = (const float*)d_in[8];
    const float* wk       = (const float*)d_in[9];
    const float* bk       = (const float*)d_in[10];
    const float* wv       = (const float*)d_in[11];
    const float* bv_      = (const float*)d_in[12];
    const float* wo       = (const float*)d_in[13];
    const float* bo       = (const float*)d_in[14];
    const float* ln2_g    = (const float*)d_in[15];
    const float* ln2_b    = (const float*)d_in[16];
    const float* w1       = (const float*)d_in[17];
    const float* b1       = (const float*)d_in[18];
    const float* w2       = (const float*)d_in[19];
    const float* b2       = (const float*)d_in[20];
    const float* normf_g  = (const float*)d_in[21];
    const float* normf_b  = (const float*)d_in[22];
    const float* head_w   = (const float*)d_in[23];
    const float* head_b   = (const float*)d_in[24];
    float* out = (float*)d_out;

    float *p_h, *p_hn, *p_bqkv;
    fp16 *p_col, *p_x, *p_qkv, *p_m1, *p_o, *p_wh, *p_wl;
    cudaGetSymbolAddress((void**)&p_h, g_h);
    cudaGetSymbolAddress((void**)&p_hn, g_hn);
    cudaGetSymbolAddress((void**)&p_bqkv, g_bqkv);
    cudaGetSymbolAddress((void**)&p_col, g_col);
    cudaGetSymbolAddress((void**)&p_x, g_x);
    cudaGetSymbolAddress((void**)&p_qkv, g_qkv);
    cudaGetSymbolAddress((void**)&p_m1, g_m1);
    cudaGetSymbolAddress((void**)&p_o, g_o);
    cudaGetSymbolAddress((void**)&p_wh, g_wh);
    cudaGetSymbolAddress((void**)&p_wl, g_wl);

    const int SM2 = HGC<2>::SMEM;
    const int SM1 = HGC<1>::SMEM;
    cudaFuncSetAttribute(hgemm<0,0,2,0,1>, cudaFuncAttributeMaxDynamicSharedMemorySize, SM2);
    cudaFuncSetAttribute(hgemm<0,1,1,1,0>, cudaFuncAttributeMaxDynamicSharedMemorySize, SM1);
    cudaFuncSetAttribute(hgemm<0,0,1,0,0>, cudaFuncAttributeMaxDynamicSharedMemorySize, SM1);
    cudaFuncSetAttribute(hgemm<1,1,1,0,0>, cudaFuncAttributeMaxDynamicSharedMemorySize, SM1);
    cudaFuncSetAttribute(fattn, cudaFuncAttributeMaxDynamicSharedMemorySize, FA_SMEM);

    // ---- prep (launch #5 = patch hgemm, for ncu capture) -----------------------
    const size_t LSZ = 7077888;
    dim3 blk(32, 8);
    {
        long n = 786432;
        split_copy<<<(int)((n/4 + 255) / 256), 256>>>(patch_w, p_wh, p_wl, n);       // 1
    }
    im2col_half<<<(BV * NP * 1024 + 255) / 256, 256>>>(x);                           // 2
    pack_bias<<<(2 * QKVS + 255) / 256, 256>>>(bq, bk, bv_);                         // 3
    transT_all<<<6912, blk>>>(wq, wk, wv, wo, w1, w2, p_wh + 786432);                // 4
    // patch embed fused with pos-embed scatter into g_h
    hgemm<0,0,2,0,1><<<dim3(48, 6), 256, SM2>>>(p_col, p_wh, p_wl,
                                                patch_b, pos_emb, p_h, nullptr,
                                                BV * NP, EV, 1024);                  // 5 <- profiled
    transT_all<<<6912, blk>>>(wq + 589824, wk + 589824, wv + 589824, wo + 589824,
                              w1 + 2359296, w2 + 2359296, p_wh + 786432 + LSZ);      // 6
    cls_kernel<<<3, 256>>>(cls_tok, pos_emb);

    dim3 gEEt(49, 6);
    dim3 gQKV(49, 18);
    dim3 gE4t(49, 24);
    const int LNG = (ML + 7) / 8;

    for (int layer = 0; layer < 2; ++layer) {
        size_t base = 786432 + (size_t)layer * LSZ;
        size_t oE  = (size_t)layer * EV;
        size_t o4  = (size_t)layer * 3072;

        layernorm_kernel<1><<<LNG, 256>>>(p_h, ln1_g + oE, ln1_b + oE, nullptr, p_x);
        hgemm<0,1,1,1,0><<<gQKV, 256, SM1>>>(p_x, p_wh + base, p_wl,
                                             p_bqkv + layer * QKVS, nullptr, nullptr, p_qkv,
                                             ML, QKVS, EV);

        fattn<<<dim3(6, 288), 256, FA_SMEM>>>(p_qkv, layer);
        combine_kernel<<<(BV * LV * HH + 3) / 4, 256>>>();

        hgemm<0,0,1,0,0><<<gEEt, 256, SM1>>>(p_o, p_wh + base + 1769472, p_wl, bo + oE, p_h, p_h, nullptr, ML, EV, EV);

        layernorm_kernel<1><<<LNG, 256>>>(p_h, ln2_g + oE, ln2_b + oE, nullptr, p_x);
        hgemm<1,1,1,0,0><<<gE4t, 256, SM1>>>(p_x, p_wh + base + 2359296, p_wl, b1 + o4, nullptr, nullptr, p_m1, ML, 3072, EV);
        hgemm<0,0,1,0,0><<<gEEt, 256, SM1>>>(p_m1, p_wh + base + 4718592, p_wl, b2 + oE, p_h, p_h, nullptr, ML, EV, 3072);
    }

    layernorm_kernel<0><<<LNG, 256>>>(p_h, normf_g, normf_b, p_hn, nullptr);
    head_kernel<<<dim3(4, BV), 256>>>(p_hn, head_w, head_b, out);
}